// round 2
// baseline (speedup 1.0000x reference)
#include <cuda_runtime.h>
#include <math.h>

#define N0 4096
#define KP1 3072
#define KP2 1536
#define KP3 768
#define H 200
#define HP 256

// ---------------- device scratch (static: no allocation allowed) ----------------
__device__ float g_G[(size_t)N0 * N0];       // augment scratch (reused at all levels)
__device__ float g_A1[(size_t)KP1 * KP1];
__device__ float g_A2[(size_t)KP2 * KP2];
__device__ float g_A3[(size_t)KP3 * KP3];
__device__ float g_x0[N0 * HP];
__device__ float g_x1[KP1 * HP];
__device__ float g_x2[KP2 * HP];
__device__ float g_x3[KP3 * HP];
__device__ float g_t0[N0 * HP];
__device__ float g_t1[N0 * HP];
__device__ float g_t2[N0 * HP];
__device__ float g_cur[N0 * HP];
__device__ float g_dinv[N0];
__device__ float g_score[N0];
__device__ float g_val[N0];
__device__ int   g_perm0[KP1];
__device__ int   g_perm1[KP2];
__device__ int   g_perm2[KP3];
__device__ float g_pnorm[1];

// ---------------- fast SGEMM: 128x128 block, 8x8 per thread, BK=8 ----------------
// Requires M%128==0, N%128==0, K%8==0, lda/ldb/ldc %4==0.
__global__ void __launch_bounds__(256) gemm128(
    const float* __restrict__ A, const float* __restrict__ B, float* __restrict__ C,
    int M, int N, int K, int lda, int ldb, int ldc)
{
    __shared__ float As[8][128];
    __shared__ float Bs[8][128];
    int tid = threadIdx.x;
    int bm = blockIdx.y * 128, bn = blockIdx.x * 128;
    int tx = tid & 15, ty = tid >> 4;

    float acc[8][8];
#pragma unroll
    for (int i = 0; i < 8; i++)
#pragma unroll
        for (int j = 0; j < 8; j++) acc[i][j] = 0.f;

    int arow = tid >> 1, acol = (tid & 1) * 4;
    int brow = tid >> 5, bcol = (tid & 31) * 4;
    const float* Aptr = A + (size_t)(bm + arow) * lda + acol;
    const float* Bptr = B + (size_t)brow * ldb + bn + bcol;

    for (int k0 = 0; k0 < K; k0 += 8) {
        float4 av = *(const float4*)(Aptr + k0);
        float4 bv = *(const float4*)(Bptr + (size_t)k0 * ldb);
        As[acol + 0][arow] = av.x;
        As[acol + 1][arow] = av.y;
        As[acol + 2][arow] = av.z;
        As[acol + 3][arow] = av.w;
        *(float4*)(&Bs[brow][bcol]) = bv;
        __syncthreads();
#pragma unroll
        for (int kk = 0; kk < 8; kk++) {
            float a0[4], a1[4], b0[4], b1[4];
            *(float4*)a0 = *(const float4*)(&As[kk][ty * 4]);
            *(float4*)a1 = *(const float4*)(&As[kk][64 + ty * 4]);
            *(float4*)b0 = *(const float4*)(&Bs[kk][tx * 4]);
            *(float4*)b1 = *(const float4*)(&Bs[kk][64 + tx * 4]);
#pragma unroll
            for (int i = 0; i < 4; i++)
#pragma unroll
                for (int j = 0; j < 4; j++) {
                    acc[i][j]         += a0[i] * b0[j];
                    acc[i][j + 4]     += a0[i] * b1[j];
                    acc[i + 4][j]     += a1[i] * b0[j];
                    acc[i + 4][j + 4] += a1[i] * b1[j];
                }
        }
        __syncthreads();
    }
#pragma unroll
    for (int i = 0; i < 4; i++) {
        float* c0 = C + (size_t)(bm + ty * 4 + i) * ldc + bn;
        *(float4*)(c0 + tx * 4)      = make_float4(acc[i][0], acc[i][1], acc[i][2], acc[i][3]);
        *(float4*)(c0 + 64 + tx * 4) = make_float4(acc[i][4], acc[i][5], acc[i][6], acc[i][7]);
        float* c1 = C + (size_t)(bm + 64 + ty * 4 + i) * ldc + bn;
        *(float4*)(c1 + tx * 4)      = make_float4(acc[i + 4][0], acc[i + 4][1], acc[i + 4][2], acc[i + 4][3]);
        *(float4*)(c1 + 64 + tx * 4) = make_float4(acc[i + 4][4], acc[i + 4][5], acc[i + 4][6], acc[i + 4][7]);
    }
}

// ---------------- generic SGEMM: 64x64 block, 4x4 per thread, bounds-checked ----------------
__global__ void __launch_bounds__(256) gemm64(
    const float* __restrict__ A, const float* __restrict__ B, float* __restrict__ C,
    int M, int N, int K, int lda, int ldb, int ldc)
{
    __shared__ float As[16][65];
    __shared__ float Bs[16][64];
    int tid = threadIdx.x, tx = tid & 15, ty = tid >> 4;
    int bm = blockIdx.y * 64, bn = blockIdx.x * 64;
    float acc[4][4];
#pragma unroll
    for (int i = 0; i < 4; i++)
#pragma unroll
        for (int j = 0; j < 4; j++) acc[i][j] = 0.f;

    for (int k0 = 0; k0 < K; k0 += 16) {
        for (int t = tid; t < 64 * 16; t += 256) {
            int r = t >> 4, c = t & 15;
            int gr = bm + r, gc = k0 + c;
            As[c][r] = (gr < M && gc < K) ? A[(size_t)gr * lda + gc] : 0.f;
        }
        for (int t = tid; t < 16 * 64; t += 256) {
            int r = t >> 6, c = t & 63;
            int gr = k0 + r, gc = bn + c;
            Bs[r][c] = (gr < K && gc < N) ? B[(size_t)gr * ldb + gc] : 0.f;
        }
        __syncthreads();
#pragma unroll
        for (int kk = 0; kk < 16; kk++) {
            float a[4], b[4];
#pragma unroll
            for (int i = 0; i < 4; i++) a[i] = As[kk][ty * 4 + i];
#pragma unroll
            for (int j = 0; j < 4; j++) b[j] = Bs[kk][tx * 4 + j];
#pragma unroll
            for (int i = 0; i < 4; i++)
#pragma unroll
                for (int j = 0; j < 4; j++) acc[i][j] += a[i] * b[j];
        }
        __syncthreads();
    }
#pragma unroll
    for (int i = 0; i < 4; i++)
#pragma unroll
        for (int j = 0; j < 4; j++) {
            int gr = bm + ty * 4 + i, gc = bn + tx * 4 + j;
            if (gr < M && gc < N) C[(size_t)gr * ldc + gc] = acc[i][j];
        }
}

// ---------------- small helper kernels ----------------
__global__ void rowsum_dinv(const float* __restrict__ A, float* __restrict__ dinv, int n)
{
    int row = blockIdx.x;
    const float* Ar = A + (size_t)row * n;
    float s = 0.f;
    for (int j = threadIdx.x; j < n; j += 256) s += Ar[j];
    for (int o = 16; o > 0; o >>= 1) s += __shfl_down_sync(0xffffffffu, s, o);
    __shared__ float red[8];
    int w = threadIdx.x >> 5, l = threadIdx.x & 31;
    if (l == 0) red[w] = s;
    __syncthreads();
    if (threadIdx.x == 0) {
        float t = 0.f;
        for (int i = 0; i < 8; i++) t += red[i];
        dinv[row] = 1.0f / sqrtf(t + 2.0f);   // Ah = A + 2I, diag(A)=0
    }
}

__global__ void scale_rows(const float* __restrict__ in, const float* __restrict__ dinv,
                           float* __restrict__ out, int n, int w, int ld)
{
    int idx = blockIdx.x * 256 + threadIdx.x;
    if (idx >= n * ld) return;
    int r = idx / ld, c = idx - r * ld;
    out[idx] = (c < w) ? dinv[r] * in[idx] : 0.f;
}

__global__ void gcn_finish(const float* __restrict__ AZ, const float* __restrict__ Z,
                           const float* __restrict__ dinv, const float* __restrict__ b,
                           float* __restrict__ out, int n, int relu)
{
    int idx = blockIdx.x * 256 + threadIdx.x;
    if (idx >= n * HP) return;
    int r = idx / HP, c = idx - r * HP;
    float v = 0.f;
    if (c < H) {
        v = dinv[r] * (AZ[idx] + 2.f * Z[idx]) + b[c];
        if (relu) v = fmaxf(v, 0.f);
    }
    out[idx] = v;
}

__global__ void pnorm_kernel(const float* __restrict__ p, float* __restrict__ out)
{
    float s = 0.f;
    for (int i = threadIdx.x; i < H; i += 256) { float v = p[i]; s += v * v; }
    for (int o = 16; o > 0; o >>= 1) s += __shfl_down_sync(0xffffffffu, s, o);
    __shared__ float red[8];
    int w = threadIdx.x >> 5, l = threadIdx.x & 31;
    if (l == 0) red[w] = s;
    __syncthreads();
    if (threadIdx.x == 0) {
        float t = 0.f;
        for (int i = 0; i < 8; i++) t += red[i];
        *out = sqrtf(t);
    }
}

__global__ void score_kernel(const float* __restrict__ x, const float* __restrict__ p,
                             const float* __restrict__ pn, float* __restrict__ score, int n)
{
    int row = blockIdx.x * 8 + (threadIdx.x >> 5);
    int lane = threadIdx.x & 31;
    if (row >= n) return;
    const float* xr = x + (size_t)row * HP;
    float s = 0.f;
    for (int c = lane; c < H; c += 32) s += xr[c] * p[c];
    for (int o = 16; o > 0; o >>= 1) s += __shfl_down_sync(0xffffffffu, s, o);
    if (lane == 0) score[row] = tanhf(s / (*pn));
}

// single-block bitonic top-k: descending score, ties -> smaller index first (matches jax top_k)
__global__ void topk_kernel(const float* __restrict__ score, int n, int k,
                            int* __restrict__ perm, float* __restrict__ val)
{
    __shared__ float ss[4096];
    __shared__ int   si[4096];
    int tid = threadIdx.x;
    for (int i = tid; i < 4096; i += 1024) {
        ss[i] = (i < n) ? score[i] : -INFINITY;
        si[i] = i;
    }
    __syncthreads();
    for (int size = 2; size <= 4096; size <<= 1) {
        for (int stride = size >> 1; stride > 0; stride >>= 1) {
            for (int i = tid; i < 4096; i += 1024) {
                int j = i ^ stride;
                if (j > i) {
                    float a = ss[i], b = ss[j];
                    int ia = si[i], ib = si[j];
                    bool bBetter = (b > a) || (b == a && ib < ia);
                    bool desc = ((i & size) == 0);
                    bool sw = desc ? bBetter : !bBetter;
                    if (sw) { ss[i] = b; ss[j] = a; si[i] = ib; si[j] = ia; }
                }
            }
            __syncthreads();
        }
    }
    for (int i = tid; i < k; i += 1024) { perm[i] = si[i]; val[i] = ss[i]; }
}

__global__ void aug_finish(float* __restrict__ G, const float* __restrict__ A, int n)
{
    int idx = blockIdx.x * 256 + threadIdx.x;
    if (idx >= n * n) return;
    int r = idx / n, c = idx - r * n;
    G[idx] = (r == c) ? 0.f : (G[idx] + 2.f * A[idx]);
}

__global__ void pool_A(const float* __restrict__ G, int ldg, const int* __restrict__ perm,
                       float* __restrict__ Aout, int k)
{
    int idx = blockIdx.x * 256 + threadIdx.x;
    if (idx >= k * k) return;
    int i = idx / k, j = idx - i * k;
    Aout[idx] = G[(size_t)perm[i] * ldg + perm[j]];
}

__global__ void pool_x(const float* __restrict__ xin, const int* __restrict__ perm,
                       const float* __restrict__ val, float* __restrict__ xout, int k)
{
    int idx = blockIdx.x * 256 + threadIdx.x;
    if (idx >= k * HP) return;
    int r = idx / HP, c = idx - r * HP;
    xout[idx] = xin[(size_t)perm[r] * HP + c] * val[r];
}

__global__ void scatter_add(float* __restrict__ dst, const float* __restrict__ x,
                            const int* __restrict__ perm, int k)
{
    int idx = blockIdx.x * 256 + threadIdx.x;
    if (idx >= k * HP) return;
    int r = idx / HP, c = idx - r * HP;
    dst[(size_t)perm[r] * HP + c] += x[idx];
}

// A(n x n) @ Z(n x 2), one block per row
__global__ void gemm_n2(const float* __restrict__ A, const float* __restrict__ Z,
                        float* __restrict__ out, int n)
{
    int row = blockIdx.x;
    const float* Ar = A + (size_t)row * n;
    float a0 = 0.f, a1 = 0.f;
    for (int j = threadIdx.x; j < n; j += 256) {
        float a = Ar[j];
        a0 += a * Z[2 * j];
        a1 += a * Z[2 * j + 1];
    }
    for (int o = 16; o > 0; o >>= 1) {
        a0 += __shfl_down_sync(0xffffffffu, a0, o);
        a1 += __shfl_down_sync(0xffffffffu, a1, o);
    }
    __shared__ float r0[8], r1[8];
    int w = threadIdx.x >> 5, l = threadIdx.x & 31;
    if (l == 0) { r0[w] = a0; r1[w] = a1; }
    __syncthreads();
    if (threadIdx.x == 0) {
        float s0 = 0.f, s1 = 0.f;
        for (int i = 0; i < 8; i++) { s0 += r0[i]; s1 += r1[i]; }
        out[2 * row] = s0;
        out[2 * row + 1] = s1;
    }
}

__global__ void final_kernel(const float* __restrict__ AZ, const float* __restrict__ Z,
                             const float* __restrict__ dinv, const float* __restrict__ b,
                             float* __restrict__ out, int n)
{
    int i = blockIdx.x * 256 + threadIdx.x;
    if (i >= n) return;
    float a = dinv[i] * (AZ[2 * i]     + 2.f * Z[2 * i])     + b[0];
    float c = dinv[i] * (AZ[2 * i + 1] + 2.f * Z[2 * i + 1]) + b[1];
    float m = fmaxf(a, c);
    float l = m + logf(expf(a - m) + expf(c - m));
    out[2 * i] = a - l;
    out[2 * i + 1] = c - l;
}

// ---------------- host orchestration ----------------
template <typename T, size_t NN>
static T* symaddr(T (&sym)[NN]) {
    void* p = nullptr;
    cudaGetSymbolAddress(&p, sym);
    return (T*)p;
}

static void run_gcn(const float* A, int n, const float* xin, int lda_x, int Kdim,
                    const float* W, const float* b, float* xout, int relu,
                    float* t0, float* t1, float* t2, float* dinv)
{
    dim3 g1((H + 63) / 64, (n + 63) / 64);
    gemm64<<<g1, 256>>>(xin, W, t0, n, H, Kdim, lda_x, H, HP);
    rowsum_dinv<<<n, 256>>>(A, dinv, n);
    int tot = n * HP;
    scale_rows<<<(tot + 255) / 256, 256>>>(t0, dinv, t1, n, H, HP);
    dim3 g2(HP / 128, n / 128);
    gemm128<<<g2, 256>>>(A, t1, t2, n, HP, n, n, HP, HP);
    gcn_finish<<<(tot + 255) / 256, 256>>>(t2, t1, dinv, b, xout, n, relu);
}

extern "C" void kernel_launch(void* const* d_in, const int* in_sizes, int n_in,
                              void* d_out, int out_size)
{
    (void)in_sizes; (void)n_in; (void)out_size;
    const float* x   = (const float*)d_in[0];
    const float* adj = (const float*)d_in[1];
    const float* w0  = (const float*)d_in[2];
    const float* b0  = (const float*)d_in[3];
    const float* w1  = (const float*)d_in[4];
    const float* b1  = (const float*)d_in[5];
    const float* w2  = (const float*)d_in[6];
    const float* b2  = (const float*)d_in[7];
    const float* w3  = (const float*)d_in[8];
    const float* b3  = (const float*)d_in[9];
    const float* p1  = (const float*)d_in[10];
    const float* p2  = (const float*)d_in[11];
    const float* p3  = (const float*)d_in[12];
    const float* u0w = (const float*)d_in[13];
    const float* u0b = (const float*)d_in[14];
    const float* u1w = (const float*)d_in[15];
    const float* u1b = (const float*)d_in[16];
    const float* u2w = (const float*)d_in[17];
    const float* u2b = (const float*)d_in[18];

    float* G    = symaddr(g_G);
    float* A1   = symaddr(g_A1);
    float* A2   = symaddr(g_A2);
    float* A3   = symaddr(g_A3);
    float* X0   = symaddr(g_x0);
    float* X1   = symaddr(g_x1);
    float* X2   = symaddr(g_x2);
    float* X3   = symaddr(g_x3);
    float* T0   = symaddr(g_t0);
    float* T1   = symaddr(g_t1);
    float* T2   = symaddr(g_t2);
    float* CUR  = symaddr(g_cur);
    float* DINV = symaddr(g_dinv);
    float* SC   = symaddr(g_score);
    float* VAL  = symaddr(g_val);
    int*   P0   = symaddr(g_perm0);
    int*   P1   = symaddr(g_perm1);
    int*   P2   = symaddr(g_perm2);
    float* PN   = symaddr(g_pnorm);

    // ---- down: gcn0 ----
    run_gcn(adj, N0, x, 3, 3, w0, b0, X0, 1, T0, T1, T2, DINV);

    // ---- pool 1 (4096 -> 3072) ----
    pnorm_kernel<<<1, 256>>>(p1, PN);
    score_kernel<<<(N0 + 7) / 8, 256>>>(X0, p1, PN, SC, N0);
    topk_kernel<<<1, 1024>>>(SC, N0, KP1, P0, VAL);
    {
        dim3 g(N0 / 128, N0 / 128);
        gemm128<<<g, 256>>>(adj, adj, G, N0, N0, N0, N0, N0, N0);
        aug_finish<<<(N0 * N0 + 255) / 256, 256>>>(G, adj, N0);
        pool_A<<<(KP1 * KP1 + 255) / 256, 256>>>(G, N0, P0, A1, KP1);
        pool_x<<<(KP1 * HP + 255) / 256, 256>>>(X0, P0, VAL, CUR, KP1);
    }
    run_gcn(A1, KP1, CUR, HP, H, w1, b1, X1, 1, T0, T1, T2, DINV);

    // ---- pool 2 (3072 -> 1536) ----
    pnorm_kernel<<<1, 256>>>(p2, PN);
    score_kernel<<<(KP1 + 7) / 8, 256>>>(X1, p2, PN, SC, KP1);
    topk_kernel<<<1, 1024>>>(SC, KP1, KP2, P1, VAL);
    {
        dim3 g(KP1 / 128, KP1 / 128);
        gemm128<<<g, 256>>>(A1, A1, G, KP1, KP1, KP1, KP1, KP1, KP1);
        aug_finish<<<(KP1 * KP1 + 255) / 256, 256>>>(G, A1, KP1);
        pool_A<<<(KP2 * KP2 + 255) / 256, 256>>>(G, KP1, P1, A2, KP2);
        pool_x<<<(KP2 * HP + 255) / 256, 256>>>(X1, P1, VAL, CUR, KP2);
    }
    run_gcn(A2, KP2, CUR, HP, H, w2, b2, X2, 1, T0, T1, T2, DINV);

    // ---- pool 3 (1536 -> 768) ----
    pnorm_kernel<<<1, 256>>>(p3, PN);
    score_kernel<<<(KP2 + 7) / 8, 256>>>(X2, p3, PN, SC, KP2);
    topk_kernel<<<1, 1024>>>(SC, KP2, KP3, P2, VAL);
    {
        dim3 g(KP2 / 128, KP2 / 128);
        gemm128<<<g, 256>>>(A2, A2, G, KP2, KP2, KP2, KP2, KP2, KP2);
        aug_finish<<<(KP2 * KP2 + 255) / 256, 256>>>(G, A2, KP2);
        pool_A<<<(KP3 * KP3 + 255) / 256, 256>>>(G, KP2, P2, A3, KP3);
        pool_x<<<(KP3 * HP + 255) / 256, 256>>>(X2, P2, VAL, CUR, KP3);
    }
    run_gcn(A3, KP3, CUR, HP, H, w3, b3, X3, 1, T0, T1, T2, DINV);

    // ---- up 0: j=2 ----
    cudaMemcpyAsync(CUR, X2, (size_t)KP2 * HP * sizeof(float), cudaMemcpyDeviceToDevice, 0);
    scatter_add<<<(KP3 * HP + 255) / 256, 256>>>(CUR, X3, P2, KP3);
    run_gcn(A2, KP2, CUR, HP, H, u0w, u0b, X2, 1, T0, T1, T2, DINV);

    // ---- up 1: j=1 ----
    cudaMemcpyAsync(CUR, X1, (size_t)KP1 * HP * sizeof(float), cudaMemcpyDeviceToDevice, 0);
    scatter_add<<<(KP2 * HP + 255) / 256, 256>>>(CUR, X2, P1, KP2);
    run_gcn(A1, KP1, CUR, HP, H, u1w, u1b, X1, 1, T0, T1, T2, DINV);

    // ---- up 2: j=0, final gcn (H->2) + log_softmax ----
    cudaMemcpyAsync(CUR, X0, (size_t)N0 * HP * sizeof(float), cudaMemcpyDeviceToDevice, 0);
    scatter_add<<<(KP1 * HP + 255) / 256, 256>>>(CUR, X1, P0, KP1);
    {
        dim3 gf(1, (N0 + 63) / 64);
        gemm64<<<gf, 256>>>(CUR, u2w, T0, N0, 2, H, HP, 2, 2);
        rowsum_dinv<<<N0, 256>>>(adj, DINV, N0);
        scale_rows<<<(N0 * 2 + 255) / 256, 256>>>(T0, DINV, T1, N0, 2, 2);
        gemm_n2<<<N0, 256>>>(adj, T1, T2, N0);
        final_kernel<<<(N0 + 255) / 256, 256>>>(T2, T1, DINV, u2b, (float*)d_out, N0);
    }
}

// round 3
// speedup vs baseline: 2.3057x; 2.3057x over previous
#include <cuda_runtime.h>
#include <math.h>
#include <stdint.h>

#define N0 4096
#define KP1 3072
#define KP2 1536
#define KP3 768
#define H 200
#define HP 256
#define SKMAX 8

// ---------------- device scratch (static: no allocation allowed) ----------------
__device__ float g_G[(size_t)N0 * N0];
__device__ float g_A1[(size_t)KP1 * KP1];
__device__ float g_A2[(size_t)KP2 * KP2];
__device__ float g_A3[(size_t)KP3 * KP3];
__device__ float g_x0[N0 * HP];
__device__ float g_x1[KP1 * HP];
__device__ float g_x2[KP2 * HP];
__device__ float g_x3[KP3 * HP];
__device__ float g_t0[N0 * HP];
__device__ float g_t1[N0 * HP];
__device__ float g_part[(size_t)SKMAX * N0 * HP];
__device__ float g_cur[N0 * HP];
__device__ float g_dinv[N0];
__device__ float g_score[N0];
__device__ float g_val[N0];
__device__ int   g_perm0[KP1];
__device__ int   g_perm1[KP2];
__device__ int   g_perm2[KP3];
__device__ float g_pnorm[1];

// ================= tf32 tensor-core GEMM (exact for integer-valued inputs <=2048) ====
// C[M,N] = A[M,K] @ B[K,N], row-major. M,N % 128 == 0, K % 32 == 0.
// Block 128x128x32, 256 threads (8 warps, 2x4), warp tile 64x32, mma m16n8k8.
__global__ void __launch_bounds__(256) tf32gemm(
    const float* __restrict__ A, const float* __restrict__ B, float* __restrict__ C,
    int M, int N, int K, int lda, int ldb, int ldc)
{
    __shared__ float As[32][136];   // As[k][m]: stride 136 -> conflict-free fragment loads
    __shared__ float Bs[32][136];   // Bs[k][n]

    int t = threadIdx.x;
    int warp = t >> 5, lane = t & 31;
    int group = lane >> 2, tg = lane & 3;
    int wm = warp >> 2, wn = warp & 3;          // 2 x 4 warp grid
    int bm = blockIdx.y * 128, bn = blockIdx.x * 128;

    float c[4][4][4];
#pragma unroll
    for (int mi = 0; mi < 4; mi++)
#pragma unroll
        for (int ni = 0; ni < 4; ni++)
#pragma unroll
            for (int r = 0; r < 4; r++) c[mi][ni][r] = 0.f;

    int ar = t >> 1;             // 0..127: A row within tile
    int ac0 = (t & 1);           // float4 col 0..1 (step 2)
    int br = t >> 3;             // 0..31:  B k-row
    int bc0 = t & 7;             // float4 col 0..7 (step 8)

    const float* Arow = A + (size_t)(bm + ar) * lda;

    for (int k0g = 0; k0g < K; k0g += 32) {
#pragma unroll
        for (int q = 0; q < 4; q++) {
            int ac = ac0 + q * 2;
            float4 v = *(const float4*)(Arow + k0g + ac * 4);
            As[ac * 4 + 0][ar] = v.x;
            As[ac * 4 + 1][ar] = v.y;
            As[ac * 4 + 2][ar] = v.z;
            As[ac * 4 + 3][ar] = v.w;
        }
#pragma unroll
        for (int q = 0; q < 4; q++) {
            int bc = bc0 + q * 8;
            float4 v = *(const float4*)(B + (size_t)(k0g + br) * ldb + bn + bc * 4);
            *(float4*)(&Bs[br][bc * 4]) = v;
        }
        __syncthreads();

#pragma unroll
        for (int ks = 0; ks < 4; ks++) {
            int kb = ks * 8;
            uint32_t af[4][4], bf[4][2];
#pragma unroll
            for (int mi = 0; mi < 4; mi++) {
                int rm = wm * 64 + mi * 16 + group;
                af[mi][0] = __float_as_uint(As[kb + tg][rm]);
                af[mi][1] = __float_as_uint(As[kb + tg][rm + 8]);
                af[mi][2] = __float_as_uint(As[kb + tg + 4][rm]);
                af[mi][3] = __float_as_uint(As[kb + tg + 4][rm + 8]);
            }
#pragma unroll
            for (int ni = 0; ni < 4; ni++) {
                int cn = wn * 32 + ni * 8 + group;
                bf[ni][0] = __float_as_uint(Bs[kb + tg][cn]);
                bf[ni][1] = __float_as_uint(Bs[kb + tg + 4][cn]);
            }
#pragma unroll
            for (int mi = 0; mi < 4; mi++)
#pragma unroll
                for (int ni = 0; ni < 4; ni++) {
                    asm volatile(
                        "mma.sync.aligned.m16n8k8.row.col.f32.tf32.tf32.f32 "
                        "{%0,%1,%2,%3}, {%4,%5,%6,%7}, {%8,%9}, {%0,%1,%2,%3};\n"
                        : "+f"(c[mi][ni][0]), "+f"(c[mi][ni][1]),
                          "+f"(c[mi][ni][2]), "+f"(c[mi][ni][3])
                        : "r"(af[mi][0]), "r"(af[mi][1]), "r"(af[mi][2]), "r"(af[mi][3]),
                          "r"(bf[ni][0]), "r"(bf[ni][1]));
                }
        }
        __syncthreads();
    }

#pragma unroll
    for (int mi = 0; mi < 4; mi++) {
        int row0 = bm + wm * 64 + mi * 16 + group;
#pragma unroll
        for (int ni = 0; ni < 4; ni++) {
            int col = bn + wn * 32 + ni * 8 + tg * 2;
            *(float2*)(C + (size_t)row0 * ldc + col)       = make_float2(c[mi][ni][0], c[mi][ni][1]);
            *(float2*)(C + (size_t)(row0 + 8) * ldc + col) = make_float2(c[mi][ni][2], c[mi][ni][3]);
        }
    }
}

// ---------------- fast SGEMM: 128x128 block, 8x8 per thread, BK=8 ----------------
__global__ void __launch_bounds__(256) gemm128(
    const float* __restrict__ A, const float* __restrict__ B, float* __restrict__ C,
    int M, int N, int K, int lda, int ldb, int ldc)
{
    __shared__ float As[8][128];
    __shared__ float Bs[8][128];
    int tid = threadIdx.x;
    int bm = blockIdx.y * 128, bn = blockIdx.x * 128;
    int tx = tid & 15, ty = tid >> 4;

    float acc[8][8];
#pragma unroll
    for (int i = 0; i < 8; i++)
#pragma unroll
        for (int j = 0; j < 8; j++) acc[i][j] = 0.f;

    int arow = tid >> 1, acol = (tid & 1) * 4;
    int brow = tid >> 5, bcol = (tid & 31) * 4;
    const float* Aptr = A + (size_t)(bm + arow) * lda + acol;
    const float* Bptr = B + (size_t)brow * ldb + bn + bcol;

    for (int k0 = 0; k0 < K; k0 += 8) {
        float4 av = *(const float4*)(Aptr + k0);
        float4 bv = *(const float4*)(Bptr + (size_t)k0 * ldb);
        As[acol + 0][arow] = av.x;
        As[acol + 1][arow] = av.y;
        As[acol + 2][arow] = av.z;
        As[acol + 3][arow] = av.w;
        *(float4*)(&Bs[brow][bcol]) = bv;
        __syncthreads();
#pragma unroll
        for (int kk = 0; kk < 8; kk++) {
            float a0[4], a1[4], b0[4], b1[4];
            *(float4*)a0 = *(const float4*)(&As[kk][ty * 4]);
            *(float4*)a1 = *(const float4*)(&As[kk][64 + ty * 4]);
            *(float4*)b0 = *(const float4*)(&Bs[kk][tx * 4]);
            *(float4*)b1 = *(const float4*)(&Bs[kk][64 + tx * 4]);
#pragma unroll
            for (int i = 0; i < 4; i++)
#pragma unroll
                for (int j = 0; j < 4; j++) {
                    acc[i][j]         += a0[i] * b0[j];
                    acc[i][j + 4]     += a0[i] * b1[j];
                    acc[i + 4][j]     += a1[i] * b0[j];
                    acc[i + 4][j + 4] += a1[i] * b1[j];
                }
        }
        __syncthreads();
    }
#pragma unroll
    for (int i = 0; i < 4; i++) {
        float* c0 = C + (size_t)(bm + ty * 4 + i) * ldc + bn;
        *(float4*)(c0 + tx * 4)      = make_float4(acc[i][0], acc[i][1], acc[i][2], acc[i][3]);
        *(float4*)(c0 + 64 + tx * 4) = make_float4(acc[i][4], acc[i][5], acc[i][6], acc[i][7]);
        float* c1 = C + (size_t)(bm + 64 + ty * 4 + i) * ldc + bn;
        *(float4*)(c1 + tx * 4)      = make_float4(acc[i + 4][0], acc[i + 4][1], acc[i + 4][2], acc[i + 4][3]);
        *(float4*)(c1 + 64 + tx * 4) = make_float4(acc[i + 4][4], acc[i + 4][5], acc[i + 4][6], acc[i + 4][7]);
    }
}

// ---------------- split-K SGEMM: K chunked by blockIdx.z, partials to Cpart ---------
__global__ void __launch_bounds__(256) gemm128z(
    const float* __restrict__ A, const float* __restrict__ B, float* __restrict__ Cpart,
    int M, int N, int K, int lda, int ldb, int ldc)
{
    __shared__ float As[8][128];
    __shared__ float Bs[8][128];
    int tid = threadIdx.x;
    int bm = blockIdx.y * 128, bn = blockIdx.x * 128;
    int tx = tid & 15, ty = tid >> 4;
    int kChunk = K / gridDim.z;
    int kStart = blockIdx.z * kChunk;
    float* C = Cpart + (size_t)blockIdx.z * M * ldc;

    float acc[8][8];
#pragma unroll
    for (int i = 0; i < 8; i++)
#pragma unroll
        for (int j = 0; j < 8; j++) acc[i][j] = 0.f;

    int arow = tid >> 1, acol = (tid & 1) * 4;
    int brow = tid >> 5, bcol = (tid & 31) * 4;
    const float* Aptr = A + (size_t)(bm + arow) * lda + kStart + acol;
    const float* Bptr = B + (size_t)(kStart + brow) * ldb + bn + bcol;

    for (int k0 = 0; k0 < kChunk; k0 += 8) {
        float4 av = *(const float4*)(Aptr + k0);
        float4 bv = *(const float4*)(Bptr + (size_t)k0 * ldb);
        As[acol + 0][arow] = av.x;
        As[acol + 1][arow] = av.y;
        As[acol + 2][arow] = av.z;
        As[acol + 3][arow] = av.w;
        *(float4*)(&Bs[brow][bcol]) = bv;
        __syncthreads();
#pragma unroll
        for (int kk = 0; kk < 8; kk++) {
            float a0[4], a1[4], b0[4], b1[4];
            *(float4*)a0 = *(const float4*)(&As[kk][ty * 4]);
            *(float4*)a1 = *(const float4*)(&As[kk][64 + ty * 4]);
            *(float4*)b0 = *(const float4*)(&Bs[kk][tx * 4]);
            *(float4*)b1 = *(const float4*)(&Bs[kk][64 + tx * 4]);
#pragma unroll
            for (int i = 0; i < 4; i++)
#pragma unroll
                for (int j = 0; j < 4; j++) {
                    acc[i][j]         += a0[i] * b0[j];
                    acc[i][j + 4]     += a0[i] * b1[j];
                    acc[i + 4][j]     += a1[i] * b0[j];
                    acc[i + 4][j + 4] += a1[i] * b1[j];
                }
        }
        __syncthreads();
    }
#pragma unroll
    for (int i = 0; i < 4; i++) {
        float* c0 = C + (size_t)(bm + ty * 4 + i) * ldc + bn;
        *(float4*)(c0 + tx * 4)      = make_float4(acc[i][0], acc[i][1], acc[i][2], acc[i][3]);
        *(float4*)(c0 + 64 + tx * 4) = make_float4(acc[i][4], acc[i][5], acc[i][6], acc[i][7]);
        float* c1 = C + (size_t)(bm + 64 + ty * 4 + i) * ldc + bn;
        *(float4*)(c1 + tx * 4)      = make_float4(acc[i + 4][0], acc[i + 4][1], acc[i + 4][2], acc[i + 4][3]);
        *(float4*)(c1 + 64 + tx * 4) = make_float4(acc[i + 4][4], acc[i + 4][5], acc[i + 4][6], acc[i + 4][7]);
    }
}

// ---------------- generic SGEMM: 64x64 block, 4x4 per thread, bounds-checked --------
__global__ void __launch_bounds__(256) gemm64(
    const float* __restrict__ A, const float* __restrict__ B, float* __restrict__ C,
    int M, int N, int K, int lda, int ldb, int ldc)
{
    __shared__ float As[16][65];
    __shared__ float Bs[16][64];
    int tid = threadIdx.x, tx = tid & 15, ty = tid >> 4;
    int bm = blockIdx.y * 64, bn = blockIdx.x * 64;
    float acc[4][4];
#pragma unroll
    for (int i = 0; i < 4; i++)
#pragma unroll
        for (int j = 0; j < 4; j++) acc[i][j] = 0.f;

    for (int k0 = 0; k0 < K; k0 += 16) {
        for (int t = tid; t < 64 * 16; t += 256) {
            int r = t >> 4, c = t & 15;
            int gr = bm + r, gc = k0 + c;
            As[c][r] = (gr < M && gc < K) ? A[(size_t)gr * lda + gc] : 0.f;
        }
        for (int t = tid; t < 16 * 64; t += 256) {
            int r = t >> 6, c = t & 63;
            int gr = k0 + r, gc = bn + c;
            Bs[r][c] = (gr < K && gc < N) ? B[(size_t)gr * ldb + gc] : 0.f;
        }
        __syncthreads();
#pragma unroll
        for (int kk = 0; kk < 16; kk++) {
            float a[4], b[4];
#pragma unroll
            for (int i = 0; i < 4; i++) a[i] = As[kk][ty * 4 + i];
#pragma unroll
            for (int j = 0; j < 4; j++) b[j] = Bs[kk][tx * 4 + j];
#pragma unroll
            for (int i = 0; i < 4; i++)
#pragma unroll
                for (int j = 0; j < 4; j++) acc[i][j] += a[i] * b[j];
        }
        __syncthreads();
    }
#pragma unroll
    for (int i = 0; i < 4; i++)
#pragma unroll
        for (int j = 0; j < 4; j++) {
            int gr = bm + ty * 4 + i, gc = bn + tx * 4 + j;
            if (gr < M && gc < N) C[(size_t)gr * ldc + gc] = acc[i][j];
        }
}

// ---------------- small helper kernels ----------------
__global__ void rowsum_dinv(const float* __restrict__ A, float* __restrict__ dinv, int n)
{
    int row = blockIdx.x;
    const float* Ar = A + (size_t)row * n;
    float s = 0.f;
    for (int j = threadIdx.x; j < n; j += 256) s += Ar[j];
    for (int o = 16; o > 0; o >>= 1) s += __shfl_down_sync(0xffffffffu, s, o);
    __shared__ float red[8];
    int w = threadIdx.x >> 5, l = threadIdx.x & 31;
    if (l == 0) red[w] = s;
    __syncthreads();
    if (threadIdx.x == 0) {
        float t = 0.f;
        for (int i = 0; i < 8; i++) t += red[i];
        dinv[row] = 1.0f / sqrtf(t + 2.0f);
    }
}

__global__ void scale_rows(const float* __restrict__ in, const float* __restrict__ dinv,
                           float* __restrict__ out, int n, int w, int ld)
{
    int idx = blockIdx.x * 256 + threadIdx.x;
    if (idx >= n * ld) return;
    int r = idx / ld, c = idx - r * ld;
    out[idx] = (c < w) ? dinv[r] * in[idx] : 0.f;
}

__global__ void gcn_finish_sk(const float* __restrict__ part, const float* __restrict__ Z,
                              const float* __restrict__ dinv, const float* __restrict__ b,
                              float* __restrict__ out, int n, int relu, int S)
{
    int idx = blockIdx.x * 256 + threadIdx.x;
    if (idx >= n * HP) return;
    int r = idx / HP, c = idx - r * HP;
    float v = 0.f;
    if (c < H) {
        float az = 0.f;
        size_t stride = (size_t)n * HP;
        for (int s = 0; s < S; s++) az += part[s * stride + idx];
        v = dinv[r] * (az + 2.f * Z[idx]) + b[c];
        if (relu) v = fmaxf(v, 0.f);
    }
    out[idx] = v;
}

__global__ void pnorm_kernel(const float* __restrict__ p, float* __restrict__ out)
{
    float s = 0.f;
    for (int i = threadIdx.x; i < H; i += 256) { float v = p[i]; s += v * v; }
    for (int o = 16; o > 0; o >>= 1) s += __shfl_down_sync(0xffffffffu, s, o);
    __shared__ float red[8];
    int w = threadIdx.x >> 5, l = threadIdx.x & 31;
    if (l == 0) red[w] = s;
    __syncthreads();
    if (threadIdx.x == 0) {
        float t = 0.f;
        for (int i = 0; i < 8; i++) t += red[i];
        *out = sqrtf(t);
    }
}

__global__ void score_kernel(const float* __restrict__ x, const float* __restrict__ p,
                             const float* __restrict__ pn, float* __restrict__ score, int n)
{
    int row = blockIdx.x * 8 + (threadIdx.x >> 5);
    int lane = threadIdx.x & 31;
    if (row >= n) return;
    const float* xr = x + (size_t)row * HP;
    float s = 0.f;
    for (int c = lane; c < H; c += 32) s += xr[c] * p[c];
    for (int o = 16; o > 0; o >>= 1) s += __shfl_down_sync(0xffffffffu, s, o);
    if (lane == 0) score[row] = tanhf(s / (*pn));
}

__global__ void topk_kernel(const float* __restrict__ score, int n, int k,
                            int* __restrict__ perm, float* __restrict__ val)
{
    __shared__ float ss[4096];
    __shared__ int   si[4096];
    int tid = threadIdx.x;
    for (int i = tid; i < 4096; i += 1024) {
        ss[i] = (i < n) ? score[i] : -INFINITY;
        si[i] = i;
    }
    __syncthreads();
    for (int size = 2; size <= 4096; size <<= 1) {
        for (int stride = size >> 1; stride > 0; stride >>= 1) {
            for (int i = tid; i < 4096; i += 1024) {
                int j = i ^ stride;
                if (j > i) {
                    float a = ss[i], b = ss[j];
                    int ia = si[i], ib = si[j];
                    bool bBetter = (b > a) || (b == a && ib < ia);
                    bool desc = ((i & size) == 0);
                    bool sw = desc ? bBetter : !bBetter;
                    if (sw) { ss[i] = b; ss[j] = a; si[i] = ib; si[j] = ia; }
                }
            }
            __syncthreads();
        }
    }
    for (int i = tid; i < k; i += 1024) { perm[i] = si[i]; val[i] = ss[i]; }
}

__global__ void aug_finish(float* __restrict__ G, const float* __restrict__ A, int n)
{
    int idx = blockIdx.x * 256 + threadIdx.x;
    if (idx >= n * n) return;
    int r = idx / n, c = idx - r * n;
    G[idx] = (r == c) ? 0.f : (G[idx] + 2.f * A[idx]);
}

__global__ void pool_A(const float* __restrict__ G, int ldg, const int* __restrict__ perm,
                       float* __restrict__ Aout, int k)
{
    int idx = blockIdx.x * 256 + threadIdx.x;
    if (idx >= k * k) return;
    int i = idx / k, j = idx - i * k;
    Aout[idx] = G[(size_t)perm[i] * ldg + perm[j]];
}

__global__ void pool_x(const float* __restrict__ xin, const int* __restrict__ perm,
                       const float* __restrict__ val, float* __restrict__ xout, int k)
{
    int idx = blockIdx.x * 256 + threadIdx.x;
    if (idx >= k * HP) return;
    int r = idx / HP, c = idx - r * HP;
    xout[idx] = xin[(size_t)perm[r] * HP + c] * val[r];
}

__global__ void scatter_add(float* __restrict__ dst, const float* __restrict__ x,
                            const int* __restrict__ perm, int k)
{
    int idx = blockIdx.x * 256 + threadIdx.x;
    if (idx >= k * HP) return;
    int r = idx / HP, c = idx - r * HP;
    dst[(size_t)perm[r] * HP + c] += x[idx];
}

__global__ void gemm_n2(const float* __restrict__ A, const float* __restrict__ Z,
                        float* __restrict__ out, int n)
{
    int row = blockIdx.x;
    const float* Ar = A + (size_t)row * n;
    float a0 = 0.f, a1 = 0.f;
    for (int j = threadIdx.x; j < n; j += 256) {
        float a = Ar[j];
        a0 += a * Z[2 * j];
        a1 += a * Z[2 * j + 1];
    }
    for (int o = 16; o > 0; o >>= 1) {
        a0 += __shfl_down_sync(0xffffffffu, a0, o);
        a1 += __shfl_down_sync(0xffffffffu, a1, o);
    }
    __shared__ float r0[8], r1[8];
    int w = threadIdx.x >> 5, l = threadIdx.x & 31;
    if (l == 0) { r0[w] = a0; r1[w] = a1; }
    __syncthreads();
    if (threadIdx.x == 0) {
        float s0 = 0.f, s1 = 0.f;
        for (int i = 0; i < 8; i++) { s0 += r0[i]; s1 += r1[i]; }
        out[2 * row] = s0;
        out[2 * row + 1] = s1;
    }
}

__global__ void final_kernel(const float* __restrict__ AZ, const float* __restrict__ Z,
                             const float* __restrict__ dinv, const float* __restrict__ b,
                             float* __restrict__ out, int n)
{
    int i = blockIdx.x * 256 + threadIdx.x;
    if (i >= n) return;
    float a = dinv[i] * (AZ[2 * i]     + 2.f * Z[2 * i])     + b[0];
    float c = dinv[i] * (AZ[2 * i + 1] + 2.f * Z[2 * i + 1]) + b[1];
    float m = fmaxf(a, c);
    float l = m + logf(expf(a - m) + expf(c - m));
    out[2 * i] = a - l;
    out[2 * i + 1] = c - l;
}

// ---------------- host orchestration ----------------
template <typename T, size_t NN>
static T* symaddr(T (&sym)[NN]) {
    void* p = nullptr;
    cudaGetSymbolAddress(&p, sym);
    return (T*)p;
}

static void run_gcn(const float* A, int n, const float* xin, int lda_x, int Kdim,
                    const float* W, const float* b, float* xout, int relu, int S,
                    float* t0, float* t1, float* part, float* dinv)
{
    dim3 g1((H + 63) / 64, (n + 63) / 64);
    gemm64<<<g1, 256>>>(xin, W, t0, n, H, Kdim, lda_x, H, HP);
    rowsum_dinv<<<n, 256>>>(A, dinv, n);
    int tot = n * HP;
    scale_rows<<<(tot + 255) / 256, 256>>>(t0, dinv, t1, n, H, HP);
    dim3 g2(HP / 128, n / 128, S);
    gemm128z<<<g2, 256>>>(A, t1, part, n, HP, n, n, HP, HP);
    gcn_finish_sk<<<(tot + 255) / 256, 256>>>(part, t1, dinv, b, xout, n, relu, S);
}

extern "C" void kernel_launch(void* const* d_in, const int* in_sizes, int n_in,
                              void* d_out, int out_size)
{
    (void)in_sizes; (void)n_in; (void)out_size;
    const float* x   = (const float*)d_in[0];
    const float* adj = (const float*)d_in[1];
    const float* w0  = (const float*)d_in[2];
    const float* b0  = (const float*)d_in[3];
    const float* w1  = (const float*)d_in[4];
    const float* b1  = (const float*)d_in[5];
    const float* w2  = (const float*)d_in[6];
    const float* b2  = (const float*)d_in[7];
    const float* w3  = (const float*)d_in[8];
    const float* b3  = (const float*)d_in[9];
    const float* p1  = (const float*)d_in[10];
    const float* p2  = (const float*)d_in[11];
    const float* p3  = (const float*)d_in[12];
    const float* u0w = (const float*)d_in[13];
    const float* u0b = (const float*)d_in[14];
    const float* u1w = (const float*)d_in[15];
    const float* u1b = (const float*)d_in[16];
    const float* u2w = (const float*)d_in[17];
    const float* u2b = (const float*)d_in[18];

    float* G    = symaddr(g_G);
    float* A1   = symaddr(g_A1);
    float* A2   = symaddr(g_A2);
    float* A3   = symaddr(g_A3);
    float* X0   = symaddr(g_x0);
    float* X1   = symaddr(g_x1);
    float* X2   = symaddr(g_x2);
    float* X3   = symaddr(g_x3);
    float* T0   = symaddr(g_t0);
    float* T1   = symaddr(g_t1);
    float* PART = symaddr(g_part);
    float* CUR  = symaddr(g_cur);
    float* DINV = symaddr(g_dinv);
    float* SC   = symaddr(g_score);
    float* VAL  = symaddr(g_val);
    int*   P0   = symaddr(g_perm0);
    int*   P1   = symaddr(g_perm1);
    int*   P2   = symaddr(g_perm2);
    float* PN   = symaddr(g_pnorm);

    // ---- down: gcn0 ----
    run_gcn(adj, N0, x, 3, 3, w0, b0, X0, 1, 4, T0, T1, PART, DINV);

    // ---- pool 1 (4096 -> 3072) ----
    pnorm_kernel<<<1, 256>>>(p1, PN);
    score_kernel<<<(N0 + 7) / 8, 256>>>(X0, p1, PN, SC, N0);
    topk_kernel<<<1, 1024>>>(SC, N0, KP1, P0, VAL);
    {
        dim3 g(N0 / 128, N0 / 128);
        tf32gemm<<<g, 256>>>(adj, adj, G, N0, N0, N0, N0, N0, N0);  // exact: binary inputs
        aug_finish<<<(N0 * N0 + 255) / 256, 256>>>(G, adj, N0);
        pool_A<<<(KP1 * KP1 + 255) / 256, 256>>>(G, N0, P0, A1, KP1);
        pool_x<<<(KP1 * HP + 255) / 256, 256>>>(X0, P0, VAL, CUR, KP1);
    }
    run_gcn(A1, KP1, CUR, HP, H, w1, b1, X1, 1, 4, T0, T1, PART, DINV);

    // ---- pool 2 (3072 -> 1536) ----
    pnorm_kernel<<<1, 256>>>(p2, PN);
    score_kernel<<<(KP1 + 7) / 8, 256>>>(X1, p2, PN, SC, KP1);
    topk_kernel<<<1, 1024>>>(SC, KP1, KP2, P1, VAL);
    {
        dim3 g(KP1 / 128, KP1 / 128);
        tf32gemm<<<g, 256>>>(A1, A1, G, KP1, KP1, KP1, KP1, KP1, KP1);  // exact: ints <= 2048
        aug_finish<<<(KP1 * KP1 + 255) / 256, 256>>>(G, A1, KP1);
        pool_A<<<(KP2 * KP2 + 255) / 256, 256>>>(G, KP1, P1, A2, KP2);
        pool_x<<<(KP2 * HP + 255) / 256, 256>>>(X1, P1, VAL, CUR, KP2);
    }
    run_gcn(A2, KP2, CUR, HP, H, w2, b2, X2, 1, 8, T0, T1, PART, DINV);

    // ---- pool 3 (1536 -> 768) ----
    pnorm_kernel<<<1, 256>>>(p3, PN);
    score_kernel<<<(KP2 + 7) / 8, 256>>>(X2, p3, PN, SC, KP2);
    topk_kernel<<<1, 1024>>>(SC, KP2, KP3, P2, VAL);
    {
        dim3 g(KP2 / 128, KP2 / 128);
        gemm128<<<g, 256>>>(A2, A2, G, KP2, KP2, KP2, KP2, KP2, KP2);  // A2 may exceed 2048: fp32
        aug_finish<<<(KP2 * KP2 + 255) / 256, 256>>>(G, A2, KP2);
        pool_A<<<(KP3 * KP3 + 255) / 256, 256>>>(G, KP2, P2, A3, KP3);
        pool_x<<<(KP3 * HP + 255) / 256, 256>>>(X2, P2, VAL, CUR, KP3);
    }
    run_gcn(A3, KP3, CUR, HP, H, w3, b3, X3, 1, 8, T0, T1, PART, DINV);

    // ---- up 0: j=2 ----
    cudaMemcpyAsync(CUR, X2, (size_t)KP2 * HP * sizeof(float), cudaMemcpyDeviceToDevice, 0);
    scatter_add<<<(KP3 * HP + 255) / 256, 256>>>(CUR, X3, P2, KP3);
    run_gcn(A2, KP2, CUR, HP, H, u0w, u0b, X2, 1, 8, T0, T1, PART, DINV);

    // ---- up 1: j=1 ----
    cudaMemcpyAsync(CUR, X1, (size_t)KP1 * HP * sizeof(float), cudaMemcpyDeviceToDevice, 0);
    scatter_add<<<(KP2 * HP + 255) / 256, 256>>>(CUR, X2, P1, KP2);
    run_gcn(A1, KP1, CUR, HP, H, u1w, u1b, X1, 1, 4, T0, T1, PART, DINV);

    // ---- up 2: j=0, final gcn (H->2) + log_softmax ----
    cudaMemcpyAsync(CUR, X0, (size_t)N0 * HP * sizeof(float), cudaMemcpyDeviceToDevice, 0);
    scatter_add<<<(KP1 * HP + 255) / 256, 256>>>(CUR, X1, P0, KP1);
    {
        dim3 gf(1, (N0 + 63) / 64);
        gemm64<<<gf, 256>>>(CUR, u2w, T0, N0, 2, H, HP, 2, 2);
        rowsum_dinv<<<N0, 256>>>(adj, DINV, N0);
        scale_rows<<<(N0 * 2 + 255) / 256, 256>>>(T0, DINV, T1, N0, 2, 2);
        gemm_n2<<<N0, 256>>>(adj, T1, T0, N0);   // T0 free after scale_rows consumed it
        final_kernel<<<(N0 + 255) / 256, 256>>>(T0, T1, DINV, u2b, (float*)d_out, N0);
    }
}

// round 4
// speedup vs baseline: 2.4622x; 1.0679x over previous
#include <cuda_runtime.h>
#include <math.h>
#include <stdint.h>

#define N0 4096
#define KP1 3072
#define KP2 1536
#define KP3 768
#define H 200
#define HP 256
#define SKMAX 8

// ---------------- device scratch (static: no allocation allowed) ----------------
__device__ float g_G[(size_t)N0 * N0];
__device__ float g_A1[(size_t)KP1 * KP1];
__device__ float g_A2[(size_t)KP2 * KP2];
__device__ float g_A3[(size_t)KP3 * KP3];
__device__ float g_x0[N0 * HP];
__device__ float g_x1[KP1 * HP];
__device__ float g_x2[KP2 * HP];
__device__ float g_x3[KP3 * HP];
__device__ float g_t0[N0 * HP];
__device__ float g_t1[N0 * HP];
__device__ float g_part[(size_t)SKMAX * N0 * HP];
__device__ float g_cur[N0 * HP];
__device__ float g_dinv[N0];
__device__ float g_score[N0];
__device__ float g_val[N0];
__device__ int   g_perm0[KP1];
__device__ int   g_perm1[KP2];
__device__ int   g_perm2[KP3];
__device__ float g_pnorm[1];

__device__ __forceinline__ uint32_t f2tf(float x) {
    uint32_t r;
    asm("cvt.rna.tf32.f32 %0, %1;" : "=r"(r) : "f"(x));
    return r;
}

// ================= plain tf32 GEMM (EXACT for integer-valued inputs <= 2048) =========
// C[M,N] = A[M,K] @ B[K,N], row-major. M,N % 128 == 0, K % 32 == 0.
__global__ void __launch_bounds__(256) tf32gemm(
    const float* __restrict__ A, const float* __restrict__ B, float* __restrict__ C,
    int M, int N, int K, int lda, int ldb, int ldc)
{
    __shared__ float As[32][136];
    __shared__ float Bs[32][136];

    int t = threadIdx.x;
    int warp = t >> 5, lane = t & 31;
    int group = lane >> 2, tg = lane & 3;
    int wm = warp >> 2, wn = warp & 3;
    int bm = blockIdx.y * 128, bn = blockIdx.x * 128;

    float c[4][4][4];
#pragma unroll
    for (int mi = 0; mi < 4; mi++)
#pragma unroll
        for (int ni = 0; ni < 4; ni++)
#pragma unroll
            for (int r = 0; r < 4; r++) c[mi][ni][r] = 0.f;

    int ar = t >> 1, ac0 = (t & 1);
    int br = t >> 3, bc0 = t & 7;
    const float* Arow = A + (size_t)(bm + ar) * lda;

    for (int k0g = 0; k0g < K; k0g += 32) {
#pragma unroll
        for (int q = 0; q < 4; q++) {
            int ac = ac0 + q * 2;
            float4 v = *(const float4*)(Arow + k0g + ac * 4);
            As[ac * 4 + 0][ar] = v.x;
            As[ac * 4 + 1][ar] = v.y;
            As[ac * 4 + 2][ar] = v.z;
            As[ac * 4 + 3][ar] = v.w;
        }
#pragma unroll
        for (int q = 0; q < 4; q++) {
            int bc = bc0 + q * 8;
            float4 v = *(const float4*)(B + (size_t)(k0g + br) * ldb + bn + bc * 4);
            *(float4*)(&Bs[br][bc * 4]) = v;
        }
        __syncthreads();

#pragma unroll
        for (int ks = 0; ks < 4; ks++) {
            int kb = ks * 8;
            uint32_t af[4][4], bf[4][2];
#pragma unroll
            for (int mi = 0; mi < 4; mi++) {
                int rm = wm * 64 + mi * 16 + group;
                af[mi][0] = __float_as_uint(As[kb + tg][rm]);
                af[mi][1] = __float_as_uint(As[kb + tg][rm + 8]);
                af[mi][2] = __float_as_uint(As[kb + tg + 4][rm]);
                af[mi][3] = __float_as_uint(As[kb + tg + 4][rm + 8]);
            }
#pragma unroll
            for (int ni = 0; ni < 4; ni++) {
                int cn = wn * 32 + ni * 8 + group;
                bf[ni][0] = __float_as_uint(Bs[kb + tg][cn]);
                bf[ni][1] = __float_as_uint(Bs[kb + tg + 4][cn]);
            }
#pragma unroll
            for (int mi = 0; mi < 4; mi++)
#pragma unroll
                for (int ni = 0; ni < 4; ni++) {
                    asm volatile(
                        "mma.sync.aligned.m16n8k8.row.col.f32.tf32.tf32.f32 "
                        "{%0,%1,%2,%3}, {%4,%5,%6,%7}, {%8,%9}, {%0,%1,%2,%3};\n"
                        : "+f"(c[mi][ni][0]), "+f"(c[mi][ni][1]),
                          "+f"(c[mi][ni][2]), "+f"(c[mi][ni][3])
                        : "r"(af[mi][0]), "r"(af[mi][1]), "r"(af[mi][2]), "r"(af[mi][3]),
                          "r"(bf[ni][0]), "r"(bf[ni][1]));
                }
        }
        __syncthreads();
    }

#pragma unroll
    for (int mi = 0; mi < 4; mi++) {
        int row0 = bm + wm * 64 + mi * 16 + group;
#pragma unroll
        for (int ni = 0; ni < 4; ni++) {
            int col = bn + wn * 32 + ni * 8 + tg * 2;
            *(float2*)(C + (size_t)row0 * ldc + col)       = make_float2(c[mi][ni][0], c[mi][ni][1]);
            *(float2*)(C + (size_t)(row0 + 8) * ldc + col) = make_float2(c[mi][ni][2], c[mi][ni][3]);
        }
    }
}

// ============ split-TF32 GEMM with optional split-K partials ==========================
// C[M,N] = A[M,K] @ B[K,N]. B always split hi/lo (2 mma); if asplit, adds alo*bhi (3 mma).
// Error <= ~2^-21 rel (asplit=0, A exact in tf32) or ~2^-22 rel dropped term (asplit=1).
// gridDim.z = S split-K slices, each writes its own slice Cpart + z*M*ldc.
// M,N % 128 == 0, (K/S) % 32 == 0.
__global__ void __launch_bounds__(256) tf32gemm3z(
    const float* __restrict__ A, const float* __restrict__ B, float* __restrict__ Cpart,
    int M, int N, int K, int lda, int ldb, int ldc, int asplit)
{
    __shared__ float As[32][136];
    __shared__ float Bs[32][136];

    int t = threadIdx.x;
    int warp = t >> 5, lane = t & 31;
    int group = lane >> 2, tg = lane & 3;
    int wm = warp >> 2, wn = warp & 3;
    int bm = blockIdx.y * 128, bn = blockIdx.x * 128;
    int kChunk = K / gridDim.z;
    int kStart = blockIdx.z * kChunk;
    float* C = Cpart + (size_t)blockIdx.z * M * ldc;

    float c[4][4][4];
#pragma unroll
    for (int mi = 0; mi < 4; mi++)
#pragma unroll
        for (int ni = 0; ni < 4; ni++)
#pragma unroll
            for (int r = 0; r < 4; r++) c[mi][ni][r] = 0.f;

    int ar = t >> 1, ac0 = (t & 1);
    int br = t >> 3, bc0 = t & 7;
    const float* Arow = A + (size_t)(bm + ar) * lda + kStart;

    for (int k0g = 0; k0g < kChunk; k0g += 32) {
#pragma unroll
        for (int q = 0; q < 4; q++) {
            int ac = ac0 + q * 2;
            float4 v = *(const float4*)(Arow + k0g + ac * 4);
            As[ac * 4 + 0][ar] = v.x;
            As[ac * 4 + 1][ar] = v.y;
            As[ac * 4 + 2][ar] = v.z;
            As[ac * 4 + 3][ar] = v.w;
        }
#pragma unroll
        for (int q = 0; q < 4; q++) {
            int bc = bc0 + q * 8;
            float4 v = *(const float4*)(B + (size_t)(kStart + k0g + br) * ldb + bn + bc * 4);
            *(float4*)(&Bs[br][bc * 4]) = v;
        }
        __syncthreads();

#pragma unroll
        for (int ks = 0; ks < 4; ks++) {
            int kb = ks * 8;
            uint32_t afh[4][4], afl[4][4], bfh[4][2], bfl[4][2];
#pragma unroll
            for (int mi = 0; mi < 4; mi++) {
                int rm = wm * 64 + mi * 16 + group;
                float a0 = As[kb + tg][rm];
                float a1 = As[kb + tg][rm + 8];
                float a2 = As[kb + tg + 4][rm];
                float a3 = As[kb + tg + 4][rm + 8];
                afh[mi][0] = f2tf(a0); afh[mi][1] = f2tf(a1);
                afh[mi][2] = f2tf(a2); afh[mi][3] = f2tf(a3);
                if (asplit) {
                    afl[mi][0] = f2tf(a0 - __uint_as_float(afh[mi][0]));
                    afl[mi][1] = f2tf(a1 - __uint_as_float(afh[mi][1]));
                    afl[mi][2] = f2tf(a2 - __uint_as_float(afh[mi][2]));
                    afl[mi][3] = f2tf(a3 - __uint_as_float(afh[mi][3]));
                }
            }
#pragma unroll
            for (int ni = 0; ni < 4; ni++) {
                int cn = wn * 32 + ni * 8 + group;
                float b0 = Bs[kb + tg][cn];
                float b1 = Bs[kb + tg + 4][cn];
                bfh[ni][0] = f2tf(b0);
                bfh[ni][1] = f2tf(b1);
                bfl[ni][0] = f2tf(b0 - __uint_as_float(bfh[ni][0]));
                bfl[ni][1] = f2tf(b1 - __uint_as_float(bfh[ni][1]));
            }
#pragma unroll
            for (int mi = 0; mi < 4; mi++)
#pragma unroll
                for (int ni = 0; ni < 4; ni++) {
                    asm volatile(
                        "mma.sync.aligned.m16n8k8.row.col.f32.tf32.tf32.f32 "
                        "{%0,%1,%2,%3}, {%4,%5,%6,%7}, {%8,%9}, {%0,%1,%2,%3};\n"
                        : "+f"(c[mi][ni][0]), "+f"(c[mi][ni][1]),
                          "+f"(c[mi][ni][2]), "+f"(c[mi][ni][3])
                        : "r"(afh[mi][0]), "r"(afh[mi][1]), "r"(afh[mi][2]), "r"(afh[mi][3]),
                          "r"(bfl[ni][0]), "r"(bfl[ni][1]));
                    if (asplit) {
                        asm volatile(
                            "mma.sync.aligned.m16n8k8.row.col.f32.tf32.tf32.f32 "
                            "{%0,%1,%2,%3}, {%4,%5,%6,%7}, {%8,%9}, {%0,%1,%2,%3};\n"
                            : "+f"(c[mi][ni][0]), "+f"(c[mi][ni][1]),
                              "+f"(c[mi][ni][2]), "+f"(c[mi][ni][3])
                            : "r"(afl[mi][0]), "r"(afl[mi][1]), "r"(afl[mi][2]), "r"(afl[mi][3]),
                              "r"(bfh[ni][0]), "r"(bfh[ni][1]));
                    }
                    asm volatile(
                        "mma.sync.aligned.m16n8k8.row.col.f32.tf32.tf32.f32 "
                        "{%0,%1,%2,%3}, {%4,%5,%6,%7}, {%8,%9}, {%0,%1,%2,%3};\n"
                        : "+f"(c[mi][ni][0]), "+f"(c[mi][ni][1]),
                          "+f"(c[mi][ni][2]), "+f"(c[mi][ni][3])
                        : "r"(afh[mi][0]), "r"(afh[mi][1]), "r"(afh[mi][2]), "r"(afh[mi][3]),
                          "r"(bfh[ni][0]), "r"(bfh[ni][1]));
                }
        }
        __syncthreads();
    }

#pragma unroll
    for (int mi = 0; mi < 4; mi++) {
        int row0 = bm + wm * 64 + mi * 16 + group;
#pragma unroll
        for (int ni = 0; ni < 4; ni++) {
            int col = bn + wn * 32 + ni * 8 + tg * 2;
            *(float2*)(C + (size_t)row0 * ldc + col)       = make_float2(c[mi][ni][0], c[mi][ni][1]);
            *(float2*)(C + (size_t)(row0 + 8) * ldc + col) = make_float2(c[mi][ni][2], c[mi][ni][3]);
        }
    }
}

// ---------------- generic SGEMM: 64x64 block, 4x4 per thread, bounds-checked --------
__global__ void __launch_bounds__(256) gemm64(
    const float* __restrict__ A, const float* __restrict__ B, float* __restrict__ C,
    int M, int N, int K, int lda, int ldb, int ldc)
{
    __shared__ float As[16][65];
    __shared__ float Bs[16][64];
    int tid = threadIdx.x, tx = tid & 15, ty = tid >> 4;
    int bm = blockIdx.y * 64, bn = blockIdx.x * 64;
    float acc[4][4];
#pragma unroll
    for (int i = 0; i < 4; i++)
#pragma unroll
        for (int j = 0; j < 4; j++) acc[i][j] = 0.f;

    for (int k0 = 0; k0 < K; k0 += 16) {
        for (int t = tid; t < 64 * 16; t += 256) {
            int r = t >> 4, c = t & 15;
            int gr = bm + r, gc = k0 + c;
            As[c][r] = (gr < M && gc < K) ? A[(size_t)gr * lda + gc] : 0.f;
        }
        for (int t = tid; t < 16 * 64; t += 256) {
            int r = t >> 6, c = t & 63;
            int gr = k0 + r, gc = bn + c;
            Bs[r][c] = (gr < K && gc < N) ? B[(size_t)gr * ldb + gc] : 0.f;
        }
        __syncthreads();
#pragma unroll
        for (int kk = 0; kk < 16; kk++) {
            float a[4], b[4];
#pragma unroll
            for (int i = 0; i < 4; i++) a[i] = As[kk][ty * 4 + i];
#pragma unroll
            for (int j = 0; j < 4; j++) b[j] = Bs[kk][tx * 4 + j];
#pragma unroll
            for (int i = 0; i < 4; i++)
#pragma unroll
                for (int j = 0; j < 4; j++) acc[i][j] += a[i] * b[j];
        }
        __syncthreads();
    }
#pragma unroll
    for (int i = 0; i < 4; i++)
#pragma unroll
        for (int j = 0; j < 4; j++) {
            int gr = bm + ty * 4 + i, gc = bn + tx * 4 + j;
            if (gr < M && gc < N) C[(size_t)gr * ldc + gc] = acc[i][j];
        }
}

// ---------------- small helper kernels ----------------
__global__ void rowsum_dinv(const float* __restrict__ A, float* __restrict__ dinv, int n)
{
    int row = blockIdx.x;
    const float* Ar = A + (size_t)row * n;
    float s = 0.f;
    for (int j = threadIdx.x; j < n; j += 256) s += Ar[j];
    for (int o = 16; o > 0; o >>= 1) s += __shfl_down_sync(0xffffffffu, s, o);
    __shared__ float red[8];
    int w = threadIdx.x >> 5, l = threadIdx.x & 31;
    if (l == 0) red[w] = s;
    __syncthreads();
    if (threadIdx.x == 0) {
        float t = 0.f;
        for (int i = 0; i < 8; i++) t += red[i];
        dinv[row] = 1.0f / sqrtf(t + 2.0f);
    }
}

__global__ void scale_rows(const float* __restrict__ in, const float* __restrict__ dinv,
                           float* __restrict__ out, int n, int w, int ld)
{
    int idx = blockIdx.x * 256 + threadIdx.x;
    if (idx >= n * ld) return;
    int r = idx / ld, c = idx - r * ld;
    out[idx] = (c < w) ? dinv[r] * in[idx] : 0.f;
}

__global__ void gcn_finish_sk(const float* __restrict__ part, const float* __restrict__ Z,
                              const float* __restrict__ dinv, const float* __restrict__ b,
                              float* __restrict__ out, int n, int relu, int S)
{
    int idx = blockIdx.x * 256 + threadIdx.x;
    if (idx >= n * HP) return;
    int r = idx / HP, c = idx - r * HP;
    float v = 0.f;
    if (c < H) {
        float az = 0.f;
        size_t stride = (size_t)n * HP;
        for (int s = 0; s < S; s++) az += part[s * stride + idx];
        v = dinv[r] * (az + 2.f * Z[idx]) + b[c];
        if (relu) v = fmaxf(v, 0.f);
    }
    out[idx] = v;
}

__global__ void pnorm_kernel(const float* __restrict__ p, float* __restrict__ out)
{
    float s = 0.f;
    for (int i = threadIdx.x; i < H; i += 256) { float v = p[i]; s += v * v; }
    for (int o = 16; o > 0; o >>= 1) s += __shfl_down_sync(0xffffffffu, s, o);
    __shared__ float red[8];
    int w = threadIdx.x >> 5, l = threadIdx.x & 31;
    if (l == 0) red[w] = s;
    __syncthreads();
    if (threadIdx.x == 0) {
        float t = 0.f;
        for (int i = 0; i < 8; i++) t += red[i];
        *out = sqrtf(t);
    }
}

__global__ void score_kernel(const float* __restrict__ x, const float* __restrict__ p,
                             const float* __restrict__ pn, float* __restrict__ score, int n)
{
    int row = blockIdx.x * 8 + (threadIdx.x >> 5);
    int lane = threadIdx.x & 31;
    if (row >= n) return;
    const float* xr = x + (size_t)row * HP;
    float s = 0.f;
    for (int c = lane; c < H; c += 32) s += xr[c] * p[c];
    for (int o = 16; o > 0; o >>= 1) s += __shfl_down_sync(0xffffffffu, s, o);
    if (lane == 0) score[row] = tanhf(s / (*pn));
}

__global__ void topk_kernel(const float* __restrict__ score, int n, int k,
                            int* __restrict__ perm, float* __restrict__ val)
{
    __shared__ float ss[4096];
    __shared__ int   si[4096];
    int tid = threadIdx.x;
    for (int i = tid; i < 4096; i += 1024) {
        ss[i] = (i < n) ? score[i] : -INFINITY;
        si[i] = i;
    }
    __syncthreads();
    for (int size = 2; size <= 4096; size <<= 1) {
        for (int stride = size >> 1; stride > 0; stride >>= 1) {
            for (int i = tid; i < 4096; i += 1024) {
                int j = i ^ stride;
                if (j > i) {
                    float a = ss[i], b = ss[j];
                    int ia = si[i], ib = si[j];
                    bool bBetter = (b > a) || (b == a && ib < ia);
                    bool desc = ((i & size) == 0);
                    bool sw = desc ? bBetter : !bBetter;
                    if (sw) { ss[i] = b; ss[j] = a; si[i] = ib; si[j] = ia; }
                }
            }
            __syncthreads();
        }
    }
    for (int i = tid; i < k; i += 1024) { perm[i] = si[i]; val[i] = ss[i]; }
}

// fused: A_out[i][j] = (i==j) ? 0 : G[pi][pj] + 2*A[pi][pj]   (G = A@A)
__global__ void pool_A_fused(const float* __restrict__ G, const float* __restrict__ Asrc,
                             int ldg, const int* __restrict__ perm,
                             float* __restrict__ Aout, int k)
{
    int idx = blockIdx.x * 256 + threadIdx.x;
    if (idx >= k * k) return;
    int i = idx / k, j = idx - i * k;
    if (i == j) { Aout[idx] = 0.f; return; }
    size_t off = (size_t)perm[i] * ldg + perm[j];
    Aout[idx] = G[off] + 2.f * Asrc[off];
}

__global__ void pool_x(const float* __restrict__ xin, const int* __restrict__ perm,
                       const float* __restrict__ val, float* __restrict__ xout, int k)
{
    int idx = blockIdx.x * 256 + threadIdx.x;
    if (idx >= k * HP) return;
    int r = idx / HP, c = idx - r * HP;
    xout[idx] = xin[(size_t)perm[r] * HP + c] * val[r];
}

__global__ void scatter_add(float* __restrict__ dst, const float* __restrict__ x,
                            const int* __restrict__ perm, int k)
{
    int idx = blockIdx.x * 256 + threadIdx.x;
    if (idx >= k * HP) return;
    int r = idx / HP, c = idx - r * HP;
    dst[(size_t)perm[r] * HP + c] += x[idx];
}

__global__ void gemm_n2(const float* __restrict__ A, const float* __restrict__ Z,
                        float* __restrict__ out, int n)
{
    int row = blockIdx.x;
    const float* Ar = A + (size_t)row * n;
    float a0 = 0.f, a1 = 0.f;
    for (int j = threadIdx.x; j < n; j += 256) {
        float a = Ar[j];
        a0 += a * Z[2 * j];
        a1 += a * Z[2 * j + 1];
    }
    for (int o = 16; o > 0; o >>= 1) {
        a0 += __shfl_down_sync(0xffffffffu, a0, o);
        a1 += __shfl_down_sync(0xffffffffu, a1, o);
    }
    __shared__ float r0[8], r1[8];
    int w = threadIdx.x >> 5, l = threadIdx.x & 31;
    if (l == 0) { r0[w] = a0; r1[w] = a1; }
    __syncthreads();
    if (threadIdx.x == 0) {
        float s0 = 0.f, s1 = 0.f;
        for (int i = 0; i < 8; i++) { s0 += r0[i]; s1 += r1[i]; }
        out[2 * row] = s0;
        out[2 * row + 1] = s1;
    }
}

__global__ void final_kernel(const float* __restrict__ AZ, const float* __restrict__ Z,
                             const float* __restrict__ dinv, const float* __restrict__ b,
                             float* __restrict__ out, int n)
{
    int i = blockIdx.x * 256 + threadIdx.x;
    if (i >= n) return;
    float a = dinv[i] * (AZ[2 * i]     + 2.f * Z[2 * i])     + b[0];
    float c = dinv[i] * (AZ[2 * i + 1] + 2.f * Z[2 * i + 1]) + b[1];
    float m = fmaxf(a, c);
    float l = m + logf(expf(a - m) + expf(c - m));
    out[2 * i] = a - l;
    out[2 * i + 1] = c - l;
}

// ---------------- host orchestration ----------------
template <typename T, size_t NN>
static T* symaddr(T (&sym)[NN]) {
    void* p = nullptr;
    cudaGetSymbolAddress(&p, sym);
    return (T*)p;
}

static void run_gcn(const float* A, int n, const float* xin, int lda_x, int Kdim,
                    const float* W, const float* b, float* xout, int relu,
                    int S, int asplit,
                    float* t0, float* t1, float* part, float* dinv)
{
    dim3 g1((H + 63) / 64, (n + 63) / 64);
    gemm64<<<g1, 256>>>(xin, W, t0, n, H, Kdim, lda_x, H, HP);
    rowsum_dinv<<<n, 256>>>(A, dinv, n);
    int tot = n * HP;
    scale_rows<<<(tot + 255) / 256, 256>>>(t0, dinv, t1, n, H, HP);
    dim3 g2(HP / 128, n / 128, S);
    tf32gemm3z<<<g2, 256>>>(A, t1, part, n, HP, n, n, HP, HP, asplit);
    gcn_finish_sk<<<(tot + 255) / 256, 256>>>(part, t1, dinv, b, xout, n, relu, S);
}

extern "C" void kernel_launch(void* const* d_in, const int* in_sizes, int n_in,
                              void* d_out, int out_size)
{
    (void)in_sizes; (void)n_in; (void)out_size;
    const float* x   = (const float*)d_in[0];
    const float* adj = (const float*)d_in[1];
    const float* w0  = (const float*)d_in[2];
    const float* b0  = (const float*)d_in[3];
    const float* w1  = (const float*)d_in[4];
    const float* b1  = (const float*)d_in[5];
    const float* w2  = (const float*)d_in[6];
    const float* b2  = (const float*)d_in[7];
    const float* w3  = (const float*)d_in[8];
    const float* b3  = (const float*)d_in[9];
    const float* p1  = (const float*)d_in[10];
    const float* p2  = (const float*)d_in[11];
    const float* p3  = (const float*)d_in[12];
    const float* u0w = (const float*)d_in[13];
    const float* u0b = (const float*)d_in[14];
    const float* u1w = (const float*)d_in[15];
    const float* u1b = (const float*)d_in[16];
    const float* u2w = (const float*)d_in[17];
    const float* u2b = (const float*)d_in[18];

    float* G    = symaddr(g_G);
    float* A1   = symaddr(g_A1);
    float* A2   = symaddr(g_A2);
    float* A3   = symaddr(g_A3);
    float* X0   = symaddr(g_x0);
    float* X1   = symaddr(g_x1);
    float* X2   = symaddr(g_x2);
    float* X3   = symaddr(g_x3);
    float* T0   = symaddr(g_t0);
    float* T1   = symaddr(g_t1);
    float* PART = symaddr(g_part);
    float* CUR  = symaddr(g_cur);
    float* DINV = symaddr(g_dinv);
    float* SC   = symaddr(g_score);
    float* VAL  = symaddr(g_val);
    int*   P0   = symaddr(g_perm0);
    int*   P1   = symaddr(g_perm1);
    int*   P2   = symaddr(g_perm2);
    float* PN   = symaddr(g_pnorm);

    // ---- down: gcn0 (adj binary -> exact in tf32, asplit=0) ----
    run_gcn(adj, N0, x, 3, 3, w0, b0, X0, 1, 4, 0, T0, T1, PART, DINV);

    // ---- pool 1 (4096 -> 3072) ----
    pnorm_kernel<<<1, 256>>>(p1, PN);
    score_kernel<<<(N0 + 7) / 8, 256>>>(X0, p1, PN, SC, N0);
    topk_kernel<<<1, 1024>>>(SC, N0, KP1, P0, VAL);
    {
        dim3 g(N0 / 128, N0 / 128);
        tf32gemm<<<g, 256>>>(adj, adj, G, N0, N0, N0, N0, N0, N0);  // exact: binary
        pool_A_fused<<<(KP1 * KP1 + 255) / 256, 256>>>(G, adj, N0, P0, A1, KP1);
        pool_x<<<(KP1 * HP + 255) / 256, 256>>>(X0, P0, VAL, CUR, KP1);
    }
    run_gcn(A1, KP1, CUR, HP, H, w1, b1, X1, 1, 4, 0, T0, T1, PART, DINV);

    // ---- pool 2 (3072 -> 1536) ----
    pnorm_kernel<<<1, 256>>>(p2, PN);
    score_kernel<<<(KP1 + 7) / 8, 256>>>(X1, p2, PN, SC, KP1);
    topk_kernel<<<1, 1024>>>(SC, KP1, KP2, P1, VAL);
    {
        dim3 g(KP1 / 128, KP1 / 128);
        tf32gemm<<<g, 256>>>(A1, A1, G, KP1, KP1, KP1, KP1, KP1, KP1);  // exact: small ints
        pool_A_fused<<<(KP2 * KP2 + 255) / 256, 256>>>(G, A1, KP1, P1, A2, KP2);
        pool_x<<<(KP2 * HP + 255) / 256, 256>>>(X1, P1, VAL, CUR, KP2);
    }
    run_gcn(A2, KP2, CUR, HP, H, w2, b2, X2, 1, 8, 1, T0, T1, PART, DINV);

    // ---- pool 3 (1536 -> 768) ----
    pnorm_kernel<<<1, 256>>>(p3, PN);
    score_kernel<<<(KP2 + 7) / 8, 256>>>(X2, p3, PN, SC, KP2);
    topk_kernel<<<1, 1024>>>(SC, KP2, KP3, P2, VAL);
    {
        dim3 g(KP2 / 128, KP2 / 128, 1);
        tf32gemm3z<<<g, 256>>>(A2, A2, G, KP2, KP2, KP2, KP2, KP2, KP2, 1);  // 3xTF32
        pool_A_fused<<<(KP3 * KP3 + 255) / 256, 256>>>(G, A2, KP2, P2, A3, KP3);
        pool_x<<<(KP3 * HP + 255) / 256, 256>>>(X2, P2, VAL, CUR, KP3);
    }
    run_gcn(A3, KP3, CUR, HP, H, w3, b3, X3, 1, 8, 1, T0, T1, PART, DINV);

    // ---- up 0: j=2 ----
    cudaMemcpyAsync(CUR, X2, (size_t)KP2 * HP * sizeof(float), cudaMemcpyDeviceToDevice, 0);
    scatter_add<<<(KP3 * HP + 255) / 256, 256>>>(CUR, X3, P2, KP3);
    run_gcn(A2, KP2, CUR, HP, H, u0w, u0b, X2, 1, 8, 1, T0, T1, PART, DINV);

    // ---- up 1: j=1 ----
    cudaMemcpyAsync(CUR, X1, (size_t)KP1 * HP * sizeof(float), cudaMemcpyDeviceToDevice, 0);
    scatter_add<<<(KP2 * HP + 255) / 256, 256>>>(CUR, X2, P1, KP2);
    run_gcn(A1, KP1, CUR, HP, H, u1w, u1b, X1, 1, 4, 0, T0, T1, PART, DINV);

    // ---- up 2: j=0, final gcn (H->2) + log_softmax ----
    cudaMemcpyAsync(CUR, X0, (size_t)N0 * HP * sizeof(float), cudaMemcpyDeviceToDevice, 0);
    scatter_add<<<(KP1 * HP + 255) / 256, 256>>>(CUR, X1, P0, KP1);
    {
        dim3 gf(1, (N0 + 63) / 64);
        gemm64<<<gf, 256>>>(CUR, u2w, T0, N0, 2, H, HP, 2, 2);
        rowsum_dinv<<<N0, 256>>>(adj, DINV, N0);
        scale_rows<<<(N0 * 2 + 255) / 256, 256>>>(T0, DINV, T1, N0, 2, 2);
        gemm_n2<<<N0, 256>>>(adj, T1, T0, N0);
        final_kernel<<<(N0 + 255) / 256, 256>>>(T0, T1, DINV, u2b, (float*)d_out, N0);
    }
}

// round 5
// speedup vs baseline: 3.7944x; 1.5411x over previous
#include <cuda_runtime.h>
#include <cuda_bf16.h>
#include <math.h>
#include <stdint.h>

#define N0 4096
#define KP1 3072
#define KP2 1536
#define KP3 768
#define H 200
#define HP 256
#define SKMAX 8

// ---------------- device scratch (static: no allocation allowed) ----------------
__device__ float g_G[(size_t)N0 * N0];
__device__ float g_A1[(size_t)KP1 * KP1];
__device__ float g_A2[(size_t)KP2 * KP2];
__device__ float g_A3[(size_t)KP3 * KP3];
__device__ __nv_bfloat16 g_adjb[(size_t)N0 * N0];
__device__ __nv_bfloat16 g_A1b[(size_t)KP1 * KP1];
__device__ float g_x0[N0 * HP];
__device__ float g_x1[KP1 * HP];
__device__ float g_x2[KP2 * HP];
__device__ float g_x3[KP3 * HP];
__device__ float g_t0[N0 * HP];
__device__ float g_t1[N0 * HP];
__device__ float g_part[(size_t)SKMAX * N0 * HP];
__device__ float g_cur[N0 * HP];
__device__ float g_dinv[N0];
__device__ float g_score[N0];
__device__ float g_val[N0];
__device__ int   g_perm0[KP1];
__device__ int   g_perm1[KP2];
__device__ int   g_perm2[KP3];
__device__ float g_pnorm[1];

__device__ __forceinline__ uint32_t f2tf(float x) {
    uint32_t r;
    asm("cvt.rna.tf32.f32 %0, %1;" : "=r"(r) : "f"(x));
    return r;
}

__device__ __forceinline__ void cpa16(uint32_t dst, const void* src) {
    asm volatile("cp.async.cg.shared.global [%0], [%1], 16;\n" :: "r"(dst), "l"(src));
}

// ============ bf16 symmetric-square GEMM: C = A @ A, A symmetric [n][n] bf16 =========
// EXACT for integer-valued A with |A| <= 256 (bf16 ints exact; fp32 accumulate).
// 128x128 tile, BK=32, double-buffered cp.async, mma m16n8k16. n % 128 == 0.
__global__ void __launch_bounds__(256) bf16gemm_sym(
    const __nv_bfloat16* __restrict__ A, float* __restrict__ C, int n)
{
    // [stage][row][40] bf16: stride 40 halves (80B) -> conflict-free 32-bit frag loads
    __shared__ __nv_bfloat16 As[2][128][40];
    __shared__ __nv_bfloat16 Bs[2][128][40];

    int t = threadIdx.x;
    int warp = t >> 5, lane = t & 31;
    int group = lane >> 2, tg = lane & 3;
    int wm = warp >> 2, wn = warp & 3;          // 2x4 warps, warp tile 64x32
    int bm = blockIdx.y * 128, bn = blockIdx.x * 128;

    float c[4][4][4];
#pragma unroll
    for (int mi = 0; mi < 4; mi++)
#pragma unroll
        for (int ni = 0; ni < 4; ni++)
#pragma unroll
            for (int r = 0; r < 4; r++) c[mi][ni][r] = 0.f;

    int lrow = t >> 1;
    int lcol0 = (t & 1) * 16;   // bf16 element offset; covers [lcol0, lcol0+16)

    uint32_t aBase = (uint32_t)__cvta_generic_to_shared(&As[0][0][0]);
    uint32_t bBase = (uint32_t)__cvta_generic_to_shared(&Bs[0][0][0]);
    const uint32_t stageB = 128 * 40 * 2;   // bytes per stage
    uint32_t aDst = aBase + lrow * 80 + lcol0 * 2;
    uint32_t bDst = bBase + lrow * 80 + lcol0 * 2;

    const __nv_bfloat16* aSrcRow = A + (size_t)(bm + lrow) * n + lcol0;
    const __nv_bfloat16* bSrcRow = A + (size_t)(bn + lrow) * n + lcol0;  // symmetry

#define LOAD_STAGE(st, k0)                                        \
    do {                                                          \
        const __nv_bfloat16* ap = aSrcRow + (k0);                 \
        const __nv_bfloat16* bp = bSrcRow + (k0);                 \
        uint32_t ad = aDst + (st) * stageB;                       \
        uint32_t bd = bDst + (st) * stageB;                       \
        cpa16(ad, ap); cpa16(ad + 16, ap + 8);                    \
        cpa16(bd, bp); cpa16(bd + 16, bp + 8);                    \
    } while (0)

    LOAD_STAGE(0, 0);
    asm volatile("cp.async.commit_group;\n");

    int s = 0;
    for (int k0 = 0; k0 < n; k0 += 32) {
        if (k0 + 32 < n) {
            LOAD_STAGE(s ^ 1, k0 + 32);
            asm volatile("cp.async.commit_group;\n");
            asm volatile("cp.async.wait_group 1;\n");
        } else {
            asm volatile("cp.async.wait_group 0;\n");
        }
        __syncthreads();

#pragma unroll
        for (int ks = 0; ks < 2; ks++) {
            int kb = ks * 16;
            uint32_t af[4][4], bf[4][2];
#pragma unroll
            for (int mi = 0; mi < 4; mi++) {
                int rm = wm * 64 + mi * 16 + group;
                af[mi][0] = *(const uint32_t*)&As[s][rm][kb + 2 * tg];
                af[mi][1] = *(const uint32_t*)&As[s][rm + 8][kb + 2 * tg];
                af[mi][2] = *(const uint32_t*)&As[s][rm][kb + 2 * tg + 8];
                af[mi][3] = *(const uint32_t*)&As[s][rm + 8][kb + 2 * tg + 8];
            }
#pragma unroll
            for (int ni = 0; ni < 4; ni++) {
                int cn = wn * 32 + ni * 8 + group;
                bf[ni][0] = *(const uint32_t*)&Bs[s][cn][kb + 2 * tg];
                bf[ni][1] = *(const uint32_t*)&Bs[s][cn][kb + 2 * tg + 8];
            }
#pragma unroll
            for (int mi = 0; mi < 4; mi++)
#pragma unroll
                for (int ni = 0; ni < 4; ni++) {
                    asm volatile(
                        "mma.sync.aligned.m16n8k16.row.col.f32.bf16.bf16.f32 "
                        "{%0,%1,%2,%3}, {%4,%5,%6,%7}, {%8,%9}, {%0,%1,%2,%3};\n"
                        : "+f"(c[mi][ni][0]), "+f"(c[mi][ni][1]),
                          "+f"(c[mi][ni][2]), "+f"(c[mi][ni][3])
                        : "r"(af[mi][0]), "r"(af[mi][1]), "r"(af[mi][2]), "r"(af[mi][3]),
                          "r"(bf[ni][0]), "r"(bf[ni][1]));
                }
        }
        __syncthreads();
        s ^= 1;
    }
#undef LOAD_STAGE

#pragma unroll
    for (int mi = 0; mi < 4; mi++) {
        int row0 = bm + wm * 64 + mi * 16 + group;
#pragma unroll
        for (int ni = 0; ni < 4; ni++) {
            int col = bn + wn * 32 + ni * 8 + tg * 2;
            *(float2*)(C + (size_t)row0 * n + col)       = make_float2(c[mi][ni][0], c[mi][ni][1]);
            *(float2*)(C + (size_t)(row0 + 8) * n + col) = make_float2(c[mi][ni][2], c[mi][ni][3]);
        }
    }
}

// ============ split-TF32 GEMM with split-K partials (templated on ASPLIT) ============
// ASPLIT=0: A exact in tf32 (raw bits); B split hi/lo (2 mma). err ~2^-21.
// ASPLIT=1: A also split, alo*bhi added (3 mma). dropped alo*blo ~2^-22.
template <int ASPLIT>
__global__ void __launch_bounds__(256, (ASPLIT ? 1 : 2)) tf32prop(
    const float* __restrict__ A, const float* __restrict__ B, float* __restrict__ Cpart,
    int M, int N, int K, int lda, int ldb, int ldc)
{
    __shared__ float As[32][136];
    __shared__ float Bs[32][136];

    int t = threadIdx.x;
    int warp = t >> 5, lane = t & 31;
    int group = lane >> 2, tg = lane & 3;
    int wm = warp >> 2, wn = warp & 3;
    int bm = blockIdx.y * 128, bn = blockIdx.x * 128;
    int kChunk = K / gridDim.z;
    int kStart = blockIdx.z * kChunk;
    float* C = Cpart + (size_t)blockIdx.z * M * ldc;

    float c[4][4][4];
#pragma unroll
    for (int mi = 0; mi < 4; mi++)
#pragma unroll
        for (int ni = 0; ni < 4; ni++)
#pragma unroll
            for (int r = 0; r < 4; r++) c[mi][ni][r] = 0.f;

    int ar = t >> 1, ac0 = (t & 1);
    int br = t >> 3, bc0 = t & 7;
    const float* Arow = A + (size_t)(bm + ar) * lda + kStart;

    for (int k0g = 0; k0g < kChunk; k0g += 32) {
#pragma unroll
        for (int q = 0; q < 4; q++) {
            int ac = ac0 + q * 2;
            float4 v = *(const float4*)(Arow + k0g + ac * 4);
            As[ac * 4 + 0][ar] = v.x;
            As[ac * 4 + 1][ar] = v.y;
            As[ac * 4 + 2][ar] = v.z;
            As[ac * 4 + 3][ar] = v.w;
        }
#pragma unroll
        for (int q = 0; q < 4; q++) {
            int bc = bc0 + q * 8;
            float4 v = *(const float4*)(B + (size_t)(kStart + k0g + br) * ldb + bn + bc * 4);
            *(float4*)(&Bs[br][bc * 4]) = v;
        }
        __syncthreads();

#pragma unroll
        for (int ks = 0; ks < 4; ks++) {
            int kb = ks * 8;
            uint32_t afh[4][4], afl[4][4], bfh[4][2], bfl[4][2];
#pragma unroll
            for (int mi = 0; mi < 4; mi++) {
                int rm = wm * 64 + mi * 16 + group;
                float a0 = As[kb + tg][rm];
                float a1 = As[kb + tg][rm + 8];
                float a2 = As[kb + tg + 4][rm];
                float a3 = As[kb + tg + 4][rm + 8];
                if (ASPLIT) {
                    afh[mi][0] = f2tf(a0); afh[mi][1] = f2tf(a1);
                    afh[mi][2] = f2tf(a2); afh[mi][3] = f2tf(a3);
                    afl[mi][0] = f2tf(a0 - __uint_as_float(afh[mi][0]));
                    afl[mi][1] = f2tf(a1 - __uint_as_float(afh[mi][1]));
                    afl[mi][2] = f2tf(a2 - __uint_as_float(afh[mi][2]));
                    afl[mi][3] = f2tf(a3 - __uint_as_float(afh[mi][3]));
                } else {
                    afh[mi][0] = __float_as_uint(a0); afh[mi][1] = __float_as_uint(a1);
                    afh[mi][2] = __float_as_uint(a2); afh[mi][3] = __float_as_uint(a3);
                }
            }
#pragma unroll
            for (int ni = 0; ni < 4; ni++) {
                int cn = wn * 32 + ni * 8 + group;
                float b0 = Bs[kb + tg][cn];
                float b1 = Bs[kb + tg + 4][cn];
                bfh[ni][0] = f2tf(b0);
                bfh[ni][1] = f2tf(b1);
                bfl[ni][0] = f2tf(b0 - __uint_as_float(bfh[ni][0]));
                bfl[ni][1] = f2tf(b1 - __uint_as_float(bfh[ni][1]));
            }
#pragma unroll
            for (int mi = 0; mi < 4; mi++)
#pragma unroll
                for (int ni = 0; ni < 4; ni++) {
                    asm volatile(
                        "mma.sync.aligned.m16n8k8.row.col.f32.tf32.tf32.f32 "
                        "{%0,%1,%2,%3}, {%4,%5,%6,%7}, {%8,%9}, {%0,%1,%2,%3};\n"
                        : "+f"(c[mi][ni][0]), "+f"(c[mi][ni][1]),
                          "+f"(c[mi][ni][2]), "+f"(c[mi][ni][3])
                        : "r"(afh[mi][0]), "r"(afh[mi][1]), "r"(afh[mi][2]), "r"(afh[mi][3]),
                          "r"(bfl[ni][0]), "r"(bfl[ni][1]));
                    if (ASPLIT) {
                        asm volatile(
                            "mma.sync.aligned.m16n8k8.row.col.f32.tf32.tf32.f32 "
                            "{%0,%1,%2,%3}, {%4,%5,%6,%7}, {%8,%9}, {%0,%1,%2,%3};\n"
                            : "+f"(c[mi][ni][0]), "+f"(c[mi][ni][1]),
                              "+f"(c[mi][ni][2]), "+f"(c[mi][ni][3])
                            : "r"(afl[mi][0]), "r"(afl[mi][1]), "r"(afl[mi][2]), "r"(afl[mi][3]),
                              "r"(bfh[ni][0]), "r"(bfh[ni][1]));
                    }
                    asm volatile(
                        "mma.sync.aligned.m16n8k8.row.col.f32.tf32.tf32.f32 "
                        "{%0,%1,%2,%3}, {%4,%5,%6,%7}, {%8,%9}, {%0,%1,%2,%3};\n"
                        : "+f"(c[mi][ni][0]), "+f"(c[mi][ni][1]),
                          "+f"(c[mi][ni][2]), "+f"(c[mi][ni][3])
                        : "r"(afh[mi][0]), "r"(afh[mi][1]), "r"(afh[mi][2]), "r"(afh[mi][3]),
                          "r"(bfh[ni][0]), "r"(bfh[ni][1]));
                }
        }
        __syncthreads();
    }

#pragma unroll
    for (int mi = 0; mi < 4; mi++) {
        int row0 = bm + wm * 64 + mi * 16 + group;
#pragma unroll
        for (int ni = 0; ni < 4; ni++) {
            int col = bn + wn * 32 + ni * 8 + tg * 2;
            *(float2*)(C + (size_t)row0 * ldc + col)       = make_float2(c[mi][ni][0], c[mi][ni][1]);
            *(float2*)(C + (size_t)(row0 + 8) * ldc + col) = make_float2(c[mi][ni][2], c[mi][ni][3]);
        }
    }
}

// ---------------- generic SGEMM: 64x64 block, 4x4 per thread, bounds-checked --------
__global__ void __launch_bounds__(256) gemm64(
    const float* __restrict__ A, const float* __restrict__ B, float* __restrict__ C,
    int M, int N, int K, int lda, int ldb, int ldc)
{
    __shared__ float As[16][65];
    __shared__ float Bs[16][64];
    int tid = threadIdx.x, tx = tid & 15, ty = tid >> 4;
    int bm = blockIdx.y * 64, bn = blockIdx.x * 64;
    float acc[4][4];
#pragma unroll
    for (int i = 0; i < 4; i++)
#pragma unroll
        for (int j = 0; j < 4; j++) acc[i][j] = 0.f;

    for (int k0 = 0; k0 < K; k0 += 16) {
        for (int t = tid; t < 64 * 16; t += 256) {
            int r = t >> 4, c = t & 15;
            int gr = bm + r, gc = k0 + c;
            As[c][r] = (gr < M && gc < K) ? A[(size_t)gr * lda + gc] : 0.f;
        }
        for (int t = tid; t < 16 * 64; t += 256) {
            int r = t >> 6, c = t & 63;
            int gr = k0 + r, gc = bn + c;
            Bs[r][c] = (gr < K && gc < N) ? B[(size_t)gr * ldb + gc] : 0.f;
        }
        __syncthreads();
#pragma unroll
        for (int kk = 0; kk < 16; kk++) {
            float a[4], b[4];
#pragma unroll
            for (int i = 0; i < 4; i++) a[i] = As[kk][ty * 4 + i];
#pragma unroll
            for (int j = 0; j < 4; j++) b[j] = Bs[kk][tx * 4 + j];
#pragma unroll
            for (int i = 0; i < 4; i++)
#pragma unroll
                for (int j = 0; j < 4; j++) acc[i][j] += a[i] * b[j];
        }
        __syncthreads();
    }
#pragma unroll
    for (int i = 0; i < 4; i++)
#pragma unroll
        for (int j = 0; j < 4; j++) {
            int gr = bm + ty * 4 + i, gc = bn + tx * 4 + j;
            if (gr < M && gc < N) C[(size_t)gr * ldc + gc] = acc[i][j];
        }
}

// ---------------- small helper kernels ----------------
__global__ void f32_to_bf16_kernel(const float* __restrict__ in,
                                   __nv_bfloat16* __restrict__ out, size_t n4)
{
    size_t i = (size_t)blockIdx.x * 256 + threadIdx.x;
    if (i >= n4) return;
    float4 v = *(const float4*)(in + i * 4);
    __nv_bfloat162 a = __floats2bfloat162_rn(v.x, v.y);
    __nv_bfloat162 b = __floats2bfloat162_rn(v.z, v.w);
    *(__nv_bfloat162*)(out + i * 4)     = a;
    *(__nv_bfloat162*)(out + i * 4 + 2) = b;
}

__global__ void rowsum_dinv(const float* __restrict__ A, float* __restrict__ dinv, int n)
{
    int row = blockIdx.x;
    const float* Ar = A + (size_t)row * n;
    float s = 0.f;
    for (int j = threadIdx.x; j < n; j += 256) s += Ar[j];
    for (int o = 16; o > 0; o >>= 1) s += __shfl_down_sync(0xffffffffu, s, o);
    __shared__ float red[8];
    int w = threadIdx.x >> 5, l = threadIdx.x & 31;
    if (l == 0) red[w] = s;
    __syncthreads();
    if (threadIdx.x == 0) {
        float t = 0.f;
        for (int i = 0; i < 8; i++) t += red[i];
        dinv[row] = 1.0f / sqrtf(t + 2.0f);
    }
}

__global__ void scale_rows(const float* __restrict__ in, const float* __restrict__ dinv,
                           float* __restrict__ out, int n, int w, int ld)
{
    int idx = blockIdx.x * 256 + threadIdx.x;
    if (idx >= n * ld) return;
    int r = idx / ld, c = idx - r * ld;
    out[idx] = (c < w) ? dinv[r] * in[idx] : 0.f;
}

__global__ void gcn_finish_sk(const float* __restrict__ part, const float* __restrict__ Z,
                              const float* __restrict__ dinv, const float* __restrict__ b,
                              float* __restrict__ out, int n, int relu, int S)
{
    int idx = blockIdx.x * 256 + threadIdx.x;
    if (idx >= n * HP) return;
    int r = idx / HP, c = idx - r * HP;
    float v = 0.f;
    if (c < H) {
        float az = 0.f;
        size_t stride = (size_t)n * HP;
        for (int s = 0; s < S; s++) az += part[s * stride + idx];
        v = dinv[r] * (az + 2.f * Z[idx]) + b[c];
        if (relu) v = fmaxf(v, 0.f);
    }
    out[idx] = v;
}

__global__ void pnorm_kernel(const float* __restrict__ p, float* __restrict__ out)
{
    float s = 0.f;
    for (int i = threadIdx.x; i < H; i += 256) { float v = p[i]; s += v * v; }
    for (int o = 16; o > 0; o >>= 1) s += __shfl_down_sync(0xffffffffu, s, o);
    __shared__ float red[8];
    int w = threadIdx.x >> 5, l = threadIdx.x & 31;
    if (l == 0) red[w] = s;
    __syncthreads();
    if (threadIdx.x == 0) {
        float t = 0.f;
        for (int i = 0; i < 8; i++) t += red[i];
        *out = sqrtf(t);
    }
}

__global__ void score_kernel(const float* __restrict__ x, const float* __restrict__ p,
                             const float* __restrict__ pn, float* __restrict__ score, int n)
{
    int row = blockIdx.x * 8 + (threadIdx.x >> 5);
    int lane = threadIdx.x & 31;
    if (row >= n) return;
    const float* xr = x + (size_t)row * HP;
    float s = 0.f;
    for (int c = lane; c < H; c += 32) s += xr[c] * p[c];
    for (int o = 16; o > 0; o >>= 1) s += __shfl_down_sync(0xffffffffu, s, o);
    if (lane == 0) score[row] = tanhf(s / (*pn));
}

// uint64-key bitonic topk: key = (~sortable(score) << 32) | index, ascending sort.
// Result: descending score, ties -> smaller index first (matches jax top_k).
__global__ void topk_kernel(const float* __restrict__ score, int n, int k,
                            int* __restrict__ perm, float* __restrict__ val)
{
    __shared__ unsigned long long key[4096];
    int tid = threadIdx.x;
    for (int i = tid; i < 4096; i += 1024) {
        float s = (i < n) ? score[i] : -INFINITY;
        uint32_t u = __float_as_uint(s);
        u = (u & 0x80000000u) ? ~u : (u | 0x80000000u);   // ascending-sortable
        uint32_t d = ~u;                                   // descending score
        key[i] = ((unsigned long long)d << 32) | (uint32_t)i;
    }
    __syncthreads();
    for (int size = 2; size <= 4096; size <<= 1) {
        for (int stride = size >> 1; stride > 0; stride >>= 1) {
            for (int i = tid; i < 4096; i += 1024) {
                int j = i ^ stride;
                if (j > i) {
                    unsigned long long a = key[i], b = key[j];
                    bool up = ((i & size) == 0);
                    if (up ? (a > b) : (a < b)) { key[i] = b; key[j] = a; }
                }
            }
            __syncthreads();
        }
    }
    for (int i = tid; i < k; i += 1024) {
        int si = (int)(uint32_t)key[i];
        perm[i] = si;
        val[i] = score[si];
    }
}

// fused: A_out[i][j] = (i==j) ? 0 : G[pi][pj] + 2*A[pi][pj]   (G = A@A)
__global__ void pool_A_fused(const float* __restrict__ G, const float* __restrict__ Asrc,
                             int ldg, const int* __restrict__ perm,
                             float* __restrict__ Aout, int k)
{
    int idx = blockIdx.x * 256 + threadIdx.x;
    if (idx >= k * k) return;
    int i = idx / k, j = idx - i * k;
    if (i == j) { Aout[idx] = 0.f; return; }
    size_t off = (size_t)perm[i] * ldg + perm[j];
    Aout[idx] = G[off] + 2.f * Asrc[off];
}

__global__ void pool_x(const float* __restrict__ xin, const int* __restrict__ perm,
                       const float* __restrict__ val, float* __restrict__ xout, int k)
{
    int idx = blockIdx.x * 256 + threadIdx.x;
    if (idx >= k * HP) return;
    int r = idx / HP, c = idx - r * HP;
    xout[idx] = xin[(size_t)perm[r] * HP + c] * val[r];
}

__global__ void scatter_add(float* __restrict__ dst, const float* __restrict__ x,
                            const int* __restrict__ perm, int k)
{
    int idx = blockIdx.x * 256 + threadIdx.x;
    if (idx >= k * HP) return;
    int r = idx / HP, c = idx - r * HP;
    dst[(size_t)perm[r] * HP + c] += x[idx];
}

__global__ void gemm_n2(const float* __restrict__ A, const float* __restrict__ Z,
                        float* __restrict__ out, int n)
{
    int row = blockIdx.x;
    const float* Ar = A + (size_t)row * n;
    float a0 = 0.f, a1 = 0.f;
    for (int j = threadIdx.x; j < n; j += 256) {
        float a = Ar[j];
        a0 += a * Z[2 * j];
        a1 += a * Z[2 * j + 1];
    }
    for (int o = 16; o > 0; o >>= 1) {
        a0 += __shfl_down_sync(0xffffffffu, a0, o);
        a1 += __shfl_down_sync(0xffffffffu, a1, o);
    }
    __shared__ float r0[8], r1[8];
    int w = threadIdx.x >> 5, l = threadIdx.x & 31;
    if (l == 0) { r0[w] = a0; r1[w] = a1; }
    __syncthreads();
    if (threadIdx.x == 0) {
        float s0 = 0.f, s1 = 0.f;
        for (int i = 0; i < 8; i++) { s0 += r0[i]; s1 += r1[i]; }
        out[2 * row] = s0;
        out[2 * row + 1] = s1;
    }
}

__global__ void final_kernel(const float* __restrict__ AZ, const float* __restrict__ Z,
                             const float* __restrict__ dinv, const float* __restrict__ b,
                             float* __restrict__ out, int n)
{
    int i = blockIdx.x * 256 + threadIdx.x;
    if (i >= n) return;
    float a = dinv[i] * (AZ[2 * i]     + 2.f * Z[2 * i])     + b[0];
    float c = dinv[i] * (AZ[2 * i + 1] + 2.f * Z[2 * i + 1]) + b[1];
    float m = fmaxf(a, c);
    float l = m + logf(expf(a - m) + expf(c - m));
    out[2 * i] = a - l;
    out[2 * i + 1] = c - l;
}

// ---------------- host orchestration ----------------
template <typename T, size_t NN>
static T* symaddr(T (&sym)[NN]) {
    void* p = nullptr;
    cudaGetSymbolAddress(&p, sym);
    return (T*)p;
}

static void run_gcn(const float* A, int n, const float* xin, int lda_x, int Kdim,
                    const float* W, const float* b, float* xout, int relu,
                    int S, int asplit,
                    float* t0, float* t1, float* part, float* dinv)
{
    dim3 g1((H + 63) / 64, (n + 63) / 64);
    gemm64<<<g1, 256>>>(xin, W, t0, n, H, Kdim, lda_x, H, HP);
    rowsum_dinv<<<n, 256>>>(A, dinv, n);
    int tot = n * HP;
    scale_rows<<<(tot + 255) / 256, 256>>>(t0, dinv, t1, n, H, HP);
    dim3 g2(HP / 128, n / 128, S);
    if (asplit)
        tf32prop<1><<<g2, 256>>>(A, t1, part, n, HP, n, n, HP, HP);
    else
        tf32prop<0><<<g2, 256>>>(A, t1, part, n, HP, n, n, HP, HP);
    gcn_finish_sk<<<(tot + 255) / 256, 256>>>(part, t1, dinv, b, xout, n, relu, S);
}

extern "C" void kernel_launch(void* const* d_in, const int* in_sizes, int n_in,
                              void* d_out, int out_size)
{
    (void)in_sizes; (void)n_in; (void)out_size;
    const float* x   = (const float*)d_in[0];
    const float* adj = (const float*)d_in[1];
    const float* w0  = (const float*)d_in[2];
    const float* b0  = (const float*)d_in[3];
    const float* w1  = (const float*)d_in[4];
    const float* b1  = (const float*)d_in[5];
    const float* w2  = (const float*)d_in[6];
    const float* b2  = (const float*)d_in[7];
    const float* w3  = (const float*)d_in[8];
    const float* b3  = (const float*)d_in[9];
    const float* p1  = (const float*)d_in[10];
    const float* p2  = (const float*)d_in[11];
    const float* p3  = (const float*)d_in[12];
    const float* u0w = (const float*)d_in[13];
    const float* u0b = (const float*)d_in[14];
    const float* u1w = (const float*)d_in[15];
    const float* u1b = (const float*)d_in[16];
    const float* u2w = (const float*)d_in[17];
    const float* u2b = (const float*)d_in[18];

    float* G    = symaddr(g_G);
    float* A1   = symaddr(g_A1);
    float* A2   = symaddr(g_A2);
    float* A3   = symaddr(g_A3);
    __nv_bfloat16* ADJB = symaddr(g_adjb);
    __nv_bfloat16* A1B  = symaddr(g_A1b);
    float* X0   = symaddr(g_x0);
    float* X1   = symaddr(g_x1);
    float* X2   = symaddr(g_x2);
    float* X3   = symaddr(g_x3);
    float* T0   = symaddr(g_t0);
    float* T1   = symaddr(g_t1);
    float* PART = symaddr(g_part);
    float* CUR  = symaddr(g_cur);
    float* DINV = symaddr(g_dinv);
    float* SC   = symaddr(g_score);
    float* VAL  = symaddr(g_val);
    int*   P0   = symaddr(g_perm0);
    int*   P1   = symaddr(g_perm1);
    int*   P2   = symaddr(g_perm2);
    float* PN   = symaddr(g_pnorm);

    // ---- bf16 copy of adj (exact: binary) ----
    {
        size_t n4 = ((size_t)N0 * N0) / 4;
        f32_to_bf16_kernel<<<(unsigned)((n4 + 255) / 256), 256>>>(adj, ADJB, n4);
    }

    // ---- down: gcn0 (adj binary -> exact in tf32, asplit=0) ----
    run_gcn(adj, N0, x, 3, 3, w0, b0, X0, 1, 4, 0, T0, T1, PART, DINV);

    // ---- pool 1 (4096 -> 3072) ----
    pnorm_kernel<<<1, 256>>>(p1, PN);
    score_kernel<<<(N0 + 7) / 8, 256>>>(X0, p1, PN, SC, N0);
    topk_kernel<<<1, 1024>>>(SC, N0, KP1, P0, VAL);
    {
        dim3 g(N0 / 128, N0 / 128);
        bf16gemm_sym<<<g, 256>>>(ADJB, G, N0);   // exact: binary, symmetric
        pool_A_fused<<<(KP1 * KP1 + 255) / 256, 256>>>(G, adj, N0, P0, A1, KP1);
        pool_x<<<(KP1 * HP + 255) / 256, 256>>>(X0, P0, VAL, CUR, KP1);
        size_t n4 = ((size_t)KP1 * KP1) / 4;
        f32_to_bf16_kernel<<<(unsigned)((n4 + 255) / 256), 256>>>(A1, A1B, n4);  // exact: ints <= 62
    }
    run_gcn(A1, KP1, CUR, HP, H, w1, b1, X1, 1, 6, 0, T0, T1, PART, DINV);

    // ---- pool 2 (3072 -> 1536) ----
    pnorm_kernel<<<1, 256>>>(p2, PN);
    score_kernel<<<(KP1 + 7) / 8, 256>>>(X1, p2, PN, SC, KP1);
    topk_kernel<<<1, 1024>>>(SC, KP1, KP2, P1, VAL);
    {
        dim3 g(KP1 / 128, KP1 / 128);
        bf16gemm_sym<<<g, 256>>>(A1B, G, KP1);   // exact: small ints, symmetric
        pool_A_fused<<<(KP2 * KP2 + 255) / 256, 256>>>(G, A1, KP1, P1, A2, KP2);
        pool_x<<<(KP2 * HP + 255) / 256, 256>>>(X1, P1, VAL, CUR, KP2);
    }
    run_gcn(A2, KP2, CUR, HP, H, w2, b2, X2, 1, 8, 1, T0, T1, PART, DINV);

    // ---- pool 3 (1536 -> 768) ----
    pnorm_kernel<<<1, 256>>>(p3, PN);
    score_kernel<<<(KP2 + 7) / 8, 256>>>(X2, p3, PN, SC, KP2);
    topk_kernel<<<1, 1024>>>(SC, KP2, KP3, P2, VAL);
    {
        dim3 g(KP2 / 128, KP2 / 128, 1);
        tf32prop<1><<<g, 256>>>(A2, A2, G, KP2, KP2, KP2, KP2, KP2, KP2);  // 3xTF32, S=1
        pool_A_fused<<<(KP3 * KP3 + 255) / 256, 256>>>(G, A2, KP2, P2, A3, KP3);
        pool_x<<<(KP3 * HP + 255) / 256, 256>>>(X2, P2, VAL, CUR, KP3);
    }
    run_gcn(A3, KP3, CUR, HP, H, w3, b3, X3, 1, 8, 1, T0, T1, PART, DINV);

    // ---- up 0: j=2 ----
    cudaMemcpyAsync(CUR, X2, (size_t)KP2 * HP * sizeof(float), cudaMemcpyDeviceToDevice, 0);
    scatter_add<<<(KP3 * HP + 255) / 256, 256>>>(CUR, X3, P2, KP3);
    run_gcn(A2, KP2, CUR, HP, H, u0w, u0b, X2, 1, 8, 1, T0, T1, PART, DINV);

    // ---- up 1: j=1 ----
    cudaMemcpyAsync(CUR, X1, (size_t)KP1 * HP * sizeof(float), cudaMemcpyDeviceToDevice, 0);
    scatter_add<<<(KP2 * HP + 255) / 256, 256>>>(CUR, X2, P1, KP2);
    run_gcn(A1, KP1, CUR, HP, H, u1w, u1b, X1, 1, 6, 0, T0, T1, PART, DINV);

    // ---- up 2: j=0, final gcn (H->2) + log_softmax ----
    cudaMemcpyAsync(CUR, X0, (size_t)N0 * HP * sizeof(float), cudaMemcpyDeviceToDevice, 0);
    scatter_add<<<(KP1 * HP + 255) / 256, 256>>>(CUR, X1, P0, KP1);
    {
        dim3 gf(1, (N0 + 63) / 64);
        gemm64<<<gf, 256>>>(CUR, u2w, T0, N0, 2, H, HP, 2, 2);
        rowsum_dinv<<<N0, 256>>>(adj, DINV, N0);
        scale_rows<<<(N0 * 2 + 255) / 256, 256>>>(T0, DINV, T1, N0, 2, 2);
        gemm_n2<<<N0, 256>>>(adj, T1, T0, N0);
        final_kernel<<<(N0 + 255) / 256, 256>>>(T0, T1, DINV, u2b, (float*)d_out, N0);
    }
}

// round 6
// speedup vs baseline: 5.4869x; 1.4460x over previous
#include <cuda_runtime.h>
#include <cuda_bf16.h>
#include <math.h>
#include <stdint.h>

#define N0 4096
#define KP1 3072
#define KP2 1536
#define KP3 768
#define H 200
#define HP 256
#define SKMAX 8

// ---------------- device scratch (static: no allocation allowed) ----------------
__device__ float g_G[(size_t)N0 * N0];                 // augment output (level sized)
__device__ __nv_bfloat16 g_rows[(size_t)KP1 * N0];     // gathered bf16 rows
__device__ float g_A1[(size_t)KP1 * KP1];
__device__ float g_A2[(size_t)KP2 * KP2];
__device__ float g_A3[(size_t)KP3 * KP3];
__device__ float g_x0[N0 * HP];
__device__ float g_x1[KP1 * HP];
__device__ float g_x2[KP2 * HP];
__device__ float g_x3[KP3 * HP];
__device__ float g_t0[N0 * HP];
__device__ float g_t1[N0 * HP];
__device__ float g_part[(size_t)SKMAX * N0 * HP];
__device__ float g_cur[N0 * HP];
__device__ float g_dinv[N0];
__device__ float g_score[N0];
__device__ float g_val[N0];
__device__ int   g_perm0[KP1];
__device__ int   g_perm1[KP2];
__device__ int   g_perm2[KP3];
__device__ float g_pnorm[1];

__device__ __forceinline__ uint32_t f2tf(float x) {
    uint32_t r;
    asm("cvt.rna.tf32.f32 %0, %1;" : "=r"(r) : "f"(x));
    return r;
}

__device__ __forceinline__ void cpa16(uint32_t dst, const void* src) {
    asm volatile("cp.async.cg.shared.global [%0], [%1], 16;\n" :: "r"(dst), "l"(src));
}

// ============ bf16 X·X^T GEMM, lower triangle only ===================================
// C[k][k] = X[k][K] @ X[k][K]^T. Only blocks with blockIdx.x <= blockIdx.y computed;
// consumer reads C[max][min]. EXACT for integer X with |X| <= 256 (fp32 accumulate,
// sums < 2^24). k % 128 == 0, K % 32 == 0.
__global__ void __launch_bounds__(256) bf16gemm_xxt(
    const __nv_bfloat16* __restrict__ X, float* __restrict__ C, int k, int K)
{
    if (blockIdx.x > blockIdx.y) return;   // lower triangle only (bn <= bm)

    __shared__ __nv_bfloat16 As[2][128][40];
    __shared__ __nv_bfloat16 Bs[2][128][40];

    int t = threadIdx.x;
    int warp = t >> 5, lane = t & 31;
    int group = lane >> 2, tg = lane & 3;
    int wm = warp >> 2, wn = warp & 3;
    int bm = blockIdx.y * 128, bn = blockIdx.x * 128;

    float c[4][4][4];
#pragma unroll
    for (int mi = 0; mi < 4; mi++)
#pragma unroll
        for (int ni = 0; ni < 4; ni++)
#pragma unroll
            for (int r = 0; r < 4; r++) c[mi][ni][r] = 0.f;

    int lrow = t >> 1;
    int lcol0 = (t & 1) * 16;

    uint32_t aBase = (uint32_t)__cvta_generic_to_shared(&As[0][0][0]);
    uint32_t bBase = (uint32_t)__cvta_generic_to_shared(&Bs[0][0][0]);
    const uint32_t stageB = 128 * 40 * 2;
    uint32_t aDst = aBase + lrow * 80 + lcol0 * 2;
    uint32_t bDst = bBase + lrow * 80 + lcol0 * 2;

    const __nv_bfloat16* aSrcRow = X + (size_t)(bm + lrow) * K + lcol0;
    const __nv_bfloat16* bSrcRow = X + (size_t)(bn + lrow) * K + lcol0;

#define LOAD_STAGE(st, k0)                                        \
    do {                                                          \
        const __nv_bfloat16* ap = aSrcRow + (k0);                 \
        const __nv_bfloat16* bp = bSrcRow + (k0);                 \
        uint32_t ad = aDst + (st) * stageB;                       \
        uint32_t bd = bDst + (st) * stageB;                       \
        cpa16(ad, ap); cpa16(ad + 16, ap + 8);                    \
        cpa16(bd, bp); cpa16(bd + 16, bp + 8);                    \
    } while (0)

    LOAD_STAGE(0, 0);
    asm volatile("cp.async.commit_group;\n");

    int s = 0;
    for (int k0 = 0; k0 < K; k0 += 32) {
        if (k0 + 32 < K) {
            LOAD_STAGE(s ^ 1, k0 + 32);
            asm volatile("cp.async.commit_group;\n");
            asm volatile("cp.async.wait_group 1;\n");
        } else {
            asm volatile("cp.async.wait_group 0;\n");
        }
        __syncthreads();

#pragma unroll
        for (int ks = 0; ks < 2; ks++) {
            int kb = ks * 16;
            uint32_t af[4][4], bf[4][2];
#pragma unroll
            for (int mi = 0; mi < 4; mi++) {
                int rm = wm * 64 + mi * 16 + group;
                af[mi][0] = *(const uint32_t*)&As[s][rm][kb + 2 * tg];
                af[mi][1] = *(const uint32_t*)&As[s][rm + 8][kb + 2 * tg];
                af[mi][2] = *(const uint32_t*)&As[s][rm][kb + 2 * tg + 8];
                af[mi][3] = *(const uint32_t*)&As[s][rm + 8][kb + 2 * tg + 8];
            }
#pragma unroll
            for (int ni = 0; ni < 4; ni++) {
                int cn = wn * 32 + ni * 8 + group;
                bf[ni][0] = *(const uint32_t*)&Bs[s][cn][kb + 2 * tg];
                bf[ni][1] = *(const uint32_t*)&Bs[s][cn][kb + 2 * tg + 8];
            }
#pragma unroll
            for (int mi = 0; mi < 4; mi++)
#pragma unroll
                for (int ni = 0; ni < 4; ni++) {
                    asm volatile(
                        "mma.sync.aligned.m16n8k16.row.col.f32.bf16.bf16.f32 "
                        "{%0,%1,%2,%3}, {%4,%5,%6,%7}, {%8,%9}, {%0,%1,%2,%3};\n"
                        : "+f"(c[mi][ni][0]), "+f"(c[mi][ni][1]),
                          "+f"(c[mi][ni][2]), "+f"(c[mi][ni][3])
                        : "r"(af[mi][0]), "r"(af[mi][1]), "r"(af[mi][2]), "r"(af[mi][3]),
                          "r"(bf[ni][0]), "r"(bf[ni][1]));
                }
        }
        __syncthreads();
        s ^= 1;
    }
#undef LOAD_STAGE

#pragma unroll
    for (int mi = 0; mi < 4; mi++) {
        int row0 = bm + wm * 64 + mi * 16 + group;
#pragma unroll
        for (int ni = 0; ni < 4; ni++) {
            int col = bn + wn * 32 + ni * 8 + tg * 2;
            *(float2*)(C + (size_t)row0 * k + col)       = make_float2(c[mi][ni][0], c[mi][ni][1]);
            *(float2*)(C + (size_t)(row0 + 8) * k + col) = make_float2(c[mi][ni][2], c[mi][ni][3]);
        }
    }
}

// ============ split-TF32 GEMM with split-K partials (templated on ASPLIT) ============
template <int ASPLIT>
__global__ void __launch_bounds__(256, (ASPLIT ? 1 : 2)) tf32prop(
    const float* __restrict__ A, const float* __restrict__ B, float* __restrict__ Cpart,
    int M, int N, int K, int lda, int ldb, int ldc)
{
    __shared__ float As[32][136];
    __shared__ float Bs[32][136];

    int t = threadIdx.x;
    int warp = t >> 5, lane = t & 31;
    int group = lane >> 2, tg = lane & 3;
    int wm = warp >> 2, wn = warp & 3;
    int bm = blockIdx.y * 128, bn = blockIdx.x * 128;
    int kChunk = K / gridDim.z;
    int kStart = blockIdx.z * kChunk;
    float* C = Cpart + (size_t)blockIdx.z * M * ldc;

    float c[4][4][4];
#pragma unroll
    for (int mi = 0; mi < 4; mi++)
#pragma unroll
        for (int ni = 0; ni < 4; ni++)
#pragma unroll
            for (int r = 0; r < 4; r++) c[mi][ni][r] = 0.f;

    int ar = t >> 1, ac0 = (t & 1);
    int br = t >> 3, bc0 = t & 7;
    const float* Arow = A + (size_t)(bm + ar) * lda + kStart;

    for (int k0g = 0; k0g < kChunk; k0g += 32) {
#pragma unroll
        for (int q = 0; q < 4; q++) {
            int ac = ac0 + q * 2;
            float4 v = *(const float4*)(Arow + k0g + ac * 4);
            As[ac * 4 + 0][ar] = v.x;
            As[ac * 4 + 1][ar] = v.y;
            As[ac * 4 + 2][ar] = v.z;
            As[ac * 4 + 3][ar] = v.w;
        }
#pragma unroll
        for (int q = 0; q < 4; q++) {
            int bc = bc0 + q * 8;
            float4 v = *(const float4*)(B + (size_t)(kStart + k0g + br) * ldb + bn + bc * 4);
            *(float4*)(&Bs[br][bc * 4]) = v;
        }
        __syncthreads();

#pragma unroll
        for (int ks = 0; ks < 4; ks++) {
            int kb = ks * 8;
            uint32_t afh[4][4], afl[4][4], bfh[4][2], bfl[4][2];
#pragma unroll
            for (int mi = 0; mi < 4; mi++) {
                int rm = wm * 64 + mi * 16 + group;
                float a0 = As[kb + tg][rm];
                float a1 = As[kb + tg][rm + 8];
                float a2 = As[kb + tg + 4][rm];
                float a3 = As[kb + tg + 4][rm + 8];
                if (ASPLIT) {
                    afh[mi][0] = f2tf(a0); afh[mi][1] = f2tf(a1);
                    afh[mi][2] = f2tf(a2); afh[mi][3] = f2tf(a3);
                    afl[mi][0] = f2tf(a0 - __uint_as_float(afh[mi][0]));
                    afl[mi][1] = f2tf(a1 - __uint_as_float(afh[mi][1]));
                    afl[mi][2] = f2tf(a2 - __uint_as_float(afh[mi][2]));
                    afl[mi][3] = f2tf(a3 - __uint_as_float(afh[mi][3]));
                } else {
                    afh[mi][0] = __float_as_uint(a0); afh[mi][1] = __float_as_uint(a1);
                    afh[mi][2] = __float_as_uint(a2); afh[mi][3] = __float_as_uint(a3);
                }
            }
#pragma unroll
            for (int ni = 0; ni < 4; ni++) {
                int cn = wn * 32 + ni * 8 + group;
                float b0 = Bs[kb + tg][cn];
                float b1 = Bs[kb + tg + 4][cn];
                bfh[ni][0] = f2tf(b0);
                bfh[ni][1] = f2tf(b1);
                bfl[ni][0] = f2tf(b0 - __uint_as_float(bfh[ni][0]));
                bfl[ni][1] = f2tf(b1 - __uint_as_float(bfh[ni][1]));
            }
#pragma unroll
            for (int mi = 0; mi < 4; mi++)
#pragma unroll
                for (int ni = 0; ni < 4; ni++) {
                    asm volatile(
                        "mma.sync.aligned.m16n8k8.row.col.f32.tf32.tf32.f32 "
                        "{%0,%1,%2,%3}, {%4,%5,%6,%7}, {%8,%9}, {%0,%1,%2,%3};\n"
                        : "+f"(c[mi][ni][0]), "+f"(c[mi][ni][1]),
                          "+f"(c[mi][ni][2]), "+f"(c[mi][ni][3])
                        : "r"(afh[mi][0]), "r"(afh[mi][1]), "r"(afh[mi][2]), "r"(afh[mi][3]),
                          "r"(bfl[ni][0]), "r"(bfl[ni][1]));
                    if (ASPLIT) {
                        asm volatile(
                            "mma.sync.aligned.m16n8k8.row.col.f32.tf32.tf32.f32 "
                            "{%0,%1,%2,%3}, {%4,%5,%6,%7}, {%8,%9}, {%0,%1,%2,%3};\n"
                            : "+f"(c[mi][ni][0]), "+f"(c[mi][ni][1]),
                              "+f"(c[mi][ni][2]), "+f"(c[mi][ni][3])
                            : "r"(afl[mi][0]), "r"(afl[mi][1]), "r"(afl[mi][2]), "r"(afl[mi][3]),
                              "r"(bfh[ni][0]), "r"(bfh[ni][1]));
                    }
                    asm volatile(
                        "mma.sync.aligned.m16n8k8.row.col.f32.tf32.tf32.f32 "
                        "{%0,%1,%2,%3}, {%4,%5,%6,%7}, {%8,%9}, {%0,%1,%2,%3};\n"
                        : "+f"(c[mi][ni][0]), "+f"(c[mi][ni][1]),
                          "+f"(c[mi][ni][2]), "+f"(c[mi][ni][3])
                        : "r"(afh[mi][0]), "r"(afh[mi][1]), "r"(afh[mi][2]), "r"(afh[mi][3]),
                          "r"(bfh[ni][0]), "r"(bfh[ni][1]));
                }
        }
        __syncthreads();
    }

#pragma unroll
    for (int mi = 0; mi < 4; mi++) {
        int row0 = bm + wm * 64 + mi * 16 + group;
#pragma unroll
        for (int ni = 0; ni < 4; ni++) {
            int col = bn + wn * 32 + ni * 8 + tg * 2;
            *(float2*)(C + (size_t)row0 * ldc + col)       = make_float2(c[mi][ni][0], c[mi][ni][1]);
            *(float2*)(C + (size_t)(row0 + 8) * ldc + col) = make_float2(c[mi][ni][2], c[mi][ni][3]);
        }
    }
}

// ---------------- generic SGEMM: 64x64 block, 4x4 per thread, bounds-checked --------
__global__ void __launch_bounds__(256) gemm64(
    const float* __restrict__ A, const float* __restrict__ B, float* __restrict__ C,
    int M, int N, int K, int lda, int ldb, int ldc)
{
    __shared__ float As[16][65];
    __shared__ float Bs[16][64];
    int tid = threadIdx.x, tx = tid & 15, ty = tid >> 4;
    int bm = blockIdx.y * 64, bn = blockIdx.x * 64;
    float acc[4][4];
#pragma unroll
    for (int i = 0; i < 4; i++)
#pragma unroll
        for (int j = 0; j < 4; j++) acc[i][j] = 0.f;

    for (int k0 = 0; k0 < K; k0 += 16) {
        for (int t = tid; t < 64 * 16; t += 256) {
            int r = t >> 4, c = t & 15;
            int gr = bm + r, gc = k0 + c;
            As[c][r] = (gr < M && gc < K) ? A[(size_t)gr * lda + gc] : 0.f;
        }
        for (int t = tid; t < 16 * 64; t += 256) {
            int r = t >> 6, c = t & 63;
            int gr = k0 + r, gc = bn + c;
            Bs[r][c] = (gr < K && gc < N) ? B[(size_t)gr * ldb + gc] : 0.f;
        }
        __syncthreads();
#pragma unroll
        for (int kk = 0; kk < 16; kk++) {
            float a[4], b[4];
#pragma unroll
            for (int i = 0; i < 4; i++) a[i] = As[kk][ty * 4 + i];
#pragma unroll
            for (int j = 0; j < 4; j++) b[j] = Bs[kk][tx * 4 + j];
#pragma unroll
            for (int i = 0; i < 4; i++)
#pragma unroll
                for (int j = 0; j < 4; j++) acc[i][j] += a[i] * b[j];
        }
        __syncthreads();
    }
#pragma unroll
    for (int i = 0; i < 4; i++)
#pragma unroll
        for (int j = 0; j < 4; j++) {
            int gr = bm + ty * 4 + i, gc = bn + tx * 4 + j;
            if (gr < M && gc < N) C[(size_t)gr * ldc + gc] = acc[i][j];
        }
}

// ---------------- small helper kernels ----------------
// gather rows by perm + convert to bf16: out[i][j] = bf16(A[perm[i]][j])
__global__ void rowgather_bf16(const float* __restrict__ A, int n,
                               const int* __restrict__ perm,
                               __nv_bfloat16* __restrict__ out, int krows)
{
    size_t idx = (size_t)blockIdx.x * 256 + threadIdx.x;
    size_t n4 = (size_t)n / 4;
    if (idx >= (size_t)krows * n4) return;
    int i = (int)(idx / n4);
    int j4 = (int)(idx - (size_t)i * n4);
    float4 v = *(const float4*)(A + (size_t)perm[i] * n + j4 * 4);
    __nv_bfloat162 a = __floats2bfloat162_rn(v.x, v.y);
    __nv_bfloat162 b = __floats2bfloat162_rn(v.z, v.w);
    *(__nv_bfloat162*)(out + (size_t)i * n + j4 * 4)     = a;
    *(__nv_bfloat162*)(out + (size_t)i * n + j4 * 4 + 2) = b;
}

__global__ void rowsum_dinv(const float* __restrict__ A, float* __restrict__ dinv, int n)
{
    int row = blockIdx.x;
    const float* Ar = A + (size_t)row * n;
    float s = 0.f;
    for (int j = threadIdx.x; j < n; j += 256) s += Ar[j];
    for (int o = 16; o > 0; o >>= 1) s += __shfl_down_sync(0xffffffffu, s, o);
    __shared__ float red[8];
    int w = threadIdx.x >> 5, l = threadIdx.x & 31;
    if (l == 0) red[w] = s;
    __syncthreads();
    if (threadIdx.x == 0) {
        float t = 0.f;
        for (int i = 0; i < 8; i++) t += red[i];
        dinv[row] = 1.0f / sqrtf(t + 2.0f);
    }
}

__global__ void scale_rows(const float* __restrict__ in, const float* __restrict__ dinv,
                           float* __restrict__ out, int n, int w, int ld)
{
    int idx = blockIdx.x * 256 + threadIdx.x;
    if (idx >= n * ld) return;
    int r = idx / ld, c = idx - r * ld;
    out[idx] = (c < w) ? dinv[r] * in[idx] : 0.f;
}

__global__ void gcn_finish_sk(const float* __restrict__ part, const float* __restrict__ Z,
                              const float* __restrict__ dinv, const float* __restrict__ b,
                              float* __restrict__ out, int n, int relu, int S)
{
    int idx = blockIdx.x * 256 + threadIdx.x;
    if (idx >= n * HP) return;
    int r = idx / HP, c = idx - r * HP;
    float v = 0.f;
    if (c < H) {
        float az = 0.f;
        size_t stride = (size_t)n * HP;
        for (int s = 0; s < S; s++) az += part[s * stride + idx];
        v = dinv[r] * (az + 2.f * Z[idx]) + b[c];
        if (relu) v = fmaxf(v, 0.f);
    }
    out[idx] = v;
}

__global__ void pnorm_kernel(const float* __restrict__ p, float* __restrict__ out)
{
    float s = 0.f;
    for (int i = threadIdx.x; i < H; i += 256) { float v = p[i]; s += v * v; }
    for (int o = 16; o > 0; o >>= 1) s += __shfl_down_sync(0xffffffffu, s, o);
    __shared__ float red[8];
    int w = threadIdx.x >> 5, l = threadIdx.x & 31;
    if (l == 0) red[w] = s;
    __syncthreads();
    if (threadIdx.x == 0) {
        float t = 0.f;
        for (int i = 0; i < 8; i++) t += red[i];
        *out = sqrtf(t);
    }
}

__global__ void score_kernel(const float* __restrict__ x, const float* __restrict__ p,
                             const float* __restrict__ pn, float* __restrict__ score, int n)
{
    int row = blockIdx.x * 8 + (threadIdx.x >> 5);
    int lane = threadIdx.x & 31;
    if (row >= n) return;
    const float* xr = x + (size_t)row * HP;
    float s = 0.f;
    for (int c = lane; c < H; c += 32) s += xr[c] * p[c];
    for (int o = 16; o > 0; o >>= 1) s += __shfl_down_sync(0xffffffffu, s, o);
    if (lane == 0) score[row] = tanhf(s / (*pn));
}

// uint64-key bitonic topk (descending score, ascending index ties — matches jax)
__global__ void topk_kernel(const float* __restrict__ score, int n, int k,
                            int* __restrict__ perm, float* __restrict__ val)
{
    __shared__ unsigned long long key[4096];
    int tid = threadIdx.x;
    for (int i = tid; i < 4096; i += 1024) {
        float s = (i < n) ? score[i] : -INFINITY;
        uint32_t u = __float_as_uint(s);
        u = (u & 0x80000000u) ? ~u : (u | 0x80000000u);
        uint32_t d = ~u;
        key[i] = ((unsigned long long)d << 32) | (uint32_t)i;
    }
    __syncthreads();
    for (int size = 2; size <= 4096; size <<= 1) {
        for (int stride = size >> 1; stride > 0; stride >>= 1) {
            for (int i = tid; i < 4096; i += 1024) {
                int j = i ^ stride;
                if (j > i) {
                    unsigned long long a = key[i], b = key[j];
                    bool up = ((i & size) == 0);
                    if (up ? (a > b) : (a < b)) { key[i] = b; key[j] = a; }
                }
            }
            __syncthreads();
        }
    }
    for (int i = tid; i < k; i += 1024) {
        int si = (int)(uint32_t)key[i];
        perm[i] = si;
        val[i] = score[si];
    }
}

// consume triangular C: A_out[i][j] = (i==j) ? 0 : C[max][min] + 2*Asrc[pi][pj]
__global__ void pool_A_tri(const float* __restrict__ C, const float* __restrict__ Asrc,
                           int ldA, const int* __restrict__ perm,
                           float* __restrict__ Aout, int k)
{
    int idx = blockIdx.x * 256 + threadIdx.x;
    if (idx >= k * k) return;
    int i = idx / k, j = idx - i * k;
    if (i == j) { Aout[idx] = 0.f; return; }
    int hi = i > j ? i : j, lo = i > j ? j : i;
    float g = C[(size_t)hi * k + lo];
    Aout[idx] = g + 2.f * Asrc[(size_t)perm[i] * ldA + perm[j]];
}

// full-G variant (level 3, G from tf32prop): A_out[i][j] = (i==j)?0 : G[pi][pj]+2*A[pi][pj]
__global__ void pool_A_fused(const float* __restrict__ G, const float* __restrict__ Asrc,
                             int ldg, const int* __restrict__ perm,
                             float* __restrict__ Aout, int k)
{
    int idx = blockIdx.x * 256 + threadIdx.x;
    if (idx >= k * k) return;
    int i = idx / k, j = idx - i * k;
    if (i == j) { Aout[idx] = 0.f; return; }
    size_t off = (size_t)perm[i] * ldg + perm[j];
    Aout[idx] = G[off] + 2.f * Asrc[off];
}

__global__ void pool_x(const float* __restrict__ xin, const int* __restrict__ perm,
                       const float* __restrict__ val, float* __restrict__ xout, int k)
{
    int idx = blockIdx.x * 256 + threadIdx.x;
    if (idx >= k * HP) return;
    int r = idx / HP, c = idx - r * HP;
    xout[idx] = xin[(size_t)perm[r] * HP + c] * val[r];
}

__global__ void scatter_add(float* __restrict__ dst, const float* __restrict__ x,
                            const int* __restrict__ perm, int k)
{
    int idx = blockIdx.x * 256 + threadIdx.x;
    if (idx >= k * HP) return;
    int r = idx / HP, c = idx - r * HP;
    dst[(size_t)perm[r] * HP + c] += x[idx];
}

__global__ void gemm_n2(const float* __restrict__ A, const float* __restrict__ Z,
                        float* __restrict__ out, int n)
{
    int row = blockIdx.x;
    const float* Ar = A + (size_t)row * n;
    float a0 = 0.f, a1 = 0.f;
    for (int j = threadIdx.x; j < n; j += 256) {
        float a = Ar[j];
        a0 += a * Z[2 * j];
        a1 += a * Z[2 * j + 1];
    }
    for (int o = 16; o > 0; o >>= 1) {
        a0 += __shfl_down_sync(0xffffffffu, a0, o);
        a1 += __shfl_down_sync(0xffffffffu, a1, o);
    }
    __shared__ float r0[8], r1[8];
    int w = threadIdx.x >> 5, l = threadIdx.x & 31;
    if (l == 0) { r0[w] = a0; r1[w] = a1; }
    __syncthreads();
    if (threadIdx.x == 0) {
        float s0 = 0.f, s1 = 0.f;
        for (int i = 0; i < 8; i++) { s0 += r0[i]; s1 += r1[i]; }
        out[2 * row] = s0;
        out[2 * row + 1] = s1;
    }
}

__global__ void final_kernel(const float* __restrict__ AZ, const float* __restrict__ Z,
                             const float* __restrict__ dinv, const float* __restrict__ b,
                             float* __restrict__ out, int n)
{
    int i = blockIdx.x * 256 + threadIdx.x;
    if (i >= n) return;
    float a = dinv[i] * (AZ[2 * i]     + 2.f * Z[2 * i])     + b[0];
    float c = dinv[i] * (AZ[2 * i + 1] + 2.f * Z[2 * i + 1]) + b[1];
    float m = fmaxf(a, c);
    float l = m + logf(expf(a - m) + expf(c - m));
    out[2 * i] = a - l;
    out[2 * i + 1] = c - l;
}

// ---------------- host orchestration ----------------
template <typename T, size_t NN>
static T* symaddr(T (&sym)[NN]) {
    void* p = nullptr;
    cudaGetSymbolAddress(&p, sym);
    return (T*)p;
}

static void run_gcn(const float* A, int n, const float* xin, int lda_x, int Kdim,
                    const float* W, const float* b, float* xout, int relu,
                    int S, int asplit,
                    float* t0, float* t1, float* part, float* dinv)
{
    dim3 g1((H + 63) / 64, (n + 63) / 64);
    gemm64<<<g1, 256>>>(xin, W, t0, n, H, Kdim, lda_x, H, HP);
    rowsum_dinv<<<n, 256>>>(A, dinv, n);
    int tot = n * HP;
    scale_rows<<<(tot + 255) / 256, 256>>>(t0, dinv, t1, n, H, HP);
    dim3 g2(HP / 128, n / 128, S);
    if (asplit)
        tf32prop<1><<<g2, 256>>>(A, t1, part, n, HP, n, n, HP, HP);
    else
        tf32prop<0><<<g2, 256>>>(A, t1, part, n, HP, n, n, HP, HP);
    gcn_finish_sk<<<(tot + 255) / 256, 256>>>(part, t1, dinv, b, xout, n, relu, S);
}

extern "C" void kernel_launch(void* const* d_in, const int* in_sizes, int n_in,
                              void* d_out, int out_size)
{
    (void)in_sizes; (void)n_in; (void)out_size;
    const float* x   = (const float*)d_in[0];
    const float* adj = (const float*)d_in[1];
    const float* w0  = (const float*)d_in[2];
    const float* b0  = (const float*)d_in[3];
    const float* w1  = (const float*)d_in[4];
    const float* b1  = (const float*)d_in[5];
    const float* w2  = (const float*)d_in[6];
    const float* b2  = (const float*)d_in[7];
    const float* w3  = (const float*)d_in[8];
    const float* b3  = (const float*)d_in[9];
    const float* p1  = (const float*)d_in[10];
    const float* p2  = (const float*)d_in[11];
    const float* p3  = (const float*)d_in[12];
    const float* u0w = (const float*)d_in[13];
    const float* u0b = (const float*)d_in[14];
    const float* u1w = (const float*)d_in[15];
    const float* u1b = (const float*)d_in[16];
    const float* u2w = (const float*)d_in[17];
    const float* u2b = (const float*)d_in[18];

    float* G    = symaddr(g_G);
    __nv_bfloat16* ROWS = symaddr(g_rows);
    float* A1   = symaddr(g_A1);
    float* A2   = symaddr(g_A2);
    float* A3   = symaddr(g_A3);
    float* X0   = symaddr(g_x0);
    float* X1   = symaddr(g_x1);
    float* X2   = symaddr(g_x2);
    float* X3   = symaddr(g_x3);
    float* T0   = symaddr(g_t0);
    float* T1   = symaddr(g_t1);
    float* PART = symaddr(g_part);
    float* CUR  = symaddr(g_cur);
    float* DINV = symaddr(g_dinv);
    float* SC   = symaddr(g_score);
    float* VAL  = symaddr(g_val);
    int*   P0   = symaddr(g_perm0);
    int*   P1   = symaddr(g_perm1);
    int*   P2   = symaddr(g_perm2);
    float* PN   = symaddr(g_pnorm);

    // ---- down: gcn0 (adj binary -> exact in tf32, asplit=0) ----
    run_gcn(adj, N0, x, 3, 3, w0, b0, X0, 1, 4, 0, T0, T1, PART, DINV);

    // ---- pool 1 (4096 -> 3072): gather rows, C = Rows·Rows^T (tri), fuse finish ----
    pnorm_kernel<<<1, 256>>>(p1, PN);
    score_kernel<<<(N0 + 7) / 8, 256>>>(X0, p1, PN, SC, N0);
    topk_kernel<<<1, 1024>>>(SC, N0, KP1, P0, VAL);
    {
        size_t tot = (size_t)KP1 * (N0 / 4);
        rowgather_bf16<<<(unsigned)((tot + 255) / 256), 256>>>(adj, N0, P0, ROWS, KP1);
        dim3 g(KP1 / 128, KP1 / 128);
        bf16gemm_xxt<<<g, 256>>>(ROWS, G, KP1, N0);   // exact: binary
        pool_A_tri<<<(KP1 * KP1 + 255) / 256, 256>>>(G, adj, N0, P0, A1, KP1);
        pool_x<<<(KP1 * HP + 255) / 256, 256>>>(X0, P0, VAL, CUR, KP1);
    }
    run_gcn(A1, KP1, CUR, HP, H, w1, b1, X1, 1, 6, 0, T0, T1, PART, DINV);

    // ---- pool 2 (3072 -> 1536) ----
    pnorm_kernel<<<1, 256>>>(p2, PN);
    score_kernel<<<(KP1 + 7) / 8, 256>>>(X1, p2, PN, SC, KP1);
    topk_kernel<<<1, 1024>>>(SC, KP1, KP2, P1, VAL);
    {
        size_t tot = (size_t)KP2 * (KP1 / 4);
        rowgather_bf16<<<(unsigned)((tot + 255) / 256), 256>>>(A1, KP1, P1, ROWS, KP2);
        dim3 g(KP2 / 128, KP2 / 128);
        bf16gemm_xxt<<<g, 256>>>(ROWS, G, KP2, KP1);  // exact: small ints
        pool_A_tri<<<(KP2 * KP2 + 255) / 256, 256>>>(G, A1, KP1, P1, A2, KP2);
        pool_x<<<(KP2 * HP + 255) / 256, 256>>>(X1, P1, VAL, CUR, KP2);
    }
    run_gcn(A2, KP2, CUR, HP, H, w2, b2, X2, 1, 8, 1, T0, T1, PART, DINV);

    // ---- pool 3 (1536 -> 768): A2 may exceed bf16-exact range -> 3xTF32 full ----
    pnorm_kernel<<<1, 256>>>(p3, PN);
    score_kernel<<<(KP2 + 7) / 8, 256>>>(X2, p3, PN, SC, KP2);
    topk_kernel<<<1, 1024>>>(SC, KP2, KP3, P2, VAL);
    {
        dim3 g(KP2 / 128, KP2 / 128, 1);
        tf32prop<1><<<g, 256>>>(A2, A2, G, KP2, KP2, KP2, KP2, KP2, KP2);
        pool_A_fused<<<(KP3 * KP3 + 255) / 256, 256>>>(G, A2, KP2, P2, A3, KP3);
        pool_x<<<(KP3 * HP + 255) / 256, 256>>>(X2, P2, VAL, CUR, KP3);
    }
    run_gcn(A3, KP3, CUR, HP, H, w3, b3, X3, 1, 8, 1, T0, T1, PART, DINV);

    // ---- up 0: j=2 ----
    cudaMemcpyAsync(CUR, X2, (size_t)KP2 * HP * sizeof(float), cudaMemcpyDeviceToDevice, 0);
    scatter_add<<<(KP3 * HP + 255) / 256, 256>>>(CUR, X3, P2, KP3);
    run_gcn(A2, KP2, CUR, HP, H, u0w, u0b, X2, 1, 8, 1, T0, T1, PART, DINV);

    // ---- up 1: j=1 ----
    cudaMemcpyAsync(CUR, X1, (size_t)KP1 * HP * sizeof(float), cudaMemcpyDeviceToDevice, 0);
    scatter_add<<<(KP2 * HP + 255) / 256, 256>>>(CUR, X2, P1, KP2);
    run_gcn(A1, KP1, CUR, HP, H, u1w, u1b, X1, 1, 6, 0, T0, T1, PART, DINV);

    // ---- up 2: j=0, final gcn (H->2) + log_softmax ----
    cudaMemcpyAsync(CUR, X0, (size_t)N0 * HP * sizeof(float), cudaMemcpyDeviceToDevice, 0);
    scatter_add<<<(KP1 * HP + 255) / 256, 256>>>(CUR, X1, P0, KP1);
    {
        dim3 gf(1, (N0 + 63) / 64);
        gemm64<<<gf, 256>>>(CUR, u2w, T0, N0, 2, H, HP, 2, 2);
        rowsum_dinv<<<N0, 256>>>(adj, DINV, N0);
        scale_rows<<<(N0 * 2 + 255) / 256, 256>>>(T0, DINV, T1, N0, 2, 2);
        gemm_n2<<<N0, 256>>>(adj, T1, T0, N0);
        final_kernel<<<(N0 + 255) / 256, 256>>>(T0, T1, DINV, u2b, (float*)d_out, N0);
    }
}

// round 7
// speedup vs baseline: 5.9717x; 1.0884x over previous
#include <cuda_runtime.h>
#include <cuda_bf16.h>
#include <math.h>
#include <stdint.h>

#define N0 4096
#define KP1 3072
#define KP2 1536
#define KP3 768
#define H 200
#define HP 256
#define SKMAX 8

// ---------------- device scratch (static: no allocation allowed) ----------------
__device__ float g_G[(size_t)N0 * N0];
__device__ __nv_bfloat16 g_rows[(size_t)KP1 * N0];     // gathered bf16 rows
__device__ float g_A1[(size_t)KP1 * KP1];
__device__ float g_A2[(size_t)KP2 * KP2];
__device__ float g_A3[(size_t)KP3 * KP3];
__device__ float g_x0[N0 * HP];
__device__ float g_x1[KP1 * HP];
__device__ float g_x2[KP2 * HP];
__device__ float g_x3[KP3 * HP];
__device__ float g_t0[N0 * HP];
__device__ float g_t1[N0 * HP];
__device__ float g_part[(size_t)SKMAX * N0 * HP];      // split-K partials / fp32 row scratch
__device__ float g_cur[N0 * HP];
__device__ float g_dinv[N0];
__device__ float g_score[N0];
__device__ float g_val[N0];
__device__ int   g_perm0[KP1];
__device__ int   g_perm1[KP2];
__device__ int   g_perm2[KP3];
__device__ float g_pnorm[1];

__device__ __forceinline__ uint32_t f2tf(float x) {
    uint32_t r;
    asm("cvt.rna.tf32.f32 %0, %1;" : "=r"(r) : "f"(x));
    return r;
}

__device__ __forceinline__ void cpa16(uint32_t dst, const void* src) {
    asm volatile("cp.async.cg.shared.global [%0], [%1], 16;\n" :: "r"(dst), "l"(src));
}

// ============ bf16 X·X^T GEMM, lower triangle only (levels 1-2 augment) ==============
__global__ void __launch_bounds__(256) bf16gemm_xxt(
    const __nv_bfloat16* __restrict__ X, float* __restrict__ C, int k, int K)
{
    if (blockIdx.x > blockIdx.y) return;

    __shared__ __nv_bfloat16 As[2][128][40];
    __shared__ __nv_bfloat16 Bs[2][128][40];

    int t = threadIdx.x;
    int warp = t >> 5, lane = t & 31;
    int group = lane >> 2, tg = lane & 3;
    int wm = warp >> 2, wn = warp & 3;
    int bm = blockIdx.y * 128, bn = blockIdx.x * 128;

    float c[4][4][4];
#pragma unroll
    for (int mi = 0; mi < 4; mi++)
#pragma unroll
        for (int ni = 0; ni < 4; ni++)
#pragma unroll
            for (int r = 0; r < 4; r++) c[mi][ni][r] = 0.f;

    int lrow = t >> 1;
    int lcol0 = (t & 1) * 16;

    uint32_t aBase = (uint32_t)__cvta_generic_to_shared(&As[0][0][0]);
    uint32_t bBase = (uint32_t)__cvta_generic_to_shared(&Bs[0][0][0]);
    const uint32_t stageB = 128 * 40 * 2;
    uint32_t aDst = aBase + lrow * 80 + lcol0 * 2;
    uint32_t bDst = bBase + lrow * 80 + lcol0 * 2;

    const __nv_bfloat16* aSrcRow = X + (size_t)(bm + lrow) * K + lcol0;
    const __nv_bfloat16* bSrcRow = X + (size_t)(bn + lrow) * K + lcol0;

#define LOAD_STAGE(st, k0)                                        \
    do {                                                          \
        const __nv_bfloat16* ap = aSrcRow + (k0);                 \
        const __nv_bfloat16* bp = bSrcRow + (k0);                 \
        uint32_t ad = aDst + (st) * stageB;                       \
        uint32_t bd = bDst + (st) * stageB;                       \
        cpa16(ad, ap); cpa16(ad + 16, ap + 8);                    \
        cpa16(bd, bp); cpa16(bd + 16, bp + 8);                    \
    } while (0)

    LOAD_STAGE(0, 0);
    asm volatile("cp.async.commit_group;\n");

    int s = 0;
    for (int k0 = 0; k0 < K; k0 += 32) {
        if (k0 + 32 < K) {
            LOAD_STAGE(s ^ 1, k0 + 32);
            asm volatile("cp.async.commit_group;\n");
            asm volatile("cp.async.wait_group 1;\n");
        } else {
            asm volatile("cp.async.wait_group 0;\n");
        }
        __syncthreads();

#pragma unroll
        for (int ks = 0; ks < 2; ks++) {
            int kb = ks * 16;
            uint32_t af[4][4], bf[4][2];
#pragma unroll
            for (int mi = 0; mi < 4; mi++) {
                int rm = wm * 64 + mi * 16 + group;
                af[mi][0] = *(const uint32_t*)&As[s][rm][kb + 2 * tg];
                af[mi][1] = *(const uint32_t*)&As[s][rm + 8][kb + 2 * tg];
                af[mi][2] = *(const uint32_t*)&As[s][rm][kb + 2 * tg + 8];
                af[mi][3] = *(const uint32_t*)&As[s][rm + 8][kb + 2 * tg + 8];
            }
#pragma unroll
            for (int ni = 0; ni < 4; ni++) {
                int cn = wn * 32 + ni * 8 + group;
                bf[ni][0] = *(const uint32_t*)&Bs[s][cn][kb + 2 * tg];
                bf[ni][1] = *(const uint32_t*)&Bs[s][cn][kb + 2 * tg + 8];
            }
#pragma unroll
            for (int mi = 0; mi < 4; mi++)
#pragma unroll
                for (int ni = 0; ni < 4; ni++) {
                    asm volatile(
                        "mma.sync.aligned.m16n8k16.row.col.f32.bf16.bf16.f32 "
                        "{%0,%1,%2,%3}, {%4,%5,%6,%7}, {%8,%9}, {%0,%1,%2,%3};\n"
                        : "+f"(c[mi][ni][0]), "+f"(c[mi][ni][1]),
                          "+f"(c[mi][ni][2]), "+f"(c[mi][ni][3])
                        : "r"(af[mi][0]), "r"(af[mi][1]), "r"(af[mi][2]), "r"(af[mi][3]),
                          "r"(bf[ni][0]), "r"(bf[ni][1]));
                }
        }
        __syncthreads();
        s ^= 1;
    }
#undef LOAD_STAGE

#pragma unroll
    for (int mi = 0; mi < 4; mi++) {
        int row0 = bm + wm * 64 + mi * 16 + group;
#pragma unroll
        for (int ni = 0; ni < 4; ni++) {
            int col = bn + wn * 32 + ni * 8 + tg * 2;
            *(float2*)(C + (size_t)row0 * k + col)       = make_float2(c[mi][ni][0], c[mi][ni][1]);
            *(float2*)(C + (size_t)(row0 + 8) * k + col) = make_float2(c[mi][ni][2], c[mi][ni][3]);
        }
    }
}

// ============ tf32 GEMM, cp.async double-buffered ====================================
// ASPLIT=0: A raw bits (exact tf32 ints), B split hi/lo (2 mma).
// ASPLIT=1: A split too (3 mma).
// XXT=1: C = A·B^T with B row-major [n][K] (for X·X^T pass X twice); lower-tri blocks only.
// Split-K via gridDim.z (partials at Cpart + z*M*ldc). (K/gridDim.z) % 32 == 0.
// Dynamic smem: 73728 B.
template <int ASPLIT, int XXT>
__global__ void __launch_bounds__(256, (ASPLIT ? 1 : 2)) tf32g(
    const float* __restrict__ A, const float* __restrict__ B, float* __restrict__ Cpart,
    int M, int N, int K, int lda, int ldb, int ldc)
{
    if (XXT && (int)blockIdx.x > (int)blockIdx.y) return;
    extern __shared__ float smd[];
    const int STAGEF = 9216;            // floats per stage
    const int BOFF = 128 * 36;

    int t = threadIdx.x;
    int warp = t >> 5, lane = t & 31;
    int group = lane >> 2, tg = lane & 3;
    int wm = warp >> 2, wn = warp & 3;
    int bm = blockIdx.y * 128, bn = blockIdx.x * 128;
    int kChunk = K / gridDim.z;
    int kStart = blockIdx.z * kChunk;
    float* C = Cpart + (size_t)blockIdx.z * M * ldc;

    float c[4][4][4];
#pragma unroll
    for (int mi = 0; mi < 4; mi++)
#pragma unroll
        for (int ni = 0; ni < 4; ni++)
#pragma unroll
            for (int r = 0; r < 4; r++) c[mi][ni][r] = 0.f;

    auto LOADST = [&](int st, int k0) {
        float* as = smd + st * STAGEF;
        float* bs = as + BOFF;
#pragma unroll
        for (int q = 0; q < 4; q++) {
            int cc = t + q * 256;
            int m = cc >> 3, kc = cc & 7;
            uint32_t ad = (uint32_t)__cvta_generic_to_shared(as + m * 36 + kc * 4);
            cpa16(ad, A + (size_t)(bm + m) * lda + kStart + k0 + kc * 4);
        }
        if (XXT) {
#pragma unroll
            for (int q = 0; q < 4; q++) {
                int cc = t + q * 256;
                int m = cc >> 3, kc = cc & 7;
                uint32_t bd = (uint32_t)__cvta_generic_to_shared(bs + m * 36 + kc * 4);
                cpa16(bd, B + (size_t)(bn + m) * ldb + kStart + k0 + kc * 4);
            }
        } else {
#pragma unroll
            for (int q = 0; q < 4; q++) {
                int cc = t + q * 256;
                int r = cc >> 5, nc = cc & 31;
                uint32_t bd = (uint32_t)__cvta_generic_to_shared(bs + r * 136 + nc * 4);
                cpa16(bd, B + (size_t)(kStart + k0 + r) * ldb + bn + nc * 4);
            }
        }
        asm volatile("cp.async.commit_group;\n");
    };

    LOADST(0, 0);

    int s = 0;
    for (int k0 = 0; k0 < kChunk; k0 += 32) {
        if (k0 + 32 < kChunk) {
            LOADST(s ^ 1, k0 + 32);
            asm volatile("cp.async.wait_group 1;\n");
        } else {
            asm volatile("cp.async.wait_group 0;\n");
        }
        __syncthreads();

        const float* as = smd + s * STAGEF;
        const float* bs = as + BOFF;

#pragma unroll
        for (int ks = 0; ks < 4; ks++) {
            int kb = ks * 8;
            uint32_t afh[4][4], afl[4][4], bfh[4][2], bfl[4][2];
#pragma unroll
            for (int mi = 0; mi < 4; mi++) {
                int rm = wm * 64 + mi * 16 + group;
                float a0 = as[rm * 36 + kb + tg];
                float a1 = as[(rm + 8) * 36 + kb + tg];
                float a2 = as[rm * 36 + kb + tg + 4];
                float a3 = as[(rm + 8) * 36 + kb + tg + 4];
                if (ASPLIT) {
                    afh[mi][0] = f2tf(a0); afh[mi][1] = f2tf(a1);
                    afh[mi][2] = f2tf(a2); afh[mi][3] = f2tf(a3);
                    afl[mi][0] = f2tf(a0 - __uint_as_float(afh[mi][0]));
                    afl[mi][1] = f2tf(a1 - __uint_as_float(afh[mi][1]));
                    afl[mi][2] = f2tf(a2 - __uint_as_float(afh[mi][2]));
                    afl[mi][3] = f2tf(a3 - __uint_as_float(afh[mi][3]));
                } else {
                    afh[mi][0] = __float_as_uint(a0); afh[mi][1] = __float_as_uint(a1);
                    afh[mi][2] = __float_as_uint(a2); afh[mi][3] = __float_as_uint(a3);
                }
            }
#pragma unroll
            for (int ni = 0; ni < 4; ni++) {
                int cn = wn * 32 + ni * 8 + group;
                float b0, b1;
                if (XXT) {
                    b0 = bs[cn * 36 + kb + tg];
                    b1 = bs[cn * 36 + kb + tg + 4];
                } else {
                    b0 = bs[(kb + tg) * 136 + cn];
                    b1 = bs[(kb + tg + 4) * 136 + cn];
                }
                bfh[ni][0] = f2tf(b0);
                bfh[ni][1] = f2tf(b1);
                bfl[ni][0] = f2tf(b0 - __uint_as_float(bfh[ni][0]));
                bfl[ni][1] = f2tf(b1 - __uint_as_float(bfh[ni][1]));
            }
#pragma unroll
            for (int mi = 0; mi < 4; mi++)
#pragma unroll
                for (int ni = 0; ni < 4; ni++) {
                    asm volatile(
                        "mma.sync.aligned.m16n8k8.row.col.f32.tf32.tf32.f32 "
                        "{%0,%1,%2,%3}, {%4,%5,%6,%7}, {%8,%9}, {%0,%1,%2,%3};\n"
                        : "+f"(c[mi][ni][0]), "+f"(c[mi][ni][1]),
                          "+f"(c[mi][ni][2]), "+f"(c[mi][ni][3])
                        : "r"(afh[mi][0]), "r"(afh[mi][1]), "r"(afh[mi][2]), "r"(afh[mi][3]),
                          "r"(bfl[ni][0]), "r"(bfl[ni][1]));
                    if (ASPLIT) {
                        asm volatile(
                            "mma.sync.aligned.m16n8k8.row.col.f32.tf32.tf32.f32 "
                            "{%0,%1,%2,%3}, {%4,%5,%6,%7}, {%8,%9}, {%0,%1,%2,%3};\n"
                            : "+f"(c[mi][ni][0]), "+f"(c[mi][ni][1]),
                              "+f"(c[mi][ni][2]), "+f"(c[mi][ni][3])
                            : "r"(afl[mi][0]), "r"(afl[mi][1]), "r"(afl[mi][2]), "r"(afl[mi][3]),
                              "r"(bfh[ni][0]), "r"(bfh[ni][1]));
                    }
                    asm volatile(
                        "mma.sync.aligned.m16n8k8.row.col.f32.tf32.tf32.f32 "
                        "{%0,%1,%2,%3}, {%4,%5,%6,%7}, {%8,%9}, {%0,%1,%2,%3};\n"
                        : "+f"(c[mi][ni][0]), "+f"(c[mi][ni][1]),
                          "+f"(c[mi][ni][2]), "+f"(c[mi][ni][3])
                        : "r"(afh[mi][0]), "r"(afh[mi][1]), "r"(afh[mi][2]), "r"(afh[mi][3]),
                          "r"(bfh[ni][0]), "r"(bfh[ni][1]));
                }
        }
        __syncthreads();
        s ^= 1;
    }

#pragma unroll
    for (int mi = 0; mi < 4; mi++) {
        int row0 = bm + wm * 64 + mi * 16 + group;
#pragma unroll
        for (int ni = 0; ni < 4; ni++) {
            int col = bn + wn * 32 + ni * 8 + tg * 2;
            *(float2*)(C + (size_t)row0 * ldc + col)       = make_float2(c[mi][ni][0], c[mi][ni][1]);
            *(float2*)(C + (size_t)(row0 + 8) * ldc + col) = make_float2(c[mi][ni][2], c[mi][ni][3]);
        }
    }
}

// ---------------- generic SGEMM: 64x64 block, bounds-checked ------------------------
__global__ void __launch_bounds__(256) gemm64(
    const float* __restrict__ A, const float* __restrict__ B, float* __restrict__ C,
    int M, int N, int K, int lda, int ldb, int ldc)
{
    __shared__ float As[16][65];
    __shared__ float Bs[16][64];
    int tid = threadIdx.x, tx = tid & 15, ty = tid >> 4;
    int bm = blockIdx.y * 64, bn = blockIdx.x * 64;
    float acc[4][4];
#pragma unroll
    for (int i = 0; i < 4; i++)
#pragma unroll
        for (int j = 0; j < 4; j++) acc[i][j] = 0.f;

    for (int k0 = 0; k0 < K; k0 += 16) {
        for (int t = tid; t < 64 * 16; t += 256) {
            int r = t >> 4, c = t & 15;
            int gr = bm + r, gc = k0 + c;
            As[c][r] = (gr < M && gc < K) ? A[(size_t)gr * lda + gc] : 0.f;
        }
        for (int t = tid; t < 16 * 64; t += 256) {
            int r = t >> 6, c = t & 63;
            int gr = k0 + r, gc = bn + c;
            Bs[r][c] = (gr < K && gc < N) ? B[(size_t)gr * ldb + gc] : 0.f;
        }
        __syncthreads();
#pragma unroll
        for (int kk = 0; kk < 16; kk++) {
            float a[4], b[4];
#pragma unroll
            for (int i = 0; i < 4; i++) a[i] = As[kk][ty * 4 + i];
#pragma unroll
            for (int j = 0; j < 4; j++) b[j] = Bs[kk][tx * 4 + j];
#pragma unroll
            for (int i = 0; i < 4; i++)
#pragma unroll
                for (int j = 0; j < 4; j++) acc[i][j] += a[i] * b[j];
        }
        __syncthreads();
    }
#pragma unroll
    for (int i = 0; i < 4; i++)
#pragma unroll
        for (int j = 0; j < 4; j++) {
            int gr = bm + ty * 4 + i, gc = bn + tx * 4 + j;
            if (gr < M && gc < N) C[(size_t)gr * ldc + gc] = acc[i][j];
        }
}

// ---------------- small helper kernels ----------------
__global__ void rowgather_bf16(const float* __restrict__ A, int n,
                               const int* __restrict__ perm,
                               __nv_bfloat16* __restrict__ out, int krows)
{
    size_t idx = (size_t)blockIdx.x * 256 + threadIdx.x;
    size_t n4 = (size_t)n / 4;
    if (idx >= (size_t)krows * n4) return;
    int i = (int)(idx / n4);
    int j4 = (int)(idx - (size_t)i * n4);
    float4 v = *(const float4*)(A + (size_t)perm[i] * n + j4 * 4);
    __nv_bfloat162 a = __floats2bfloat162_rn(v.x, v.y);
    __nv_bfloat162 b = __floats2bfloat162_rn(v.z, v.w);
    *(__nv_bfloat162*)(out + (size_t)i * n + j4 * 4)     = a;
    *(__nv_bfloat162*)(out + (size_t)i * n + j4 * 4 + 2) = b;
}

__global__ void rowgather_f32(const float* __restrict__ A, int n,
                              const int* __restrict__ perm,
                              float* __restrict__ out, int krows)
{
    size_t idx = (size_t)blockIdx.x * 256 + threadIdx.x;
    size_t n4 = (size_t)n / 4;
    if (idx >= (size_t)krows * n4) return;
    int i = (int)(idx / n4);
    int j4 = (int)(idx - (size_t)i * n4);
    float4 v = *(const float4*)(A + (size_t)perm[i] * n + j4 * 4);
    *(float4*)(out + (size_t)i * n + j4 * 4) = v;
}

__global__ void rowsum_dinv(const float* __restrict__ A, float* __restrict__ dinv, int n)
{
    int row = blockIdx.x;
    const float* Ar = A + (size_t)row * n;
    float s = 0.f;
    for (int j = threadIdx.x; j < n; j += 256) s += Ar[j];
    for (int o = 16; o > 0; o >>= 1) s += __shfl_down_sync(0xffffffffu, s, o);
    __shared__ float red[8];
    int w = threadIdx.x >> 5, l = threadIdx.x & 31;
    if (l == 0) red[w] = s;
    __syncthreads();
    if (threadIdx.x == 0) {
        float t = 0.f;
        for (int i = 0; i < 8; i++) t += red[i];
        dinv[row] = 1.0f / sqrtf(t + 2.0f);
    }
}

__global__ void scale_rows(const float* __restrict__ in, const float* __restrict__ dinv,
                           float* __restrict__ out, int n, int w, int ld)
{
    int idx = blockIdx.x * 256 + threadIdx.x;
    if (idx >= n * ld) return;
    int r = idx / ld, c = idx - r * ld;
    out[idx] = (c < w) ? dinv[r] * in[idx] : 0.f;
}

__global__ void gcn_finish_sk(const float* __restrict__ part, const float* __restrict__ Z,
                              const float* __restrict__ dinv, const float* __restrict__ b,
                              float* __restrict__ out, int n, int relu, int S)
{
    int idx = blockIdx.x * 256 + threadIdx.x;
    if (idx >= n * HP) return;
    int r = idx / HP, c = idx - r * HP;
    float v = 0.f;
    if (c < H) {
        float az = 0.f;
        size_t stride = (size_t)n * HP;
        for (int s = 0; s < S; s++) az += part[s * stride + idx];
        v = dinv[r] * (az + 2.f * Z[idx]) + b[c];
        if (relu) v = fmaxf(v, 0.f);
    }
    out[idx] = v;
}

__global__ void pnorm_kernel(const float* __restrict__ p, float* __restrict__ out)
{
    float s = 0.f;
    for (int i = threadIdx.x; i < H; i += 256) { float v = p[i]; s += v * v; }
    for (int o = 16; o > 0; o >>= 1) s += __shfl_down_sync(0xffffffffu, s, o);
    __shared__ float red[8];
    int w = threadIdx.x >> 5, l = threadIdx.x & 31;
    if (l == 0) red[w] = s;
    __syncthreads();
    if (threadIdx.x == 0) {
        float t = 0.f;
        for (int i = 0; i < 8; i++) t += red[i];
        *out = sqrtf(t);
    }
}

__global__ void score_kernel(const float* __restrict__ x, const float* __restrict__ p,
                             const float* __restrict__ pn, float* __restrict__ score, int n)
{
    int row = blockIdx.x * 8 + (threadIdx.x >> 5);
    int lane = threadIdx.x & 31;
    if (row >= n) return;
    const float* xr = x + (size_t)row * HP;
    float s = 0.f;
    for (int c = lane; c < H; c += 32) s += xr[c] * p[c];
    for (int o = 16; o > 0; o >>= 1) s += __shfl_down_sync(0xffffffffu, s, o);
    if (lane == 0) score[row] = tanhf(s / (*pn));
}

// uint64-key bitonic topk (descending score, ascending index ties — matches jax)
template <int SIZE>
__global__ void topk_kernel(const float* __restrict__ score, int n, int k,
                            int* __restrict__ perm, float* __restrict__ val)
{
    __shared__ unsigned long long key[SIZE];
    int tid = threadIdx.x;
    for (int i = tid; i < SIZE; i += 1024) {
        float s = (i < n) ? score[i] : -INFINITY;
        uint32_t u = __float_as_uint(s);
        u = (u & 0x80000000u) ? ~u : (u | 0x80000000u);
        uint32_t d = ~u;
        key[i] = ((unsigned long long)d << 32) | (uint32_t)i;
    }
    __syncthreads();
    for (int size = 2; size <= SIZE; size <<= 1) {
        for (int stride = size >> 1; stride > 0; stride >>= 1) {
            for (int i = tid; i < SIZE; i += 1024) {
                int j = i ^ stride;
                if (j > i) {
                    unsigned long long a = key[i], b = key[j];
                    bool up = ((i & size) == 0);
                    if (up ? (a > b) : (a < b)) { key[i] = b; key[j] = a; }
                }
            }
            __syncthreads();
        }
    }
    for (int i = tid; i < k; i += 1024) {
        int si = (int)(uint32_t)key[i];
        perm[i] = si;
        val[i] = score[si];
    }
}

// levels 1-2: A_out[i][j] = (i==j) ? 0 : C[max][min] + 2*Rows[i][perm[j]]  (Rows bf16 exact)
__global__ void pool_A_tri(const float* __restrict__ C, const __nv_bfloat16* __restrict__ Rows,
                           int K, const int* __restrict__ perm,
                           float* __restrict__ Aout, int k)
{
    int idx = blockIdx.x * 256 + threadIdx.x;
    if (idx >= k * k) return;
    int i = idx / k, j = idx - i * k;
    if (i == j) { Aout[idx] = 0.f; return; }
    int hi = i > j ? i : j, lo = i > j ? j : i;
    float g = C[(size_t)hi * k + lo];
    float a = __bfloat162float(Rows[(size_t)i * K + __ldg(&perm[j])]);
    Aout[idx] = g + 2.f * a;
}

// level 3: C triangular over pooled idx; Rows fp32: A_out[i][j]= (i==j)?0: C[max][min]+2*Rows[i][perm[j]]
__global__ void pool_A_tri_f32(const float* __restrict__ C, const float* __restrict__ Rows,
                               int K, const int* __restrict__ perm,
                               float* __restrict__ Aout, int k)
{
    int idx = blockIdx.x * 256 + threadIdx.x;
    if (idx >= k * k) return;
    int i = idx / k, j = idx - i * k;
    if (i == j) { Aout[idx] = 0.f; return; }
    int hi = i > j ? i : j, lo = i > j ? j : i;
    Aout[idx] = C[(size_t)hi * k + lo] + 2.f * Rows[(size_t)i * K + __ldg(&perm[j])];
}

__global__ void pool_x(const float* __restrict__ xin, const int* __restrict__ perm,
                       const float* __restrict__ val, float* __restrict__ xout, int k)
{
    int idx = blockIdx.x * 256 + threadIdx.x;
    if (idx >= k * HP) return;
    int r = idx / HP, c = idx - r * HP;
    xout[idx] = xin[(size_t)perm[r] * HP + c] * val[r];
}

__global__ void scatter_add(float* __restrict__ dst, const float* __restrict__ x,
                            const int* __restrict__ perm, int k)
{
    int idx = blockIdx.x * 256 + threadIdx.x;
    if (idx >= k * HP) return;
    int r = idx / HP, c = idx - r * HP;
    dst[(size_t)perm[r] * HP + c] += x[idx];
}

__global__ void gemm_n2(const float* __restrict__ A, const float* __restrict__ Z,
                        float* __restrict__ out, int n)
{
    int row = blockIdx.x;
    const float* Ar = A + (size_t)row * n;
    float a0 = 0.f, a1 = 0.f;
    for (int j = threadIdx.x; j < n; j += 256) {
        float a = Ar[j];
        a0 += a * Z[2 * j];
        a1 += a * Z[2 * j + 1];
    }
    for (int o = 16; o > 0; o >>= 1) {
        a0 += __shfl_down_sync(0xffffffffu, a0, o);
        a1 += __shfl_down_sync(0xffffffffu, a1, o);
    }
    __shared__ float r0[8], r1[8];
    int w = threadIdx.x >> 5, l = threadIdx.x & 31;
    if (l == 0) { r0[w] = a0; r1[w] = a1; }
    __syncthreads();
    if (threadIdx.x == 0) {
        float s0 = 0.f, s1 = 0.f;
        for (int i = 0; i < 8; i++) { s0 += r0[i]; s1 += r1[i]; }
        out[2 * row] = s0;
        out[2 * row + 1] = s1;
    }
}

__global__ void final_kernel(const float* __restrict__ AZ, const float* __restrict__ Z,
                             const float* __restrict__ dinv, const float* __restrict__ b,
                             float* __restrict__ out, int n)
{
    int i = blockIdx.x * 256 + threadIdx.x;
    if (i >= n) return;
    float a = dinv[i] * (AZ[2 * i]     + 2.f * Z[2 * i])     + b[0];
    float c = dinv[i] * (AZ[2 * i + 1] + 2.f * Z[2 * i + 1]) + b[1];
    float m = fmaxf(a, c);
    float l = m + logf(expf(a - m) + expf(c - m));
    out[2 * i] = a - l;
    out[2 * i + 1] = c - l;
}

// ---------------- host orchestration ----------------
template <typename T, size_t NN>
static T* symaddr(T (&sym)[NN]) {
    void* p = nullptr;
    cudaGetSymbolAddress(&p, sym);
    return (T*)p;
}

#define TF32G_SMEM 73728

static void run_gcn(const float* A, int n, const float* xin, int lda_x, int Kdim,
                    const float* W, const float* b, float* xout, int relu,
                    int S, int asplit,
                    float* t0, float* t1, float* part, float* dinv)
{
    dim3 g1((H + 63) / 64, (n + 63) / 64);
    gemm64<<<g1, 256>>>(xin, W, t0, n, H, Kdim, lda_x, H, HP);
    rowsum_dinv<<<n, 256>>>(A, dinv, n);
    int tot = n * HP;
    scale_rows<<<(tot + 255) / 256, 256>>>(t0, dinv, t1, n, H, HP);
    dim3 g2(HP / 128, n / 128, S);
    if (asplit)
        tf32g<1, 0><<<g2, 256, TF32G_SMEM>>>(A, t1, part, n, HP, n, n, HP, HP);
    else
        tf32g<0, 0><<<g2, 256, TF32G_SMEM>>>(A, t1, part, n, HP, n, n, HP, HP);
    gcn_finish_sk<<<(tot + 255) / 256, 256>>>(part, t1, dinv, b, xout, n, relu, S);
}

extern "C" void kernel_launch(void* const* d_in, const int* in_sizes, int n_in,
                              void* d_out, int out_size)
{
    (void)in_sizes; (void)n_in; (void)out_size;
    const float* x   = (const float*)d_in[0];
    const float* adj = (const float*)d_in[1];
    const float* w0  = (const float*)d_in[2];
    const float* b0  = (const float*)d_in[3];
    const float* w1  = (const float*)d_in[4];
    const float* b1  = (const float*)d_in[5];
    const float* w2  = (const float*)d_in[6];
    const float* b2  = (const float*)d_in[7];
    const float* w3  = (const float*)d_in[8];
    const float* b3  = (const float*)d_in[9];
    const float* p1  = (const float*)d_in[10];
    const float* p2  = (const float*)d_in[11];
    const float* p3  = (const float*)d_in[12];
    const float* u0w = (const float*)d_in[13];
    const float* u0b = (const float*)d_in[14];
    const float* u1w = (const float*)d_in[15];
    const float* u1b = (const float*)d_in[16];
    const float* u2w = (const float*)d_in[17];
    const float* u2b = (const float*)d_in[18];

    static bool attr_done = false;
    if (!attr_done) {
        cudaFuncSetAttribute(tf32g<0, 0>, cudaFuncAttributeMaxDynamicSharedMemorySize, TF32G_SMEM);
        cudaFuncSetAttribute(tf32g<1, 0>, cudaFuncAttributeMaxDynamicSharedMemorySize, TF32G_SMEM);
        cudaFuncSetAttribute(tf32g<1, 1>, cudaFuncAttributeMaxDynamicSharedMemorySize, TF32G_SMEM);
        attr_done = true;
    }

    float* G    = symaddr(g_G);
    __nv_bfloat16* ROWS = symaddr(g_rows);
    float* A1   = symaddr(g_A1);
    float* A2   = symaddr(g_A2);
    float* A3   = symaddr(g_A3);
    float* X0   = symaddr(g_x0);
    float* X1   = symaddr(g_x1);
    float* X2   = symaddr(g_x2);
    float* X3   = symaddr(g_x3);
    float* T0   = symaddr(g_t0);
    float* T1   = symaddr(g_t1);
    float* PART = symaddr(g_part);
    float* CUR  = symaddr(g_cur);
    float* DINV = symaddr(g_dinv);
    float* SC   = symaddr(g_score);
    float* VAL  = symaddr(g_val);
    int*   P0   = symaddr(g_perm0);
    int*   P1   = symaddr(g_perm1);
    int*   P2   = symaddr(g_perm2);
    float* PN   = symaddr(g_pnorm);

    // ---- down: gcn0 ----
    run_gcn(adj, N0, x, 3, 3, w0, b0, X0, 1, 4, 0, T0, T1, PART, DINV);

    // ---- pool 1 (4096 -> 3072) ----
    pnorm_kernel<<<1, 256>>>(p1, PN);
    score_kernel<<<(N0 + 7) / 8, 256>>>(X0, p1, PN, SC, N0);
    topk_kernel<4096><<<1, 1024>>>(SC, N0, KP1, P0, VAL);
    {
        size_t tot = (size_t)KP1 * (N0 / 4);
        rowgather_bf16<<<(unsigned)((tot + 255) / 256), 256>>>(adj, N0, P0, ROWS, KP1);
        dim3 g(KP1 / 128, KP1 / 128);
        bf16gemm_xxt<<<g, 256>>>(ROWS, G, KP1, N0);
        pool_A_tri<<<(KP1 * KP1 + 255) / 256, 256>>>(G, ROWS, N0, P0, A1, KP1);
        pool_x<<<(KP1 * HP + 255) / 256, 256>>>(X0, P0, VAL, CUR, KP1);
    }
    run_gcn(A1, KP1, CUR, HP, H, w1, b1, X1, 1, 6, 0, T0, T1, PART, DINV);

    // ---- pool 2 (3072 -> 1536) ----
    pnorm_kernel<<<1, 256>>>(p2, PN);
    score_kernel<<<(KP1 + 7) / 8, 256>>>(X1, p2, PN, SC, KP1);
    topk_kernel<4096><<<1, 1024>>>(SC, KP1, KP2, P1, VAL);
    {
        size_t tot = (size_t)KP2 * (KP1 / 4);
        rowgather_bf16<<<(unsigned)((tot + 255) / 256), 256>>>(A1, KP1, P1, ROWS, KP2);
        dim3 g(KP2 / 128, KP2 / 128);
        bf16gemm_xxt<<<g, 256>>>(ROWS, G, KP2, KP1);
        pool_A_tri<<<(KP2 * KP2 + 255) / 256, 256>>>(G, ROWS, KP1, P1, A2, KP2);
        pool_x<<<(KP2 * HP + 255) / 256, 256>>>(X1, P1, VAL, CUR, KP2);
    }
    run_gcn(A2, KP2, CUR, HP, H, w2, b2, X2, 1, 8, 1, T0, T1, PART, DINV);

    // ---- pool 3 (1536 -> 768): fp32 gather + 3xTF32 tri X·X^T ----
    pnorm_kernel<<<1, 256>>>(p3, PN);
    score_kernel<<<(KP2 + 7) / 8, 256>>>(X2, p3, PN, SC, KP2);
    topk_kernel<2048><<<1, 1024>>>(SC, KP2, KP3, P2, VAL);
    {
        size_t tot = (size_t)KP3 * (KP2 / 4);
        rowgather_f32<<<(unsigned)((tot + 255) / 256), 256>>>(A2, KP2, P2, PART, KP3);
        dim3 g(KP3 / 128, KP3 / 128, 1);
        tf32g<1, 1><<<g, 256, TF32G_SMEM>>>(PART, PART, G, KP3, KP3, KP2, KP2, KP2, KP3);
        pool_A_tri_f32<<<(KP3 * KP3 + 255) / 256, 256>>>(G, PART, KP2, P2, A3, KP3);
        pool_x<<<(KP3 * HP + 255) / 256, 256>>>(X2, P2, VAL, CUR, KP3);
    }
    run_gcn(A3, KP3, CUR, HP, H, w3, b3, X3, 1, 8, 1, T0, T1, PART, DINV);

    // ---- up 0: j=2 ----
    cudaMemcpyAsync(CUR, X2, (size_t)KP2 * HP * sizeof(float), cudaMemcpyDeviceToDevice, 0);
    scatter_add<<<(KP3 * HP + 255) / 256, 256>>>(CUR, X3, P2, KP3);
    run_gcn(A2, KP2, CUR, HP, H, u0w, u0b, X2, 1, 8, 1, T0, T1, PART, DINV);

    // ---- up 1: j=1 ----
    cudaMemcpyAsync(CUR, X1, (size_t)KP1 * HP * sizeof(float), cudaMemcpyDeviceToDevice, 0);
    scatter_add<<<(KP2 * HP + 255) / 256, 256>>>(CUR, X2, P1, KP2);
    run_gcn(A1, KP1, CUR, HP, H, u1w, u1b, X1, 1, 6, 0, T0, T1, PART, DINV);

    // ---- up 2: j=0, final gcn (H->2) + log_softmax ----
    cudaMemcpyAsync(CUR, X0, (size_t)N0 * HP * sizeof(float), cudaMemcpyDeviceToDevice, 0);
    scatter_add<<<(KP1 * HP + 255) / 256, 256>>>(CUR, X1, P0, KP1);
    {
        dim3 gf(1, (N0 + 63) / 64);
        gemm64<<<gf, 256>>>(CUR, u2w, T0, N0, 2, H, HP, 2, 2);
        rowsum_dinv<<<N0, 256>>>(adj, DINV, N0);
        scale_rows<<<(N0 * 2 + 255) / 256, 256>>>(T0, DINV, T1, N0, 2, 2);
        gemm_n2<<<N0, 256>>>(adj, T1, T0, N0);
        final_kernel<<<(N0 + 255) / 256, 256>>>(T0, T1, DINV, u2b, (float*)d_out, N0);
    }
}

// round 8
// speedup vs baseline: 6.6957x; 1.1212x over previous
#include <cuda_runtime.h>
#include <cuda_bf16.h>
#include <math.h>
#include <stdint.h>

#define N0 4096
#define KP1 3072
#define KP2 1536
#define KP3 768
#define H 200
#define HP 256
#define SKMAX 12

// ---------------- device scratch (static: no allocation allowed) ----------------
__device__ float g_G[(size_t)N0 * N0];
__device__ __nv_bfloat16 g_rows[(size_t)KP1 * N0];     // gathered bf16 rows
__device__ float g_A1[(size_t)KP1 * KP1];
__device__ float g_A2[(size_t)KP2 * KP2];
__device__ float g_A3[(size_t)KP3 * KP3];
__device__ float g_x0[N0 * HP];
__device__ float g_x1[KP1 * HP];
__device__ float g_x2[KP2 * HP];
__device__ float g_x3[KP3 * HP];
__device__ float g_t0[N0 * HP];
__device__ float g_t1[N0 * HP];
__device__ float g_part[(size_t)SKMAX * N0 * HP];      // split-K partials / fp32 row scratch
__device__ float g_cur[N0 * HP];
__device__ float g_wpad[5][HP * HP];                   // padded weights (w1,w2,w3,u0w,u1w)
__device__ float g_d0[N0];
__device__ float g_d1[KP1];
__device__ float g_d2[KP2];
__device__ float g_d3[KP3];
__device__ float g_score[N0];
__device__ float g_val[N0];
__device__ int   g_perm0[KP1];
__device__ int   g_perm1[KP2];
__device__ int   g_perm2[KP3];
__device__ float g_pnorm[1];

__device__ __forceinline__ uint32_t f2tf(float x) {
    uint32_t r;
    asm("cvt.rna.tf32.f32 %0, %1;" : "=r"(r) : "f"(x));
    return r;
}

__device__ __forceinline__ void cpa16(uint32_t dst, const void* src) {
    asm volatile("cp.async.cg.shared.global [%0], [%1], 16;\n" :: "r"(dst), "l"(src));
}

// ============ bf16 X·X^T GEMM, lower triangle only (levels 1-2 augment) ==============
__global__ void __launch_bounds__(256) bf16gemm_xxt(
    const __nv_bfloat16* __restrict__ X, float* __restrict__ C, int k, int K)
{
    if (blockIdx.x > blockIdx.y) return;

    __shared__ __nv_bfloat16 As[2][128][40];
    __shared__ __nv_bfloat16 Bs[2][128][40];

    int t = threadIdx.x;
    int warp = t >> 5, lane = t & 31;
    int group = lane >> 2, tg = lane & 3;
    int wm = warp >> 2, wn = warp & 3;
    int bm = blockIdx.y * 128, bn = blockIdx.x * 128;

    float c[4][4][4];
#pragma unroll
    for (int mi = 0; mi < 4; mi++)
#pragma unroll
        for (int ni = 0; ni < 4; ni++)
#pragma unroll
            for (int r = 0; r < 4; r++) c[mi][ni][r] = 0.f;

    int lrow = t >> 1;
    int lcol0 = (t & 1) * 16;

    uint32_t aBase = (uint32_t)__cvta_generic_to_shared(&As[0][0][0]);
    uint32_t bBase = (uint32_t)__cvta_generic_to_shared(&Bs[0][0][0]);
    const uint32_t stageB = 128 * 40 * 2;
    uint32_t aDst = aBase + lrow * 80 + lcol0 * 2;
    uint32_t bDst = bBase + lrow * 80 + lcol0 * 2;

    const __nv_bfloat16* aSrcRow = X + (size_t)(bm + lrow) * K + lcol0;
    const __nv_bfloat16* bSrcRow = X + (size_t)(bn + lrow) * K + lcol0;

#define LOAD_STAGE(st, k0)                                        \
    do {                                                          \
        const __nv_bfloat16* ap = aSrcRow + (k0);                 \
        const __nv_bfloat16* bp = bSrcRow + (k0);                 \
        uint32_t ad = aDst + (st) * stageB;                       \
        uint32_t bd = bDst + (st) * stageB;                       \
        cpa16(ad, ap); cpa16(ad + 16, ap + 8);                    \
        cpa16(bd, bp); cpa16(bd + 16, bp + 8);                    \
    } while (0)

    LOAD_STAGE(0, 0);
    asm volatile("cp.async.commit_group;\n");

    int s = 0;
    for (int k0 = 0; k0 < K; k0 += 32) {
        if (k0 + 32 < K) {
            LOAD_STAGE(s ^ 1, k0 + 32);
            asm volatile("cp.async.commit_group;\n");
            asm volatile("cp.async.wait_group 1;\n");
        } else {
            asm volatile("cp.async.wait_group 0;\n");
        }
        __syncthreads();

#pragma unroll
        for (int ks = 0; ks < 2; ks++) {
            int kb = ks * 16;
            uint32_t af[4][4], bf[4][2];
#pragma unroll
            for (int mi = 0; mi < 4; mi++) {
                int rm = wm * 64 + mi * 16 + group;
                af[mi][0] = *(const uint32_t*)&As[s][rm][kb + 2 * tg];
                af[mi][1] = *(const uint32_t*)&As[s][rm + 8][kb + 2 * tg];
                af[mi][2] = *(const uint32_t*)&As[s][rm][kb + 2 * tg + 8];
                af[mi][3] = *(const uint32_t*)&As[s][rm + 8][kb + 2 * tg + 8];
            }
#pragma unroll
            for (int ni = 0; ni < 4; ni++) {
                int cn = wn * 32 + ni * 8 + group;
                bf[ni][0] = *(const uint32_t*)&Bs[s][cn][kb + 2 * tg];
                bf[ni][1] = *(const uint32_t*)&Bs[s][cn][kb + 2 * tg + 8];
            }
#pragma unroll
            for (int mi = 0; mi < 4; mi++)
#pragma unroll
                for (int ni = 0; ni < 4; ni++) {
                    asm volatile(
                        "mma.sync.aligned.m16n8k16.row.col.f32.bf16.bf16.f32 "
                        "{%0,%1,%2,%3}, {%4,%5,%6,%7}, {%8,%9}, {%0,%1,%2,%3};\n"
                        : "+f"(c[mi][ni][0]), "+f"(c[mi][ni][1]),
                          "+f"(c[mi][ni][2]), "+f"(c[mi][ni][3])
                        : "r"(af[mi][0]), "r"(af[mi][1]), "r"(af[mi][2]), "r"(af[mi][3]),
                          "r"(bf[ni][0]), "r"(bf[ni][1]));
                }
        }
        __syncthreads();
        s ^= 1;
    }
#undef LOAD_STAGE

#pragma unroll
    for (int mi = 0; mi < 4; mi++) {
        int row0 = bm + wm * 64 + mi * 16 + group;
#pragma unroll
        for (int ni = 0; ni < 4; ni++) {
            int col = bn + wn * 32 + ni * 8 + tg * 2;
            *(float2*)(C + (size_t)row0 * k + col)       = make_float2(c[mi][ni][0], c[mi][ni][1]);
            *(float2*)(C + (size_t)(row0 + 8) * k + col) = make_float2(c[mi][ni][2], c[mi][ni][3]);
        }
    }
}

// ============ tf32 GEMM, cp.async double-buffered ====================================
// ASPLIT=0: A raw bits (exact tf32 ints), B split hi/lo (2 mma).
// ASPLIT=1: A split too (3 mma).
// XXT=1: C = A·B^T with B row-major [n][K]; lower-tri blocks only.
// Split-K via gridDim.z. (K/gridDim.z) % 32 == 0. Dynamic smem: 73728 B.
template <int ASPLIT, int XXT>
__global__ void __launch_bounds__(256, (ASPLIT ? 1 : 2)) tf32g(
    const float* __restrict__ A, const float* __restrict__ B, float* __restrict__ Cpart,
    int M, int N, int K, int lda, int ldb, int ldc)
{
    if (XXT && (int)blockIdx.x > (int)blockIdx.y) return;
    extern __shared__ float smd[];
    const int STAGEF = 9216;
    const int BOFF = 128 * 36;

    int t = threadIdx.x;
    int warp = t >> 5, lane = t & 31;
    int group = lane >> 2, tg = lane & 3;
    int wm = warp >> 2, wn = warp & 3;
    int bm = blockIdx.y * 128, bn = blockIdx.x * 128;
    int kChunk = K / gridDim.z;
    int kStart = blockIdx.z * kChunk;
    float* C = Cpart + (size_t)blockIdx.z * M * ldc;

    float c[4][4][4];
#pragma unroll
    for (int mi = 0; mi < 4; mi++)
#pragma unroll
        for (int ni = 0; ni < 4; ni++)
#pragma unroll
            for (int r = 0; r < 4; r++) c[mi][ni][r] = 0.f;

    auto LOADST = [&](int st, int k0) {
        float* as = smd + st * STAGEF;
        float* bs = as + BOFF;
#pragma unroll
        for (int q = 0; q < 4; q++) {
            int cc = t + q * 256;
            int m = cc >> 3, kc = cc & 7;
            uint32_t ad = (uint32_t)__cvta_generic_to_shared(as + m * 36 + kc * 4);
            cpa16(ad, A + (size_t)(bm + m) * lda + kStart + k0 + kc * 4);
        }
        if (XXT) {
#pragma unroll
            for (int q = 0; q < 4; q++) {
                int cc = t + q * 256;
                int m = cc >> 3, kc = cc & 7;
                uint32_t bd = (uint32_t)__cvta_generic_to_shared(bs + m * 36 + kc * 4);
                cpa16(bd, B + (size_t)(bn + m) * ldb + kStart + k0 + kc * 4);
            }
        } else {
#pragma unroll
            for (int q = 0; q < 4; q++) {
                int cc = t + q * 256;
                int r = cc >> 5, nc = cc & 31;
                uint32_t bd = (uint32_t)__cvta_generic_to_shared(bs + r * 136 + nc * 4);
                cpa16(bd, B + (size_t)(kStart + k0 + r) * ldb + bn + nc * 4);
            }
        }
        asm volatile("cp.async.commit_group;\n");
    };

    LOADST(0, 0);

    int s = 0;
    for (int k0 = 0; k0 < kChunk; k0 += 32) {
        if (k0 + 32 < kChunk) {
            LOADST(s ^ 1, k0 + 32);
            asm volatile("cp.async.wait_group 1;\n");
        } else {
            asm volatile("cp.async.wait_group 0;\n");
        }
        __syncthreads();

        const float* as = smd + s * STAGEF;
        const float* bs = as + BOFF;

#pragma unroll
        for (int ks = 0; ks < 4; ks++) {
            int kb = ks * 8;
            uint32_t afh[4][4], afl[4][4], bfh[4][2], bfl[4][2];
#pragma unroll
            for (int mi = 0; mi < 4; mi++) {
                int rm = wm * 64 + mi * 16 + group;
                float a0 = as[rm * 36 + kb + tg];
                float a1 = as[(rm + 8) * 36 + kb + tg];
                float a2 = as[rm * 36 + kb + tg + 4];
                float a3 = as[(rm + 8) * 36 + kb + tg + 4];
                if (ASPLIT) {
                    afh[mi][0] = f2tf(a0); afh[mi][1] = f2tf(a1);
                    afh[mi][2] = f2tf(a2); afh[mi][3] = f2tf(a3);
                    afl[mi][0] = f2tf(a0 - __uint_as_float(afh[mi][0]));
                    afl[mi][1] = f2tf(a1 - __uint_as_float(afh[mi][1]));
                    afl[mi][2] = f2tf(a2 - __uint_as_float(afh[mi][2]));
                    afl[mi][3] = f2tf(a3 - __uint_as_float(afh[mi][3]));
                } else {
                    afh[mi][0] = __float_as_uint(a0); afh[mi][1] = __float_as_uint(a1);
                    afh[mi][2] = __float_as_uint(a2); afh[mi][3] = __float_as_uint(a3);
                }
            }
#pragma unroll
            for (int ni = 0; ni < 4; ni++) {
                int cn = wn * 32 + ni * 8 + group;
                float b0, b1;
                if (XXT) {
                    b0 = bs[cn * 36 + kb + tg];
                    b1 = bs[cn * 36 + kb + tg + 4];
                } else {
                    b0 = bs[(kb + tg) * 136 + cn];
                    b1 = bs[(kb + tg + 4) * 136 + cn];
                }
                bfh[ni][0] = f2tf(b0);
                bfh[ni][1] = f2tf(b1);
                bfl[ni][0] = f2tf(b0 - __uint_as_float(bfh[ni][0]));
                bfl[ni][1] = f2tf(b1 - __uint_as_float(bfh[ni][1]));
            }
#pragma unroll
            for (int mi = 0; mi < 4; mi++)
#pragma unroll
                for (int ni = 0; ni < 4; ni++) {
                    asm volatile(
                        "mma.sync.aligned.m16n8k8.row.col.f32.tf32.tf32.f32 "
                        "{%0,%1,%2,%3}, {%4,%5,%6,%7}, {%8,%9}, {%0,%1,%2,%3};\n"
                        : "+f"(c[mi][ni][0]), "+f"(c[mi][ni][1]),
                          "+f"(c[mi][ni][2]), "+f"(c[mi][ni][3])
                        : "r"(afh[mi][0]), "r"(afh[mi][1]), "r"(afh[mi][2]), "r"(afh[mi][3]),
                          "r"(bfl[ni][0]), "r"(bfl[ni][1]));
                    if (ASPLIT) {
                        asm volatile(
                            "mma.sync.aligned.m16n8k8.row.col.f32.tf32.tf32.f32 "
                            "{%0,%1,%2,%3}, {%4,%5,%6,%7}, {%8,%9}, {%0,%1,%2,%3};\n"
                            : "+f"(c[mi][ni][0]), "+f"(c[mi][ni][1]),
                              "+f"(c[mi][ni][2]), "+f"(c[mi][ni][3])
                            : "r"(afl[mi][0]), "r"(afl[mi][1]), "r"(afl[mi][2]), "r"(afl[mi][3]),
                              "r"(bfh[ni][0]), "r"(bfh[ni][1]));
                    }
                    asm volatile(
                        "mma.sync.aligned.m16n8k8.row.col.f32.tf32.tf32.f32 "
                        "{%0,%1,%2,%3}, {%4,%5,%6,%7}, {%8,%9}, {%0,%1,%2,%3};\n"
                        : "+f"(c[mi][ni][0]), "+f"(c[mi][ni][1]),
                          "+f"(c[mi][ni][2]), "+f"(c[mi][ni][3])
                        : "r"(afh[mi][0]), "r"(afh[mi][1]), "r"(afh[mi][2]), "r"(afh[mi][3]),
                          "r"(bfh[ni][0]), "r"(bfh[ni][1]));
                }
        }
        __syncthreads();
        s ^= 1;
    }

#pragma unroll
    for (int mi = 0; mi < 4; mi++) {
        int row0 = bm + wm * 64 + mi * 16 + group;
#pragma unroll
        for (int ni = 0; ni < 4; ni++) {
            int col = bn + wn * 32 + ni * 8 + tg * 2;
            *(float2*)(C + (size_t)row0 * ldc + col)       = make_float2(c[mi][ni][0], c[mi][ni][1]);
            *(float2*)(C + (size_t)(row0 + 8) * ldc + col) = make_float2(c[mi][ni][2], c[mi][ni][3]);
        }
    }
}

// ---------------- generic SGEMM: 64x64 block, bounds-checked (small K paths) --------
__global__ void __launch_bounds__(256) gemm64(
    const float* __restrict__ A, const float* __restrict__ B, float* __restrict__ C,
    int M, int N, int K, int lda, int ldb, int ldc)
{
    __shared__ float As[16][65];
    __shared__ float Bs[16][64];
    int tid = threadIdx.x, tx = tid & 15, ty = tid >> 4;
    int bm = blockIdx.y * 64, bn = blockIdx.x * 64;
    float acc[4][4];
#pragma unroll
    for (int i = 0; i < 4; i++)
#pragma unroll
        for (int j = 0; j < 4; j++) acc[i][j] = 0.f;

    for (int k0 = 0; k0 < K; k0 += 16) {
        for (int t = tid; t < 64 * 16; t += 256) {
            int r = t >> 4, c = t & 15;
            int gr = bm + r, gc = k0 + c;
            As[c][r] = (gr < M && gc < K) ? A[(size_t)gr * lda + gc] : 0.f;
        }
        for (int t = tid; t < 16 * 64; t += 256) {
            int r = t >> 6, c = t & 63;
            int gr = k0 + r, gc = bn + c;
            Bs[r][c] = (gr < K && gc < N) ? B[(size_t)gr * ldb + gc] : 0.f;
        }
        __syncthreads();
#pragma unroll
        for (int kk = 0; kk < 16; kk++) {
            float a[4], b[4];
#pragma unroll
            for (int i = 0; i < 4; i++) a[i] = As[kk][ty * 4 + i];
#pragma unroll
            for (int j = 0; j < 4; j++) b[j] = Bs[kk][tx * 4 + j];
#pragma unroll
            for (int i = 0; i < 4; i++)
#pragma unroll
                for (int j = 0; j < 4; j++) acc[i][j] += a[i] * b[j];
        }
        __syncthreads();
    }
#pragma unroll
    for (int i = 0; i < 4; i++)
#pragma unroll
        for (int j = 0; j < 4; j++) {
            int gr = bm + ty * 4 + i, gc = bn + tx * 4 + j;
            if (gr < M && gc < N) C[(size_t)gr * ldc + gc] = acc[i][j];
        }
}

// ---------------- small helper kernels ----------------
__global__ void pad_w(const float* __restrict__ W, float* __restrict__ out)
{
    int idx = blockIdx.x * 256 + threadIdx.x;
    if (idx >= HP * HP) return;
    int i = idx >> 8, j = idx & 255;
    out[idx] = (i < H && j < H) ? W[i * H + j] : 0.f;
}

__global__ void rowgather_bf16(const float* __restrict__ A, int n,
                               const int* __restrict__ perm,
                               __nv_bfloat16* __restrict__ out, int krows)
{
    size_t idx = (size_t)blockIdx.x * 256 + threadIdx.x;
    size_t n4 = (size_t)n / 4;
    if (idx >= (size_t)krows * n4) return;
    int i = (int)(idx / n4);
    int j4 = (int)(idx - (size_t)i * n4);
    float4 v = *(const float4*)(A + (size_t)perm[i] * n + j4 * 4);
    __nv_bfloat162 a = __floats2bfloat162_rn(v.x, v.y);
    __nv_bfloat162 b = __floats2bfloat162_rn(v.z, v.w);
    *(__nv_bfloat162*)(out + (size_t)i * n + j4 * 4)     = a;
    *(__nv_bfloat162*)(out + (size_t)i * n + j4 * 4 + 2) = b;
}

__global__ void rowgather_f32(const float* __restrict__ A, int n,
                              const int* __restrict__ perm,
                              float* __restrict__ out, int krows)
{
    size_t idx = (size_t)blockIdx.x * 256 + threadIdx.x;
    size_t n4 = (size_t)n / 4;
    if (idx >= (size_t)krows * n4) return;
    int i = (int)(idx / n4);
    int j4 = (int)(idx - (size_t)i * n4);
    float4 v = *(const float4*)(A + (size_t)perm[i] * n + j4 * 4);
    *(float4*)(out + (size_t)i * n + j4 * 4) = v;
}

__global__ void rowsum_dinv(const float* __restrict__ A, float* __restrict__ dinv, int n)
{
    int row = blockIdx.x;
    const float* Ar = A + (size_t)row * n;
    float s = 0.f;
    for (int j = threadIdx.x; j < n; j += 256) s += Ar[j];
    for (int o = 16; o > 0; o >>= 1) s += __shfl_down_sync(0xffffffffu, s, o);
    __shared__ float red[8];
    int w = threadIdx.x >> 5, l = threadIdx.x & 31;
    if (l == 0) red[w] = s;
    __syncthreads();
    if (threadIdx.x == 0) {
        float t = 0.f;
        for (int i = 0; i < 8; i++) t += red[i];
        dinv[row] = 1.0f / sqrtf(t + 2.0f);
    }
}

__global__ void scale_rows(const float* __restrict__ in, const float* __restrict__ dinv,
                           float* __restrict__ out, int n, int w, int ld)
{
    int idx = blockIdx.x * 256 + threadIdx.x;
    if (idx >= n * ld) return;
    int r = idx / ld, c = idx - r * ld;
    out[idx] = (c < w) ? dinv[r] * in[idx] : 0.f;
}

__global__ void gcn_finish_sk(const float* __restrict__ part, const float* __restrict__ Z,
                              const float* __restrict__ dinv, const float* __restrict__ b,
                              float* __restrict__ out, int n, int relu, int S)
{
    int idx = blockIdx.x * 256 + threadIdx.x;
    if (idx >= n * HP) return;
    int r = idx / HP, c = idx - r * HP;
    float v = 0.f;
    if (c < H) {
        float az = 0.f;
        size_t stride = (size_t)n * HP;
        for (int s = 0; s < S; s++) az += part[s * stride + idx];
        v = dinv[r] * (az + 2.f * Z[idx]) + b[c];
        if (relu) v = fmaxf(v, 0.f);
    }
    out[idx] = v;
}

__global__ void pnorm_kernel(const float* __restrict__ p, float* __restrict__ out)
{
    float s = 0.f;
    for (int i = threadIdx.x; i < H; i += 256) { float v = p[i]; s += v * v; }
    for (int o = 16; o > 0; o >>= 1) s += __shfl_down_sync(0xffffffffu, s, o);
    __shared__ float red[8];
    int w = threadIdx.x >> 5, l = threadIdx.x & 31;
    if (l == 0) red[w] = s;
    __syncthreads();
    if (threadIdx.x == 0) {
        float t = 0.f;
        for (int i = 0; i < 8; i++) t += red[i];
        *out = sqrtf(t);
    }
}

__global__ void score_kernel(const float* __restrict__ x, const float* __restrict__ p,
                             const float* __restrict__ pn, float* __restrict__ score, int n)
{
    int row = blockIdx.x * 8 + (threadIdx.x >> 5);
    int lane = threadIdx.x & 31;
    if (row >= n) return;
    const float* xr = x + (size_t)row * HP;
    float s = 0.f;
    for (int c = lane; c < H; c += 32) s += xr[c] * p[c];
    for (int o = 16; o > 0; o >>= 1) s += __shfl_down_sync(0xffffffffu, s, o);
    if (lane == 0) score[row] = tanhf(s / (*pn));
}

// uint64-key bitonic topk (descending score, ascending index ties — matches jax)
template <int SIZE>
__global__ void topk_kernel(const float* __restrict__ score, int n, int k,
                            int* __restrict__ perm, float* __restrict__ val)
{
    __shared__ unsigned long long key[SIZE];
    int tid = threadIdx.x;
    for (int i = tid; i < SIZE; i += 1024) {
        float s = (i < n) ? score[i] : -INFINITY;
        uint32_t u = __float_as_uint(s);
        u = (u & 0x80000000u) ? ~u : (u | 0x80000000u);
        uint32_t d = ~u;
        key[i] = ((unsigned long long)d << 32) | (uint32_t)i;
    }
    __syncthreads();
    for (int size = 2; size <= SIZE; size <<= 1) {
        for (int stride = size >> 1; stride > 0; stride >>= 1) {
            for (int i = tid; i < SIZE; i += 1024) {
                int j = i ^ stride;
                if (j > i) {
                    unsigned long long a = key[i], b = key[j];
                    bool up = ((i & size) == 0);
                    if (up ? (a > b) : (a < b)) { key[i] = b; key[j] = a; }
                }
            }
            __syncthreads();
        }
    }
    for (int i = tid; i < k; i += 1024) {
        int si = (int)(uint32_t)key[i];
        perm[i] = si;
        val[i] = score[si];
    }
}

// levels 1-2: A_out[i][j] = (i==j) ? 0 : C[max][min] + 2*Rows[i][perm[j]]
__global__ void pool_A_tri(const float* __restrict__ C, const __nv_bfloat16* __restrict__ Rows,
                           int K, const int* __restrict__ perm,
                           float* __restrict__ Aout, int k)
{
    int idx = blockIdx.x * 256 + threadIdx.x;
    if (idx >= k * k) return;
    int i = idx / k, j = idx - i * k;
    if (i == j) { Aout[idx] = 0.f; return; }
    int hi = i > j ? i : j, lo = i > j ? j : i;
    float g = C[(size_t)hi * k + lo];
    float a = __bfloat162float(Rows[(size_t)i * K + __ldg(&perm[j])]);
    Aout[idx] = g + 2.f * a;
}

// level 3 (fp32 rows)
__global__ void pool_A_tri_f32(const float* __restrict__ C, const float* __restrict__ Rows,
                               int K, const int* __restrict__ perm,
                               float* __restrict__ Aout, int k)
{
    int idx = blockIdx.x * 256 + threadIdx.x;
    if (idx >= k * k) return;
    int i = idx / k, j = idx - i * k;
    if (i == j) { Aout[idx] = 0.f; return; }
    int hi = i > j ? i : j, lo = i > j ? j : i;
    Aout[idx] = C[(size_t)hi * k + lo] + 2.f * Rows[(size_t)i * K + __ldg(&perm[j])];
}

__global__ void pool_x(const float* __restrict__ xin, const int* __restrict__ perm,
                       const float* __restrict__ val, float* __restrict__ xout, int k)
{
    int idx = blockIdx.x * 256 + threadIdx.x;
    if (idx >= k * HP) return;
    int r = idx / HP, c = idx - r * HP;
    xout[idx] = xin[(size_t)perm[r] * HP + c] * val[r];
}

__global__ void scatter_add(float* __restrict__ dst, const float* __restrict__ x,
                            const int* __restrict__ perm, int k)
{
    int idx = blockIdx.x * 256 + threadIdx.x;
    if (idx >= k * HP) return;
    int r = idx / HP, c = idx - r * HP;
    dst[(size_t)perm[r] * HP + c] += x[idx];
}

__global__ void gemm_n2(const float* __restrict__ A, const float* __restrict__ Z,
                        float* __restrict__ out, int n)
{
    int row = blockIdx.x;
    const float* Ar = A + (size_t)row * n;
    float a0 = 0.f, a1 = 0.f;
    for (int j = threadIdx.x; j < n; j += 256) {
        float a = Ar[j];
        a0 += a * Z[2 * j];
        a1 += a * Z[2 * j + 1];
    }
    for (int o = 16; o > 0; o >>= 1) {
        a0 += __shfl_down_sync(0xffffffffu, a0, o);
        a1 += __shfl_down_sync(0xffffffffu, a1, o);
    }
    __shared__ float r0[8], r1[8];
    int w = threadIdx.x >> 5, l = threadIdx.x & 31;
    if (l == 0) { r0[w] = a0; r1[w] = a1; }
    __syncthreads();
    if (threadIdx.x == 0) {
        float s0 = 0.f, s1 = 0.f;
        for (int i = 0; i < 8; i++) { s0 += r0[i]; s1 += r1[i]; }
        out[2 * row] = s0;
        out[2 * row + 1] = s1;
    }
}

__global__ void final_kernel(const float* __restrict__ AZ, const float* __restrict__ Z,
                             const float* __restrict__ dinv, const float* __restrict__ b,
                             float* __restrict__ out, int n)
{
    int i = blockIdx.x * 256 + threadIdx.x;
    if (i >= n) return;
    float a = dinv[i] * (AZ[2 * i]     + 2.f * Z[2 * i])     + b[0];
    float c = dinv[i] * (AZ[2 * i + 1] + 2.f * Z[2 * i + 1]) + b[1];
    float m = fmaxf(a, c);
    float l = m + logf(expf(a - m) + expf(c - m));
    out[2 * i] = a - l;
    out[2 * i + 1] = c - l;
}

// ---------------- host orchestration ----------------
template <typename T, size_t NN>
static T* symaddr(T (&sym)[NN]) {
    void* p = nullptr;
    cudaGetSymbolAddress(&p, sym);
    return (T*)p;
}
template <typename T, size_t M2, size_t NN>
static T* symaddr2(T (&sym)[M2][NN]) {
    void* p = nullptr;
    cudaGetSymbolAddress(&p, sym);
    return (T*)p;
}

#define TF32G_SMEM 73728

// GCN with tensor-core xW (Wpad is HP x HP zero-padded) and cached dinv
static void run_gcn_tc(const float* A, int n, const float* xin, const float* Wpad,
                       const float* b, float* xout, int relu, int S, int asplit,
                       const float* dinv, float* t0, float* t1, float* part)
{
    dim3 gw(HP / 128, n / 128, 1);
    tf32g<1, 0><<<gw, 256, TF32G_SMEM>>>(xin, Wpad, t0, n, HP, HP, HP, HP, HP);
    int tot = n * HP;
    scale_rows<<<(tot + 255) / 256, 256>>>(t0, dinv, t1, n, H, HP);
    dim3 g2(HP / 128, n / 128, S);
    if (asplit)
        tf32g<1, 0><<<g2, 256, TF32G_SMEM>>>(A, t1, part, n, HP, n, n, HP, HP);
    else
        tf32g<0, 0><<<g2, 256, TF32G_SMEM>>>(A, t1, part, n, HP, n, n, HP, HP);
    gcn_finish_sk<<<(tot + 255) / 256, 256>>>(part, t1, dinv, b, xout, n, relu, S);
}

extern "C" void kernel_launch(void* const* d_in, const int* in_sizes, int n_in,
                              void* d_out, int out_size)
{
    (void)in_sizes; (void)n_in; (void)out_size;
    const float* x   = (const float*)d_in[0];
    const float* adj = (const float*)d_in[1];
    const float* w0  = (const float*)d_in[2];
    const float* b0  = (const float*)d_in[3];
    const float* w1  = (const float*)d_in[4];
    const float* b1  = (const float*)d_in[5];
    const float* w2  = (const float*)d_in[6];
    const float* b2  = (const float*)d_in[7];
    const float* w3  = (const float*)d_in[8];
    const float* b3  = (const float*)d_in[9];
    const float* p1  = (const float*)d_in[10];
    const float* p2  = (const float*)d_in[11];
    const float* p3  = (const float*)d_in[12];
    const float* u0w = (const float*)d_in[13];
    const float* u0b = (const float*)d_in[14];
    const float* u1w = (const float*)d_in[15];
    const float* u1b = (const float*)d_in[16];
    const float* u2w = (const float*)d_in[17];
    const float* u2b = (const float*)d_in[18];

    static bool attr_done = false;
    if (!attr_done) {
        cudaFuncSetAttribute(tf32g<0, 0>, cudaFuncAttributeMaxDynamicSharedMemorySize, TF32G_SMEM);
        cudaFuncSetAttribute(tf32g<1, 0>, cudaFuncAttributeMaxDynamicSharedMemorySize, TF32G_SMEM);
        cudaFuncSetAttribute(tf32g<1, 1>, cudaFuncAttributeMaxDynamicSharedMemorySize, TF32G_SMEM);
        attr_done = true;
    }

    float* G    = symaddr(g_G);
    __nv_bfloat16* ROWS = symaddr(g_rows);
    float* A1   = symaddr(g_A1);
    float* A2   = symaddr(g_A2);
    float* A3   = symaddr(g_A3);
    float* X0   = symaddr(g_x0);
    float* X1   = symaddr(g_x1);
    float* X2   = symaddr(g_x2);
    float* X3   = symaddr(g_x3);
    float* T0   = symaddr(g_t0);
    float* T1   = symaddr(g_t1);
    float* PART = symaddr(g_part);
    float* CUR  = symaddr(g_cur);
    float* WP   = symaddr2(g_wpad);
    float* D0   = symaddr(g_d0);
    float* D1   = symaddr(g_d1);
    float* D2   = symaddr(g_d2);
    float* D3   = symaddr(g_d3);
    float* SC   = symaddr(g_score);
    float* VAL  = symaddr(g_val);
    int*   P0   = symaddr(g_perm0);
    int*   P1   = symaddr(g_perm1);
    int*   P2   = symaddr(g_perm2);
    float* PN   = symaddr(g_pnorm);

    float* WP_w1  = WP + 0 * HP * HP;
    float* WP_w2  = WP + 1 * HP * HP;
    float* WP_w3  = WP + 2 * HP * HP;
    float* WP_u0w = WP + 3 * HP * HP;
    float* WP_u1w = WP + 4 * HP * HP;

    // ---- prep: padded weights + adj dinv ----
    const int PG = (HP * HP + 255) / 256;
    pad_w<<<PG, 256>>>(w1, WP_w1);
    pad_w<<<PG, 256>>>(w2, WP_w2);
    pad_w<<<PG, 256>>>(w3, WP_w3);
    pad_w<<<PG, 256>>>(u0w, WP_u0w);
    pad_w<<<PG, 256>>>(u1w, WP_u1w);
    rowsum_dinv<<<N0, 256>>>(adj, D0, N0);

    // ---- down: gcn0 (xW via gemm64: K=3) ----
    {
        dim3 g1((H + 63) / 64, (N0 + 63) / 64);
        gemm64<<<g1, 256>>>(x, w0, T0, N0, H, 3, 3, H, HP);
        int tot = N0 * HP;
        scale_rows<<<(tot + 255) / 256, 256>>>(T0, D0, T1, N0, H, HP);
        dim3 g2(HP / 128, N0 / 128, 4);
        tf32g<0, 0><<<g2, 256, TF32G_SMEM>>>(adj, T1, PART, N0, HP, N0, N0, HP, HP);
        gcn_finish_sk<<<(tot + 255) / 256, 256>>>(PART, T1, D0, b0, X0, N0, 1, 4);
    }

    // ---- pool 1 (4096 -> 3072) ----
    pnorm_kernel<<<1, 256>>>(p1, PN);
    score_kernel<<<(N0 + 7) / 8, 256>>>(X0, p1, PN, SC, N0);
    topk_kernel<4096><<<1, 1024>>>(SC, N0, KP1, P0, VAL);
    {
        size_t tot = (size_t)KP1 * (N0 / 4);
        rowgather_bf16<<<(unsigned)((tot + 255) / 256), 256>>>(adj, N0, P0, ROWS, KP1);
        dim3 g(KP1 / 128, KP1 / 128);
        bf16gemm_xxt<<<g, 256>>>(ROWS, G, KP1, N0);
        pool_A_tri<<<(KP1 * KP1 + 255) / 256, 256>>>(G, ROWS, N0, P0, A1, KP1);
        pool_x<<<(KP1 * HP + 255) / 256, 256>>>(X0, P0, VAL, CUR, KP1);
    }
    rowsum_dinv<<<KP1, 256>>>(A1, D1, KP1);
    run_gcn_tc(A1, KP1, CUR, WP_w1, b1, X1, 1, 6, 0, D1, T0, T1, PART);

    // ---- pool 2 (3072 -> 1536) ----
    pnorm_kernel<<<1, 256>>>(p2, PN);
    score_kernel<<<(KP1 + 7) / 8, 256>>>(X1, p2, PN, SC, KP1);
    topk_kernel<4096><<<1, 1024>>>(SC, KP1, KP2, P1, VAL);
    {
        size_t tot = (size_t)KP2 * (KP1 / 4);
        rowgather_bf16<<<(unsigned)((tot + 255) / 256), 256>>>(A1, KP1, P1, ROWS, KP2);
        dim3 g(KP2 / 128, KP2 / 128);
        bf16gemm_xxt<<<g, 256>>>(ROWS, G, KP2, KP1);
        pool_A_tri<<<(KP2 * KP2 + 255) / 256, 256>>>(G, ROWS, KP1, P1, A2, KP2);
        pool_x<<<(KP2 * HP + 255) / 256, 256>>>(X1, P1, VAL, CUR, KP2);
    }
    rowsum_dinv<<<KP2, 256>>>(A2, D2, KP2);
    run_gcn_tc(A2, KP2, CUR, WP_w2, b2, X2, 1, 6, 1, D2, T0, T1, PART);

    // ---- pool 3 (1536 -> 768): fp32 gather + 3xTF32 tri X·X^T ----
    pnorm_kernel<<<1, 256>>>(p3, PN);
    score_kernel<<<(KP2 + 7) / 8, 256>>>(X2, p3, PN, SC, KP2);
    topk_kernel<2048><<<1, 1024>>>(SC, KP2, KP3, P2, VAL);
    {
        size_t tot = (size_t)KP3 * (KP2 / 4);
        rowgather_f32<<<(unsigned)((tot + 255) / 256), 256>>>(A2, KP2, P2, PART, KP3);
        dim3 g(KP3 / 128, KP3 / 128, 1);
        tf32g<1, 1><<<g, 256, TF32G_SMEM>>>(PART, PART, G, KP3, KP3, KP2, KP2, KP2, KP3);
        pool_A_tri_f32<<<(KP3 * KP3 + 255) / 256, 256>>>(G, PART, KP2, P2, A3, KP3);
        pool_x<<<(KP3 * HP + 255) / 256, 256>>>(X2, P2, VAL, CUR, KP3);
    }
    rowsum_dinv<<<KP3, 256>>>(A3, D3, KP3);
    run_gcn_tc(A3, KP3, CUR, WP_w3, b3, X3, 1, 12, 1, D3, T0, T1, PART);

    // ---- up 0: j=2 ----
    cudaMemcpyAsync(CUR, X2, (size_t)KP2 * HP * sizeof(float), cudaMemcpyDeviceToDevice, 0);
    scatter_add<<<(KP3 * HP + 255) / 256, 256>>>(CUR, X3, P2, KP3);
    run_gcn_tc(A2, KP2, CUR, WP_u0w, u0b, X2, 1, 6, 1, D2, T0, T1, PART);

    // ---- up 1: j=1 ----
    cudaMemcpyAsync(CUR, X1, (size_t)KP1 * HP * sizeof(float), cudaMemcpyDeviceToDevice, 0);
    scatter_add<<<(KP2 * HP + 255) / 256, 256>>>(CUR, X2, P1, KP2);
    run_gcn_tc(A1, KP1, CUR, WP_u1w, u1b, X1, 1, 6, 0, D1, T0, T1, PART);

    // ---- up 2: j=0, final gcn (H->2) + log_softmax ----
    cudaMemcpyAsync(CUR, X0, (size_t)N0 * HP * sizeof(float), cudaMemcpyDeviceToDevice, 0);
    scatter_add<<<(KP1 * HP + 255) / 256, 256>>>(CUR, X1, P0, KP1);
    {
        dim3 gf(1, (N0 + 63) / 64);
        gemm64<<<gf, 256>>>(CUR, u2w, T0, N0, 2, H, HP, 2, 2);
        scale_rows<<<(N0 * 2 + 255) / 256, 256>>>(T0, D0, T1, N0, 2, 2);
        gemm_n2<<<N0, 256>>>(adj, T1, T0, N0);
        final_kernel<<<(N0 + 255) / 256, 256>>>(T0, T1, D0, u2b, (float*)d_out, N0);
    }
}

// round 9
// speedup vs baseline: 7.2409x; 1.0814x over previous
#include <cuda_runtime.h>
#include <cuda_bf16.h>
#include <math.h>
#include <stdint.h>

#define N0 4096
#define KP1 3072
#define KP2 1536
#define KP3 768
#define H 200
#define HP 256
#define SKMAX 12

// ---------------- device scratch (static: no allocation allowed) ----------------
__device__ float g_G[(size_t)N0 * N0];
__device__ __nv_bfloat16 g_rows[(size_t)KP1 * N0];
__device__ float g_A1[(size_t)KP1 * KP1];
__device__ float g_A2[(size_t)KP2 * KP2];
__device__ float g_A3[(size_t)KP3 * KP3];
__device__ float g_x0[N0 * HP];
__device__ float g_x1[KP1 * HP];
__device__ float g_x2[KP2 * HP];
__device__ float g_x3[KP3 * HP];
__device__ float g_t0[N0 * HP];
__device__ float g_t1[N0 * HP];
__device__ float g_part[(size_t)SKMAX * N0 * HP];
__device__ float g_cur[N0 * HP];
__device__ float g_wpad[5][HP * HP];
__device__ float g_d0[N0];
__device__ float g_d1[KP1];
__device__ float g_d2[KP2];
__device__ float g_d3[KP3];
__device__ float g_score[N0];
__device__ float g_val[N0];
__device__ int   g_perm0[KP1];
__device__ int   g_perm1[KP2];
__device__ int   g_perm2[KP3];
__device__ float g_pnorm[1];

__device__ __forceinline__ uint32_t f2tf(float x) {
    uint32_t r;
    asm("cvt.rna.tf32.f32 %0, %1;" : "=r"(r) : "f"(x));
    return r;
}

__device__ __forceinline__ void cpa16(uint32_t dst, const void* src) {
    asm volatile("cp.async.cg.shared.global [%0], [%1], 16;\n" :: "r"(dst), "l"(src));
}

__device__ __forceinline__ uint32_t packbf(float x, float y) {
    __nv_bfloat162 h = __floats2bfloat162_rn(x, y);
    return *(uint32_t*)&h;
}
__device__ __forceinline__ uint32_t packbf_res(float x, float y, uint32_t hi) {
    __nv_bfloat162 h = *(__nv_bfloat162*)&hi;
    return packbf(x - __bfloat162float(h.x), y - __bfloat162float(h.y));
}

#define MMA_BF16(c, a, b)                                                         \
    asm volatile(                                                                 \
        "mma.sync.aligned.m16n8k16.row.col.f32.bf16.bf16.f32 "                    \
        "{%0,%1,%2,%3}, {%4,%5,%6,%7}, {%8,%9}, {%0,%1,%2,%3};\n"                 \
        : "+f"((c)[0]), "+f"((c)[1]), "+f"((c)[2]), "+f"((c)[3])                  \
        : "r"((a)[0]), "r"((a)[1]), "r"((a)[2]), "r"((a)[3]),                     \
          "r"((b)[0]), "r"((b)[1]))

// ============ bf16 X·X^T GEMM (bf16 input), lower triangle (levels 1-2 augment) ======
__global__ void __launch_bounds__(256) bf16gemm_xxt(
    const __nv_bfloat16* __restrict__ X, float* __restrict__ C, int k, int K)
{
    if (blockIdx.x > blockIdx.y) return;

    __shared__ __nv_bfloat16 As[2][128][40];
    __shared__ __nv_bfloat16 Bs[2][128][40];

    int t = threadIdx.x;
    int warp = t >> 5, lane = t & 31;
    int group = lane >> 2, tg = lane & 3;
    int wm = warp >> 2, wn = warp & 3;
    int bm = blockIdx.y * 128, bn = blockIdx.x * 128;

    float c[4][4][4];
#pragma unroll
    for (int mi = 0; mi < 4; mi++)
#pragma unroll
        for (int ni = 0; ni < 4; ni++)
#pragma unroll
            for (int r = 0; r < 4; r++) c[mi][ni][r] = 0.f;

    int lrow = t >> 1;
    int lcol0 = (t & 1) * 16;

    uint32_t aBase = (uint32_t)__cvta_generic_to_shared(&As[0][0][0]);
    uint32_t bBase = (uint32_t)__cvta_generic_to_shared(&Bs[0][0][0]);
    const uint32_t stageB = 128 * 40 * 2;
    uint32_t aDst = aBase + lrow * 80 + lcol0 * 2;
    uint32_t bDst = bBase + lrow * 80 + lcol0 * 2;

    const __nv_bfloat16* aSrcRow = X + (size_t)(bm + lrow) * K + lcol0;
    const __nv_bfloat16* bSrcRow = X + (size_t)(bn + lrow) * K + lcol0;

#define LOAD_STAGE(st, k0)                                        \
    do {                                                          \
        const __nv_bfloat16* ap = aSrcRow + (k0);                 \
        const __nv_bfloat16* bp = bSrcRow + (k0);                 \
        uint32_t ad = aDst + (st) * stageB;                       \
        uint32_t bd = bDst + (st) * stageB;                       \
        cpa16(ad, ap); cpa16(ad + 16, ap + 8);                    \
        cpa16(bd, bp); cpa16(bd + 16, bp + 8);                    \
    } while (0)

    LOAD_STAGE(0, 0);
    asm volatile("cp.async.commit_group;\n");

    int s = 0;
    for (int k0 = 0; k0 < K; k0 += 32) {
        if (k0 + 32 < K) {
            LOAD_STAGE(s ^ 1, k0 + 32);
            asm volatile("cp.async.commit_group;\n");
            asm volatile("cp.async.wait_group 1;\n");
        } else {
            asm volatile("cp.async.wait_group 0;\n");
        }
        __syncthreads();

#pragma unroll
        for (int ks = 0; ks < 2; ks++) {
            int kb = ks * 16;
            uint32_t af[4][4], bf[4][2];
#pragma unroll
            for (int mi = 0; mi < 4; mi++) {
                int rm = wm * 64 + mi * 16 + group;
                af[mi][0] = *(const uint32_t*)&As[s][rm][kb + 2 * tg];
                af[mi][1] = *(const uint32_t*)&As[s][rm + 8][kb + 2 * tg];
                af[mi][2] = *(const uint32_t*)&As[s][rm][kb + 2 * tg + 8];
                af[mi][3] = *(const uint32_t*)&As[s][rm + 8][kb + 2 * tg + 8];
            }
#pragma unroll
            for (int ni = 0; ni < 4; ni++) {
                int cn = wn * 32 + ni * 8 + group;
                bf[ni][0] = *(const uint32_t*)&Bs[s][cn][kb + 2 * tg];
                bf[ni][1] = *(const uint32_t*)&Bs[s][cn][kb + 2 * tg + 8];
            }
#pragma unroll
            for (int mi = 0; mi < 4; mi++)
#pragma unroll
                for (int ni = 0; ni < 4; ni++)
                    MMA_BF16(c[mi][ni], af[mi], bf[ni]);
        }
        __syncthreads();
        s ^= 1;
    }
#undef LOAD_STAGE

#pragma unroll
    for (int mi = 0; mi < 4; mi++) {
        int row0 = bm + wm * 64 + mi * 16 + group;
#pragma unroll
        for (int ni = 0; ni < 4; ni++) {
            int col = bn + wn * 32 + ni * 8 + tg * 2;
            *(float2*)(C + (size_t)row0 * k + col)       = make_float2(c[mi][ni][0], c[mi][ni][1]);
            *(float2*)(C + (size_t)(row0 + 8) * k + col) = make_float2(c[mi][ni][2], c[mi][ni][3]);
        }
    }
}

// ============ bf16-split GEMM from fp32 inputs, cp.async double-buffered =============
// ASPLIT=0: A exact in bf16 (ints <= 256); C = A·bh + A·bl  (B-split err ~2^-18).
// ASPLIT=1: A split too; C = ah·bh + ah·bl + al·bh          (err ~2^-16.4).
// XXT=1: C = A·B^T, B row-major [n][K], lower-tri blocks only.
// Split-K via gridDim.z. (K/gridDim.z) % 32 == 0. Dynamic smem: 73728 B.
template <int ASPLIT, int XXT>
__global__ void __launch_bounds__(256, (ASPLIT ? 1 : 2)) bf16g(
    const float* __restrict__ A, const float* __restrict__ B, float* __restrict__ Cpart,
    int M, int N, int K, int lda, int ldb, int ldc)
{
    if (XXT && (int)blockIdx.x > (int)blockIdx.y) return;
    extern __shared__ float smd[];
    const int STAGEF = 9216;
    const int BOFF = 128 * 36;

    int t = threadIdx.x;
    int warp = t >> 5, lane = t & 31;
    int group = lane >> 2, tg = lane & 3;
    int wm = warp >> 2, wn = warp & 3;
    int bm = blockIdx.y * 128, bn = blockIdx.x * 128;
    int kChunk = K / gridDim.z;
    int kStart = blockIdx.z * kChunk;
    float* C = Cpart + (size_t)blockIdx.z * M * ldc;

    float c[4][4][4];
#pragma unroll
    for (int mi = 0; mi < 4; mi++)
#pragma unroll
        for (int ni = 0; ni < 4; ni++)
#pragma unroll
            for (int r = 0; r < 4; r++) c[mi][ni][r] = 0.f;

    auto LOADST = [&](int st, int k0) {
        float* as = smd + st * STAGEF;
        float* bs = as + BOFF;
#pragma unroll
        for (int q = 0; q < 4; q++) {
            int cc = t + q * 256;
            int m = cc >> 3, kc = cc & 7;
            uint32_t ad = (uint32_t)__cvta_generic_to_shared(as + m * 36 + kc * 4);
            cpa16(ad, A + (size_t)(bm + m) * lda + kStart + k0 + kc * 4);
        }
        if (XXT) {
#pragma unroll
            for (int q = 0; q < 4; q++) {
                int cc = t + q * 256;
                int m = cc >> 3, kc = cc & 7;
                uint32_t bd = (uint32_t)__cvta_generic_to_shared(bs + m * 36 + kc * 4);
                cpa16(bd, B + (size_t)(bn + m) * ldb + kStart + k0 + kc * 4);
            }
        } else {
#pragma unroll
            for (int q = 0; q < 4; q++) {
                int cc = t + q * 256;
                int r = cc >> 5, nc = cc & 31;
                uint32_t bd = (uint32_t)__cvta_generic_to_shared(bs + r * 136 + nc * 4);
                cpa16(bd, B + (size_t)(kStart + k0 + r) * ldb + bn + nc * 4);
            }
        }
        asm volatile("cp.async.commit_group;\n");
    };

    LOADST(0, 0);

    int s = 0;
    for (int k0 = 0; k0 < kChunk; k0 += 32) {
        if (k0 + 32 < kChunk) {
            LOADST(s ^ 1, k0 + 32);
            asm volatile("cp.async.wait_group 1;\n");
        } else {
            asm volatile("cp.async.wait_group 0;\n");
        }
        __syncthreads();

        const float* as = smd + s * STAGEF;
        const float* bs = as + BOFF;

#pragma unroll
        for (int ks = 0; ks < 2; ks++) {
            int kb = ks * 16;
            uint32_t ah[4][4], al[4][4], bh[4][2], bl[4][2];
#pragma unroll
            for (int mi = 0; mi < 4; mi++) {
                int rm = wm * 64 + mi * 16 + group;
                const float* r0 = as + rm * 36 + kb + 2 * tg;
                const float* r1 = as + (rm + 8) * 36 + kb + 2 * tg;
                float x0 = r0[0], x1 = r0[1], x2 = r1[0], x3 = r1[1];
                float x4 = r0[8], x5 = r0[9], x6 = r1[8], x7 = r1[9];
                ah[mi][0] = packbf(x0, x1);
                ah[mi][1] = packbf(x2, x3);
                ah[mi][2] = packbf(x4, x5);
                ah[mi][3] = packbf(x6, x7);
                if (ASPLIT) {
                    al[mi][0] = packbf_res(x0, x1, ah[mi][0]);
                    al[mi][1] = packbf_res(x2, x3, ah[mi][1]);
                    al[mi][2] = packbf_res(x4, x5, ah[mi][2]);
                    al[mi][3] = packbf_res(x6, x7, ah[mi][3]);
                }
            }
#pragma unroll
            for (int ni = 0; ni < 4; ni++) {
                int cn = wn * 32 + ni * 8 + group;
                float b0a, b0b, b1a, b1b;
                if (XXT) {
                    const float* rb = bs + cn * 36 + kb + 2 * tg;
                    b0a = rb[0]; b0b = rb[1]; b1a = rb[8]; b1b = rb[9];
                } else {
                    b0a = bs[(kb + 2 * tg) * 136 + cn];
                    b0b = bs[(kb + 2 * tg + 1) * 136 + cn];
                    b1a = bs[(kb + 8 + 2 * tg) * 136 + cn];
                    b1b = bs[(kb + 9 + 2 * tg) * 136 + cn];
                }
                bh[ni][0] = packbf(b0a, b0b);
                bh[ni][1] = packbf(b1a, b1b);
                bl[ni][0] = packbf_res(b0a, b0b, bh[ni][0]);
                bl[ni][1] = packbf_res(b1a, b1b, bh[ni][1]);
            }
#pragma unroll
            for (int mi = 0; mi < 4; mi++)
#pragma unroll
                for (int ni = 0; ni < 4; ni++) {
                    MMA_BF16(c[mi][ni], ah[mi], bh[ni]);
                    MMA_BF16(c[mi][ni], ah[mi], bl[ni]);
                    if (ASPLIT) MMA_BF16(c[mi][ni], al[mi], bh[ni]);
                }
        }
        __syncthreads();
        s ^= 1;
    }

#pragma unroll
    for (int mi = 0; mi < 4; mi++) {
        int row0 = bm + wm * 64 + mi * 16 + group;
#pragma unroll
        for (int ni = 0; ni < 4; ni++) {
            int col = bn + wn * 32 + ni * 8 + tg * 2;
            *(float2*)(C + (size_t)row0 * ldc + col)       = make_float2(c[mi][ni][0], c[mi][ni][1]);
            *(float2*)(C + (size_t)(row0 + 8) * ldc + col) = make_float2(c[mi][ni][2], c[mi][ni][3]);
        }
    }
}

// ============ tf32 GEMM (3-split), used for xW feature GEMMs ========================
template <int ASPLIT, int XXT>
__global__ void __launch_bounds__(256, (ASPLIT ? 1 : 2)) tf32g(
    const float* __restrict__ A, const float* __restrict__ B, float* __restrict__ Cpart,
    int M, int N, int K, int lda, int ldb, int ldc)
{
    if (XXT && (int)blockIdx.x > (int)blockIdx.y) return;
    extern __shared__ float smd[];
    const int STAGEF = 9216;
    const int BOFF = 128 * 36;

    int t = threadIdx.x;
    int warp = t >> 5, lane = t & 31;
    int group = lane >> 2, tg = lane & 3;
    int wm = warp >> 2, wn = warp & 3;
    int bm = blockIdx.y * 128, bn = blockIdx.x * 128;
    int kChunk = K / gridDim.z;
    int kStart = blockIdx.z * kChunk;
    float* C = Cpart + (size_t)blockIdx.z * M * ldc;

    float c[4][4][4];
#pragma unroll
    for (int mi = 0; mi < 4; mi++)
#pragma unroll
        for (int ni = 0; ni < 4; ni++)
#pragma unroll
            for (int r = 0; r < 4; r++) c[mi][ni][r] = 0.f;

    auto LOADST = [&](int st, int k0) {
        float* as = smd + st * STAGEF;
        float* bs = as + BOFF;
#pragma unroll
        for (int q = 0; q < 4; q++) {
            int cc = t + q * 256;
            int m = cc >> 3, kc = cc & 7;
            uint32_t ad = (uint32_t)__cvta_generic_to_shared(as + m * 36 + kc * 4);
            cpa16(ad, A + (size_t)(bm + m) * lda + kStart + k0 + kc * 4);
        }
#pragma unroll
        for (int q = 0; q < 4; q++) {
            int cc = t + q * 256;
            int r = cc >> 5, nc = cc & 31;
            uint32_t bd = (uint32_t)__cvta_generic_to_shared(bs + r * 136 + nc * 4);
            cpa16(bd, B + (size_t)(kStart + k0 + r) * ldb + bn + nc * 4);
        }
        asm volatile("cp.async.commit_group;\n");
    };

    LOADST(0, 0);

    int s = 0;
    for (int k0 = 0; k0 < kChunk; k0 += 32) {
        if (k0 + 32 < kChunk) {
            LOADST(s ^ 1, k0 + 32);
            asm volatile("cp.async.wait_group 1;\n");
        } else {
            asm volatile("cp.async.wait_group 0;\n");
        }
        __syncthreads();

        const float* as = smd + s * STAGEF;
        const float* bs = as + BOFF;

#pragma unroll
        for (int ks = 0; ks < 4; ks++) {
            int kb = ks * 8;
            uint32_t afh[4][4], afl[4][4], bfh[4][2], bfl[4][2];
#pragma unroll
            for (int mi = 0; mi < 4; mi++) {
                int rm = wm * 64 + mi * 16 + group;
                float a0 = as[rm * 36 + kb + tg];
                float a1 = as[(rm + 8) * 36 + kb + tg];
                float a2 = as[rm * 36 + kb + tg + 4];
                float a3 = as[(rm + 8) * 36 + kb + tg + 4];
                if (ASPLIT) {
                    afh[mi][0] = f2tf(a0); afh[mi][1] = f2tf(a1);
                    afh[mi][2] = f2tf(a2); afh[mi][3] = f2tf(a3);
                    afl[mi][0] = f2tf(a0 - __uint_as_float(afh[mi][0]));
                    afl[mi][1] = f2tf(a1 - __uint_as_float(afh[mi][1]));
                    afl[mi][2] = f2tf(a2 - __uint_as_float(afh[mi][2]));
                    afl[mi][3] = f2tf(a3 - __uint_as_float(afh[mi][3]));
                } else {
                    afh[mi][0] = __float_as_uint(a0); afh[mi][1] = __float_as_uint(a1);
                    afh[mi][2] = __float_as_uint(a2); afh[mi][3] = __float_as_uint(a3);
                }
            }
#pragma unroll
            for (int ni = 0; ni < 4; ni++) {
                int cn = wn * 32 + ni * 8 + group;
                float b0 = bs[(kb + tg) * 136 + cn];
                float b1 = bs[(kb + tg + 4) * 136 + cn];
                bfh[ni][0] = f2tf(b0);
                bfh[ni][1] = f2tf(b1);
                bfl[ni][0] = f2tf(b0 - __uint_as_float(bfh[ni][0]));
                bfl[ni][1] = f2tf(b1 - __uint_as_float(bfh[ni][1]));
            }
#pragma unroll
            for (int mi = 0; mi < 4; mi++)
#pragma unroll
                for (int ni = 0; ni < 4; ni++) {
                    asm volatile(
                        "mma.sync.aligned.m16n8k8.row.col.f32.tf32.tf32.f32 "
                        "{%0,%1,%2,%3}, {%4,%5,%6,%7}, {%8,%9}, {%0,%1,%2,%3};\n"
                        : "+f"(c[mi][ni][0]), "+f"(c[mi][ni][1]),
                          "+f"(c[mi][ni][2]), "+f"(c[mi][ni][3])
                        : "r"(afh[mi][0]), "r"(afh[mi][1]), "r"(afh[mi][2]), "r"(afh[mi][3]),
                          "r"(bfl[ni][0]), "r"(bfl[ni][1]));
                    if (ASPLIT) {
                        asm volatile(
                            "mma.sync.aligned.m16n8k8.row.col.f32.tf32.tf32.f32 "
                            "{%0,%1,%2,%3}, {%4,%5,%6,%7}, {%8,%9}, {%0,%1,%2,%3};\n"
                            : "+f"(c[mi][ni][0]), "+f"(c[mi][ni][1]),
                              "+f"(c[mi][ni][2]), "+f"(c[mi][ni][3])
                            : "r"(afl[mi][0]), "r"(afl[mi][1]), "r"(afl[mi][2]), "r"(afl[mi][3]),
                              "r"(bfh[ni][0]), "r"(bfh[ni][1]));
                    }
                    asm volatile(
                        "mma.sync.aligned.m16n8k8.row.col.f32.tf32.tf32.f32 "
                        "{%0,%1,%2,%3}, {%4,%5,%6,%7}, {%8,%9}, {%0,%1,%2,%3};\n"
                        : "+f"(c[mi][ni][0]), "+f"(c[mi][ni][1]),
                          "+f"(c[mi][ni][2]), "+f"(c[mi][ni][3])
                        : "r"(afh[mi][0]), "r"(afh[mi][1]), "r"(afh[mi][2]), "r"(afh[mi][3]),
                          "r"(bfh[ni][0]), "r"(bfh[ni][1]));
                }
        }
        __syncthreads();
        s ^= 1;
    }

#pragma unroll
    for (int mi = 0; mi < 4; mi++) {
        int row0 = bm + wm * 64 + mi * 16 + group;
#pragma unroll
        for (int ni = 0; ni < 4; ni++) {
            int col = bn + wn * 32 + ni * 8 + tg * 2;
            *(float2*)(C + (size_t)row0 * ldc + col)       = make_float2(c[mi][ni][0], c[mi][ni][1]);
            *(float2*)(C + (size_t)(row0 + 8) * ldc + col) = make_float2(c[mi][ni][2], c[mi][ni][3]);
        }
    }
}

// ---------------- generic SGEMM: 64x64 block, bounds-checked (small K paths) --------
__global__ void __launch_bounds__(256) gemm64(
    const float* __restrict__ A, const float* __restrict__ B, float* __restrict__ C,
    int M, int N, int K, int lda, int ldb, int ldc)
{
    __shared__ float As[16][65];
    __shared__ float Bs[16][64];
    int tid = threadIdx.x, tx = tid & 15, ty = tid >> 4;
    int bm = blockIdx.y * 64, bn = blockIdx.x * 64;
    float acc[4][4];
#pragma unroll
    for (int i = 0; i < 4; i++)
#pragma unroll
        for (int j = 0; j < 4; j++) acc[i][j] = 0.f;

    for (int k0 = 0; k0 < K; k0 += 16) {
        for (int t = tid; t < 64 * 16; t += 256) {
            int r = t >> 4, c = t & 15;
            int gr = bm + r, gc = k0 + c;
            As[c][r] = (gr < M && gc < K) ? A[(size_t)gr * lda + gc] : 0.f;
        }
        for (int t = tid; t < 16 * 64; t += 256) {
            int r = t >> 6, c = t & 63;
            int gr = k0 + r, gc = bn + c;
            Bs[r][c] = (gr < K && gc < N) ? B[(size_t)gr * ldb + gc] : 0.f;
        }
        __syncthreads();
#pragma unroll
        for (int kk = 0; kk < 16; kk++) {
            float a[4], b[4];
#pragma unroll
            for (int i = 0; i < 4; i++) a[i] = As[kk][ty * 4 + i];
#pragma unroll
            for (int j = 0; j < 4; j++) b[j] = Bs[kk][tx * 4 + j];
#pragma unroll
            for (int i = 0; i < 4; i++)
#pragma unroll
                for (int j = 0; j < 4; j++) acc[i][j] += a[i] * b[j];
        }
        __syncthreads();
    }
#pragma unroll
    for (int i = 0; i < 4; i++)
#pragma unroll
        for (int j = 0; j < 4; j++) {
            int gr = bm + ty * 4 + i, gc = bn + tx * 4 + j;
            if (gr < M && gc < N) C[(size_t)gr * ldc + gc] = acc[i][j];
        }
}

// ---------------- small helper kernels ----------------
__global__ void pad_w(const float* __restrict__ W, float* __restrict__ out)
{
    int idx = blockIdx.x * 256 + threadIdx.x;
    if (idx >= HP * HP) return;
    int i = idx >> 8, j = idx & 255;
    out[idx] = (i < H && j < H) ? W[i * H + j] : 0.f;
}

__global__ void rowgather_bf16(const float* __restrict__ A, int n,
                               const int* __restrict__ perm,
                               __nv_bfloat16* __restrict__ out, int krows)
{
    size_t idx = (size_t)blockIdx.x * 256 + threadIdx.x;
    size_t n4 = (size_t)n / 4;
    if (idx >= (size_t)krows * n4) return;
    int i = (int)(idx / n4);
    int j4 = (int)(idx - (size_t)i * n4);
    float4 v = *(const float4*)(A + (size_t)perm[i] * n + j4 * 4);
    __nv_bfloat162 a = __floats2bfloat162_rn(v.x, v.y);
    __nv_bfloat162 b = __floats2bfloat162_rn(v.z, v.w);
    *(__nv_bfloat162*)(out + (size_t)i * n + j4 * 4)     = a;
    *(__nv_bfloat162*)(out + (size_t)i * n + j4 * 4 + 2) = b;
}

__global__ void rowgather_f32(const float* __restrict__ A, int n,
                              const int* __restrict__ perm,
                              float* __restrict__ out, int krows)
{
    size_t idx = (size_t)blockIdx.x * 256 + threadIdx.x;
    size_t n4 = (size_t)n / 4;
    if (idx >= (size_t)krows * n4) return;
    int i = (int)(idx / n4);
    int j4 = (int)(idx - (size_t)i * n4);
    float4 v = *(const float4*)(A + (size_t)perm[i] * n + j4 * 4);
    *(float4*)(out + (size_t)i * n + j4 * 4) = v;
}

__global__ void rowsum_dinv(const float* __restrict__ A, float* __restrict__ dinv, int n)
{
    int row = blockIdx.x;
    const float* Ar = A + (size_t)row * n;
    float s = 0.f;
    for (int j = threadIdx.x; j < n; j += 256) s += Ar[j];
    for (int o = 16; o > 0; o >>= 1) s += __shfl_down_sync(0xffffffffu, s, o);
    __shared__ float red[8];
    int w = threadIdx.x >> 5, l = threadIdx.x & 31;
    if (l == 0) red[w] = s;
    __syncthreads();
    if (threadIdx.x == 0) {
        float t = 0.f;
        for (int i = 0; i < 8; i++) t += red[i];
        dinv[row] = 1.0f / sqrtf(t + 2.0f);
    }
}

__global__ void scale_rows(const float* __restrict__ in, const float* __restrict__ dinv,
                           float* __restrict__ out, int n, int w, int ld)
{
    int idx = blockIdx.x * 256 + threadIdx.x;
    if (idx >= n * ld) return;
    int r = idx / ld, c = idx - r * ld;
    out[idx] = (c < w) ? dinv[r] * in[idx] : 0.f;
}

__global__ void gcn_finish_sk(const float* __restrict__ part, const float* __restrict__ Z,
                              const float* __restrict__ dinv, const float* __restrict__ b,
                              float* __restrict__ out, int n, int relu, int S)
{
    int idx = blockIdx.x * 256 + threadIdx.x;
    if (idx >= n * HP) return;
    int r = idx / HP, c = idx - r * HP;
    float v = 0.f;
    if (c < H) {
        float az = 0.f;
        size_t stride = (size_t)n * HP;
        for (int s = 0; s < S; s++) az += part[s * stride + idx];
        v = dinv[r] * (az + 2.f * Z[idx]) + b[c];
        if (relu) v = fmaxf(v, 0.f);
    }
    out[idx] = v;
}

__global__ void pnorm_kernel(const float* __restrict__ p, float* __restrict__ out)
{
    float s = 0.f;
    for (int i = threadIdx.x; i < H; i += 256) { float v = p[i]; s += v * v; }
    for (int o = 16; o > 0; o >>= 1) s += __shfl_down_sync(0xffffffffu, s, o);
    __shared__ float red[8];
    int w = threadIdx.x >> 5, l = threadIdx.x & 31;
    if (l == 0) red[w] = s;
    __syncthreads();
    if (threadIdx.x == 0) {
        float t = 0.f;
        for (int i = 0; i < 8; i++) t += red[i];
        *out = sqrtf(t);
    }
}

__global__ void score_kernel(const float* __restrict__ x, const float* __restrict__ p,
                             const float* __restrict__ pn, float* __restrict__ score, int n)
{
    int row = blockIdx.x * 8 + (threadIdx.x >> 5);
    int lane = threadIdx.x & 31;
    if (row >= n) return;
    const float* xr = x + (size_t)row * HP;
    float s = 0.f;
    for (int c = lane; c < H; c += 32) s += xr[c] * p[c];
    for (int o = 16; o > 0; o >>= 1) s += __shfl_down_sync(0xffffffffu, s, o);
    if (lane == 0) score[row] = tanhf(s / (*pn));
}

// uint64-key bitonic topk (descending score, ascending index ties — matches jax)
template <int SIZE>
__global__ void topk_kernel(const float* __restrict__ score, int n, int k,
                            int* __restrict__ perm, float* __restrict__ val)
{
    __shared__ unsigned long long key[SIZE];
    int tid = threadIdx.x;
    for (int i = tid; i < SIZE; i += 1024) {
        float s = (i < n) ? score[i] : -INFINITY;
        uint32_t u = __float_as_uint(s);
        u = (u & 0x80000000u) ? ~u : (u | 0x80000000u);
        uint32_t d = ~u;
        key[i] = ((unsigned long long)d << 32) | (uint32_t)i;
    }
    __syncthreads();
    for (int size = 2; size <= SIZE; size <<= 1) {
        for (int stride = size >> 1; stride > 0; stride >>= 1) {
            for (int i = tid; i < SIZE; i += 1024) {
                int j = i ^ stride;
                if (j > i) {
                    unsigned long long a = key[i], b = key[j];
                    bool up = ((i & size) == 0);
                    if (up ? (a > b) : (a < b)) { key[i] = b; key[j] = a; }
                }
            }
            __syncthreads();
        }
    }
    for (int i = tid; i < k; i += 1024) {
        int si = (int)(uint32_t)key[i];
        perm[i] = si;
        val[i] = score[si];
    }
}

// levels 1-2: A_out[i][j] = (i==j) ? 0 : C[max][min] + 2*Rows[i][perm[j]]
__global__ void pool_A_tri(const float* __restrict__ C, const __nv_bfloat16* __restrict__ Rows,
                           int K, const int* __restrict__ perm,
                           float* __restrict__ Aout, int k)
{
    int idx = blockIdx.x * 256 + threadIdx.x;
    if (idx >= k * k) return;
    int i = idx / k, j = idx - i * k;
    if (i == j) { Aout[idx] = 0.f; return; }
    int hi = i > j ? i : j, lo = i > j ? j : i;
    float g = C[(size_t)hi * k + lo];
    float a = __bfloat162float(Rows[(size_t)i * K + __ldg(&perm[j])]);
    Aout[idx] = g + 2.f * a;
}

// level 3 (fp32 rows)
__global__ void pool_A_tri_f32(const float* __restrict__ C, const float* __restrict__ Rows,
                               int K, const int* __restrict__ perm,
                               float* __restrict__ Aout, int k)
{
    int idx = blockIdx.x * 256 + threadIdx.x;
    if (idx >= k * k) return;
    int i = idx / k, j = idx - i * k;
    if (i == j) { Aout[idx] = 0.f; return; }
    int hi = i > j ? i : j, lo = i > j ? j : i;
    Aout[idx] = C[(size_t)hi * k + lo] + 2.f * Rows[(size_t)i * K + __ldg(&perm[j])];
}

__global__ void pool_x(const float* __restrict__ xin, const int* __restrict__ perm,
                       const float* __restrict__ val, float* __restrict__ xout, int k)
{
    int idx = blockIdx.x * 256 + threadIdx.x;
    if (idx >= k * HP) return;
    int r = idx / HP, c = idx - r * HP;
    xout[idx] = xin[(size_t)perm[r] * HP + c] * val[r];
}

__global__ void scatter_add(float* __restrict__ dst, const float* __restrict__ x,
                            const int* __restrict__ perm, int k)
{
    int idx = blockIdx.x * 256 + threadIdx.x;
    if (idx >= k * HP) return;
    int r = idx / HP, c = idx - r * HP;
    dst[(size_t)perm[r] * HP + c] += x[idx];
}

__global__ void gemm_n2(const float* __restrict__ A, const float* __restrict__ Z,
                        float* __restrict__ out, int n)
{
    int row = blockIdx.x;
    const float* Ar = A + (size_t)row * n;
    float a0 = 0.f, a1 = 0.f;
    for (int j = threadIdx.x; j < n; j += 256) {
        float a = Ar[j];
        a0 += a * Z[2 * j];
        a1 += a * Z[2 * j + 1];
    }
    for (int o = 16; o > 0; o >>= 1) {
        a0 += __shfl_down_sync(0xffffffffu, a0, o);
        a1 += __shfl_down_sync(0xffffffffu, a1, o);
    }
    __shared__ float r0[8], r1[8];
    int w = threadIdx.x >> 5, l = threadIdx.x & 31;
    if (l == 0) { r0[w] = a0; r1[w] = a1; }
    __syncthreads();
    if (threadIdx.x == 0) {
        float s0 = 0.f, s1 = 0.f;
        for (int i = 0; i < 8; i++) { s0 += r0[i]; s1 += r1[i]; }
        out[2 * row] = s0;
        out[2 * row + 1] = s1;
    }
}

__global__ void final_kernel(const float* __restrict__ AZ, const float* __restrict__ Z,
                             const float* __restrict__ dinv, const float* __restrict__ b,
                             float* __restrict__ out, int n)
{
    int i = blockIdx.x * 256 + threadIdx.x;
    if (i >= n) return;
    float a = dinv[i] * (AZ[2 * i]     + 2.f * Z[2 * i])     + b[0];
    float c = dinv[i] * (AZ[2 * i + 1] + 2.f * Z[2 * i + 1]) + b[1];
    float m = fmaxf(a, c);
    float l = m + logf(expf(a - m) + expf(c - m));
    out[2 * i] = a - l;
    out[2 * i + 1] = c - l;
}

// ---------------- host orchestration ----------------
template <typename T, size_t NN>
static T* symaddr(T (&sym)[NN]) {
    void* p = nullptr;
    cudaGetSymbolAddress(&p, sym);
    return (T*)p;
}
template <typename T, size_t M2, size_t NN>
static T* symaddr2(T (&sym)[M2][NN]) {
    void* p = nullptr;
    cudaGetSymbolAddress(&p, sym);
    return (T*)p;
}

#define TF32G_SMEM 73728

// GCN with tensor-core xW (Wpad HP x HP) + bf16-split propagation + cached dinv
static void run_gcn_tc(const float* A, int n, const float* xin, const float* Wpad,
                       const float* b, float* xout, int relu, int S, int asplit,
                       const float* dinv, float* t0, float* t1, float* part)
{
    dim3 gw(HP / 128, n / 128, 1);
    tf32g<1, 0><<<gw, 256, TF32G_SMEM>>>(xin, Wpad, t0, n, HP, HP, HP, HP, HP);
    int tot = n * HP;
    scale_rows<<<(tot + 255) / 256, 256>>>(t0, dinv, t1, n, H, HP);
    dim3 g2(HP / 128, n / 128, S);
    if (asplit)
        bf16g<1, 0><<<g2, 256, TF32G_SMEM>>>(A, t1, part, n, HP, n, n, HP, HP);
    else
        bf16g<0, 0><<<g2, 256, TF32G_SMEM>>>(A, t1, part, n, HP, n, n, HP, HP);
    gcn_finish_sk<<<(tot + 255) / 256, 256>>>(part, t1, dinv, b, xout, n, relu, S);
}

extern "C" void kernel_launch(void* const* d_in, const int* in_sizes, int n_in,
                              void* d_out, int out_size)
{
    (void)in_sizes; (void)n_in; (void)out_size;
    const float* x   = (const float*)d_in[0];
    const float* adj = (const float*)d_in[1];
    const float* w0  = (const float*)d_in[2];
    const float* b0  = (const float*)d_in[3];
    const float* w1  = (const float*)d_in[4];
    const float* b1  = (const float*)d_in[5];
    const float* w2  = (const float*)d_in[6];
    const float* b2  = (const float*)d_in[7];
    const float* w3  = (const float*)d_in[8];
    const float* b3  = (const float*)d_in[9];
    const float* p1  = (const float*)d_in[10];
    const float* p2  = (const float*)d_in[11];
    const float* p3  = (const float*)d_in[12];
    const float* u0w = (const float*)d_in[13];
    const float* u0b = (const float*)d_in[14];
    const float* u1w = (const float*)d_in[15];
    const float* u1b = (const float*)d_in[16];
    const float* u2w = (const float*)d_in[17];
    const float* u2b = (const float*)d_in[18];

    static bool attr_done = false;
    if (!attr_done) {
        cudaFuncSetAttribute(tf32g<1, 0>, cudaFuncAttributeMaxDynamicSharedMemorySize, TF32G_SMEM);
        cudaFuncSetAttribute(bf16g<0, 0>, cudaFuncAttributeMaxDynamicSharedMemorySize, TF32G_SMEM);
        cudaFuncSetAttribute(bf16g<1, 0>, cudaFuncAttributeMaxDynamicSharedMemorySize, TF32G_SMEM);
        cudaFuncSetAttribute(bf16g<1, 1>, cudaFuncAttributeMaxDynamicSharedMemorySize, TF32G_SMEM);
        attr_done = true;
    }

    float* G    = symaddr(g_G);
    __nv_bfloat16* ROWS = symaddr(g_rows);
    float* A1   = symaddr(g_A1);
    float* A2   = symaddr(g_A2);
    float* A3   = symaddr(g_A3);
    float* X0   = symaddr(g_x0);
    float* X1   = symaddr(g_x1);
    float* X2   = symaddr(g_x2);
    float* X3   = symaddr(g_x3);
    float* T0   = symaddr(g_t0);
    float* T1   = symaddr(g_t1);
    float* PART = symaddr(g_part);
    float* CUR  = symaddr(g_cur);
    float* WP   = symaddr2(g_wpad);
    float* D0   = symaddr(g_d0);
    float* D1   = symaddr(g_d1);
    float* D2   = symaddr(g_d2);
    float* D3   = symaddr(g_d3);
    float* SC   = symaddr(g_score);
    float* VAL  = symaddr(g_val);
    int*   P0   = symaddr(g_perm0);
    int*   P1   = symaddr(g_perm1);
    int*   P2   = symaddr(g_perm2);
    float* PN   = symaddr(g_pnorm);

    float* WP_w1  = WP + 0 * HP * HP;
    float* WP_w2  = WP + 1 * HP * HP;
    float* WP_w3  = WP + 2 * HP * HP;
    float* WP_u0w = WP + 3 * HP * HP;
    float* WP_u1w = WP + 4 * HP * HP;

    // ---- prep: padded weights + adj dinv ----
    const int PG = (HP * HP + 255) / 256;
    pad_w<<<PG, 256>>>(w1, WP_w1);
    pad_w<<<PG, 256>>>(w2, WP_w2);
    pad_w<<<PG, 256>>>(w3, WP_w3);
    pad_w<<<PG, 256>>>(u0w, WP_u0w);
    pad_w<<<PG, 256>>>(u1w, WP_u1w);
    rowsum_dinv<<<N0, 256>>>(adj, D0, N0);

    // ---- down: gcn0 (xW via gemm64: K=3; prop bf16 exact-A) ----
    {
        dim3 g1((H + 63) / 64, (N0 + 63) / 64);
        gemm64<<<g1, 256>>>(x, w0, T0, N0, H, 3, 3, H, HP);
        int tot = N0 * HP;
        scale_rows<<<(tot + 255) / 256, 256>>>(T0, D0, T1, N0, H, HP);
        dim3 g2(HP / 128, N0 / 128, 4);
        bf16g<0, 0><<<g2, 256, TF32G_SMEM>>>(adj, T1, PART, N0, HP, N0, N0, HP, HP);
        gcn_finish_sk<<<(tot + 255) / 256, 256>>>(PART, T1, D0, b0, X0, N0, 1, 4);
    }

    // ---- pool 1 (4096 -> 3072) ----
    pnorm_kernel<<<1, 256>>>(p1, PN);
    score_kernel<<<(N0 + 7) / 8, 256>>>(X0, p1, PN, SC, N0);
    topk_kernel<4096><<<1, 1024>>>(SC, N0, KP1, P0, VAL);
    {
        size_t tot = (size_t)KP1 * (N0 / 4);
        rowgather_bf16<<<(unsigned)((tot + 255) / 256), 256>>>(adj, N0, P0, ROWS, KP1);
        dim3 g(KP1 / 128, KP1 / 128);
        bf16gemm_xxt<<<g, 256>>>(ROWS, G, KP1, N0);
        pool_A_tri<<<(KP1 * KP1 + 255) / 256, 256>>>(G, ROWS, N0, P0, A1, KP1);
        pool_x<<<(KP1 * HP + 255) / 256, 256>>>(X0, P0, VAL, CUR, KP1);
    }
    rowsum_dinv<<<KP1, 256>>>(A1, D1, KP1);
    run_gcn_tc(A1, KP1, CUR, WP_w1, b1, X1, 1, 6, 0, D1, T0, T1, PART);

    // ---- pool 2 (3072 -> 1536) ----
    pnorm_kernel<<<1, 256>>>(p2, PN);
    score_kernel<<<(KP1 + 7) / 8, 256>>>(X1, p2, PN, SC, KP1);
    topk_kernel<4096><<<1, 1024>>>(SC, KP1, KP2, P1, VAL);
    {
        size_t tot = (size_t)KP2 * (KP1 / 4);
        rowgather_bf16<<<(unsigned)((tot + 255) / 256), 256>>>(A1, KP1, P1, ROWS, KP2);
        dim3 g(KP2 / 128, KP2 / 128);
        bf16gemm_xxt<<<g, 256>>>(ROWS, G, KP2, KP1);
        pool_A_tri<<<(KP2 * KP2 + 255) / 256, 256>>>(G, ROWS, KP1, P1, A2, KP2);
        pool_x<<<(KP2 * HP + 255) / 256, 256>>>(X1, P1, VAL, CUR, KP2);
    }
    rowsum_dinv<<<KP2, 256>>>(A2, D2, KP2);
    run_gcn_tc(A2, KP2, CUR, WP_w2, b2, X2, 1, 6, 1, D2, T0, T1, PART);

    // ---- pool 3 (1536 -> 768): fp32 gather + bf16-split tri X·X^T ----
    pnorm_kernel<<<1, 256>>>(p3, PN);
    score_kernel<<<(KP2 + 7) / 8, 256>>>(X2, p3, PN, SC, KP2);
    topk_kernel<2048><<<1, 1024>>>(SC, KP2, KP3, P2, VAL);
    {
        size_t tot = (size_t)KP3 * (KP2 / 4);
        rowgather_f32<<<(unsigned)((tot + 255) / 256), 256>>>(A2, KP2, P2, PART, KP3);
        dim3 g(KP3 / 128, KP3 / 128, 1);
        bf16g<1, 1><<<g, 256, TF32G_SMEM>>>(PART, PART, G, KP3, KP3, KP2, KP2, KP2, KP3);
        pool_A_tri_f32<<<(KP3 * KP3 + 255) / 256, 256>>>(G, PART, KP2, P2, A3, KP3);
        pool_x<<<(KP3 * HP + 255) / 256, 256>>>(X2, P2, VAL, CUR, KP3);
    }
    rowsum_dinv<<<KP3, 256>>>(A3, D3, KP3);
    run_gcn_tc(A3, KP3, CUR, WP_w3, b3, X3, 1, 12, 1, D3, T0, T1, PART);

    // ---- up 0: j=2 ----
    cudaMemcpyAsync(CUR, X2, (size_t)KP2 * HP * sizeof(float), cudaMemcpyDeviceToDevice, 0);
    scatter_add<<<(KP3 * HP + 255) / 256, 256>>>(CUR, X3, P2, KP3);
    run_gcn_tc(A2, KP2, CUR, WP_u0w, u0b, X2, 1, 6, 1, D2, T0, T1, PART);

    // ---- up 1: j=1 ----
    cudaMemcpyAsync(CUR, X1, (size_t)KP1 * HP * sizeof(float), cudaMemcpyDeviceToDevice, 0);
    scatter_add<<<(KP2 * HP + 255) / 256, 256>>>(CUR, X2, P1, KP2);
    run_gcn_tc(A1, KP1, CUR, WP_u1w, u1b, X1, 1, 6, 0, D1, T0, T1, PART);

    // ---- up 2: j=0, final gcn (H->2) + log_softmax ----
    cudaMemcpyAsync(CUR, X0, (size_t)N0 * HP * sizeof(float), cudaMemcpyDeviceToDevice, 0);
    scatter_add<<<(KP1 * HP + 255) / 256, 256>>>(CUR, X1, P0, KP1);
    {
        dim3 gf(1, (N0 + 63) / 64);
        gemm64<<<gf, 256>>>(CUR, u2w, T0, N0, 2, H, HP, 2, 2);
        scale_rows<<<(N0 * 2 + 255) / 256, 256>>>(T0, D0, T1, N0, 2, 2);
        gemm_n2<<<N0, 256>>>(adj, T1, T0, N0);
        final_kernel<<<(N0 + 255) / 256, 256>>>(T0, T1, D0, u2b, (float*)d_out, N0);
    }
}

// round 10
// speedup vs baseline: 7.9673x; 1.1003x over previous
#include <cuda_runtime.h>
#include <cuda_bf16.h>
#include <math.h>
#include <stdint.h>

#define N0 4096
#define KP1 3072
#define KP2 1536
#define KP3 768
#define H 200
#define HP 256
#define SKMAX 12

// ---------------- device scratch ----------------
__device__ float g_G[(size_t)N0 * N0];
__device__ __nv_bfloat16 g_rows[(size_t)KP1 * N0];
__device__ float g_A1[(size_t)KP1 * KP1];
__device__ float g_A2[(size_t)KP2 * KP2];
__device__ float g_A3[(size_t)KP3 * KP3];
__device__ float g_x0[N0 * HP];
__device__ float g_x1[KP1 * HP];
__device__ float g_x2[KP2 * HP];
__device__ float g_x3[KP3 * HP];
__device__ float g_t0[N0 * HP];
__device__ float g_t1[N0 * HP];
__device__ float g_part[(size_t)SKMAX * N0 * HP];
__device__ float g_cur[N0 * HP];
__device__ float g_wpad[5 * HP * HP];
__device__ float g_d0[N0];
__device__ float g_d1[KP1];
__device__ float g_d2[KP2];
__device__ float g_d3[KP3];
__device__ float g_score[N0];
__device__ float g_val[N0];
__device__ int   g_perm0[KP1];
__device__ int   g_perm1[KP2];
__device__ int   g_perm2[KP3];
__device__ int   g_ip0[N0];
__device__ int   g_ip1[KP1];
__device__ int   g_ip2[KP2];

__device__ __forceinline__ uint32_t f2tf(float x) {
    uint32_t r;
    asm("cvt.rna.tf32.f32 %0, %1;" : "=r"(r) : "f"(x));
    return r;
}
__device__ __forceinline__ void cpa16(uint32_t dst, const void* src) {
    asm volatile("cp.async.cg.shared.global [%0], [%1], 16;\n" :: "r"(dst), "l"(src));
}
__device__ __forceinline__ uint32_t packbf(float x, float y) {
    __nv_bfloat162 h = __floats2bfloat162_rn(x, y);
    return *(uint32_t*)&h;
}
__device__ __forceinline__ uint32_t packbf_res(float x, float y, uint32_t hi) {
    __nv_bfloat162 h = *(__nv_bfloat162*)&hi;
    return packbf(x - __bfloat162float(h.x), y - __bfloat162float(h.y));
}

#define MMA_BF16(c, a, b)                                                         \
    asm volatile(                                                                 \
        "mma.sync.aligned.m16n8k16.row.col.f32.bf16.bf16.f32 "                    \
        "{%0,%1,%2,%3}, {%4,%5,%6,%7}, {%8,%9}, {%0,%1,%2,%3};\n"                 \
        : "+f"((c)[0]), "+f"((c)[1]), "+f"((c)[2]), "+f"((c)[3])                  \
        : "r"((a)[0]), "r"((a)[1]), "r"((a)[2]), "r"((a)[3]),                     \
          "r"((b)[0]), "r"((b)[1]))

// ============ bf16 X·X^T GEMM (bf16 input), lower triangle (levels 1-2 augment) ======
__global__ void __launch_bounds__(256) bf16gemm_xxt(
    const __nv_bfloat16* __restrict__ X, float* __restrict__ C, int k, int K)
{
    if (blockIdx.x > blockIdx.y) return;

    __shared__ __nv_bfloat16 As[2][128][40];
    __shared__ __nv_bfloat16 Bs[2][128][40];

    int t = threadIdx.x;
    int warp = t >> 5, lane = t & 31;
    int group = lane >> 2, tg = lane & 3;
    int wm = warp >> 2, wn = warp & 3;
    int bm = blockIdx.y * 128, bn = blockIdx.x * 128;

    float c[4][4][4];
#pragma unroll
    for (int mi = 0; mi < 4; mi++)
#pragma unroll
        for (int ni = 0; ni < 4; ni++)
#pragma unroll
            for (int r = 0; r < 4; r++) c[mi][ni][r] = 0.f;

    int lrow = t >> 1;
    int lcol0 = (t & 1) * 16;

    uint32_t aBase = (uint32_t)__cvta_generic_to_shared(&As[0][0][0]);
    uint32_t bBase = (uint32_t)__cvta_generic_to_shared(&Bs[0][0][0]);
    const uint32_t stageB = 128 * 40 * 2;
    uint32_t aDst = aBase + lrow * 80 + lcol0 * 2;
    uint32_t bDst = bBase + lrow * 80 + lcol0 * 2;

    const __nv_bfloat16* aSrcRow = X + (size_t)(bm + lrow) * K + lcol0;
    const __nv_bfloat16* bSrcRow = X + (size_t)(bn + lrow) * K + lcol0;

#define LOAD_STAGE(st, k0)                                        \
    do {                                                          \
        const __nv_bfloat16* ap = aSrcRow + (k0);                 \
        const __nv_bfloat16* bp = bSrcRow + (k0);                 \
        uint32_t ad = aDst + (st) * stageB;                       \
        uint32_t bd = bDst + (st) * stageB;                       \
        cpa16(ad, ap); cpa16(ad + 16, ap + 8);                    \
        cpa16(bd, bp); cpa16(bd + 16, bp + 8);                    \
    } while (0)

    LOAD_STAGE(0, 0);
    asm volatile("cp.async.commit_group;\n");

    int s = 0;
    for (int k0 = 0; k0 < K; k0 += 32) {
        if (k0 + 32 < K) {
            LOAD_STAGE(s ^ 1, k0 + 32);
            asm volatile("cp.async.commit_group;\n");
            asm volatile("cp.async.wait_group 1;\n");
        } else {
            asm volatile("cp.async.wait_group 0;\n");
        }
        __syncthreads();

#pragma unroll
        for (int ks = 0; ks < 2; ks++) {
            int kb = ks * 16;
            uint32_t af[4][4], bf[4][2];
#pragma unroll
            for (int mi = 0; mi < 4; mi++) {
                int rm = wm * 64 + mi * 16 + group;
                af[mi][0] = *(const uint32_t*)&As[s][rm][kb + 2 * tg];
                af[mi][1] = *(const uint32_t*)&As[s][rm + 8][kb + 2 * tg];
                af[mi][2] = *(const uint32_t*)&As[s][rm][kb + 2 * tg + 8];
                af[mi][3] = *(const uint32_t*)&As[s][rm + 8][kb + 2 * tg + 8];
            }
#pragma unroll
            for (int ni = 0; ni < 4; ni++) {
                int cn = wn * 32 + ni * 8 + group;
                bf[ni][0] = *(const uint32_t*)&Bs[s][cn][kb + 2 * tg];
                bf[ni][1] = *(const uint32_t*)&Bs[s][cn][kb + 2 * tg + 8];
            }
#pragma unroll
            for (int mi = 0; mi < 4; mi++)
#pragma unroll
                for (int ni = 0; ni < 4; ni++)
                    MMA_BF16(c[mi][ni], af[mi], bf[ni]);
        }
        __syncthreads();
        s ^= 1;
    }
#undef LOAD_STAGE

#pragma unroll
    for (int mi = 0; mi < 4; mi++) {
        int row0 = bm + wm * 64 + mi * 16 + group;
#pragma unroll
        for (int ni = 0; ni < 4; ni++) {
            int col = bn + wn * 32 + ni * 8 + tg * 2;
            *(float2*)(C + (size_t)row0 * k + col)       = make_float2(c[mi][ni][0], c[mi][ni][1]);
            *(float2*)(C + (size_t)(row0 + 8) * k + col) = make_float2(c[mi][ni][2], c[mi][ni][3]);
        }
    }
}

// ============ bf16-split GEMM from fp32 inputs, cp.async double-buffered =============
// ASPLIT=0: A exact in bf16; C = A·bh + A·bl. ASPLIT=1: + al·bh.
// XXT=1: C = A·B^T (lower-tri blocks only). DSCALE=1: B row k scaled by dinv[k] pre-split.
// Split-K via gridDim.z. Dynamic smem: 73984 B (bf), dv slice appended.
template <int ASPLIT, int XXT, int DSCALE>
__global__ void __launch_bounds__(256, (ASPLIT ? 1 : 2)) bf16g(
    const float* __restrict__ A, const float* __restrict__ B, float* __restrict__ Cpart,
    int M, int N, int K, int lda, int ldb, int ldc, const float* __restrict__ dinv)
{
    if (XXT && (int)blockIdx.x > (int)blockIdx.y) return;
    extern __shared__ float smd[];
    const int STAGEF = 9216;
    const int BOFF = 128 * 36;
    float* dvbase = smd + 2 * STAGEF;

    int t = threadIdx.x;
    int warp = t >> 5, lane = t & 31;
    int group = lane >> 2, tg = lane & 3;
    int wm = warp >> 2, wn = warp & 3;
    int bm = blockIdx.y * 128, bn = blockIdx.x * 128;
    int kChunk = K / gridDim.z;
    int kStart = blockIdx.z * kChunk;
    float* C = Cpart + (size_t)blockIdx.z * M * ldc;

    float c[4][4][4];
#pragma unroll
    for (int mi = 0; mi < 4; mi++)
#pragma unroll
        for (int ni = 0; ni < 4; ni++)
#pragma unroll
            for (int r = 0; r < 4; r++) c[mi][ni][r] = 0.f;

    auto LOADST = [&](int st, int k0) {
        float* as = smd + st * STAGEF;
        float* bs = as + BOFF;
#pragma unroll
        for (int q = 0; q < 4; q++) {
            int cc = t + q * 256;
            int m = cc >> 3, kc = cc & 7;
            uint32_t ad = (uint32_t)__cvta_generic_to_shared(as + m * 36 + kc * 4);
            cpa16(ad, A + (size_t)(bm + m) * lda + kStart + k0 + kc * 4);
        }
        if (XXT) {
#pragma unroll
            for (int q = 0; q < 4; q++) {
                int cc = t + q * 256;
                int m = cc >> 3, kc = cc & 7;
                uint32_t bd = (uint32_t)__cvta_generic_to_shared(bs + m * 36 + kc * 4);
                cpa16(bd, B + (size_t)(bn + m) * ldb + kStart + k0 + kc * 4);
            }
        } else {
#pragma unroll
            for (int q = 0; q < 4; q++) {
                int cc = t + q * 256;
                int r = cc >> 5, nc = cc & 31;
                uint32_t bd = (uint32_t)__cvta_generic_to_shared(bs + r * 136 + nc * 4);
                cpa16(bd, B + (size_t)(kStart + k0 + r) * ldb + bn + nc * 4);
            }
            if (DSCALE && t < 8) {
                uint32_t dd = (uint32_t)__cvta_generic_to_shared(dvbase + st * 32 + t * 4);
                cpa16(dd, dinv + kStart + k0 + t * 4);
            }
        }
        asm volatile("cp.async.commit_group;\n");
    };

    LOADST(0, 0);

    int s = 0;
    for (int k0 = 0; k0 < kChunk; k0 += 32) {
        if (k0 + 32 < kChunk) {
            LOADST(s ^ 1, k0 + 32);
            asm volatile("cp.async.wait_group 1;\n");
        } else {
            asm volatile("cp.async.wait_group 0;\n");
        }
        __syncthreads();

        const float* as = smd + s * STAGEF;
        const float* bs = as + BOFF;
        const float* dv = dvbase + s * 32;

#pragma unroll
        for (int ks = 0; ks < 2; ks++) {
            int kb = ks * 16;
            uint32_t ah[4][4], al[4][4], bh[4][2], bl[4][2];
#pragma unroll
            for (int mi = 0; mi < 4; mi++) {
                int rm = wm * 64 + mi * 16 + group;
                const float* r0 = as + rm * 36 + kb + 2 * tg;
                const float* r1 = as + (rm + 8) * 36 + kb + 2 * tg;
                float x0 = r0[0], x1 = r0[1], x2 = r1[0], x3 = r1[1];
                float x4 = r0[8], x5 = r0[9], x6 = r1[8], x7 = r1[9];
                ah[mi][0] = packbf(x0, x1);
                ah[mi][1] = packbf(x2, x3);
                ah[mi][2] = packbf(x4, x5);
                ah[mi][3] = packbf(x6, x7);
                if (ASPLIT) {
                    al[mi][0] = packbf_res(x0, x1, ah[mi][0]);
                    al[mi][1] = packbf_res(x2, x3, ah[mi][1]);
                    al[mi][2] = packbf_res(x4, x5, ah[mi][2]);
                    al[mi][3] = packbf_res(x6, x7, ah[mi][3]);
                }
            }
#pragma unroll
            for (int ni = 0; ni < 4; ni++) {
                int cn = wn * 32 + ni * 8 + group;
                float b0a, b0b, b1a, b1b;
                if (XXT) {
                    const float* rb = bs + cn * 36 + kb + 2 * tg;
                    b0a = rb[0]; b0b = rb[1]; b1a = rb[8]; b1b = rb[9];
                } else {
                    b0a = bs[(kb + 2 * tg) * 136 + cn];
                    b0b = bs[(kb + 2 * tg + 1) * 136 + cn];
                    b1a = bs[(kb + 8 + 2 * tg) * 136 + cn];
                    b1b = bs[(kb + 9 + 2 * tg) * 136 + cn];
                    if (DSCALE) {
                        b0a *= dv[kb + 2 * tg];
                        b0b *= dv[kb + 2 * tg + 1];
                        b1a *= dv[kb + 8 + 2 * tg];
                        b1b *= dv[kb + 9 + 2 * tg];
                    }
                }
                bh[ni][0] = packbf(b0a, b0b);
                bh[ni][1] = packbf(b1a, b1b);
                bl[ni][0] = packbf_res(b0a, b0b, bh[ni][0]);
                bl[ni][1] = packbf_res(b1a, b1b, bh[ni][1]);
            }
#pragma unroll
            for (int mi = 0; mi < 4; mi++)
#pragma unroll
                for (int ni = 0; ni < 4; ni++) {
                    MMA_BF16(c[mi][ni], ah[mi], bh[ni]);
                    MMA_BF16(c[mi][ni], ah[mi], bl[ni]);
                    if (ASPLIT) MMA_BF16(c[mi][ni], al[mi], bh[ni]);
                }
        }
        __syncthreads();
        s ^= 1;
    }

#pragma unroll
    for (int mi = 0; mi < 4; mi++) {
        int row0 = bm + wm * 64 + mi * 16 + group;
#pragma unroll
        for (int ni = 0; ni < 4; ni++) {
            int col = bn + wn * 32 + ni * 8 + tg * 2;
            *(float2*)(C + (size_t)row0 * ldc + col)       = make_float2(c[mi][ni][0], c[mi][ni][1]);
            *(float2*)(C + (size_t)(row0 + 8) * ldc + col) = make_float2(c[mi][ni][2], c[mi][ni][3]);
        }
    }
}

// ============ tf32 GEMM (3-split) for xW feature GEMMs ==============================
__global__ void __launch_bounds__(256) tf32w(
    const float* __restrict__ A, const float* __restrict__ B, float* __restrict__ C,
    int M, int N, int K, int lda, int ldb, int ldc)
{
    extern __shared__ float smd[];
    const int STAGEF = 9216;
    const int BOFF = 128 * 36;

    int t = threadIdx.x;
    int warp = t >> 5, lane = t & 31;
    int group = lane >> 2, tg = lane & 3;
    int wm = warp >> 2, wn = warp & 3;
    int bm = blockIdx.y * 128, bn = blockIdx.x * 128;

    float c[4][4][4];
#pragma unroll
    for (int mi = 0; mi < 4; mi++)
#pragma unroll
        for (int ni = 0; ni < 4; ni++)
#pragma unroll
            for (int r = 0; r < 4; r++) c[mi][ni][r] = 0.f;

    auto LOADST = [&](int st, int k0) {
        float* as = smd + st * STAGEF;
        float* bs = as + BOFF;
#pragma unroll
        for (int q = 0; q < 4; q++) {
            int cc = t + q * 256;
            int m = cc >> 3, kc = cc & 7;
            uint32_t ad = (uint32_t)__cvta_generic_to_shared(as + m * 36 + kc * 4);
            cpa16(ad, A + (size_t)(bm + m) * lda + k0 + kc * 4);
        }
#pragma unroll
        for (int q = 0; q < 4; q++) {
            int cc = t + q * 256;
            int r = cc >> 5, nc = cc & 31;
            uint32_t bd = (uint32_t)__cvta_generic_to_shared(bs + r * 136 + nc * 4);
            cpa16(bd, B + (size_t)(k0 + r) * ldb + bn + nc * 4);
        }
        asm volatile("cp.async.commit_group;\n");
    };

    LOADST(0, 0);

    int s = 0;
    for (int k0 = 0; k0 < K; k0 += 32) {
        if (k0 + 32 < K) {
            LOADST(s ^ 1, k0 + 32);
            asm volatile("cp.async.wait_group 1;\n");
        } else {
            asm volatile("cp.async.wait_group 0;\n");
        }
        __syncthreads();

        const float* as = smd + s * STAGEF;
        const float* bs = as + BOFF;

#pragma unroll
        for (int ks = 0; ks < 4; ks++) {
            int kb = ks * 8;
            uint32_t afh[4][4], afl[4][4], bfh[4][2], bfl[4][2];
#pragma unroll
            for (int mi = 0; mi < 4; mi++) {
                int rm = wm * 64 + mi * 16 + group;
                float a0 = as[rm * 36 + kb + tg];
                float a1 = as[(rm + 8) * 36 + kb + tg];
                float a2 = as[rm * 36 + kb + tg + 4];
                float a3 = as[(rm + 8) * 36 + kb + tg + 4];
                afh[mi][0] = f2tf(a0); afh[mi][1] = f2tf(a1);
                afh[mi][2] = f2tf(a2); afh[mi][3] = f2tf(a3);
                afl[mi][0] = f2tf(a0 - __uint_as_float(afh[mi][0]));
                afl[mi][1] = f2tf(a1 - __uint_as_float(afh[mi][1]));
                afl[mi][2] = f2tf(a2 - __uint_as_float(afh[mi][2]));
                afl[mi][3] = f2tf(a3 - __uint_as_float(afh[mi][3]));
            }
#pragma unroll
            for (int ni = 0; ni < 4; ni++) {
                int cn = wn * 32 + ni * 8 + group;
                float b0 = bs[(kb + tg) * 136 + cn];
                float b1 = bs[(kb + tg + 4) * 136 + cn];
                bfh[ni][0] = f2tf(b0);
                bfh[ni][1] = f2tf(b1);
                bfl[ni][0] = f2tf(b0 - __uint_as_float(bfh[ni][0]));
                bfl[ni][1] = f2tf(b1 - __uint_as_float(bfh[ni][1]));
            }
#pragma unroll
            for (int mi = 0; mi < 4; mi++)
#pragma unroll
                for (int ni = 0; ni < 4; ni++) {
                    asm volatile(
                        "mma.sync.aligned.m16n8k8.row.col.f32.tf32.tf32.f32 "
                        "{%0,%1,%2,%3}, {%4,%5,%6,%7}, {%8,%9}, {%0,%1,%2,%3};\n"
                        : "+f"(c[mi][ni][0]), "+f"(c[mi][ni][1]),
                          "+f"(c[mi][ni][2]), "+f"(c[mi][ni][3])
                        : "r"(afh[mi][0]), "r"(afh[mi][1]), "r"(afh[mi][2]), "r"(afh[mi][3]),
                          "r"(bfl[ni][0]), "r"(bfl[ni][1]));
                    asm volatile(
                        "mma.sync.aligned.m16n8k8.row.col.f32.tf32.tf32.f32 "
                        "{%0,%1,%2,%3}, {%4,%5,%6,%7}, {%8,%9}, {%0,%1,%2,%3};\n"
                        : "+f"(c[mi][ni][0]), "+f"(c[mi][ni][1]),
                          "+f"(c[mi][ni][2]), "+f"(c[mi][ni][3])
                        : "r"(afl[mi][0]), "r"(afl[mi][1]), "r"(afl[mi][2]), "r"(afl[mi][3]),
                          "r"(bfh[ni][0]), "r"(bfh[ni][1]));
                    asm volatile(
                        "mma.sync.aligned.m16n8k8.row.col.f32.tf32.tf32.f32 "
                        "{%0,%1,%2,%3}, {%4,%5,%6,%7}, {%8,%9}, {%0,%1,%2,%3};\n"
                        : "+f"(c[mi][ni][0]), "+f"(c[mi][ni][1]),
                          "+f"(c[mi][ni][2]), "+f"(c[mi][ni][3])
                        : "r"(afh[mi][0]), "r"(afh[mi][1]), "r"(afh[mi][2]), "r"(afh[mi][3]),
                          "r"(bfh[ni][0]), "r"(bfh[ni][1]));
                }
        }
        __syncthreads();
        s ^= 1;
    }

#pragma unroll
    for (int mi = 0; mi < 4; mi++) {
        int row0 = bm + wm * 64 + mi * 16 + group;
#pragma unroll
        for (int ni = 0; ni < 4; ni++) {
            int col = bn + wn * 32 + ni * 8 + tg * 2;
            *(float2*)(C + (size_t)row0 * ldc + col)       = make_float2(c[mi][ni][0], c[mi][ni][1]);
            *(float2*)(C + (size_t)(row0 + 8) * ldc + col) = make_float2(c[mi][ni][2], c[mi][ni][3]);
        }
    }
}

// ---------------- generic SGEMM (small K paths) ----------------
__global__ void __launch_bounds__(256) gemm64(
    const float* __restrict__ A, const float* __restrict__ B, float* __restrict__ C,
    int M, int N, int K, int lda, int ldb, int ldc)
{
    __shared__ float As[16][65];
    __shared__ float Bs[16][64];
    int tid = threadIdx.x, tx = tid & 15, ty = tid >> 4;
    int bm = blockIdx.y * 64, bn = blockIdx.x * 64;
    float acc[4][4];
#pragma unroll
    for (int i = 0; i < 4; i++)
#pragma unroll
        for (int j = 0; j < 4; j++) acc[i][j] = 0.f;

    for (int k0 = 0; k0 < K; k0 += 16) {
        for (int t = tid; t < 64 * 16; t += 256) {
            int r = t >> 4, c = t & 15;
            int gr = bm + r, gc = k0 + c;
            As[c][r] = (gr < M && gc < K) ? A[(size_t)gr * lda + gc] : 0.f;
        }
        for (int t = tid; t < 16 * 64; t += 256) {
            int r = t >> 6, c = t & 63;
            int gr = k0 + r, gc = bn + c;
            Bs[r][c] = (gr < K && gc < N) ? B[(size_t)gr * ldb + gc] : 0.f;
        }
        __syncthreads();
#pragma unroll
        for (int kk = 0; kk < 16; kk++) {
            float a[4], b[4];
#pragma unroll
            for (int i = 0; i < 4; i++) a[i] = As[kk][ty * 4 + i];
#pragma unroll
            for (int j = 0; j < 4; j++) b[j] = Bs[kk][tx * 4 + j];
#pragma unroll
            for (int i = 0; i < 4; i++)
#pragma unroll
                for (int j = 0; j < 4; j++) acc[i][j] += a[i] * b[j];
        }
        __syncthreads();
    }
#pragma unroll
    for (int i = 0; i < 4; i++)
#pragma unroll
        for (int j = 0; j < 4; j++) {
            int gr = bm + ty * 4 + i, gc = bn + tx * 4 + j;
            if (gr < M && gc < N) C[(size_t)gr * ldc + gc] = acc[i][j];
        }
}

// ---------------- small helper kernels ----------------
__global__ void pad_w5(const float* __restrict__ a, const float* __restrict__ b,
                       const float* __restrict__ c, const float* __restrict__ d,
                       const float* __restrict__ e, float* __restrict__ out)
{
    int idx = blockIdx.x * 256 + threadIdx.x;
    if (idx >= 5 * HP * HP) return;
    int w = idx / (HP * HP), r = idx - w * (HP * HP);
    int i = r >> 8, j = r & 255;
    const float* W = (w == 0) ? a : (w == 1) ? b : (w == 2) ? c : (w == 3) ? d : e;
    out[idx] = (i < H && j < H) ? W[i * H + j] : 0.f;
}

__global__ void zeropad_cols(float* __restrict__ t0, int n)
{
    int cols = HP - H;
    int idx = blockIdx.x * 256 + threadIdx.x;
    if (idx >= n * cols) return;
    int r = idx / cols, c = H + idx - r * cols;
    t0[r * HP + c] = 0.f;
}

__global__ void rowgather_bf16(const float* __restrict__ A, int n,
                               const int* __restrict__ perm,
                               __nv_bfloat16* __restrict__ out, int krows)
{
    size_t idx = (size_t)blockIdx.x * 256 + threadIdx.x;
    size_t n4 = (size_t)n / 4;
    if (idx >= (size_t)krows * n4) return;
    int i = (int)(idx / n4);
    int j4 = (int)(idx - (size_t)i * n4);
    float4 v = *(const float4*)(A + (size_t)perm[i] * n + j4 * 4);
    __nv_bfloat162 a = __floats2bfloat162_rn(v.x, v.y);
    __nv_bfloat162 b = __floats2bfloat162_rn(v.z, v.w);
    *(__nv_bfloat162*)(out + (size_t)i * n + j4 * 4)     = a;
    *(__nv_bfloat162*)(out + (size_t)i * n + j4 * 4 + 2) = b;
}

__global__ void rowgather_f32(const float* __restrict__ A, int n,
                              const int* __restrict__ perm,
                              float* __restrict__ out, int krows)
{
    size_t idx = (size_t)blockIdx.x * 256 + threadIdx.x;
    size_t n4 = (size_t)n / 4;
    if (idx >= (size_t)krows * n4) return;
    int i = (int)(idx / n4);
    int j4 = (int)(idx - (size_t)i * n4);
    float4 v = *(const float4*)(A + (size_t)perm[i] * n + j4 * 4);
    *(float4*)(out + (size_t)i * n + j4 * 4) = v;
}

__global__ void rowsum_dinv(const float* __restrict__ A, float* __restrict__ dinv, int n)
{
    int row = blockIdx.x;
    const float* Ar = A + (size_t)row * n;
    float s = 0.f;
    for (int j = threadIdx.x; j < n; j += 256) s += Ar[j];
    for (int o = 16; o > 0; o >>= 1) s += __shfl_down_sync(0xffffffffu, s, o);
    __shared__ float red[8];
    int w = threadIdx.x >> 5, l = threadIdx.x & 31;
    if (l == 0) red[w] = s;
    __syncthreads();
    if (threadIdx.x == 0) {
        float t = 0.f;
        for (int i = 0; i < 8; i++) t += red[i];
        dinv[row] = 1.0f / sqrtf(t + 2.0f);
    }
}

__global__ void scale_rows(const float* __restrict__ in, const float* __restrict__ dinv,
                           float* __restrict__ out, int n, int w, int ld)
{
    int idx = blockIdx.x * 256 + threadIdx.x;
    if (idx >= n * ld) return;
    int r = idx / ld, c = idx - r * ld;
    out[idx] = (c < w) ? dinv[r] * in[idx] : 0.f;
}

// out = dinv*(az + 2*(dinv*t0)) + b, relu; az = sum of S split-K partials
__global__ void gcn_finish_sk(const float* __restrict__ part, const float* __restrict__ Z,
                              const float* __restrict__ dinv, const float* __restrict__ b,
                              float* __restrict__ out, int n, int relu, int S)
{
    int idx = blockIdx.x * 256 + threadIdx.x;
    if (idx >= n * HP) return;
    int r = idx >> 8, c = idx & 255;
    float v = 0.f;
    if (c < H) {
        float az = 0.f;
        size_t stride = (size_t)n * HP;
        for (int s = 0; s < S; s++) az += part[s * stride + idx];
        float dr = dinv[r];
        v = dr * (az + 2.f * (dr * Z[idx])) + b[c];
        if (relu) v = fmaxf(v, 0.f);
    }
    out[idx] = v;
}

// score with inline ||p||
__global__ void score_kernel(const float* __restrict__ x, const float* __restrict__ p,
                             float* __restrict__ score, int n)
{
    int row = blockIdx.x * 8 + (threadIdx.x >> 5);
    int lane = threadIdx.x & 31;
    if (row >= n) return;
    const float* xr = x + (size_t)row * HP;
    float s = 0.f, pp = 0.f;
    for (int c = lane; c < H; c += 32) {
        float pv = p[c];
        s += xr[c] * pv;
        pp += pv * pv;
    }
    for (int o = 16; o > 0; o >>= 1) {
        s  += __shfl_down_sync(0xffffffffu, s, o);
        pp += __shfl_down_sync(0xffffffffu, pp, o);
    }
    if (lane == 0) score[row] = tanhf(s / sqrtf(pp));
}

// uint64-key bitonic topk + inverse perm (descending score, ascending index ties)
template <int SIZE>
__global__ void topk_kernel(const float* __restrict__ score, int n, int k,
                            int* __restrict__ perm, float* __restrict__ val,
                            int* __restrict__ iperm)
{
    __shared__ unsigned long long key[SIZE];
    int tid = threadIdx.x;
    for (int i = tid; i < SIZE; i += 1024) {
        float s = (i < n) ? score[i] : -INFINITY;
        uint32_t u = __float_as_uint(s);
        u = (u & 0x80000000u) ? ~u : (u | 0x80000000u);
        uint32_t d = ~u;
        key[i] = ((unsigned long long)d << 32) | (uint32_t)i;
        if (i < n) iperm[i] = -1;
    }
    __syncthreads();
    for (int size = 2; size <= SIZE; size <<= 1) {
        for (int stride = size >> 1; stride > 0; stride >>= 1) {
            for (int i = tid; i < SIZE; i += 1024) {
                int j = i ^ stride;
                if (j > i) {
                    unsigned long long a = key[i], b = key[j];
                    bool up = ((i & size) == 0);
                    if (up ? (a > b) : (a < b)) { key[i] = b; key[j] = a; }
                }
            }
            __syncthreads();
        }
    }
    for (int i = tid; i < k; i += 1024) {
        int si = (int)(uint32_t)key[i];
        perm[i] = si;
        val[i] = score[si];
        iperm[si] = i;
    }
}

__global__ void pool_A_tri(const float* __restrict__ C, const __nv_bfloat16* __restrict__ Rows,
                           int K, const int* __restrict__ perm,
                           float* __restrict__ Aout, int k)
{
    int idx = blockIdx.x * 256 + threadIdx.x;
    if (idx >= k * k) return;
    int i = idx / k, j = idx - i * k;
    if (i == j) { Aout[idx] = 0.f; return; }
    int hi = i > j ? i : j, lo = i > j ? j : i;
    float g = C[(size_t)hi * k + lo];
    float a = __bfloat162float(Rows[(size_t)i * K + __ldg(&perm[j])]);
    Aout[idx] = g + 2.f * a;
}

__global__ void pool_A_tri_f32(const float* __restrict__ C, const float* __restrict__ Rows,
                               int K, const int* __restrict__ perm,
                               float* __restrict__ Aout, int k)
{
    int idx = blockIdx.x * 256 + threadIdx.x;
    if (idx >= k * k) return;
    int i = idx / k, j = idx - i * k;
    if (i == j) { Aout[idx] = 0.f; return; }
    int hi = i > j ? i : j, lo = i > j ? j : i;
    Aout[idx] = C[(size_t)hi * k + lo] + 2.f * Rows[(size_t)i * K + __ldg(&perm[j])];
}

__global__ void pool_x(const float* __restrict__ xin, const int* __restrict__ perm,
                       const float* __restrict__ val, float* __restrict__ xout, int k)
{
    int idx = blockIdx.x * 256 + threadIdx.x;
    if (idx >= k * HP) return;
    int r = idx >> 8, c = idx & 255;
    xout[idx] = xin[(size_t)perm[r] * HP + c] * val[r];
}

// CUR = Xj + scatter(Xn by perm) via inverse perm
__global__ void fuse_up(const float* __restrict__ Xj, const float* __restrict__ Xn,
                        const int* __restrict__ iperm, float* __restrict__ out, int n)
{
    int idx = blockIdx.x * 256 + threadIdx.x;
    if (idx >= n * HP) return;
    int r = idx >> 8, c = idx & 255;
    int p = iperm[r];
    float v = Xj[idx];
    if (p >= 0) v += Xn[p * HP + c];
    out[idx] = v;
}

__global__ void gemm_n2(const float* __restrict__ A, const float* __restrict__ Z,
                        float* __restrict__ out, int n)
{
    int row = blockIdx.x;
    const float* Ar = A + (size_t)row * n;
    float a0 = 0.f, a1 = 0.f;
    for (int j = threadIdx.x; j < n; j += 256) {
        float a = Ar[j];
        a0 += a * Z[2 * j];
        a1 += a * Z[2 * j + 1];
    }
    for (int o = 16; o > 0; o >>= 1) {
        a0 += __shfl_down_sync(0xffffffffu, a0, o);
        a1 += __shfl_down_sync(0xffffffffu, a1, o);
    }
    __shared__ float r0[8], r1[8];
    int w = threadIdx.x >> 5, l = threadIdx.x & 31;
    if (l == 0) { r0[w] = a0; r1[w] = a1; }
    __syncthreads();
    if (threadIdx.x == 0) {
        float s0 = 0.f, s1 = 0.f;
        for (int i = 0; i < 8; i++) { s0 += r0[i]; s1 += r1[i]; }
        out[2 * row] = s0;
        out[2 * row + 1] = s1;
    }
}

__global__ void final_kernel(const float* __restrict__ AZ, const float* __restrict__ Z,
                             const float* __restrict__ dinv, const float* __restrict__ b,
                             float* __restrict__ out, int n)
{
    int i = blockIdx.x * 256 + threadIdx.x;
    if (i >= n) return;
    float a = dinv[i] * (AZ[2 * i]     + 2.f * Z[2 * i])     + b[0];
    float c = dinv[i] * (AZ[2 * i + 1] + 2.f * Z[2 * i + 1]) + b[1];
    float m = fmaxf(a, c);
    float l = m + logf(expf(a - m) + expf(c - m));
    out[2 * i] = a - l;
    out[2 * i + 1] = c - l;
}

// ---------------- host orchestration ----------------
template <typename T, size_t NN>
static T* symaddr(T (&sym)[NN]) {
    void* p = nullptr;
    cudaGetSymbolAddress(&p, sym);
    return (T*)p;
}

#define SMEM_TF 73728
#define SMEM_BF 73984

extern "C" void kernel_launch(void* const* d_in, const int* in_sizes, int n_in,
                              void* d_out, int out_size)
{
    (void)in_sizes; (void)n_in; (void)out_size;
    const float* x   = (const float*)d_in[0];
    const float* adj = (const float*)d_in[1];
    const float* w0  = (const float*)d_in[2];
    const float* b0  = (const float*)d_in[3];
    const float* w1  = (const float*)d_in[4];
    const float* b1  = (const float*)d_in[5];
    const float* w2  = (const float*)d_in[6];
    const float* b2  = (const float*)d_in[7];
    const float* w3  = (const float*)d_in[8];
    const float* b3  = (const float*)d_in[9];
    const float* p1  = (const float*)d_in[10];
    const float* p2  = (const float*)d_in[11];
    const float* p3  = (const float*)d_in[12];
    const float* u0w = (const float*)d_in[13];
    const float* u0b = (const float*)d_in[14];
    const float* u1w = (const float*)d_in[15];
    const float* u1b = (const float*)d_in[16];
    const float* u2w = (const float*)d_in[17];
    const float* u2b = (const float*)d_in[18];

    static cudaStream_t sA = nullptr;
    static cudaEvent_t evF = nullptr, evA = nullptr;
    static bool init_done = false;
    if (!init_done) {
        cudaFuncSetAttribute(tf32w, cudaFuncAttributeMaxDynamicSharedMemorySize, SMEM_TF);
        cudaFuncSetAttribute(bf16g<0, 0, 1>, cudaFuncAttributeMaxDynamicSharedMemorySize, SMEM_BF);
        cudaFuncSetAttribute(bf16g<1, 0, 1>, cudaFuncAttributeMaxDynamicSharedMemorySize, SMEM_BF);
        cudaFuncSetAttribute(bf16g<1, 1, 0>, cudaFuncAttributeMaxDynamicSharedMemorySize, SMEM_BF);
        cudaStreamCreateWithFlags(&sA, cudaStreamNonBlocking);
        cudaEventCreateWithFlags(&evF, cudaEventDisableTiming);
        cudaEventCreateWithFlags(&evA, cudaEventDisableTiming);
        init_done = true;
    }

    float* G    = symaddr(g_G);
    __nv_bfloat16* ROWS = symaddr(g_rows);
    float* A1   = symaddr(g_A1);
    float* A2   = symaddr(g_A2);
    float* A3   = symaddr(g_A3);
    float* X0   = symaddr(g_x0);
    float* X1   = symaddr(g_x1);
    float* X2   = symaddr(g_x2);
    float* X3   = symaddr(g_x3);
    float* T0   = symaddr(g_t0);
    float* T1   = symaddr(g_t1);
    float* PART = symaddr(g_part);
    float* CUR  = symaddr(g_cur);
    float* WP   = symaddr(g_wpad);
    float* D0   = symaddr(g_d0);
    float* D1   = symaddr(g_d1);
    float* D2   = symaddr(g_d2);
    float* D3   = symaddr(g_d3);
    float* SC   = symaddr(g_score);
    float* VAL  = symaddr(g_val);
    int*   P0   = symaddr(g_perm0);
    int*   P1   = symaddr(g_perm1);
    int*   P2   = symaddr(g_perm2);
    int*   IP0  = symaddr(g_ip0);
    int*   IP1  = symaddr(g_ip1);
    int*   IP2  = symaddr(g_ip2);

    float* WP_w1  = WP + 0 * HP * HP;
    float* WP_w2  = WP + 1 * HP * HP;
    float* WP_w3  = WP + 2 * HP * HP;
    float* WP_u0w = WP + 3 * HP * HP;
    float* WP_u1w = WP + 4 * HP * HP;

    // ---- prep ----
    pad_w5<<<(5 * HP * HP + 255) / 256, 256>>>(w1, w2, w3, u0w, u1w, WP);
    rowsum_dinv<<<N0, 256>>>(adj, D0, N0);

    // ---- gcn0 ----
    {
        dim3 g1((H + 63) / 64, (N0 + 63) / 64);
        gemm64<<<g1, 256>>>(x, w0, T0, N0, H, 3, 3, H, HP);
        zeropad_cols<<<(N0 * (HP - H) + 255) / 256, 256>>>(T0, N0);
        dim3 g2(HP / 128, N0 / 128, 4);
        bf16g<0, 0, 1><<<g2, 256, SMEM_BF>>>(adj, T0, PART, N0, HP, N0, N0, HP, HP, D0);
        gcn_finish_sk<<<(N0 * HP + 255) / 256, 256>>>(PART, T0, D0, b0, X0, N0, 1, 4);
    }

    // ==== pool 1 (4096 -> 3072) ====
    score_kernel<<<(N0 + 7) / 8, 256>>>(X0, p1, SC, N0);
    topk_kernel<4096><<<1, 1024>>>(SC, N0, KP1, P0, VAL, IP0);
    cudaEventRecord(evF, 0);
    cudaStreamWaitEvent(sA, evF, 0);
    {
        size_t tot = (size_t)KP1 * (N0 / 4);
        rowgather_bf16<<<(unsigned)((tot + 255) / 256), 256, 0, sA>>>(adj, N0, P0, ROWS, KP1);
        dim3 g(KP1 / 128, KP1 / 128);
        bf16gemm_xxt<<<g, 256, 0, sA>>>(ROWS, G, KP1, N0);
        pool_A_tri<<<(KP1 * KP1 + 255) / 256, 256, 0, sA>>>(G, ROWS, N0, P0, A1, KP1);
        rowsum_dinv<<<KP1, 256, 0, sA>>>(A1, D1, KP1);
    }
    cudaEventRecord(evA, sA);
    pool_x<<<(KP1 * HP + 255) / 256, 256>>>(X0, P0, VAL, CUR, KP1);
    {
        dim3 gw(HP / 128, KP1 / 128, 1);
        tf32w<<<gw, 256, SMEM_TF>>>(CUR, WP_w1, T0, KP1, HP, HP, HP, HP, HP);
    }
    cudaStreamWaitEvent(0, evA, 0);
    {
        dim3 g2(HP / 128, KP1 / 128, 6);
        bf16g<0, 0, 1><<<g2, 256, SMEM_BF>>>(A1, T0, PART, KP1, HP, KP1, KP1, HP, HP, D1);
        gcn_finish_sk<<<(KP1 * HP + 255) / 256, 256>>>(PART, T0, D1, b1, X1, KP1, 1, 6);
    }

    // ==== pool 2 (3072 -> 1536) ====
    score_kernel<<<(KP1 + 7) / 8, 256>>>(X1, p2, SC, KP1);
    topk_kernel<4096><<<1, 1024>>>(SC, KP1, KP2, P1, VAL, IP1);
    cudaEventRecord(evF, 0);
    cudaStreamWaitEvent(sA, evF, 0);
    {
        size_t tot = (size_t)KP2 * (KP1 / 4);
        rowgather_bf16<<<(unsigned)((tot + 255) / 256), 256, 0, sA>>>(A1, KP1, P1, ROWS, KP2);
        dim3 g(KP2 / 128, KP2 / 128);
        bf16gemm_xxt<<<g, 256, 0, sA>>>(ROWS, G, KP2, KP1);
        pool_A_tri<<<(KP2 * KP2 + 255) / 256, 256, 0, sA>>>(G, ROWS, KP1, P1, A2, KP2);
        rowsum_dinv<<<KP2, 256, 0, sA>>>(A2, D2, KP2);
    }
    cudaEventRecord(evA, sA);
    pool_x<<<(KP2 * HP + 255) / 256, 256>>>(X1, P1, VAL, CUR, KP2);
    {
        dim3 gw(HP / 128, KP2 / 128, 1);
        tf32w<<<gw, 256, SMEM_TF>>>(CUR, WP_w2, T0, KP2, HP, HP, HP, HP, HP);
    }
    cudaStreamWaitEvent(0, evA, 0);
    {
        dim3 g2(HP / 128, KP2 / 128, 6);
        bf16g<1, 0, 1><<<g2, 256, SMEM_BF>>>(A2, T0, PART, KP2, HP, KP2, KP2, HP, HP, D2);
        gcn_finish_sk<<<(KP2 * HP + 255) / 256, 256>>>(PART, T0, D2, b2, X2, KP2, 1, 6);
    }

    // ==== pool 3 (1536 -> 768) ====
    score_kernel<<<(KP2 + 7) / 8, 256>>>(X2, p3, SC, KP2);
    topk_kernel<2048><<<1, 1024>>>(SC, KP2, KP3, P2, VAL, IP2);
    cudaEventRecord(evF, 0);
    cudaStreamWaitEvent(sA, evF, 0);
    {
        size_t tot = (size_t)KP3 * (KP2 / 4);
        rowgather_f32<<<(unsigned)((tot + 255) / 256), 256, 0, sA>>>(A2, KP2, P2, PART, KP3);
        dim3 g(KP3 / 128, KP3 / 128, 1);
        bf16g<1, 1, 0><<<g, 256, SMEM_BF, sA>>>(PART, PART, G, KP3, KP3, KP2, KP2, KP2, KP3, nullptr);
        pool_A_tri_f32<<<(KP3 * KP3 + 255) / 256, 256, 0, sA>>>(G, PART, KP2, P2, A3, KP3);
        rowsum_dinv<<<KP3, 256, 0, sA>>>(A3, D3, KP3);
    }
    cudaEventRecord(evA, sA);
    pool_x<<<(KP3 * HP + 255) / 256, 256>>>(X2, P2, VAL, CUR, KP3);
    {
        dim3 gw(HP / 128, KP3 / 128, 1);
        tf32w<<<gw, 256, SMEM_TF>>>(CUR, WP_w3, T0, KP3, HP, HP, HP, HP, HP);
    }
    cudaStreamWaitEvent(0, evA, 0);
    {
        dim3 g2(HP / 128, KP3 / 128, 12);
        bf16g<1, 0, 1><<<g2, 256, SMEM_BF>>>(A3, T0, PART, KP3, HP, KP3, KP3, HP, HP, D3);
        gcn_finish_sk<<<(KP3 * HP + 255) / 256, 256>>>(PART, T0, D3, b3, X3, KP3, 1, 12);
    }

    // ==== up 0 ====
    fuse_up<<<(KP2 * HP + 255) / 256, 256>>>(X2, X3, IP2, CUR, KP2);
    {
        dim3 gw(HP / 128, KP2 / 128, 1);
        tf32w<<<gw, 256, SMEM_TF>>>(CUR, WP_u0w, T0, KP2, HP, HP, HP, HP, HP);
        dim3 g2(HP / 128, KP2 / 128, 6);
        bf16g<1, 0, 1><<<g2, 256, SMEM_BF>>>(A2, T0, PART, KP2, HP, KP2, KP2, HP, HP, D2);
        gcn_finish_sk<<<(KP2 * HP + 255) / 256, 256>>>(PART, T0, D2, u0b, X2, KP2, 1, 6);
    }

    // ==== up 1 ====
    fuse_up<<<(KP1 * HP + 255) / 256, 256>>>(X1, X2, IP1, CUR, KP1);
    {
        dim3 gw(HP / 128, KP1 / 128, 1);
        tf32w<<<gw, 256, SMEM_TF>>>(CUR, WP_u1w, T0, KP1, HP, HP, HP, HP, HP);
        dim3 g2(HP / 128, KP1 / 128, 6);
        bf16g<0, 0, 1><<<g2, 256, SMEM_BF>>>(A1, T0, PART, KP1, HP, KP1, KP1, HP, HP, D1);
        gcn_finish_sk<<<(KP1 * HP + 255) / 256, 256>>>(PART, T0, D1, u1b, X1, KP1, 1, 6);
    }

    // ==== up 2: final gcn (H->2) + log_softmax ====
    fuse_up<<<(N0 * HP + 255) / 256, 256>>>(X0, X1, IP0, CUR, N0);
    {
        dim3 gf(1, (N0 + 63) / 64);
        gemm64<<<gf, 256>>>(CUR, u2w, T0, N0, 2, H, HP, 2, 2);
        scale_rows<<<(N0 * 2 + 255) / 256, 256>>>(T0, D0, T1, N0, 2, 2);
        gemm_n2<<<N0, 256>>>(adj, T1, T0, N0);
        final_kernel<<<(N0 + 255) / 256, 256>>>(T0, T1, D0, u2b, (float*)d_out, N0);
    }
}

// round 15
// speedup vs baseline: 8.1754x; 1.0261x over previous
#include <cuda_runtime.h>
#include <cuda_bf16.h>
#include <math.h>
#include <stdint.h>

#define N0 4096
#define KP1 3072
#define KP2 1536
#define KP3 768
#define H 200
#define HP 256
#define SKMAX 12

// ---------------- device scratch ----------------
__device__ float g_G[(size_t)N0 * N0];
__device__ __nv_bfloat16 g_adjb[(size_t)N0 * N0];
__device__ __nv_bfloat16 g_rows[(size_t)KP1 * N0];
__device__ __nv_bfloat16 g_A1b[(size_t)KP1 * KP1];
__device__ float g_A2[(size_t)KP2 * KP2];
__device__ float g_A3[(size_t)KP3 * KP3];
__device__ float g_x0[N0 * HP];
__device__ float g_x1[KP1 * HP];
__device__ float g_x2[KP2 * HP];
__device__ float g_x3[KP3 * HP];
__device__ float g_t0[N0 * HP];
__device__ float g_t1[N0 * HP];
__device__ float g_part[(size_t)SKMAX * N0 * HP];
__device__ float g_cur[N0 * HP];
__device__ float g_wpad[5 * HP * HP];
__device__ float g_d0[N0];
__device__ float g_d1[KP1];
__device__ float g_d2[KP2];
__device__ float g_d3[KP3];
__device__ float g_score[N0];
__device__ float g_val[N0];
__device__ int   g_perm0[KP1];
__device__ int   g_perm1[KP2];
__device__ int   g_perm2[KP3];
__device__ int   g_ip0[N0];
__device__ int   g_ip1[KP1];
__device__ int   g_ip2[KP2];

__device__ __forceinline__ void cpa16(uint32_t dst, const void* src) {
    asm volatile("cp.async.cg.shared.global [%0], [%1], 16;\n" :: "r"(dst), "l"(src));
}
__device__ __forceinline__ uint32_t packbf(float x, float y) {
    __nv_bfloat162 h = __floats2bfloat162_rn(x, y);
    return *(uint32_t*)&h;
}
__device__ __forceinline__ uint32_t packbf_res(float x, float y, uint32_t hi) {
    __nv_bfloat162 h = *(__nv_bfloat162*)&hi;
    return packbf(x - __bfloat162float(h.x), y - __bfloat162float(h.y));
}

#define MMA_BF16(c, a, b)                                                         \
    asm volatile(                                                                 \
        "mma.sync.aligned.m16n8k16.row.col.f32.bf16.bf16.f32 "                    \
        "{%0,%1,%2,%3}, {%4,%5,%6,%7}, {%8,%9}, {%0,%1,%2,%3};\n"                 \
        : "+f"((c)[0]), "+f"((c)[1]), "+f"((c)[2]), "+f"((c)[3])                  \
        : "r"((a)[0]), "r"((a)[1]), "r"((a)[2]), "r"((a)[3]),                     \
          "r"((b)[0]), "r"((b)[1]))

// ============ bf16 X·X^T GEMM (bf16 input), lower triangle ===========================
__global__ void __launch_bounds__(256) bf16gemm_xxt(
    const __nv_bfloat16* __restrict__ X, float* __restrict__ C, int k, int K)
{
    if (blockIdx.x > blockIdx.y) return;

    __shared__ __nv_bfloat16 As[2][128][40];
    __shared__ __nv_bfloat16 Bs[2][128][40];

    int t = threadIdx.x;
    int warp = t >> 5, lane = t & 31;
    int group = lane >> 2, tg = lane & 3;
    int wm = warp >> 2, wn = warp & 3;
    int bm = blockIdx.y * 128, bn = blockIdx.x * 128;

    float c[4][4][4];
#pragma unroll
    for (int mi = 0; mi < 4; mi++)
#pragma unroll
        for (int ni = 0; ni < 4; ni++)
#pragma unroll
            for (int r = 0; r < 4; r++) c[mi][ni][r] = 0.f;

    int lrow = t >> 1;
    int lcol0 = (t & 1) * 16;

    uint32_t aBase = (uint32_t)__cvta_generic_to_shared(&As[0][0][0]);
    uint32_t bBase = (uint32_t)__cvta_generic_to_shared(&Bs[0][0][0]);
    const uint32_t stageB = 128 * 40 * 2;
    uint32_t aDst = aBase + lrow * 80 + lcol0 * 2;
    uint32_t bDst = bBase + lrow * 80 + lcol0 * 2;

    const __nv_bfloat16* aSrcRow = X + (size_t)(bm + lrow) * K + lcol0;
    const __nv_bfloat16* bSrcRow = X + (size_t)(bn + lrow) * K + lcol0;

#define LOAD_STAGE(st, k0)                                        \
    do {                                                          \
        const __nv_bfloat16* ap = aSrcRow + (k0);                 \
        const __nv_bfloat16* bp = bSrcRow + (k0);                 \
        uint32_t ad = aDst + (st) * stageB;                       \
        uint32_t bd = bDst + (st) * stageB;                       \
        cpa16(ad, ap); cpa16(ad + 16, ap + 8);                    \
        cpa16(bd, bp); cpa16(bd + 16, bp + 8);                    \
    } while (0)

    LOAD_STAGE(0, 0);
    asm volatile("cp.async.commit_group;\n");

    int s = 0;
    for (int k0 = 0; k0 < K; k0 += 32) {
        if (k0 + 32 < K) {
            LOAD_STAGE(s ^ 1, k0 + 32);
            asm volatile("cp.async.commit_group;\n");
            asm volatile("cp.async.wait_group 1;\n");
        } else {
            asm volatile("cp.async.wait_group 0;\n");
        }
        __syncthreads();

#pragma unroll
        for (int ks = 0; ks < 2; ks++) {
            int kb = ks * 16;
            uint32_t af[4][4], bf[4][2];
#pragma unroll
            for (int mi = 0; mi < 4; mi++) {
                int rm = wm * 64 + mi * 16 + group;
                af[mi][0] = *(const uint32_t*)&As[s][rm][kb + 2 * tg];
                af[mi][1] = *(const uint32_t*)&As[s][rm + 8][kb + 2 * tg];
                af[mi][2] = *(const uint32_t*)&As[s][rm][kb + 2 * tg + 8];
                af[mi][3] = *(const uint32_t*)&As[s][rm + 8][kb + 2 * tg + 8];
            }
#pragma unroll
            for (int ni = 0; ni < 4; ni++) {
                int cn = wn * 32 + ni * 8 + group;
                bf[ni][0] = *(const uint32_t*)&Bs[s][cn][kb + 2 * tg];
                bf[ni][1] = *(const uint32_t*)&Bs[s][cn][kb + 2 * tg + 8];
            }
#pragma unroll
            for (int mi = 0; mi < 4; mi++)
#pragma unroll
                for (int ni = 0; ni < 4; ni++)
                    MMA_BF16(c[mi][ni], af[mi], bf[ni]);
        }
        __syncthreads();
        s ^= 1;
    }
#undef LOAD_STAGE

#pragma unroll
    for (int mi = 0; mi < 4; mi++) {
        int row0 = bm + wm * 64 + mi * 16 + group;
#pragma unroll
        for (int ni = 0; ni < 4; ni++) {
            int col = bn + wn * 32 + ni * 8 + tg * 2;
            *(float2*)(C + (size_t)row0 * k + col)       = make_float2(c[mi][ni][0], c[mi][ni][1]);
            *(float2*)(C + (size_t)(row0 + 8) * k + col) = make_float2(c[mi][ni][2], c[mi][ni][3]);
        }
    }
}

// ============ prop GEMM: A bf16 (exact), B fp32 hi/lo split, fused dinv scale ========
__global__ void __launch_bounds__(256, 2) bf16gA(
    const __nv_bfloat16* __restrict__ A, const float* __restrict__ B, float* __restrict__ Cpart,
    int M, int N, int K, int lda, int ldb, int ldc, const float* __restrict__ dinv)
{
    extern __shared__ char smc[];
    __nv_bfloat16* asb = (__nv_bfloat16*)smc;                 // 2 x 128 x 40 halves
    float* bsf = (float*)(smc + 2 * 128 * 40 * 2);            // 2 x 32 x 136 floats
    float* dvb = bsf + 2 * 32 * 136;                          // 2 x 32

    int t = threadIdx.x;
    int warp = t >> 5, lane = t & 31;
    int group = lane >> 2, tg = lane & 3;
    int wm = warp >> 2, wn = warp & 3;
    int bm = blockIdx.y * 128, bn = blockIdx.x * 128;
    int kChunk = K / gridDim.z;
    int kStart = blockIdx.z * kChunk;
    float* C = Cpart + (size_t)blockIdx.z * M * ldc;

    float c[4][4][4];
#pragma unroll
    for (int mi = 0; mi < 4; mi++)
#pragma unroll
        for (int ni = 0; ni < 4; ni++)
#pragma unroll
            for (int r = 0; r < 4; r++) c[mi][ni][r] = 0.f;

    auto LOADST = [&](int st, int k0) {
        __nv_bfloat16* as = asb + st * (128 * 40);
        float* bs = bsf + st * (32 * 136);
#pragma unroll
        for (int q = 0; q < 2; q++) {
            int idx = t + q * 256;
            int row = idx >> 2, seg = idx & 3;
            uint32_t ad = (uint32_t)__cvta_generic_to_shared(as + row * 40 + seg * 8);
            cpa16(ad, A + (size_t)(bm + row) * lda + kStart + k0 + seg * 8);
        }
#pragma unroll
        for (int q = 0; q < 4; q++) {
            int cc = t + q * 256;
            int r = cc >> 5, nc = cc & 31;
            uint32_t bd = (uint32_t)__cvta_generic_to_shared(bs + r * 136 + nc * 4);
            cpa16(bd, B + (size_t)(kStart + k0 + r) * ldb + bn + nc * 4);
        }
        if (t < 8) {
            uint32_t dd = (uint32_t)__cvta_generic_to_shared(dvb + st * 32 + t * 4);
            cpa16(dd, dinv + kStart + k0 + t * 4);
        }
        asm volatile("cp.async.commit_group;\n");
    };

    LOADST(0, 0);

    int s = 0;
    for (int k0 = 0; k0 < kChunk; k0 += 32) {
        if (k0 + 32 < kChunk) {
            LOADST(s ^ 1, k0 + 32);
            asm volatile("cp.async.wait_group 1;\n");
        } else {
            asm volatile("cp.async.wait_group 0;\n");
        }
        __syncthreads();

        const __nv_bfloat16* as = asb + s * (128 * 40);
        const float* bs = bsf + s * (32 * 136);
        const float* dv = dvb + s * 32;

#pragma unroll
        for (int ks = 0; ks < 2; ks++) {
            int kb = ks * 16;
            uint32_t af[4][4], bh[4][2], bl[4][2];
#pragma unroll
            for (int mi = 0; mi < 4; mi++) {
                int rm = wm * 64 + mi * 16 + group;
                af[mi][0] = *(const uint32_t*)&as[rm * 40 + kb + 2 * tg];
                af[mi][1] = *(const uint32_t*)&as[(rm + 8) * 40 + kb + 2 * tg];
                af[mi][2] = *(const uint32_t*)&as[rm * 40 + kb + 2 * tg + 8];
                af[mi][3] = *(const uint32_t*)&as[(rm + 8) * 40 + kb + 2 * tg + 8];
            }
#pragma unroll
            for (int ni = 0; ni < 4; ni++) {
                int cn = wn * 32 + ni * 8 + group;
                float b0a = bs[(kb + 2 * tg) * 136 + cn]     * dv[kb + 2 * tg];
                float b0b = bs[(kb + 2 * tg + 1) * 136 + cn] * dv[kb + 2 * tg + 1];
                float b1a = bs[(kb + 8 + 2 * tg) * 136 + cn] * dv[kb + 8 + 2 * tg];
                float b1b = bs[(kb + 9 + 2 * tg) * 136 + cn] * dv[kb + 9 + 2 * tg];
                bh[ni][0] = packbf(b0a, b0b);
                bh[ni][1] = packbf(b1a, b1b);
                bl[ni][0] = packbf_res(b0a, b0b, bh[ni][0]);
                bl[ni][1] = packbf_res(b1a, b1b, bh[ni][1]);
            }
#pragma unroll
            for (int mi = 0; mi < 4; mi++)
#pragma unroll
                for (int ni = 0; ni < 4; ni++) {
                    MMA_BF16(c[mi][ni], af[mi], bh[ni]);
                    MMA_BF16(c[mi][ni], af[mi], bl[ni]);
                }
        }
        __syncthreads();
        s ^= 1;
    }

#pragma unroll
    for (int mi = 0; mi < 4; mi++) {
        int row0 = bm + wm * 64 + mi * 16 + group;
#pragma unroll
        for (int ni = 0; ni < 4; ni++) {
            int col = bn + wn * 32 + ni * 8 + tg * 2;
            *(float2*)(C + (size_t)row0 * ldc + col)       = make_float2(c[mi][ni][0], c[mi][ni][1]);
            *(float2*)(C + (size_t)(row0 + 8) * ldc + col) = make_float2(c[mi][ni][2], c[mi][ni][3]);
        }
    }
}

// ============ bf16-split GEMM from fp32 inputs (A2/A3 props, lvl3 XXT, xW) ===========
template <int ASPLIT, int XXT, int DSCALE>
__global__ void __launch_bounds__(256, (ASPLIT ? 1 : 2)) bf16g(
    const float* __restrict__ A, const float* __restrict__ B, float* __restrict__ Cpart,
    int M, int N, int K, int lda, int ldb, int ldc, const float* __restrict__ dinv)
{
    if (XXT && (int)blockIdx.x > (int)blockIdx.y) return;
    extern __shared__ float smd[];
    const int STAGEF = 9216;
    const int BOFF = 128 * 36;
    float* dvbase = smd + 2 * STAGEF;

    int t = threadIdx.x;
    int warp = t >> 5, lane = t & 31;
    int group = lane >> 2, tg = lane & 3;
    int wm = warp >> 2, wn = warp & 3;
    int bm = blockIdx.y * 128, bn = blockIdx.x * 128;
    int kChunk = K / gridDim.z;
    int kStart = blockIdx.z * kChunk;
    float* C = Cpart + (size_t)blockIdx.z * M * ldc;

    float c[4][4][4];
#pragma unroll
    for (int mi = 0; mi < 4; mi++)
#pragma unroll
        for (int ni = 0; ni < 4; ni++)
#pragma unroll
            for (int r = 0; r < 4; r++) c[mi][ni][r] = 0.f;

    auto LOADST = [&](int st, int k0) {
        float* as = smd + st * STAGEF;
        float* bs = as + BOFF;
#pragma unroll
        for (int q = 0; q < 4; q++) {
            int cc = t + q * 256;
            int m = cc >> 3, kc = cc & 7;
            uint32_t ad = (uint32_t)__cvta_generic_to_shared(as + m * 36 + kc * 4);
            cpa16(ad, A + (size_t)(bm + m) * lda + kStart + k0 + kc * 4);
        }
        if (XXT) {
#pragma unroll
            for (int q = 0; q < 4; q++) {
                int cc = t + q * 256;
                int m = cc >> 3, kc = cc & 7;
                uint32_t bd = (uint32_t)__cvta_generic_to_shared(bs + m * 36 + kc * 4);
                cpa16(bd, B + (size_t)(bn + m) * ldb + kStart + k0 + kc * 4);
            }
        } else {
#pragma unroll
            for (int q = 0; q < 4; q++) {
                int cc = t + q * 256;
                int r = cc >> 5, nc = cc & 31;
                uint32_t bd = (uint32_t)__cvta_generic_to_shared(bs + r * 136 + nc * 4);
                cpa16(bd, B + (size_t)(kStart + k0 + r) * ldb + bn + nc * 4);
            }
            if (DSCALE && t < 8) {
                uint32_t dd = (uint32_t)__cvta_generic_to_shared(dvbase + st * 32 + t * 4);
                cpa16(dd, dinv + kStart + k0 + t * 4);
            }
        }
        asm volatile("cp.async.commit_group;\n");
    };

    LOADST(0, 0);

    int s = 0;
    for (int k0 = 0; k0 < kChunk; k0 += 32) {
        if (k0 + 32 < kChunk) {
            LOADST(s ^ 1, k0 + 32);
            asm volatile("cp.async.wait_group 1;\n");
        } else {
            asm volatile("cp.async.wait_group 0;\n");
        }
        __syncthreads();

        const float* as = smd + s * STAGEF;
        const float* bs = as + BOFF;
        const float* dv = dvbase + s * 32;

#pragma unroll
        for (int ks = 0; ks < 2; ks++) {
            int kb = ks * 16;
            uint32_t ah[4][4], al[4][4], bh[4][2], bl[4][2];
#pragma unroll
            for (int mi = 0; mi < 4; mi++) {
                int rm = wm * 64 + mi * 16 + group;
                const float* r0 = as + rm * 36 + kb + 2 * tg;
                const float* r1 = as + (rm + 8) * 36 + kb + 2 * tg;
                float x0 = r0[0], x1 = r0[1], x2 = r1[0], x3 = r1[1];
                float x4 = r0[8], x5 = r0[9], x6 = r1[8], x7 = r1[9];
                ah[mi][0] = packbf(x0, x1);
                ah[mi][1] = packbf(x2, x3);
                ah[mi][2] = packbf(x4, x5);
                ah[mi][3] = packbf(x6, x7);
                if (ASPLIT) {
                    al[mi][0] = packbf_res(x0, x1, ah[mi][0]);
                    al[mi][1] = packbf_res(x2, x3, ah[mi][1]);
                    al[mi][2] = packbf_res(x4, x5, ah[mi][2]);
                    al[mi][3] = packbf_res(x6, x7, ah[mi][3]);
                }
            }
#pragma unroll
            for (int ni = 0; ni < 4; ni++) {
                int cn = wn * 32 + ni * 8 + group;
                float b0a, b0b, b1a, b1b;
                if (XXT) {
                    const float* rb = bs + cn * 36 + kb + 2 * tg;
                    b0a = rb[0]; b0b = rb[1]; b1a = rb[8]; b1b = rb[9];
                } else {
                    b0a = bs[(kb + 2 * tg) * 136 + cn];
                    b0b = bs[(kb + 2 * tg + 1) * 136 + cn];
                    b1a = bs[(kb + 8 + 2 * tg) * 136 + cn];
                    b1b = bs[(kb + 9 + 2 * tg) * 136 + cn];
                    if (DSCALE) {
                        b0a *= dv[kb + 2 * tg];
                        b0b *= dv[kb + 2 * tg + 1];
                        b1a *= dv[kb + 8 + 2 * tg];
                        b1b *= dv[kb + 9 + 2 * tg];
                    }
                }
                bh[ni][0] = packbf(b0a, b0b);
                bh[ni][1] = packbf(b1a, b1b);
                bl[ni][0] = packbf_res(b0a, b0b, bh[ni][0]);
                bl[ni][1] = packbf_res(b1a, b1b, bh[ni][1]);
            }
#pragma unroll
            for (int mi = 0; mi < 4; mi++)
#pragma unroll
                for (int ni = 0; ni < 4; ni++) {
                    MMA_BF16(c[mi][ni], ah[mi], bh[ni]);
                    MMA_BF16(c[mi][ni], ah[mi], bl[ni]);
                    if (ASPLIT) MMA_BF16(c[mi][ni], al[mi], bh[ni]);
                }
        }
        __syncthreads();
        s ^= 1;
    }

#pragma unroll
    for (int mi = 0; mi < 4; mi++) {
        int row0 = bm + wm * 64 + mi * 16 + group;
#pragma unroll
        for (int ni = 0; ni < 4; ni++) {
            int col = bn + wn * 32 + ni * 8 + tg * 2;
            *(float2*)(C + (size_t)row0 * ldc + col)       = make_float2(c[mi][ni][0], c[mi][ni][1]);
            *(float2*)(C + (size_t)(row0 + 8) * ldc + col) = make_float2(c[mi][ni][2], c[mi][ni][3]);
        }
    }
}

// ---------------- generic SGEMM (small K paths), zero-pads cols [N, npad) ------------
__global__ void __launch_bounds__(256) gemm64(
    const float* __restrict__ A, const float* __restrict__ B, float* __restrict__ C,
    int M, int N, int K, int lda, int ldb, int ldc, int npad)
{
    __shared__ float As[16][65];
    __shared__ float Bs[16][64];
    int tid = threadIdx.x, tx = tid & 15, ty = tid >> 4;
    int bm = blockIdx.y * 64, bn = blockIdx.x * 64;
    float acc[4][4];
#pragma unroll
    for (int i = 0; i < 4; i++)
#pragma unroll
        for (int j = 0; j < 4; j++) acc[i][j] = 0.f;

    for (int k0 = 0; k0 < K; k0 += 16) {
        for (int t = tid; t < 64 * 16; t += 256) {
            int r = t >> 4, c = t & 15;
            int gr = bm + r, gc = k0 + c;
            As[c][r] = (gr < M && gc < K) ? A[(size_t)gr * lda + gc] : 0.f;
        }
        for (int t = tid; t < 16 * 64; t += 256) {
            int r = t >> 6, c = t & 63;
            int gr = k0 + r, gc = bn + c;
            Bs[r][c] = (gr < K && gc < N) ? B[(size_t)gr * ldb + gc] : 0.f;
        }
        __syncthreads();
#pragma unroll
        for (int kk = 0; kk < 16; kk++) {
            float a[4], b[4];
#pragma unroll
            for (int i = 0; i < 4; i++) a[i] = As[kk][ty * 4 + i];
#pragma unroll
            for (int j = 0; j < 4; j++) b[j] = Bs[kk][tx * 4 + j];
#pragma unroll
            for (int i = 0; i < 4; i++)
#pragma unroll
                for (int j = 0; j < 4; j++) acc[i][j] += a[i] * b[j];
        }
        __syncthreads();
    }
#pragma unroll
    for (int i = 0; i < 4; i++)
#pragma unroll
        for (int j = 0; j < 4; j++) {
            int gr = bm + ty * 4 + i, gc = bn + tx * 4 + j;
            if (gr < M && gc < npad) C[(size_t)gr * ldc + gc] = (gc < N) ? acc[i][j] : 0.f;
        }
}

// ---------------- small helper kernels ----------------
__global__ void pad_w5(const float* __restrict__ a, const float* __restrict__ b,
                       const float* __restrict__ c, const float* __restrict__ d,
                       const float* __restrict__ e, float* __restrict__ out)
{
    int idx = blockIdx.x * 256 + threadIdx.x;
    if (idx >= 5 * HP * HP) return;
    int w = idx / (HP * HP), r = idx - w * (HP * HP);
    int i = r >> 8, j = r & 255;
    const float* W = (w == 0) ? a : (w == 1) ? b : (w == 2) ? c : (w == 3) ? d : e;
    out[idx] = (i < H && j < H) ? W[i * H + j] : 0.f;
}

__global__ void f32tobf16(const float* __restrict__ in, __nv_bfloat16* __restrict__ out,
                          size_t n4)
{
    size_t i = (size_t)blockIdx.x * 256 + threadIdx.x;
    if (i >= n4) return;
    float4 v = *(const float4*)(in + i * 4);
    __nv_bfloat162 a = __floats2bfloat162_rn(v.x, v.y);
    __nv_bfloat162 b = __floats2bfloat162_rn(v.z, v.w);
    *(__nv_bfloat162*)(out + i * 4)     = a;
    *(__nv_bfloat162*)(out + i * 4 + 2) = b;
}

__global__ void rowgather_b2b(const __nv_bfloat16* __restrict__ A, int n,
                              const int* __restrict__ perm,
                              __nv_bfloat16* __restrict__ out, int krows)
{
    size_t idx = (size_t)blockIdx.x * 256 + threadIdx.x;
    size_t n8 = (size_t)n / 8;
    if (idx >= (size_t)krows * n8) return;
    int i = (int)(idx / n8);
    int j8 = (int)(idx - (size_t)i * n8);
    uint4 v = *(const uint4*)(A + (size_t)perm[i] * n + j8 * 8);
    *(uint4*)(out + (size_t)i * n + j8 * 8) = v;
}

__global__ void rowgather_f32(const float* __restrict__ A, int n,
                              const int* __restrict__ perm,
                              float* __restrict__ out, int krows)
{
    size_t idx = (size_t)blockIdx.x * 256 + threadIdx.x;
    size_t n4 = (size_t)n / 4;
    if (idx >= (size_t)krows * n4) return;
    int i = (int)(idx / n4);
    int j4 = (int)(idx - (size_t)i * n4);
    float4 v = *(const float4*)(A + (size_t)perm[i] * n + j4 * 4);
    *(float4*)(out + (size_t)i * n + j4 * 4) = v;
}

__global__ void rowsum_dinv(const float* __restrict__ A, float* __restrict__ dinv, int n)
{
    int row = blockIdx.x;
    const float* Ar = A + (size_t)row * n;
    float s = 0.f;
    for (int j = threadIdx.x; j < n; j += 256) s += Ar[j];
    for (int o = 16; o > 0; o >>= 1) s += __shfl_down_sync(0xffffffffu, s, o);
    __shared__ float red[8];
    int w = threadIdx.x >> 5, l = threadIdx.x & 31;
    if (l == 0) red[w] = s;
    __syncthreads();
    if (threadIdx.x == 0) {
        float t = 0.f;
        for (int i = 0; i < 8; i++) t += red[i];
        dinv[row] = 1.0f / sqrtf(t + 2.0f);
    }
}

__global__ void rowsum_dinv_bf(const __nv_bfloat16* __restrict__ A, float* __restrict__ dinv, int n)
{
    int row = blockIdx.x;
    const __nv_bfloat16* Ar = A + (size_t)row * n;
    float s = 0.f;
    for (int j = threadIdx.x * 2; j < n; j += 512) {
        __nv_bfloat162 v = *(const __nv_bfloat162*)(Ar + j);
        s += __bfloat162float(v.x) + __bfloat162float(v.y);
    }
    for (int o = 16; o > 0; o >>= 1) s += __shfl_down_sync(0xffffffffu, s, o);
    __shared__ float red[8];
    int w = threadIdx.x >> 5, l = threadIdx.x & 31;
    if (l == 0) red[w] = s;
    __syncthreads();
    if (threadIdx.x == 0) {
        float t = 0.f;
        for (int i = 0; i < 8; i++) t += red[i];
        dinv[row] = 1.0f / sqrtf(t + 2.0f);
    }
}

__global__ void scale_rows(const float* __restrict__ in, const float* __restrict__ dinv,
                           float* __restrict__ out, int n, int w, int ld)
{
    int idx = blockIdx.x * 256 + threadIdx.x;
    if (idx >= n * ld) return;
    int r = idx / ld, c = idx - r * ld;
    out[idx] = (c < w) ? dinv[r] * in[idx] : 0.f;
}

__global__ void gcn_finish_sk(const float* __restrict__ part, const float* __restrict__ Z,
                              const float* __restrict__ dinv, const float* __restrict__ b,
                              float* __restrict__ out, int n, int relu, int S)
{
    int idx = blockIdx.x * 256 + threadIdx.x;
    if (idx >= n * HP) return;
    int r = idx >> 8, c = idx & 255;
    float v = 0.f;
    if (c < H) {
        float az = 0.f;
        size_t stride = (size_t)n * HP;
        for (int s = 0; s < S; s++) az += part[s * stride + idx];
        float dr = dinv[r];
        v = dr * (az + 2.f * (dr * Z[idx])) + b[c];
        if (relu) v = fmaxf(v, 0.f);
    }
    out[idx] = v;
}

__global__ void score_kernel(const float* __restrict__ x, const float* __restrict__ p,
                             float* __restrict__ score, int n)
{
    int row = blockIdx.x * 8 + (threadIdx.x >> 5);
    int lane = threadIdx.x & 31;
    if (row >= n) return;
    const float* xr = x + (size_t)row * HP;
    float s = 0.f, pp = 0.f;
    for (int c = lane; c < H; c += 32) {
        float pv = p[c];
        s += xr[c] * pv;
        pp += pv * pv;
    }
    for (int o = 16; o > 0; o >>= 1) {
        s  += __shfl_down_sync(0xffffffffu, s, o);
        pp += __shfl_down_sync(0xffffffffu, pp, o);
    }
    if (lane == 0) score[row] = tanhf(s / sqrtf(pp));
}

template <int SIZE>
__global__ void topk_kernel(const float* __restrict__ score, int n, int k,
                            int* __restrict__ perm, float* __restrict__ val,
                            int* __restrict__ iperm)
{
    __shared__ unsigned long long key[SIZE];
    int tid = threadIdx.x;
    for (int i = tid; i < SIZE; i += 1024) {
        float s = (i < n) ? score[i] : -INFINITY;
        uint32_t u = __float_as_uint(s);
        u = (u & 0x80000000u) ? ~u : (u | 0x80000000u);
        uint32_t d = ~u;
        key[i] = ((unsigned long long)d << 32) | (uint32_t)i;
        if (i < n) iperm[i] = -1;
    }
    __syncthreads();
    for (int size = 2; size <= SIZE; size <<= 1) {
        for (int stride = size >> 1; stride > 0; stride >>= 1) {
            for (int i = tid; i < SIZE; i += 1024) {
                int j = i ^ stride;
                if (j > i) {
                    unsigned long long a = key[i], b = key[j];
                    bool up = ((i & size) == 0);
                    if (up ? (a > b) : (a < b)) { key[i] = b; key[j] = a; }
                }
            }
            __syncthreads();
        }
    }
    for (int i = tid; i < k; i += 1024) {
        int si = (int)(uint32_t)key[i];
        perm[i] = si;
        val[i] = score[si];
        iperm[si] = i;
    }
}

// level 1: out bf16 (exact small ints)
__global__ void pool_A_tri_bf(const float* __restrict__ C, const __nv_bfloat16* __restrict__ Rows,
                              int K, const int* __restrict__ perm,
                              __nv_bfloat16* __restrict__ Aout, int k)
{
    int idx = blockIdx.x * 256 + threadIdx.x;
    if (idx >= k * k) return;
    int i = idx / k, j = idx - i * k;
    if (i == j) { Aout[idx] = __float2bfloat16(0.f); return; }
    int hi = i > j ? i : j, lo = i > j ? j : i;
    float g = C[(size_t)hi * k + lo];
    float a = __bfloat162float(Rows[(size_t)i * K + __ldg(&perm[j])]);
    Aout[idx] = __float2bfloat16(g + 2.f * a);
}

// level 2: out fp32
__global__ void pool_A_tri(const float* __restrict__ C, const __nv_bfloat16* __restrict__ Rows,
                           int K, const int* __restrict__ perm,
                           float* __restrict__ Aout, int k)
{
    int idx = blockIdx.x * 256 + threadIdx.x;
    if (idx >= k * k) return;
    int i = idx / k, j = idx - i * k;
    if (i == j) { Aout[idx] = 0.f; return; }
    int hi = i > j ? i : j, lo = i > j ? j : i;
    float g = C[(size_t)hi * k + lo];
    float a = __bfloat162float(Rows[(size_t)i * K + __ldg(&perm[j])]);
    Aout[idx] = g + 2.f * a;
}

__global__ void pool_A_tri_f32(const float* __restrict__ C, const float* __restrict__ Rows,
                               int K, const int* __restrict__ perm,
                               float* __restrict__ Aout, int k)
{
    int idx = blockIdx.x * 256 + threadIdx.x;
    if (idx >= k * k) return;
    int i = idx / k, j = idx - i * k;
    if (i == j) { Aout[idx] = 0.f; return; }
    int hi = i > j ? i : j, lo = i > j ? j : i;
    Aout[idx] = C[(size_t)hi * k + lo] + 2.f * Rows[(size_t)i * K + __ldg(&perm[j])];
}

__global__ void pool_x(const float* __restrict__ xin, const int* __restrict__ perm,
                       const float* __restrict__ val, float* __restrict__ xout, int k)
{
    int idx = blockIdx.x * 256 + threadIdx.x;
    if (idx >= k * HP) return;
    int r = idx >> 8, c = idx & 255;
    xout[idx] = xin[(size_t)perm[r] * HP + c] * val[r];
}

__global__ void fuse_up(const float* __restrict__ Xj, const float* __restrict__ Xn,
                        const int* __restrict__ iperm, float* __restrict__ out, int n)
{
    int idx = blockIdx.x * 256 + threadIdx.x;
    if (idx >= n * HP) return;
    int r = idx >> 8, c = idx & 255;
    int p = iperm[r];
    float v = Xj[idx];
    if (p >= 0) v += Xn[p * HP + c];
    out[idx] = v;
}

__global__ void gemm_n2(const float* __restrict__ A, const float* __restrict__ Z,
                        float* __restrict__ out, int n)
{
    int row = blockIdx.x;
    const float* Ar = A + (size_t)row * n;
    float a0 = 0.f, a1 = 0.f;
    for (int j = threadIdx.x; j < n; j += 256) {
        float a = Ar[j];
        a0 += a * Z[2 * j];
        a1 += a * Z[2 * j + 1];
    }
    for (int o = 16; o > 0; o >>= 1) {
        a0 += __shfl_down_sync(0xffffffffu, a0, o);
        a1 += __shfl_down_sync(0xffffffffu, a1, o);
    }
    __shared__ float r0[8], r1[8];
    int w = threadIdx.x >> 5, l = threadIdx.x & 31;
    if (l == 0) { r0[w] = a0; r1[w] = a1; }
    __syncthreads();
    if (threadIdx.x == 0) {
        float s0 = 0.f, s1 = 0.f;
        for (int i = 0; i < 8; i++) { s0 += r0[i]; s1 += r1[i]; }
        out[2 * row] = s0;
        out[2 * row + 1] = s1;
    }
}

__global__ void final_kernel(const float* __restrict__ AZ, const float* __restrict__ Z,
                             const float* __restrict__ dinv, const float* __restrict__ b,
                             float* __restrict__ out, int n)
{
    int i = blockIdx.x * 256 + threadIdx.x;
    if (i >= n) return;
    float a = dinv[i] * (AZ[2 * i]     + 2.f * Z[2 * i])     + b[0];
    float c = dinv[i] * (AZ[2 * i + 1] + 2.f * Z[2 * i + 1]) + b[1];
    float m = fmaxf(a, c);
    float l = m + logf(expf(a - m) + expf(c - m));
    out[2 * i] = a - l;
    out[2 * i + 1] = c - l;
}

// ---------------- host orchestration ----------------
template <typename T, size_t NN>
static T* symaddr(T (&sym)[NN]) {
    void* p = nullptr;
    cudaGetSymbolAddress(&p, sym);
    return (T*)p;
}

#define SMEM_BF 73984
#define SMEM_BA 55552

extern "C" void kernel_launch(void* const* d_in, const int* in_sizes, int n_in,
                              void* d_out, int out_size)
{
    (void)in_sizes; (void)n_in; (void)out_size;
    const float* x   = (const float*)d_in[0];
    const float* adj = (const float*)d_in[1];
    const float* w0  = (const float*)d_in[2];
    const float* b0  = (const float*)d_in[3];
    const float* w1  = (const float*)d_in[4];
    const float* b1  = (const float*)d_in[5];
    const float* w2  = (const float*)d_in[6];
    const float* b2  = (const float*)d_in[7];
    const float* w3  = (const float*)d_in[8];
    const float* b3  = (const float*)d_in[9];
    const float* p1  = (const float*)d_in[10];
    const float* p2  = (const float*)d_in[11];
    const float* p3  = (const float*)d_in[12];
    const float* u0w = (const float*)d_in[13];
    const float* u0b = (const float*)d_in[14];
    const float* u1w = (const float*)d_in[15];
    const float* u1b = (const float*)d_in[16];
    const float* u2w = (const float*)d_in[17];
    const float* u2b = (const float*)d_in[18];

    static cudaStream_t sA = nullptr;
    static cudaEvent_t evF = nullptr, evA = nullptr, evB = nullptr;
    static bool init_done = false;
    if (!init_done) {
        cudaFuncSetAttribute(bf16gA, cudaFuncAttributeMaxDynamicSharedMemorySize, SMEM_BA);
        cudaFuncSetAttribute(bf16g<1, 0, 1>, cudaFuncAttributeMaxDynamicSharedMemorySize, SMEM_BF);
        cudaFuncSetAttribute(bf16g<1, 0, 0>, cudaFuncAttributeMaxDynamicSharedMemorySize, SMEM_BF);
        cudaFuncSetAttribute(bf16g<1, 1, 0>, cudaFuncAttributeMaxDynamicSharedMemorySize, SMEM_BF);
        cudaStreamCreateWithFlags(&sA, cudaStreamNonBlocking);
        cudaEventCreateWithFlags(&evF, cudaEventDisableTiming);
        cudaEventCreateWithFlags(&evA, cudaEventDisableTiming);
        cudaEventCreateWithFlags(&evB, cudaEventDisableTiming);
        init_done = true;
    }

    float* G    = symaddr(g_G);
    __nv_bfloat16* ADJB = symaddr(g_adjb);
    __nv_bfloat16* ROWS = symaddr(g_rows);
    __nv_bfloat16* A1B  = symaddr(g_A1b);
    float* A2   = symaddr(g_A2);
    float* A3   = symaddr(g_A3);
    float* X0   = symaddr(g_x0);
    float* X1   = symaddr(g_x1);
    float* X2   = symaddr(g_x2);
    float* X3   = symaddr(g_x3);
    float* T0   = symaddr(g_t0);
    float* T1   = symaddr(g_t1);
    float* PART = symaddr(g_part);
    float* CUR  = symaddr(g_cur);
    float* WP   = symaddr(g_wpad);
    float* D0   = symaddr(g_d0);
    float* D1   = symaddr(g_d1);
    float* D2   = symaddr(g_d2);
    float* D3   = symaddr(g_d3);
    float* SC   = symaddr(g_score);
    float* VAL  = symaddr(g_val);
    int*   P0   = symaddr(g_perm0);
    int*   P1   = symaddr(g_perm1);
    int*   P2   = symaddr(g_perm2);
    int*   IP0  = symaddr(g_ip0);
    int*   IP1  = symaddr(g_ip1);
    int*   IP2  = symaddr(g_ip2);

    float* WP_w1  = WP + 0 * HP * HP;
    float* WP_w2  = WP + 1 * HP * HP;
    float* WP_w3  = WP + 2 * HP * HP;
    float* WP_u0w = WP + 3 * HP * HP;
    float* WP_u1w = WP + 4 * HP * HP;

    // ---- fork side stream INTO the capture first (required for graph capture),
    //      then run adj->bf16 there, hidden under gcn0 prologue ----
    cudaEventRecord(evF, 0);
    cudaStreamWaitEvent(sA, evF, 0);
    {
        size_t n4 = ((size_t)N0 * N0) / 4;
        f32tobf16<<<(unsigned)((n4 + 255) / 256), 256, 0, sA>>>(adj, ADJB, n4);
        cudaEventRecord(evB, sA);
    }
    pad_w5<<<(5 * HP * HP + 255) / 256, 256>>>(w1, w2, w3, u0w, u1w, WP);
    rowsum_dinv<<<N0, 256>>>(adj, D0, N0);

    // ---- gcn0 ----
    {
        dim3 g1((H + 63) / 64, (N0 + 63) / 64);
        gemm64<<<g1, 256>>>(x, w0, T0, N0, H, 3, 3, H, HP, HP);
        cudaStreamWaitEvent(0, evB, 0);
        dim3 g2(HP / 128, N0 / 128, 4);
        bf16gA<<<g2, 256, SMEM_BA>>>(ADJB, T0, PART, N0, HP, N0, N0, HP, HP, D0);
        gcn_finish_sk<<<(N0 * HP + 255) / 256, 256>>>(PART, T0, D0, b0, X0, N0, 1, 4);
    }

    // ==== pool 1 (4096 -> 3072) ====
    score_kernel<<<(N0 + 7) / 8, 256>>>(X0, p1, SC, N0);
    topk_kernel<4096><<<1, 1024>>>(SC, N0, KP1, P0, VAL, IP0);
    cudaEventRecord(evF, 0);
    cudaStreamWaitEvent(sA, evF, 0);
    {
        size_t tot = (size_t)KP1 * (N0 / 8);
        rowgather_b2b<<<(unsigned)((tot + 255) / 256), 256, 0, sA>>>(ADJB, N0, P0, ROWS, KP1);
        dim3 g(KP1 / 128, KP1 / 128);
        bf16gemm_xxt<<<g, 256, 0, sA>>>(ROWS, G, KP1, N0);
        pool_A_tri_bf<<<(KP1 * KP1 + 255) / 256, 256, 0, sA>>>(G, ROWS, N0, P0, A1B, KP1);
        rowsum_dinv_bf<<<KP1, 256, 0, sA>>>(A1B, D1, KP1);
    }
    cudaEventRecord(evA, sA);
    pool_x<<<(KP1 * HP + 255) / 256, 256>>>(X0, P0, VAL, CUR, KP1);
    {
        dim3 gw(HP / 128, KP1 / 128, 1);
        bf16g<1, 0, 0><<<gw, 256, SMEM_BF>>>(CUR, WP_w1, T0, KP1, HP, HP, HP, HP, HP, nullptr);
    }
    cudaStreamWaitEvent(0, evA, 0);
    {
        dim3 g2(HP / 128, KP1 / 128, 6);
        bf16gA<<<g2, 256, SMEM_BA>>>(A1B, T0, PART, KP1, HP, KP1, KP1, HP, HP, D1);
        gcn_finish_sk<<<(KP1 * HP + 255) / 256, 256>>>(PART, T0, D1, b1, X1, KP1, 1, 6);
    }

    // ==== pool 2 (3072 -> 1536) ====
    score_kernel<<<(KP1 + 7) / 8, 256>>>(X1, p2, SC, KP1);
    topk_kernel<4096><<<1, 1024>>>(SC, KP1, KP2, P1, VAL, IP1);
    cudaEventRecord(evF, 0);
    cudaStreamWaitEvent(sA, evF, 0);
    {
        size_t tot = (size_t)KP2 * (KP1 / 8);
        rowgather_b2b<<<(unsigned)((tot + 255) / 256), 256, 0, sA>>>(A1B, KP1, P1, ROWS, KP2);
        dim3 g(KP2 / 128, KP2 / 128);
        bf16gemm_xxt<<<g, 256, 0, sA>>>(ROWS, G, KP2, KP1);
        pool_A_tri<<<(KP2 * KP2 + 255) / 256, 256, 0, sA>>>(G, ROWS, KP1, P1, A2, KP2);
        rowsum_dinv<<<KP2, 256, 0, sA>>>(A2, D2, KP2);
    }
    cudaEventRecord(evA, sA);
    pool_x<<<(KP2 * HP + 255) / 256, 256>>>(X1, P1, VAL, CUR, KP2);
    {
        dim3 gw(HP / 128, KP2 / 128, 1);
        bf16g<1, 0, 0><<<gw, 256, SMEM_BF>>>(CUR, WP_w2, T0, KP2, HP, HP, HP, HP, HP, nullptr);
    }
    cudaStreamWaitEvent(0, evA, 0);
    {
        dim3 g2(HP / 128, KP2 / 128, 6);
        bf16g<1, 0, 1><<<g2, 256, SMEM_BF>>>(A2, T0, PART, KP2, HP, KP2, KP2, HP, HP, D2);
        gcn_finish_sk<<<(KP2 * HP + 255) / 256, 256>>>(PART, T0, D2, b2, X2, KP2, 1, 6);
    }

    // ==== pool 3 (1536 -> 768) ====
    score_kernel<<<(KP2 + 7) / 8, 256>>>(X2, p3, SC, KP2);
    topk_kernel<2048><<<1, 1024>>>(SC, KP2, KP3, P2, VAL, IP2);
    cudaEventRecord(evF, 0);
    cudaStreamWaitEvent(sA, evF, 0);
    {
        size_t tot = (size_t)KP3 * (KP2 / 4);
        rowgather_f32<<<(unsigned)((tot + 255) / 256), 256, 0, sA>>>(A2, KP2, P2, PART, KP3);
        dim3 g(KP3 / 128, KP3 / 128, 1);
        bf16g<1, 1, 0><<<g, 256, SMEM_BF, sA>>>(PART, PART, G, KP3, KP3, KP2, KP2, KP2, KP3, nullptr);
        pool_A_tri_f32<<<(KP3 * KP3 + 255) / 256, 256, 0, sA>>>(G, PART, KP2, P2, A3, KP3);
        rowsum_dinv<<<KP3, 256, 0, sA>>>(A3, D3, KP3);
    }
    cudaEventRecord(evA, sA);
    pool_x<<<(KP3 * HP + 255) / 256, 256>>>(X2, P2, VAL, CUR, KP3);
    {
        dim3 gw(HP / 128, KP3 / 128, 1);
        bf16g<1, 0, 0><<<gw, 256, SMEM_BF>>>(CUR, WP_w3, T0, KP3, HP, HP, HP, HP, HP, nullptr);
    }
    cudaStreamWaitEvent(0, evA, 0);
    {
        dim3 g2(HP / 128, KP3 / 128, 12);
        bf16g<1, 0, 1><<<g2, 256, SMEM_BF>>>(A3, T0, PART, KP3, HP, KP3, KP3, HP, HP, D3);
        gcn_finish_sk<<<(KP3 * HP + 255) / 256, 256>>>(PART, T0, D3, b3, X3, KP3, 1, 12);
    }

    // ==== up 0 ====
    fuse_up<<<(KP2 * HP + 255) / 256, 256>>>(X2, X3, IP2, CUR, KP2);
    {
        dim3 gw(HP / 128, KP2 / 128, 1);
        bf16g<1, 0, 0><<<gw, 256, SMEM_BF>>>(CUR, WP_u0w, T0, KP2, HP, HP, HP, HP, HP, nullptr);
        dim3 g2(HP / 128, KP2 / 128, 6);
        bf16g<1, 0, 1><<<g2, 256, SMEM_BF>>>(A2, T0, PART, KP2, HP, KP2, KP2, HP, HP, D2);
        gcn_finish_sk<<<(KP2 * HP + 255) / 256, 256>>>(PART, T0, D2, u0b, X2, KP2, 1, 6);
    }

    // ==== up 1 ====
    fuse_up<<<(KP1 * HP + 255) / 256, 256>>>(X1, X2, IP1, CUR, KP1);
    {
        dim3 gw(HP / 128, KP1 / 128, 1);
        bf16g<1, 0, 0><<<gw, 256, SMEM_BF>>>(CUR, WP_u1w, T0, KP1, HP, HP, HP, HP, HP, nullptr);
        dim3 g2(HP / 128, KP1 / 128, 6);
        bf16gA<<<g2, 256, SMEM_BA>>>(A1B, T0, PART, KP1, HP, KP1, KP1, HP, HP, D1);
        gcn_finish_sk<<<(KP1 * HP + 255) / 256, 256>>>(PART, T0, D1, u1b, X1, KP1, 1, 6);
    }

    // ==== up 2: final gcn (H->2) + log_softmax ====
    fuse_up<<<(N0 * HP + 255) / 256, 256>>>(X0, X1, IP0, CUR, N0);
    {
        dim3 gf(1, (N0 + 63) / 64);
        gemm64<<<gf, 256>>>(CUR, u2w, T0, N0, 2, H, HP, 2, 2, 2);
        scale_rows<<<(N0 * 2 + 255) / 256, 256>>>(T0, D0, T1, N0, 2, 2);
        gemm_n2<<<N0, 256>>>(adj, T1, T0, N0);
        final_kernel<<<(N0 + 255) / 256, 256>>>(T0, T1, D0, u2b, (float*)d_out, N0);
    }
}

// round 16
// speedup vs baseline: 8.1792x; 1.0005x over previous
#include <cuda_runtime.h>
#include <cuda_bf16.h>
#include <math.h>
#include <stdint.h>

#define N0 4096
#define KP1 3072
#define KP2 1536
#define KP3 768
#define H 200
#define HP 256
#define SKMAX 12

// ---------------- device scratch ----------------
__device__ float g_G[(size_t)N0 * N0];
__device__ __nv_bfloat16 g_adjb[(size_t)N0 * N0];
__device__ __nv_bfloat16 g_A1b[(size_t)KP1 * KP1];
__device__ float g_A2[(size_t)KP2 * KP2];
__device__ float g_A3[(size_t)KP3 * KP3];
__device__ float g_x0[N0 * HP];
__device__ float g_x1[KP1 * HP];
__device__ float g_x2[KP2 * HP];
__device__ float g_x3[KP3 * HP];
__device__ float g_t0[N0 * HP];
__device__ float g_t1[N0 * HP];
__device__ float g_part[(size_t)SKMAX * N0 * HP];
__device__ float g_cur[N0 * HP];
__device__ float g_wpad[5 * HP * HP];
__device__ float g_d0[N0];
__device__ float g_d1[KP1];
__device__ float g_d2[KP2];
__device__ float g_d3[KP3];
__device__ float g_score[N0];
__device__ float g_val[N0];
__device__ int   g_perm0[KP1];
__device__ int   g_perm1[KP2];
__device__ int   g_perm2[KP3];
__device__ int   g_ip0[N0];
__device__ int   g_ip1[KP1];
__device__ int   g_ip2[KP2];

__device__ __forceinline__ void cpa16(uint32_t dst, const void* src) {
    asm volatile("cp.async.cg.shared.global [%0], [%1], 16;\n" :: "r"(dst), "l"(src));
}
__device__ __forceinline__ uint32_t packbf(float x, float y) {
    __nv_bfloat162 h = __floats2bfloat162_rn(x, y);
    return *(uint32_t*)&h;
}
__device__ __forceinline__ uint32_t packbf_res(float x, float y, uint32_t hi) {
    __nv_bfloat162 h = *(__nv_bfloat162*)&hi;
    return packbf(x - __bfloat162float(h.x), y - __bfloat162float(h.y));
}

#define MMA_BF16(c, a, b)                                                         \
    asm volatile(                                                                 \
        "mma.sync.aligned.m16n8k16.row.col.f32.bf16.bf16.f32 "                    \
        "{%0,%1,%2,%3}, {%4,%5,%6,%7}, {%8,%9}, {%0,%1,%2,%3};\n"                 \
        : "+f"((c)[0]), "+f"((c)[1]), "+f"((c)[2]), "+f"((c)[3])                  \
        : "r"((a)[0]), "r"((a)[1]), "r"((a)[2]), "r"((a)[3]),                     \
          "r"((b)[0]), "r"((b)[1]))

// ============ bf16 gathered X·X^T GEMM: C = X[perm]·X[perm]^T, lower triangle ========
__global__ void __launch_bounds__(256) bf16gemm_xxt(
    const __nv_bfloat16* __restrict__ X, float* __restrict__ C, int k, int K,
    const int* __restrict__ perm)
{
    if (blockIdx.x > blockIdx.y) return;

    __shared__ __nv_bfloat16 As[2][128][40];
    __shared__ __nv_bfloat16 Bs[2][128][40];

    int t = threadIdx.x;
    int warp = t >> 5, lane = t & 31;
    int group = lane >> 2, tg = lane & 3;
    int wm = warp >> 2, wn = warp & 3;
    int bm = blockIdx.y * 128, bn = blockIdx.x * 128;

    float c[4][4][4];
#pragma unroll
    for (int mi = 0; mi < 4; mi++)
#pragma unroll
        for (int ni = 0; ni < 4; ni++)
#pragma unroll
            for (int r = 0; r < 4; r++) c[mi][ni][r] = 0.f;

    int lrow = t >> 1;
    int lcol0 = (t & 1) * 16;

    uint32_t aBase = (uint32_t)__cvta_generic_to_shared(&As[0][0][0]);
    uint32_t bBase = (uint32_t)__cvta_generic_to_shared(&Bs[0][0][0]);
    const uint32_t stageB = 128 * 40 * 2;
    uint32_t aDst = aBase + lrow * 80 + lcol0 * 2;
    uint32_t bDst = bBase + lrow * 80 + lcol0 * 2;

    const __nv_bfloat16* aSrcRow = X + (size_t)__ldg(&perm[bm + lrow]) * K + lcol0;
    const __nv_bfloat16* bSrcRow = X + (size_t)__ldg(&perm[bn + lrow]) * K + lcol0;

#define LOAD_STAGE(st, k0)                                        \
    do {                                                          \
        const __nv_bfloat16* ap = aSrcRow + (k0);                 \
        const __nv_bfloat16* bp = bSrcRow + (k0);                 \
        uint32_t ad = aDst + (st) * stageB;                       \
        uint32_t bd = bDst + (st) * stageB;                       \
        cpa16(ad, ap); cpa16(ad + 16, ap + 8);                    \
        cpa16(bd, bp); cpa16(bd + 16, bp + 8);                    \
    } while (0)

    LOAD_STAGE(0, 0);
    asm volatile("cp.async.commit_group;\n");

    int s = 0;
    for (int k0 = 0; k0 < K; k0 += 32) {
        if (k0 + 32 < K) {
            LOAD_STAGE(s ^ 1, k0 + 32);
            asm volatile("cp.async.commit_group;\n");
            asm volatile("cp.async.wait_group 1;\n");
        } else {
            asm volatile("cp.async.wait_group 0;\n");
        }
        __syncthreads();

#pragma unroll
        for (int ks = 0; ks < 2; ks++) {
            int kb = ks * 16;
            uint32_t af[4][4], bf[4][2];
#pragma unroll
            for (int mi = 0; mi < 4; mi++) {
                int rm = wm * 64 + mi * 16 + group;
                af[mi][0] = *(const uint32_t*)&As[s][rm][kb + 2 * tg];
                af[mi][1] = *(const uint32_t*)&As[s][rm + 8][kb + 2 * tg];
                af[mi][2] = *(const uint32_t*)&As[s][rm][kb + 2 * tg + 8];
                af[mi][3] = *(const uint32_t*)&As[s][rm + 8][kb + 2 * tg + 8];
            }
#pragma unroll
            for (int ni = 0; ni < 4; ni++) {
                int cn = wn * 32 + ni * 8 + group;
                bf[ni][0] = *(const uint32_t*)&Bs[s][cn][kb + 2 * tg];
                bf[ni][1] = *(const uint32_t*)&Bs[s][cn][kb + 2 * tg + 8];
            }
#pragma unroll
            for (int mi = 0; mi < 4; mi++)
#pragma unroll
                for (int ni = 0; ni < 4; ni++)
                    MMA_BF16(c[mi][ni], af[mi], bf[ni]);
        }
        __syncthreads();
        s ^= 1;
    }
#undef LOAD_STAGE

#pragma unroll
    for (int mi = 0; mi < 4; mi++) {
        int row0 = bm + wm * 64 + mi * 16 + group;
#pragma unroll
        for (int ni = 0; ni < 4; ni++) {
            int col = bn + wn * 32 + ni * 8 + tg * 2;
            *(float2*)(C + (size_t)row0 * k + col)       = make_float2(c[mi][ni][0], c[mi][ni][1]);
            *(float2*)(C + (size_t)(row0 + 8) * k + col) = make_float2(c[mi][ni][2], c[mi][ni][3]);
        }
    }
}

// ============ prop GEMM: A bf16 (exact), B fp32 hi/lo split, fused dinv scale ========
__global__ void __launch_bounds__(256, 2) bf16gA(
    const __nv_bfloat16* __restrict__ A, const float* __restrict__ B, float* __restrict__ Cpart,
    int M, int N, int K, int lda, int ldb, int ldc, const float* __restrict__ dinv)
{
    extern __shared__ char smc[];
    __nv_bfloat16* asb = (__nv_bfloat16*)smc;
    float* bsf = (float*)(smc + 2 * 128 * 40 * 2);
    float* dvb = bsf + 2 * 32 * 136;

    int t = threadIdx.x;
    int warp = t >> 5, lane = t & 31;
    int group = lane >> 2, tg = lane & 3;
    int wm = warp >> 2, wn = warp & 3;
    int bm = blockIdx.y * 128, bn = blockIdx.x * 128;
    int kChunk = K / gridDim.z;
    int kStart = blockIdx.z * kChunk;
    float* C = Cpart + (size_t)blockIdx.z * M * ldc;

    float c[4][4][4];
#pragma unroll
    for (int mi = 0; mi < 4; mi++)
#pragma unroll
        for (int ni = 0; ni < 4; ni++)
#pragma unroll
            for (int r = 0; r < 4; r++) c[mi][ni][r] = 0.f;

    auto LOADST = [&](int st, int k0) {
        __nv_bfloat16* as = asb + st * (128 * 40);
        float* bs = bsf + st * (32 * 136);
#pragma unroll
        for (int q = 0; q < 2; q++) {
            int idx = t + q * 256;
            int row = idx >> 2, seg = idx & 3;
            uint32_t ad = (uint32_t)__cvta_generic_to_shared(as + row * 40 + seg * 8);
            cpa16(ad, A + (size_t)(bm + row) * lda + kStart + k0 + seg * 8);
        }
#pragma unroll
        for (int q = 0; q < 4; q++) {
            int cc = t + q * 256;
            int r = cc >> 5, nc = cc & 31;
            uint32_t bd = (uint32_t)__cvta_generic_to_shared(bs + r * 136 + nc * 4);
            cpa16(bd, B + (size_t)(kStart + k0 + r) * ldb + bn + nc * 4);
        }
        if (t < 8) {
            uint32_t dd = (uint32_t)__cvta_generic_to_shared(dvb + st * 32 + t * 4);
            cpa16(dd, dinv + kStart + k0 + t * 4);
        }
        asm volatile("cp.async.commit_group;\n");
    };

    LOADST(0, 0);

    int s = 0;
    for (int k0 = 0; k0 < kChunk; k0 += 32) {
        if (k0 + 32 < kChunk) {
            LOADST(s ^ 1, k0 + 32);
            asm volatile("cp.async.wait_group 1;\n");
        } else {
            asm volatile("cp.async.wait_group 0;\n");
        }
        __syncthreads();

        const __nv_bfloat16* as = asb + s * (128 * 40);
        const float* bs = bsf + s * (32 * 136);
        const float* dv = dvb + s * 32;

#pragma unroll
        for (int ks = 0; ks < 2; ks++) {
            int kb = ks * 16;
            uint32_t af[4][4], bh[4][2], bl[4][2];
#pragma unroll
            for (int mi = 0; mi < 4; mi++) {
                int rm = wm * 64 + mi * 16 + group;
                af[mi][0] = *(const uint32_t*)&as[rm * 40 + kb + 2 * tg];
                af[mi][1] = *(const uint32_t*)&as[(rm + 8) * 40 + kb + 2 * tg];
                af[mi][2] = *(const uint32_t*)&as[rm * 40 + kb + 2 * tg + 8];
                af[mi][3] = *(const uint32_t*)&as[(rm + 8) * 40 + kb + 2 * tg + 8];
            }
#pragma unroll
            for (int ni = 0; ni < 4; ni++) {
                int cn = wn * 32 + ni * 8 + group;
                float b0a = bs[(kb + 2 * tg) * 136 + cn]     * dv[kb + 2 * tg];
                float b0b = bs[(kb + 2 * tg + 1) * 136 + cn] * dv[kb + 2 * tg + 1];
                float b1a = bs[(kb + 8 + 2 * tg) * 136 + cn] * dv[kb + 8 + 2 * tg];
                float b1b = bs[(kb + 9 + 2 * tg) * 136 + cn] * dv[kb + 9 + 2 * tg];
                bh[ni][0] = packbf(b0a, b0b);
                bh[ni][1] = packbf(b1a, b1b);
                bl[ni][0] = packbf_res(b0a, b0b, bh[ni][0]);
                bl[ni][1] = packbf_res(b1a, b1b, bh[ni][1]);
            }
#pragma unroll
            for (int mi = 0; mi < 4; mi++)
#pragma unroll
                for (int ni = 0; ni < 4; ni++) {
                    MMA_BF16(c[mi][ni], af[mi], bh[ni]);
                    MMA_BF16(c[mi][ni], af[mi], bl[ni]);
                }
        }
        __syncthreads();
        s ^= 1;
    }

#pragma unroll
    for (int mi = 0; mi < 4; mi++) {
        int row0 = bm + wm * 64 + mi * 16 + group;
#pragma unroll
        for (int ni = 0; ni < 4; ni++) {
            int col = bn + wn * 32 + ni * 8 + tg * 2;
            *(float2*)(C + (size_t)row0 * ldc + col)       = make_float2(c[mi][ni][0], c[mi][ni][1]);
            *(float2*)(C + (size_t)(row0 + 8) * ldc + col) = make_float2(c[mi][ni][2], c[mi][ni][3]);
        }
    }
}

// ============ bf16-split GEMM from fp32 inputs ======================================
// AMODE=0: plain A. AMODE=1: A row m = src row pidx[bm+m], scaled by pval[bm+m]
// (fused TopK pool_x: xout = X[perm]*val). Other params as before.
template <int ASPLIT, int XXT, int DSCALE, int AMODE>
__global__ void __launch_bounds__(256, (ASPLIT ? 1 : 2)) bf16g(
    const float* __restrict__ A, const float* __restrict__ B, float* __restrict__ Cpart,
    int M, int N, int K, int lda, int ldb, int ldc, const float* __restrict__ dinv,
    const int* __restrict__ pidx, const float* __restrict__ pval)
{
    if (XXT && (int)blockIdx.x > (int)blockIdx.y) return;
    extern __shared__ float smd[];
    const int STAGEF = 9216;
    const int BOFF = 128 * 36;
    float* dvbase = smd + 2 * STAGEF;

    int t = threadIdx.x;
    int warp = t >> 5, lane = t & 31;
    int group = lane >> 2, tg = lane & 3;
    int wm = warp >> 2, wn = warp & 3;
    int bm = blockIdx.y * 128, bn = blockIdx.x * 128;
    int kChunk = K / gridDim.z;
    int kStart = blockIdx.z * kChunk;
    float* C = Cpart + (size_t)blockIdx.z * M * ldc;

    float c[4][4][4];
#pragma unroll
    for (int mi = 0; mi < 4; mi++)
#pragma unroll
        for (int ni = 0; ni < 4; ni++)
#pragma unroll
            for (int r = 0; r < 4; r++) c[mi][ni][r] = 0.f;

    // per-thread A-row scales (k-invariant), AMODE=1 only
    float av0[4], av1[4];
    if (AMODE == 1) {
#pragma unroll
        for (int mi = 0; mi < 4; mi++) {
            int rm = wm * 64 + mi * 16 + group;
            av0[mi] = __ldg(&pval[bm + rm]);
            av1[mi] = __ldg(&pval[bm + rm + 8]);
        }
    }

    auto LOADST = [&](int st, int k0) {
        float* as = smd + st * STAGEF;
        float* bs = as + BOFF;
#pragma unroll
        for (int q = 0; q < 4; q++) {
            int cc = t + q * 256;
            int m = cc >> 3, kc = cc & 7;
            uint32_t ad = (uint32_t)__cvta_generic_to_shared(as + m * 36 + kc * 4);
            size_t srow = (AMODE == 1) ? (size_t)__ldg(&pidx[bm + m]) : (size_t)(bm + m);
            cpa16(ad, A + srow * lda + kStart + k0 + kc * 4);
        }
        if (XXT) {
#pragma unroll
            for (int q = 0; q < 4; q++) {
                int cc = t + q * 256;
                int m = cc >> 3, kc = cc & 7;
                uint32_t bd = (uint32_t)__cvta_generic_to_shared(bs + m * 36 + kc * 4);
                cpa16(bd, B + (size_t)(bn + m) * ldb + kStart + k0 + kc * 4);
            }
        } else {
#pragma unroll
            for (int q = 0; q < 4; q++) {
                int cc = t + q * 256;
                int r = cc >> 5, nc = cc & 31;
                uint32_t bd = (uint32_t)__cvta_generic_to_shared(bs + r * 136 + nc * 4);
                cpa16(bd, B + (size_t)(kStart + k0 + r) * ldb + bn + nc * 4);
            }
            if (DSCALE && t < 8) {
                uint32_t dd = (uint32_t)__cvta_generic_to_shared(dvbase + st * 32 + t * 4);
                cpa16(dd, dinv + kStart + k0 + t * 4);
            }
        }
        asm volatile("cp.async.commit_group;\n");
    };

    LOADST(0, 0);

    int s = 0;
    for (int k0 = 0; k0 < kChunk; k0 += 32) {
        if (k0 + 32 < kChunk) {
            LOADST(s ^ 1, k0 + 32);
            asm volatile("cp.async.wait_group 1;\n");
        } else {
            asm volatile("cp.async.wait_group 0;\n");
        }
        __syncthreads();

        const float* as = smd + s * STAGEF;
        const float* bs = as + BOFF;
        const float* dv = dvbase + s * 32;

#pragma unroll
        for (int ks = 0; ks < 2; ks++) {
            int kb = ks * 16;
            uint32_t ah[4][4], al[4][4], bh[4][2], bl[4][2];
#pragma unroll
            for (int mi = 0; mi < 4; mi++) {
                int rm = wm * 64 + mi * 16 + group;
                const float* r0 = as + rm * 36 + kb + 2 * tg;
                const float* r1 = as + (rm + 8) * 36 + kb + 2 * tg;
                float x0 = r0[0], x1 = r0[1], x2 = r1[0], x3 = r1[1];
                float x4 = r0[8], x5 = r0[9], x6 = r1[8], x7 = r1[9];
                if (AMODE == 1) {
                    x0 *= av0[mi]; x1 *= av0[mi]; x4 *= av0[mi]; x5 *= av0[mi];
                    x2 *= av1[mi]; x3 *= av1[mi]; x6 *= av1[mi]; x7 *= av1[mi];
                }
                ah[mi][0] = packbf(x0, x1);
                ah[mi][1] = packbf(x2, x3);
                ah[mi][2] = packbf(x4, x5);
                ah[mi][3] = packbf(x6, x7);
                if (ASPLIT) {
                    al[mi][0] = packbf_res(x0, x1, ah[mi][0]);
                    al[mi][1] = packbf_res(x2, x3, ah[mi][1]);
                    al[mi][2] = packbf_res(x4, x5, ah[mi][2]);
                    al[mi][3] = packbf_res(x6, x7, ah[mi][3]);
                }
            }
#pragma unroll
            for (int ni = 0; ni < 4; ni++) {
                int cn = wn * 32 + ni * 8 + group;
                float b0a, b0b, b1a, b1b;
                if (XXT) {
                    const float* rb = bs + cn * 36 + kb + 2 * tg;
                    b0a = rb[0]; b0b = rb[1]; b1a = rb[8]; b1b = rb[9];
                } else {
                    b0a = bs[(kb + 2 * tg) * 136 + cn];
                    b0b = bs[(kb + 2 * tg + 1) * 136 + cn];
                    b1a = bs[(kb + 8 + 2 * tg) * 136 + cn];
                    b1b = bs[(kb + 9 + 2 * tg) * 136 + cn];
                    if (DSCALE) {
                        b0a *= dv[kb + 2 * tg];
                        b0b *= dv[kb + 2 * tg + 1];
                        b1a *= dv[kb + 8 + 2 * tg];
                        b1b *= dv[kb + 9 + 2 * tg];
                    }
                }
                bh[ni][0] = packbf(b0a, b0b);
                bh[ni][1] = packbf(b1a, b1b);
                bl[ni][0] = packbf_res(b0a, b0b, bh[ni][0]);
                bl[ni][1] = packbf_res(b1a, b1b, bh[ni][1]);
            }
#pragma unroll
            for (int mi = 0; mi < 4; mi++)
#pragma unroll
                for (int ni = 0; ni < 4; ni++) {
                    MMA_BF16(c[mi][ni], ah[mi], bh[ni]);
                    MMA_BF16(c[mi][ni], ah[mi], bl[ni]);
                    if (ASPLIT) MMA_BF16(c[mi][ni], al[mi], bh[ni]);
                }
        }
        __syncthreads();
        s ^= 1;
    }

#pragma unroll
    for (int mi = 0; mi < 4; mi++) {
        int row0 = bm + wm * 64 + mi * 16 + group;
#pragma unroll
        for (int ni = 0; ni < 4; ni++) {
            int col = bn + wn * 32 + ni * 8 + tg * 2;
            *(float2*)(C + (size_t)row0 * ldc + col)       = make_float2(c[mi][ni][0], c[mi][ni][1]);
            *(float2*)(C + (size_t)(row0 + 8) * ldc + col) = make_float2(c[mi][ni][2], c[mi][ni][3]);
        }
    }
}

// ---------------- generic SGEMM (small K paths), zero-pads cols [N, npad) ------------
__global__ void __launch_bounds__(256) gemm64(
    const float* __restrict__ A, const float* __restrict__ B, float* __restrict__ C,
    int M, int N, int K, int lda, int ldb, int ldc, int npad)
{
    __shared__ float As[16][65];
    __shared__ float Bs[16][64];
    int tid = threadIdx.x, tx = tid & 15, ty = tid >> 4;
    int bm = blockIdx.y * 64, bn = blockIdx.x * 64;
    float acc[4][4];
#pragma unroll
    for (int i = 0; i < 4; i++)
#pragma unroll
        for (int j = 0; j < 4; j++) acc[i][j] = 0.f;

    for (int k0 = 0; k0 < K; k0 += 16) {
        for (int t = tid; t < 64 * 16; t += 256) {
            int r = t >> 4, c = t & 15;
            int gr = bm + r, gc = k0 + c;
            As[c][r] = (gr < M && gc < K) ? A[(size_t)gr * lda + gc] : 0.f;
        }
        for (int t = tid; t < 16 * 64; t += 256) {
            int r = t >> 6, c = t & 63;
            int gr = k0 + r, gc = bn + c;
            Bs[r][c] = (gr < K && gc < N) ? B[(size_t)gr * ldb + gc] : 0.f;
        }
        __syncthreads();
#pragma unroll
        for (int kk = 0; kk < 16; kk++) {
            float a[4], b[4];
#pragma unroll
            for (int i = 0; i < 4; i++) a[i] = As[kk][ty * 4 + i];
#pragma unroll
            for (int j = 0; j < 4; j++) b[j] = Bs[kk][tx * 4 + j];
#pragma unroll
            for (int i = 0; i < 4; i++)
#pragma unroll
                for (int j = 0; j < 4; j++) acc[i][j] += a[i] * b[j];
        }
        __syncthreads();
    }
#pragma unroll
    for (int i = 0; i < 4; i++)
#pragma unroll
        for (int j = 0; j < 4; j++) {
            int gr = bm + ty * 4 + i, gc = bn + tx * 4 + j;
            if (gr < M && gc < npad) C[(size_t)gr * ldc + gc] = (gc < N) ? acc[i][j] : 0.f;
        }
}

// ---------------- small helper kernels ----------------
__global__ void pad_w5(const float* __restrict__ a, const float* __restrict__ b,
                       const float* __restrict__ c, const float* __restrict__ d,
                       const float* __restrict__ e, float* __restrict__ out)
{
    int idx = blockIdx.x * 256 + threadIdx.x;
    if (idx >= 5 * HP * HP) return;
    int w = idx / (HP * HP), r = idx - w * (HP * HP);
    int i = r >> 8, j = r & 255;
    const float* W = (w == 0) ? a : (w == 1) ? b : (w == 2) ? c : (w == 3) ? d : e;
    out[idx] = (i < H && j < H) ? W[i * H + j] : 0.f;
}

__global__ void f32tobf16(const float* __restrict__ in, __nv_bfloat16* __restrict__ out,
                          size_t n4)
{
    size_t i = (size_t)blockIdx.x * 256 + threadIdx.x;
    if (i >= n4) return;
    float4 v = *(const float4*)(in + i * 4);
    __nv_bfloat162 a = __floats2bfloat162_rn(v.x, v.y);
    __nv_bfloat162 b = __floats2bfloat162_rn(v.z, v.w);
    *(__nv_bfloat162*)(out + i * 4)     = a;
    *(__nv_bfloat162*)(out + i * 4 + 2) = b;
}

__global__ void rowgather_f32(const float* __restrict__ A, int n,
                              const int* __restrict__ perm,
                              float* __restrict__ out, int krows)
{
    size_t idx = (size_t)blockIdx.x * 256 + threadIdx.x;
    size_t n4 = (size_t)n / 4;
    if (idx >= (size_t)krows * n4) return;
    int i = (int)(idx / n4);
    int j4 = (int)(idx - (size_t)i * n4);
    float4 v = *(const float4*)(A + (size_t)perm[i] * n + j4 * 4);
    *(float4*)(out + (size_t)i * n + j4 * 4) = v;
}

__global__ void rowsum_dinv(const float* __restrict__ A, float* __restrict__ dinv, int n)
{
    int row = blockIdx.x;
    const float* Ar = A + (size_t)row * n;
    float s = 0.f;
    for (int j = threadIdx.x; j < n; j += 256) s += Ar[j];
    for (int o = 16; o > 0; o >>= 1) s += __shfl_down_sync(0xffffffffu, s, o);
    __shared__ float red[8];
    int w = threadIdx.x >> 5, l = threadIdx.x & 31;
    if (l == 0) red[w] = s;
    __syncthreads();
    if (threadIdx.x == 0) {
        float t = 0.f;
        for (int i = 0; i < 8; i++) t += red[i];
        dinv[row] = 1.0f / sqrtf(t + 2.0f);
    }
}

__global__ void rowsum_dinv_bf(const __nv_bfloat16* __restrict__ A, float* __restrict__ dinv, int n)
{
    int row = blockIdx.x;
    const __nv_bfloat16* Ar = A + (size_t)row * n;
    float s = 0.f;
    for (int j = threadIdx.x * 2; j < n; j += 512) {
        __nv_bfloat162 v = *(const __nv_bfloat162*)(Ar + j);
        s += __bfloat162float(v.x) + __bfloat162float(v.y);
    }
    for (int o = 16; o > 0; o >>= 1) s += __shfl_down_sync(0xffffffffu, s, o);
    __shared__ float red[8];
    int w = threadIdx.x >> 5, l = threadIdx.x & 31;
    if (l == 0) red[w] = s;
    __syncthreads();
    if (threadIdx.x == 0) {
        float t = 0.f;
        for (int i = 0; i < 8; i++) t += red[i];
        dinv[row] = 1.0f / sqrtf(t + 2.0f);
    }
}

__global__ void scale_rows(const float* __restrict__ in, const float* __restrict__ dinv,
                           float* __restrict__ out, int n, int w, int ld)
{
    int idx = blockIdx.x * 256 + threadIdx.x;
    if (idx >= n * ld) return;
    int r = idx / ld, c = idx - r * ld;
    out[idx] = (c < w) ? dinv[r] * in[idx] : 0.f;
}

__global__ void gcn_finish_sk(const float* __restrict__ part, const float* __restrict__ Z,
                              const float* __restrict__ dinv, const float* __restrict__ b,
                              float* __restrict__ out, int n, int relu, int S)
{
    int idx = blockIdx.x * 256 + threadIdx.x;
    if (idx >= n * HP) return;
    int r = idx >> 8, c = idx & 255;
    float v = 0.f;
    if (c < H) {
        float az = 0.f;
        size_t stride = (size_t)n * HP;
        for (int s = 0; s < S; s++) az += part[s * stride + idx];
        float dr = dinv[r];
        v = dr * (az + 2.f * (dr * Z[idx])) + b[c];
        if (relu) v = fmaxf(v, 0.f);
    }
    out[idx] = v;
}

__global__ void score_kernel(const float* __restrict__ x, const float* __restrict__ p,
                             float* __restrict__ score, int n)
{
    int row = blockIdx.x * 8 + (threadIdx.x >> 5);
    int lane = threadIdx.x & 31;
    if (row >= n) return;
    const float* xr = x + (size_t)row * HP;
    float s = 0.f, pp = 0.f;
    for (int c = lane; c < H; c += 32) {
        float pv = p[c];
        s += xr[c] * pv;
        pp += pv * pv;
    }
    for (int o = 16; o > 0; o >>= 1) {
        s  += __shfl_down_sync(0xffffffffu, s, o);
        pp += __shfl_down_sync(0xffffffffu, pp, o);
    }
    if (lane == 0) score[row] = tanhf(s / sqrtf(pp));
}

template <int SIZE>
__global__ void topk_kernel(const float* __restrict__ score, int n, int k,
                            int* __restrict__ perm, float* __restrict__ val,
                            int* __restrict__ iperm)
{
    __shared__ unsigned long long key[SIZE];
    int tid = threadIdx.x;
    for (int i = tid; i < SIZE; i += 1024) {
        float s = (i < n) ? score[i] : -INFINITY;
        uint32_t u = __float_as_uint(s);
        u = (u & 0x80000000u) ? ~u : (u | 0x80000000u);
        uint32_t d = ~u;
        key[i] = ((unsigned long long)d << 32) | (uint32_t)i;
        if (i < n) iperm[i] = -1;
    }
    __syncthreads();
    for (int size = 2; size <= SIZE; size <<= 1) {
        for (int stride = size >> 1; stride > 0; stride >>= 1) {
            for (int i = tid; i < SIZE; i += 1024) {
                int j = i ^ stride;
                if (j > i) {
                    unsigned long long a = key[i], b = key[j];
                    bool up = ((i & size) == 0);
                    if (up ? (a > b) : (a < b)) { key[i] = b; key[j] = a; }
                }
            }
            __syncthreads();
        }
    }
    for (int i = tid; i < k; i += 1024) {
        int si = (int)(uint32_t)key[i];
        perm[i] = si;
        val[i] = score[si];
        iperm[si] = i;
    }
}

// level 1: out bf16 (exact small ints); Src = adjB, indexed via perm on both sides
__global__ void pool_A_tri_bf(const float* __restrict__ C, const __nv_bfloat16* __restrict__ Src,
                              int K, const int* __restrict__ perm,
                              __nv_bfloat16* __restrict__ Aout, int k)
{
    int idx = blockIdx.x * 256 + threadIdx.x;
    if (idx >= k * k) return;
    int i = idx / k, j = idx - i * k;
    if (i == j) { Aout[idx] = __float2bfloat16(0.f); return; }
    int hi = i > j ? i : j, lo = i > j ? j : i;
    float g = C[(size_t)hi * k + lo];
    float a = __bfloat162float(Src[(size_t)__ldg(&perm[i]) * K + __ldg(&perm[j])]);
    Aout[idx] = __float2bfloat16(g + 2.f * a);
}

// level 2: out fp32; Src = A1B via perm both sides
__global__ void pool_A_tri(const float* __restrict__ C, const __nv_bfloat16* __restrict__ Src,
                           int K, const int* __restrict__ perm,
                           float* __restrict__ Aout, int k)
{
    int idx = blockIdx.x * 256 + threadIdx.x;
    if (idx >= k * k) return;
    int i = idx / k, j = idx - i * k;
    if (i == j) { Aout[idx] = 0.f; return; }
    int hi = i > j ? i : j, lo = i > j ? j : i;
    float g = C[(size_t)hi * k + lo];
    float a = __bfloat162float(Src[(size_t)__ldg(&perm[i]) * K + __ldg(&perm[j])]);
    Aout[idx] = g + 2.f * a;
}

__global__ void pool_A_tri_f32(const float* __restrict__ C, const float* __restrict__ Rows,
                               int K, const int* __restrict__ perm,
                               float* __restrict__ Aout, int k)
{
    int idx = blockIdx.x * 256 + threadIdx.x;
    if (idx >= k * k) return;
    int i = idx / k, j = idx - i * k;
    if (i == j) { Aout[idx] = 0.f; return; }
    int hi = i > j ? i : j, lo = i > j ? j : i;
    Aout[idx] = C[(size_t)hi * k + lo] + 2.f * Rows[(size_t)i * K + __ldg(&perm[j])];
}

__global__ void fuse_up(const float* __restrict__ Xj, const float* __restrict__ Xn,
                        const int* __restrict__ iperm, float* __restrict__ out, int n)
{
    int idx = blockIdx.x * 256 + threadIdx.x;
    if (idx >= n * HP) return;
    int r = idx >> 8, c = idx & 255;
    int p = iperm[r];
    float v = Xj[idx];
    if (p >= 0) v += Xn[p * HP + c];
    out[idx] = v;
}

__global__ void gemm_n2(const float* __restrict__ A, const float* __restrict__ Z,
                        float* __restrict__ out, int n)
{
    int row = blockIdx.x;
    const float* Ar = A + (size_t)row * n;
    float a0 = 0.f, a1 = 0.f;
    for (int j = threadIdx.x; j < n; j += 256) {
        float a = Ar[j];
        a0 += a * Z[2 * j];
        a1 += a * Z[2 * j + 1];
    }
    for (int o = 16; o > 0; o >>= 1) {
        a0 += __shfl_down_sync(0xffffffffu, a0, o);
        a1 += __shfl_down_sync(0xffffffffu, a1, o);
    }
    __shared__ float r0[8], r1[8];
    int w = threadIdx.x >> 5, l = threadIdx.x & 31;
    if (l == 0) { r0[w] = a0; r1[w] = a1; }
    __syncthreads();
    if (threadIdx.x == 0) {
        float s0 = 0.f, s1 = 0.f;
        for (int i = 0; i < 8; i++) { s0 += r0[i]; s1 += r1[i]; }
        out[2 * row] = s0;
        out[2 * row + 1] = s1;
    }
}

__global__ void final_kernel(const float* __restrict__ AZ, const float* __restrict__ Z,
                             const float* __restrict__ dinv, const float* __restrict__ b,
                             float* __restrict__ out, int n)
{
    int i = blockIdx.x * 256 + threadIdx.x;
    if (i >= n) return;
    float a = dinv[i] * (AZ[2 * i]     + 2.f * Z[2 * i])     + b[0];
    float c = dinv[i] * (AZ[2 * i + 1] + 2.f * Z[2 * i + 1]) + b[1];
    float m = fmaxf(a, c);
    float l = m + logf(expf(a - m) + expf(c - m));
    out[2 * i] = a - l;
    out[2 * i + 1] = c - l;
}

// ---------------- host orchestration ----------------
template <typename T, size_t NN>
static T* symaddr(T (&sym)[NN]) {
    void* p = nullptr;
    cudaGetSymbolAddress(&p, sym);
    return (T*)p;
}

#define SMEM_BF 73984
#define SMEM_BA 55552

extern "C" void kernel_launch(void* const* d_in, const int* in_sizes, int n_in,
                              void* d_out, int out_size)
{
    (void)in_sizes; (void)n_in; (void)out_size;
    const float* x   = (const float*)d_in[0];
    const float* adj = (const float*)d_in[1];
    const float* w0  = (const float*)d_in[2];
    const float* b0  = (const float*)d_in[3];
    const float* w1  = (const float*)d_in[4];
    const float* b1  = (const float*)d_in[5];
    const float* w2  = (const float*)d_in[6];
    const float* b2  = (const float*)d_in[7];
    const float* w3  = (const float*)d_in[8];
    const float* b3  = (const float*)d_in[9];
    const float* p1  = (const float*)d_in[10];
    const float* p2  = (const float*)d_in[11];
    const float* p3  = (const float*)d_in[12];
    const float* u0w = (const float*)d_in[13];
    const float* u0b = (const float*)d_in[14];
    const float* u1w = (const float*)d_in[15];
    const float* u1b = (const float*)d_in[16];
    const float* u2w = (const float*)d_in[17];
    const float* u2b = (const float*)d_in[18];

    static cudaStream_t sA = nullptr;
    static cudaEvent_t evF = nullptr, evA = nullptr, evB = nullptr;
    static bool init_done = false;
    if (!init_done) {
        cudaFuncSetAttribute(bf16gA, cudaFuncAttributeMaxDynamicSharedMemorySize, SMEM_BA);
        cudaFuncSetAttribute(bf16g<1, 0, 1, 0>, cudaFuncAttributeMaxDynamicSharedMemorySize, SMEM_BF);
        cudaFuncSetAttribute(bf16g<1, 0, 0, 0>, cudaFuncAttributeMaxDynamicSharedMemorySize, SMEM_BF);
        cudaFuncSetAttribute(bf16g<1, 0, 0, 1>, cudaFuncAttributeMaxDynamicSharedMemorySize, SMEM_BF);
        cudaFuncSetAttribute(bf16g<1, 1, 0, 0>, cudaFuncAttributeMaxDynamicSharedMemorySize, SMEM_BF);
        cudaStreamCreateWithFlags(&sA, cudaStreamNonBlocking);
        cudaEventCreateWithFlags(&evF, cudaEventDisableTiming);
        cudaEventCreateWithFlags(&evA, cudaEventDisableTiming);
        cudaEventCreateWithFlags(&evB, cudaEventDisableTiming);
        init_done = true;
    }

    float* G    = symaddr(g_G);
    __nv_bfloat16* ADJB = symaddr(g_adjb);
    __nv_bfloat16* A1B  = symaddr(g_A1b);
    float* A2   = symaddr(g_A2);
    float* A3   = symaddr(g_A3);
    float* X0   = symaddr(g_x0);
    float* X1   = symaddr(g_x1);
    float* X2   = symaddr(g_x2);
    float* X3   = symaddr(g_x3);
    float* T0   = symaddr(g_t0);
    float* T1   = symaddr(g_t1);
    float* PART = symaddr(g_part);
    float* CUR  = symaddr(g_cur);
    float* WP   = symaddr(g_wpad);
    float* D0   = symaddr(g_d0);
    float* D1   = symaddr(g_d1);
    float* D2   = symaddr(g_d2);
    float* D3   = symaddr(g_d3);
    float* SC   = symaddr(g_score);
    float* VAL  = symaddr(g_val);
    int*   P0   = symaddr(g_perm0);
    int*   P1   = symaddr(g_perm1);
    int*   P2   = symaddr(g_perm2);
    int*   IP0  = symaddr(g_ip0);
    int*   IP1  = symaddr(g_ip1);
    int*   IP2  = symaddr(g_ip2);

    float* WP_w1  = WP + 0 * HP * HP;
    float* WP_w2  = WP + 1 * HP * HP;
    float* WP_w3  = WP + 2 * HP * HP;
    float* WP_u0w = WP + 3 * HP * HP;
    float* WP_u1w = WP + 4 * HP * HP;

    // ---- fork side stream into capture, then adj->bf16 there ----
    cudaEventRecord(evF, 0);
    cudaStreamWaitEvent(sA, evF, 0);
    {
        size_t n4 = ((size_t)N0 * N0) / 4;
        f32tobf16<<<(unsigned)((n4 + 255) / 256), 256, 0, sA>>>(adj, ADJB, n4);
        cudaEventRecord(evB, sA);
    }
    pad_w5<<<(5 * HP * HP + 255) / 256, 256>>>(w1, w2, w3, u0w, u1w, WP);
    rowsum_dinv<<<N0, 256>>>(adj, D0, N0);

    // ---- gcn0 ----
    {
        dim3 g1((H + 63) / 64, (N0 + 63) / 64);
        gemm64<<<g1, 256>>>(x, w0, T0, N0, H, 3, 3, H, HP, HP);
        cudaStreamWaitEvent(0, evB, 0);
        dim3 g2(HP / 128, N0 / 128, 4);
        bf16gA<<<g2, 256, SMEM_BA>>>(ADJB, T0, PART, N0, HP, N0, N0, HP, HP, D0);
        gcn_finish_sk<<<(N0 * HP + 255) / 256, 256>>>(PART, T0, D0, b0, X0, N0, 1, 4);
    }

    // ==== pool 1 (4096 -> 3072) ====
    score_kernel<<<(N0 + 7) / 8, 256>>>(X0, p1, SC, N0);
    topk_kernel<4096><<<1, 1024>>>(SC, N0, KP1, P0, VAL, IP0);
    cudaEventRecord(evF, 0);
    cudaStreamWaitEvent(sA, evF, 0);
    {
        dim3 g(KP1 / 128, KP1 / 128);
        bf16gemm_xxt<<<g, 256, 0, sA>>>(ADJB, G, KP1, N0, P0);          // gather fused
        pool_A_tri_bf<<<(KP1 * KP1 + 255) / 256, 256, 0, sA>>>(G, ADJB, N0, P0, A1B, KP1);
        rowsum_dinv_bf<<<KP1, 256, 0, sA>>>(A1B, D1, KP1);
    }
    cudaEventRecord(evA, sA);
    {
        dim3 gw(HP / 128, KP1 / 128, 1);                                 // pool_x fused
        bf16g<1, 0, 0, 1><<<gw, 256, SMEM_BF>>>(X0, WP_w1, T0, KP1, HP, HP, HP, HP, HP,
                                                nullptr, P0, VAL);
    }
    cudaStreamWaitEvent(0, evA, 0);
    {
        dim3 g2(HP / 128, KP1 / 128, 6);
        bf16gA<<<g2, 256, SMEM_BA>>>(A1B, T0, PART, KP1, HP, KP1, KP1, HP, HP, D1);
        gcn_finish_sk<<<(KP1 * HP + 255) / 256, 256>>>(PART, T0, D1, b1, X1, KP1, 1, 6);
    }

    // ==== pool 2 (3072 -> 1536) ====
    score_kernel<<<(KP1 + 7) / 8, 256>>>(X1, p2, SC, KP1);
    topk_kernel<4096><<<1, 1024>>>(SC, KP1, KP2, P1, VAL, IP1);
    cudaEventRecord(evF, 0);
    cudaStreamWaitEvent(sA, evF, 0);
    {
        dim3 g(KP2 / 128, KP2 / 128);
        bf16gemm_xxt<<<g, 256, 0, sA>>>(A1B, G, KP2, KP1, P1);          // gather fused
        pool_A_tri<<<(KP2 * KP2 + 255) / 256, 256, 0, sA>>>(G, A1B, KP1, P1, A2, KP2);
        rowsum_dinv<<<KP2, 256, 0, sA>>>(A2, D2, KP2);
    }
    cudaEventRecord(evA, sA);
    {
        dim3 gw(HP / 128, KP2 / 128, 1);
        bf16g<1, 0, 0, 1><<<gw, 256, SMEM_BF>>>(X1, WP_w2, T0, KP2, HP, HP, HP, HP, HP,
                                                nullptr, P1, VAL);
    }
    cudaStreamWaitEvent(0, evA, 0);
    {
        dim3 g2(HP / 128, KP2 / 128, 6);
        bf16g<1, 0, 1, 0><<<g2, 256, SMEM_BF>>>(A2, T0, PART, KP2, HP, KP2, KP2, HP, HP,
                                                D2, nullptr, nullptr);
        gcn_finish_sk<<<(KP2 * HP + 255) / 256, 256>>>(PART, T0, D2, b2, X2, KP2, 1, 6);
    }

    // ==== pool 3 (1536 -> 768) ====
    score_kernel<<<(KP2 + 7) / 8, 256>>>(X2, p3, SC, KP2);
    topk_kernel<2048><<<1, 1024>>>(SC, KP2, KP3, P2, VAL, IP2);
    cudaEventRecord(evF, 0);
    cudaStreamWaitEvent(sA, evF, 0);
    {
        size_t tot = (size_t)KP3 * (KP2 / 4);
        rowgather_f32<<<(unsigned)((tot + 255) / 256), 256, 0, sA>>>(A2, KP2, P2, PART, KP3);
        dim3 g(KP3 / 128, KP3 / 128, 1);
        bf16g<1, 1, 0, 0><<<g, 256, SMEM_BF, sA>>>(PART, PART, G, KP3, KP3, KP2, KP2, KP2, KP3,
                                                   nullptr, nullptr, nullptr);
        pool_A_tri_f32<<<(KP3 * KP3 + 255) / 256, 256, 0, sA>>>(G, PART, KP2, P2, A3, KP3);
        rowsum_dinv<<<KP3, 256, 0, sA>>>(A3, D3, KP3);
    }
    cudaEventRecord(evA, sA);
    {
        dim3 gw(HP / 128, KP3 / 128, 1);
        bf16g<1, 0, 0, 1><<<gw, 256, SMEM_BF>>>(X2, WP_w3, T0, KP3, HP, HP, HP, HP, HP,
                                                nullptr, P2, VAL);
    }
    cudaStreamWaitEvent(0, evA, 0);
    {
        dim3 g2(HP / 128, KP3 / 128, 12);
        bf16g<1, 0, 1, 0><<<g2, 256, SMEM_BF>>>(A3, T0, PART, KP3, HP, KP3, KP3, HP, HP,
                                                D3, nullptr, nullptr);
        gcn_finish_sk<<<(KP3 * HP + 255) / 256, 256>>>(PART, T0, D3, b3, X3, KP3, 1, 12);
    }

    // ==== up 0 ====
    fuse_up<<<(KP2 * HP + 255) / 256, 256>>>(X2, X3, IP2, CUR, KP2);
    {
        dim3 gw(HP / 128, KP2 / 128, 1);
        bf16g<1, 0, 0, 0><<<gw, 256, SMEM_BF>>>(CUR, WP_u0w, T0, KP2, HP, HP, HP, HP, HP,
                                                nullptr, nullptr, nullptr);
        dim3 g2(HP / 128, KP2 / 128, 6);
        bf16g<1, 0, 1, 0><<<g2, 256, SMEM_BF>>>(A2, T0, PART, KP2, HP, KP2, KP2, HP, HP,
                                                D2, nullptr, nullptr);
        gcn_finish_sk<<<(KP2 * HP + 255) / 256, 256>>>(PART, T0, D2, u0b, X2, KP2, 1, 6);
    }

    // ==== up 1 ====
    fuse_up<<<(KP1 * HP + 255) / 256, 256>>>(X1, X2, IP1, CUR, KP1);
    {
        dim3 gw(HP / 128, KP1 / 128, 1);
        bf16g<1, 0, 0, 0><<<gw, 256, SMEM_BF>>>(CUR, WP_u1w, T0, KP1, HP, HP, HP, HP, HP,
                                                nullptr, nullptr, nullptr);
        dim3 g2(HP / 128, KP1 / 128, 6);
        bf16gA<<<g2, 256, SMEM_BA>>>(A1B, T0, PART, KP1, HP, KP1, KP1, HP, HP, D1);
        gcn_finish_sk<<<(KP1 * HP + 255) / 256, 256>>>(PART, T0, D1, u1b, X1, KP1, 1, 6);
    }

    // ==== up 2: final gcn (H->2) + log_softmax ====
    fuse_up<<<(N0 * HP + 255) / 256, 256>>>(X0, X1, IP0, CUR, N0);
    {
        dim3 gf(1, (N0 + 63) / 64);
        gemm64<<<gf, 256>>>(CUR, u2w, T0, N0, 2, H, HP, 2, 2, 2);
        scale_rows<<<(N0 * 2 + 255) / 256, 256>>>(T0, D0, T1, N0, 2, 2);
        gemm_n2<<<N0, 256>>>(adj, T1, T0, N0);
        final_kernel<<<(N0 + 255) / 256, 256>>>(T0, T1, D0, u2b, (float*)d_out, N0);
    }
}